// round 1
// baseline (speedup 1.0000x reference)
#include <cuda_runtime.h>
#include <math.h>
#include <stdint.h>

// ---------------- constants ----------------
#define Bn   8
#define Dm_  512
#define FFNn 2048
#define Ln   8
#define OUTn 1024
#define Hn   8
#define DHn  64
#define QN   336
#define KN   335
#define SN   320          // rc(64) + utt(256) state rows (tokens)
#define RTn  64
#define Un   256
#define NSEG 16
#define NEGV (-1e8f)

// arena offsets (in floats)
#define SZ_X    (8320UL*128UL)          // input-proj output (8,1040,128)
#define SZ_S    ((size_t)SN*Bn*Dm_)     // state: rc+utt
#define SZ_MEMS (15UL*Bn*Dm_)
#define SZ_QIN  ((size_t)QN*Bn*Dm_)
#define SZ_KIN  ((size_t)KN*Bn*Dm_)
#define SZ_TOK  ((size_t)QN*Bn*Dm_)
#define SZ_F    ((size_t)SN*Bn*FFNn)
#define SZ_YT   (2048UL*512UL)
#define SZ_Y    (2048UL*1024UL)

#define OFF_X    0UL
#define OFF_S    (OFF_X + SZ_X)
#define OFF_MEMS (OFF_S + SZ_S)
#define OFF_QIN  (OFF_MEMS + SZ_MEMS)
#define OFF_KIN  (OFF_QIN + SZ_QIN)
#define OFF_Q    (OFF_KIN + SZ_KIN)
#define OFF_K    (OFF_Q + SZ_TOK)
#define OFF_V    (OFF_K + SZ_KIN)
#define OFF_ATT  (OFF_V + SZ_KIN)
#define OFF_O    (OFF_ATT + SZ_TOK)
#define OFF_H    (OFF_O + SZ_TOK)
#define OFF_F    (OFF_H + SZ_S)
#define OFF_H2   (OFF_F + SZ_F)
#define OFF_YT   (OFF_H2 + SZ_S)
#define OFF_Y    (OFF_YT + SZ_YT)
#define ARENA_TOTAL (OFF_Y + SZ_Y)

__device__ float g_arena[ARENA_TOTAL];

// ---------------- generic SGEMM: C = act(A @ W + bias) ----------------
// A: (M,K) row-major, W: (K,N) row-major, N % 128 == 0, K % 8 == 0.
__global__ __launch_bounds__(256) void gemm_k(
    const float* __restrict__ A, const float* __restrict__ Wm,
    const float* __restrict__ bias, float* __restrict__ C,
    int M, int N, int K, int act)
{
    __shared__ __align__(16) float As[8][128];
    __shared__ __align__(16) float Bs[8][128];
    const int tid  = threadIdx.x;
    const int tx   = tid & 15, ty = tid >> 4;
    const int row0 = blockIdx.y * 128, col0 = blockIdx.x * 128;
    const int aRow = tid >> 1, aCol = (tid & 1) << 2;
    const int bRow = tid >> 5, bCol = (tid & 31) << 2;

    float acc[8][8];
#pragma unroll
    for (int i = 0; i < 8; i++)
#pragma unroll
        for (int j = 0; j < 8; j++) acc[i][j] = 0.f;

    for (int k0 = 0; k0 < K; k0 += 8) {
        float4 av = make_float4(0.f, 0.f, 0.f, 0.f);
        if (row0 + aRow < M)
            av = *reinterpret_cast<const float4*>(&A[(size_t)(row0 + aRow) * K + k0 + aCol]);
        As[aCol + 0][aRow] = av.x; As[aCol + 1][aRow] = av.y;
        As[aCol + 2][aRow] = av.z; As[aCol + 3][aRow] = av.w;
        *reinterpret_cast<float4*>(&Bs[bRow][bCol]) =
            *reinterpret_cast<const float4*>(&Wm[(size_t)(k0 + bRow) * N + col0 + bCol]);
        __syncthreads();
#pragma unroll
        for (int kk = 0; kk < 8; kk++) {
            float a[8], w[8];
            float4 t0 = *reinterpret_cast<const float4*>(&As[kk][ty * 8]);
            float4 t1 = *reinterpret_cast<const float4*>(&As[kk][ty * 8 + 4]);
            a[0]=t0.x; a[1]=t0.y; a[2]=t0.z; a[3]=t0.w;
            a[4]=t1.x; a[5]=t1.y; a[6]=t1.z; a[7]=t1.w;
            float4 u0 = *reinterpret_cast<const float4*>(&Bs[kk][tx * 8]);
            float4 u1 = *reinterpret_cast<const float4*>(&Bs[kk][tx * 8 + 4]);
            w[0]=u0.x; w[1]=u0.y; w[2]=u0.z; w[3]=u0.w;
            w[4]=u1.x; w[5]=u1.y; w[6]=u1.z; w[7]=u1.w;
#pragma unroll
            for (int i = 0; i < 8; i++)
#pragma unroll
                for (int j = 0; j < 8; j++)
                    acc[i][j] = fmaf(a[i], w[j], acc[i][j]);
        }
        __syncthreads();
    }
#pragma unroll
    for (int i = 0; i < 8; i++) {
        int r = row0 + ty * 8 + i;
        if (r < M) {
#pragma unroll
            for (int j = 0; j < 8; j++) {
                int c = col0 + tx * 8 + j;
                float v = acc[i][j] + (bias ? bias[c] : 0.f);
                if (act == 1) v = fmaxf(v, 0.f);
                C[(size_t)r * N + c] = v;
            }
        }
    }
}

// ---------------- block reduce (sum, sumsq) ----------------
__device__ inline void blockReduce2(float& s, float& s2) {
    __shared__ float sh[2][32];
    int lane = threadIdx.x & 31, wid = threadIdx.x >> 5;
#pragma unroll
    for (int o = 16; o; o >>= 1) {
        s  += __shfl_xor_sync(~0u, s, o);
        s2 += __shfl_xor_sync(~0u, s2, o);
    }
    if (lane == 0) { sh[0][wid] = s; sh[1][wid] = s2; }
    __syncthreads();
    int nw = (blockDim.x + 31) >> 5;
    if (wid == 0) {
        s  = (lane < nw) ? sh[0][lane] : 0.f;
        s2 = (lane < nw) ? sh[1][lane] : 0.f;
#pragma unroll
        for (int o = 16; o; o >>= 1) {
            s  += __shfl_xor_sync(~0u, s, o);
            s2 += __shfl_xor_sync(~0u, s2, o);
        }
        if (lane == 0) { sh[0][0] = s; sh[1][0] = s2; }
    }
    __syncthreads();
    s = sh[0][0]; s2 = sh[1][0];
}

// ---------------- LayerNorm (optional residual input X2, optional dual out) ----
__global__ __launch_bounds__(256) void ln_k(
    const float* __restrict__ X, const float* __restrict__ X2,
    const float* __restrict__ g, const float* __restrict__ bta,
    float* __restrict__ out1, float* __restrict__ out2, int Dm)
{
    const int row = blockIdx.x;
    const float* x  = X + (size_t)row * Dm;
    const float* x2 = X2 ? X2 + (size_t)row * Dm : nullptr;
    float s = 0.f, s2 = 0.f;
    for (int i = threadIdx.x; i < Dm; i += blockDim.x) {
        float v = x[i] + (x2 ? x2[i] : 0.f);
        s += v; s2 += v * v;
    }
    blockReduce2(s, s2);
    float mean = s / Dm;
    float inv = rsqrtf(s2 / Dm - mean * mean + 1e-5f);
    for (int i = threadIdx.x; i < Dm; i += blockDim.x) {
        float v = x[i] + (x2 ? x2[i] : 0.f);
        float o = (v - mean) * inv * g[i] + bta[i];
        out1[(size_t)row * Dm + i] = o;
        if (out2) out2[(size_t)row * Dm + i] = o;
    }
}

// ---------------- state init from input-proj frames ----------------
// X frames: X[b*133120 + frame*512 + d]; S rows: rc(0..63) then utt(64..319)
__global__ void initS_k(const float* __restrict__ X, float* __restrict__ S)
{
    const int t = blockIdx.x, b = blockIdx.y, d = threadIdx.x;
    int frame;
    if (t < RTn) {
        int si = t >> 2;
        int st = (si == 15) ? 256 : (si + 1) * 16;
        frame = st + (t & 3);
    } else {
        frame = t - RTn;
    }
    S[((size_t)t * Bn + b) * Dm_ + d] = X[(size_t)b * 133120 + (size_t)frame * Dm_ + d];
}

// mems0[s,b,d] = mean_{k<16} utt[s*16+k, b, d]  (utt = S rows 64..)
__global__ void mems0_k(const float* __restrict__ S, float* __restrict__ M)
{
    const int s = blockIdx.x, b = blockIdx.y, d = threadIdx.x;
    size_t base = ((size_t)(RTn + s * 16) * Bn + b) * Dm_ + d;
    float acc = 0.f;
#pragma unroll
    for (int k = 0; k < 16; k++) acc += S[base + (size_t)k * Bn * Dm_];
    M[((size_t)s * Bn + b) * Dm_ + d] = acc * (1.f / 16.f);
}

// summary rows of qin: qin[320+s] = mean_{k<16} qin[64+s*16+k]
__global__ void summary_k(float* __restrict__ qin)
{
    const int s = blockIdx.x, b = blockIdx.y, d = threadIdx.x;
    size_t base = ((size_t)(RTn + s * 16) * Bn + b) * Dm_ + d;
    float acc = 0.f;
#pragma unroll
    for (int k = 0; k < 16; k++) acc += qin[base + (size_t)k * Bn * Dm_];
    qin[((size_t)(SN + s) * Bn + b) * Dm_ + d] = acc * (1.f / 16.f);
}

__global__ void copy_k(const float* __restrict__ src, float* __restrict__ dst, int n)
{
    int i = blockIdx.x * blockDim.x + threadIdx.x;
    if (i < n) dst[i] = src[i];
}
__global__ void addinto_k(float* __restrict__ dst, const float* __restrict__ src, int n)
{
    int i = blockIdx.x * blockDim.x + threadIdx.x;
    if (i < n) dst[i] += src[i];
}
__global__ void tanh_k(const float* __restrict__ src, float* __restrict__ dst, int n)
{
    int i = blockIdx.x * blockDim.x + threadIdx.x;
    if (i < n) dst[i] = tanhf(src[i]);
}

// ---------------- fused masked attention ----------------
// grid (QN, Bn), block 256 (8 warps = 8 heads). One warp = one (q,b,h) row.
__global__ __launch_bounds__(256) void attn_k(
    const float* __restrict__ Qb, const float* __restrict__ Kb,
    const float* __restrict__ Vb, const int* __restrict__ lengths,
    float* __restrict__ Att)
{
    __shared__ float sc[Hn][KN + 1];
    const int qi = blockIdx.x, b = blockIdx.y;
    const int h = threadIdx.x >> 5, lane = threadIdx.x & 31;

    int maxlr = 0;
#pragma unroll
    for (int i = 0; i < Bn; i++) maxlr = max(maxlr, lengths[i] >> 2);
    const int klen = (lengths[b] >> 2) + 335 - maxlr;

    int seg; bool summ = false;
    if (qi < RTn)      seg = qi >> 2;
    else if (qi < SN)  seg = (qi - RTn) >> 4;
    else             { seg = qi - SN; summ = true; }
    const int ms  = max(seg - 4, 0);
    const int ss  = max(seg * 16 - 32, 0);
    const int se  = min(seg * 16 + 16, Un);
    const int rcs = 15 + seg * 4;

    const float* qp = Qb + ((size_t)qi * Bn + b) * Dm_ + h * DHn;
    const float q0 = qp[2 * lane]     * 0.125f;
    const float q1 = qp[2 * lane + 1] * 0.125f;
    const float* Kbh = Kb + (size_t)b * Dm_ + h * DHn;

    for (int k = 0; k < KN; k++) {
        bool allowed;
        if (k < 15)      allowed = (!summ) && (k >= ms) && (k < seg);
        else if (k < 79) allowed = (k >= rcs) && (k < rcs + 4);
        else { int u = k - 79; allowed = (u >= ss) && (u < se); }
        allowed = allowed && (k < klen);
        float s = NEGV;
        if (allowed) {
            const float* kp = Kbh + (size_t)k * (Bn * Dm_);
            float p = fmaf(q0, kp[2 * lane], q1 * kp[2 * lane + 1]);
#pragma unroll
            for (int o = 16; o; o >>= 1) p += __shfl_xor_sync(~0u, p, o);
            s = p;
        }
        if (lane == 0) sc[h][k] = s;
    }
    __syncwarp();

    float m = -3.4e38f;
    for (int k = lane; k < KN; k += 32) m = fmaxf(m, sc[h][k]);
#pragma unroll
    for (int o = 16; o; o >>= 1) m = fmaxf(m, __shfl_xor_sync(~0u, m, o));
    float sum = 0.f;
    for (int k = lane; k < KN; k += 32) {
        float e = expf(sc[h][k] - m);
        sc[h][k] = e;
        sum += e;
    }
#pragma unroll
    for (int o = 16; o; o >>= 1) sum += __shfl_xor_sync(~0u, sum, o);
    __syncwarp();
    const float inv = 1.f / sum;

    float a0 = 0.f, a1 = 0.f;
    const float* Vbh = Vb + (size_t)b * Dm_ + h * DHn;
    for (int k = 0; k < KN; k++) {
        float p = sc[h][k];
        if (p > 0.f) {
            const float* vp = Vbh + (size_t)k * (Bn * Dm_);
            a0 = fmaf(p, vp[2 * lane], a0);
            a1 = fmaf(p, vp[2 * lane + 1], a1);
        }
    }
    float* op = Att + ((size_t)qi * Bn + b) * Dm_ + h * DHn;
    op[2 * lane]     = a0 * inv;
    op[2 * lane + 1] = a1 * inv;
}

// yt[(b*256+u), d] = S[(64+u)*8 + b, d]
__global__ void transpose_k(const float* __restrict__ S, float* __restrict__ yt)
{
    const int r = blockIdx.x, d = threadIdx.x;
    const int b = r >> 8, u = r & 255;
    yt[(size_t)r * Dm_ + d] = S[((size_t)(RTn + u) * Bn + b) * Dm_ + d];
}

__global__ void lr_k(const int* __restrict__ lengths, float* __restrict__ out)
{
    int i = threadIdx.x;
    if (i < Bn) out[i] = (float)(lengths[i] >> 2);
}

// ---------------- launch ----------------
extern "C" void kernel_launch(void* const* d_in, const int* in_sizes, int n_in,
                              void* d_out, int out_size)
{
    const float* input   = (const float*)d_in[0];
    const int*   lengths = (const int*)  d_in[1];
    const float* w_in    = (const float*)d_in[2];
    const float* ln_in_g = (const float*)d_in[3];
    const float* ln_in_b = (const float*)d_in[4];
    const float* wq = (const float*)d_in[5];
    const float* bq = (const float*)d_in[6];
    const float* wk = (const float*)d_in[7];
    const float* bk = (const float*)d_in[8];
    const float* wv = (const float*)d_in[9];
    const float* bv = (const float*)d_in[10];
    const float* wo = (const float*)d_in[11];
    const float* bo = (const float*)d_in[12];
    const float* ff_g = (const float*)d_in[13];
    const float* ff_b = (const float*)d_in[14];
    const float* w1 = (const float*)d_in[15];
    const float* b1 = (const float*)d_in[16];
    const float* w2 = (const float*)d_in[17];
    const float* b2 = (const float*)d_in[18];
    const float* lo_g = (const float*)d_in[19];
    const float* lo_b = (const float*)d_in[20];
    const float* w_out = (const float*)d_in[21];
    const float* b_out = (const float*)d_in[22];
    const float* lng = (const float*)d_in[23];
    const float* lnb = (const float*)d_in[24];
    float* out = (float*)d_out;

    float* arena = nullptr;
    cudaGetSymbolAddress((void**)&arena, g_arena);
    float* X    = arena + OFF_X;
    float* S    = arena + OFF_S;
    float* MEMS = arena + OFF_MEMS;
    float* QIN  = arena + OFF_QIN;
    float* KIN  = arena + OFF_KIN;
    float* Qb   = arena + OFF_Q;
    float* Kb   = arena + OFF_K;
    float* Vb   = arena + OFF_V;
    float* ATT  = arena + OFF_ATT;
    float* Ob   = arena + OFF_O;
    float* Hb   = arena + OFF_H;
    float* Fb   = arena + OFF_F;
    float* H2   = arena + OFF_H2;
    float* YT   = arena + OFF_YT;
    float* Yb   = arena + OFF_Y;

    const int NS  = SN * Bn * Dm_;   // 1,310,720
    const int NM  = 15 * Bn * Dm_;   // 61,440

    // input projection: (8*1040, 80) @ (80, 128)
    gemm_k<<<dim3(1, 65), 256>>>(input, w_in, nullptr, X, 8320, 128, 80, 0);
    initS_k<<<dim3(SN, Bn), Dm_>>>(X, S);
    mems0_k<<<dim3(15, Bn), Dm_>>>(S, MEMS);

    for (int l = 0; l < Ln; l++) {
        const float* Wq = wq + (size_t)l * Dm_ * Dm_;
        const float* Wk = wk + (size_t)l * Dm_ * Dm_;
        const float* Wv = wv + (size_t)l * Dm_ * Dm_;
        const float* Wo = wo + (size_t)l * Dm_ * Dm_;
        const float* W1 = w1 + (size_t)l * Dm_ * FFNn;
        const float* W2 = w2 + (size_t)l * FFNn * Dm_;

        // LN1 -> qin rows [0,320) and kin rows [15,335)
        ln_k<<<SN * Bn, 256>>>(S, nullptr, ln_in_g + l * Dm_, ln_in_b + l * Dm_,
                               QIN, KIN + 15 * Bn * Dm_, Dm_);
        summary_k<<<dim3(NSEG, Bn), Dm_>>>(QIN);
        copy_k<<<(NM + 255) / 256, 256>>>(MEMS, KIN, NM);

        gemm_k<<<dim3(4, 21), 256>>>(QIN, Wq, bq + l * Dm_, Qb, QN * Bn, Dm_, Dm_, 0);
        gemm_k<<<dim3(4, 21), 256>>>(KIN, Wk, bk + l * Dm_, Kb, KN * Bn, Dm_, Dm_, 0);
        gemm_k<<<dim3(4, 21), 256>>>(KIN, Wv, bv + l * Dm_, Vb, KN * Bn, Dm_, Dm_, 0);

        attn_k<<<dim3(QN, Bn), 256>>>(Qb, Kb, Vb, lengths, ATT);

        gemm_k<<<dim3(4, 21), 256>>>(ATT, Wo, bo + l * Dm_, Ob, QN * Bn, Dm_, Dm_, 0);

        addinto_k<<<(NS + 255) / 256, 256>>>(S, Ob, NS);
        tanh_k<<<(NM + 255) / 256, 256>>>(Ob + NS, MEMS, NM);

        ln_k<<<SN * Bn, 256>>>(S, nullptr, ff_g + l * Dm_, ff_b + l * Dm_, Hb, nullptr, Dm_);
        gemm_k<<<dim3(16, 20), 256>>>(Hb, W1, b1 + l * FFNn, Fb, SN * Bn, FFNn, Dm_, 1);
        gemm_k<<<dim3(4, 20), 256>>>(Fb, W2, b2 + l * Dm_, H2, SN * Bn, Dm_, FFNn, 0);
        // res = LN(res + h) back into S
        ln_k<<<SN * Bn, 256>>>(S, H2, lo_g + l * Dm_, lo_b + l * Dm_, S, nullptr, Dm_);
    }

    transpose_k<<<2048, Dm_>>>(S, YT);
    gemm_k<<<dim3(8, 16), 256>>>(YT, w_out, b_out, Yb, 2048, OUTn, Dm_, 0);
    ln_k<<<2048, 256>>>(Yb, nullptr, lng, lnb, out, nullptr, OUTn);

    if (out_size >= 2048 * 1024 + Bn)
        lr_k<<<1, 32>>>(lengths, out + 2048 * 1024);
}

// round 2
// speedup vs baseline: 1.7944x; 1.7944x over previous
#include <cuda_runtime.h>
#include <cuda_bf16.h>
#include <math.h>
#include <stdint.h>

// ---------------- constants ----------------
#define Bn   8
#define Dm_  512
#define FFNn 2048
#define Ln   8
#define OUTn 1024
#define Hn   8
#define DHn  64
#define QN   336
#define KN   335
#define SN   320
#define RTn  64
#define Un   256
#define NSEG 16
#define NEGV (-1e8f)

// arena offsets (in floats)
#define SZ_X    (8320UL*128UL)
#define SZ_S    ((size_t)SN*Bn*Dm_)
#define SZ_MEMS (15UL*Bn*Dm_)
#define SZ_QIN  ((size_t)QN*Bn*Dm_)
#define SZ_KIN  ((size_t)KN*Bn*Dm_)
#define SZ_TOK  ((size_t)QN*Bn*Dm_)
#define SZ_F    ((size_t)SN*Bn*FFNn)
#define SZ_YT   (2048UL*512UL)
#define SZ_Y    (2048UL*1024UL)

#define OFF_X    0UL
#define OFF_S    (OFF_X + SZ_X)
#define OFF_MEMS (OFF_S + SZ_S)
#define OFF_QIN  (OFF_MEMS + SZ_MEMS)
#define OFF_KIN  (OFF_QIN + SZ_QIN)
#define OFF_Q    (OFF_KIN + SZ_KIN)
#define OFF_K    (OFF_Q + SZ_TOK)
#define OFF_V    (OFF_K + SZ_KIN)
#define OFF_ATT  (OFF_V + SZ_KIN)
#define OFF_O    (OFF_ATT + SZ_TOK)
#define OFF_H    (OFF_O + SZ_TOK)
#define OFF_F    (OFF_H + SZ_S)
#define OFF_H2   (OFF_F + SZ_F)
#define OFF_YT   (OFF_H2 + SZ_S)
#define OFF_Y    (OFF_YT + SZ_YT)
#define ARENA_TOTAL (OFF_Y + SZ_Y)

__device__ float g_arena[ARENA_TOTAL];

// ---------------- tensor-core GEMM (split bf16, fp32 in/out) ----------------
// C = act(A @ W + bias).  A:(M,K) row-major fp32, W:(K,N) row-major fp32.
// N % 128 == 0, K % 4 == 0.  Internally: bf16 hi/lo split, 3x HMMA, fp32 acc.
#define BK  32
#define LDA 40   // smem row stride (elements) -> 20 words, conflict-free frags

__device__ __forceinline__ void mma_bf16(float c[4], const uint32_t a[4],
                                         const uint32_t b[2]) {
    asm volatile(
        "mma.sync.aligned.m16n8k16.row.col.f32.bf16.bf16.f32 "
        "{%0,%1,%2,%3}, {%4,%5,%6,%7}, {%8,%9}, {%0,%1,%2,%3};\n"
        : "+f"(c[0]), "+f"(c[1]), "+f"(c[2]), "+f"(c[3])
        : "r"(a[0]), "r"(a[1]), "r"(a[2]), "r"(a[3]), "r"(b[0]), "r"(b[1]));
}

__device__ __forceinline__ void split2(float x, __nv_bfloat16& h, __nv_bfloat16& l) {
    h = __float2bfloat16(x);
    l = __float2bfloat16(x - __bfloat162float(h));
}

__global__ __launch_bounds__(256) void gemm_tc(
    const float* __restrict__ A, const float* __restrict__ W,
    const float* __restrict__ bias, float* __restrict__ C,
    int M, int N, int K, int act)
{
    __shared__ __nv_bfloat16 Ah[128 * LDA], Al[128 * LDA];
    __shared__ __nv_bfloat16 Bh[128 * LDA], Bl[128 * LDA];   // [n][k]

    const int tid = threadIdx.x, lane = tid & 31, wid = tid >> 5;
    const int wm = wid & 3, wn = wid >> 2;       // warp tile: 32(m) x 64(n)
    const int grp = lane >> 2, tig = lane & 3;
    const long row0 = (long)blockIdx.y * 128;
    const int  col0 = blockIdx.x * 128;

    float acc[2][8][4] = {};

    const int arow = tid >> 1, acol0 = (tid & 1) * 16;  // A: 128 rows, 2 thr/row
    const int brow = tid >> 3, bcol0 = (tid & 7) * 16;  // B: 32 k-rows, 8 thr/row

    for (int k0 = 0; k0 < K; k0 += BK) {
        // ---- stage A (fp32 -> hi/lo bf16) ----
#pragma unroll
        for (int j = 0; j < 4; j++) {
            int c = acol0 + j * 4;
            float4 v = make_float4(0.f, 0.f, 0.f, 0.f);
            if (row0 + arow < M && k0 + c < K)
                v = *(const float4*)&A[(row0 + arow) * (long)K + k0 + c];
            __nv_bfloat16 h, l;
            int o = arow * LDA + c;
            split2(v.x, h, l); Ah[o]     = h; Al[o]     = l;
            split2(v.y, h, l); Ah[o + 1] = h; Al[o + 1] = l;
            split2(v.z, h, l); Ah[o + 2] = h; Al[o + 2] = l;
            split2(v.w, h, l); Ah[o + 3] = h; Al[o + 3] = l;
        }
        // ---- stage B transposed ([n][k]) ----
#pragma unroll
        for (int j = 0; j < 4; j++) {
            int n = bcol0 + j * 4;
            float4 v = make_float4(0.f, 0.f, 0.f, 0.f);
            if (k0 + brow < K)
                v = *(const float4*)&W[(long)(k0 + brow) * N + col0 + n];
            __nv_bfloat16 h, l;
            split2(v.x, h, l); Bh[(n + 0) * LDA + brow] = h; Bl[(n + 0) * LDA + brow] = l;
            split2(v.y, h, l); Bh[(n + 1) * LDA + brow] = h; Bl[(n + 1) * LDA + brow] = l;
            split2(v.z, h, l); Bh[(n + 2) * LDA + brow] = h; Bl[(n + 2) * LDA + brow] = l;
            split2(v.w, h, l); Bh[(n + 3) * LDA + brow] = h; Bl[(n + 3) * LDA + brow] = l;
        }
        __syncthreads();

#pragma unroll
        for (int kk = 0; kk < BK; kk += 16) {
            uint32_t ah[2][4], al[2][4];
#pragma unroll
            for (int mt = 0; mt < 2; mt++) {
                int r = wm * 32 + mt * 16;
                int o  = (r + grp) * LDA + kk + tig * 2;
                int o8 = o + 8 * LDA;
                ah[mt][0] = *(const uint32_t*)&Ah[o];
                ah[mt][1] = *(const uint32_t*)&Ah[o8];
                ah[mt][2] = *(const uint32_t*)&Ah[o + 8];
                ah[mt][3] = *(const uint32_t*)&Ah[o8 + 8];
                al[mt][0] = *(const uint32_t*)&Al[o];
                al[mt][1] = *(const uint32_t*)&Al[o8];
                al[mt][2] = *(const uint32_t*)&Al[o + 8];
                al[mt][3] = *(const uint32_t*)&Al[o8 + 8];
            }
#pragma unroll
            for (int nt = 0; nt < 8; nt++) {
                int nn = wn * 64 + nt * 8 + grp;
                int o = nn * LDA + kk + tig * 2;
                uint32_t bh[2], bl[2];
                bh[0] = *(const uint32_t*)&Bh[o]; bh[1] = *(const uint32_t*)&Bh[o + 8];
                bl[0] = *(const uint32_t*)&Bl[o]; bl[1] = *(const uint32_t*)&Bl[o + 8];
#pragma unroll
                for (int mt = 0; mt < 2; mt++) {
                    mma_bf16(acc[mt][nt], ah[mt], bh);
                    mma_bf16(acc[mt][nt], al[mt], bh);
                    mma_bf16(acc[mt][nt], ah[mt], bl);
                }
            }
        }
        __syncthreads();
    }

    // ---- epilogue ----
#pragma unroll
    for (int mt = 0; mt < 2; mt++) {
#pragma unroll
        for (int nt = 0; nt < 8; nt++) {
            int c = col0 + wn * 64 + nt * 8 + tig * 2;
            float b0 = bias ? bias[c] : 0.f;
            float b1 = bias ? bias[c + 1] : 0.f;
            long r = row0 + wm * 32 + mt * 16 + grp;
            float v0 = acc[mt][nt][0] + b0, v1 = acc[mt][nt][1] + b1;
            float v2 = acc[mt][nt][2] + b0, v3 = acc[mt][nt][3] + b1;
            if (act) {
                v0 = fmaxf(v0, 0.f); v1 = fmaxf(v1, 0.f);
                v2 = fmaxf(v2, 0.f); v3 = fmaxf(v3, 0.f);
            }
            if (r < M)     *(float2*)&C[r * N + c]       = make_float2(v0, v1);
            if (r + 8 < M) *(float2*)&C[(r + 8) * N + c] = make_float2(v2, v3);
        }
    }
}

// ---------------- LayerNorm: warp per row ----------------
__global__ __launch_bounds__(256) void ln_row_k(
    const float* __restrict__ X, const float* __restrict__ X2,
    const float* __restrict__ g, const float* __restrict__ bta,
    float* __restrict__ out1, float* __restrict__ out2, int rows, int D)
{
    const int wid = threadIdx.x >> 5, lane = threadIdx.x & 31;
    const int row = blockIdx.x * 8 + wid;
    if (row >= rows) return;
    const float4* x  = (const float4*)(X + (long)row * D);
    const float4* x2 = X2 ? (const float4*)(X2 + (long)row * D) : nullptr;
    const int cnt = D >> 7;   // float4's per lane (4 for D=512, 8 for D=1024)

    float s = 0.f, s2 = 0.f;
    for (int i = 0; i < cnt; i++) {
        float4 a = x[lane + i * 32];
        if (x2) {
            float4 b = x2[lane + i * 32];
            a.x += b.x; a.y += b.y; a.z += b.z; a.w += b.w;
        }
        s  += a.x + a.y + a.z + a.w;
        s2 += a.x * a.x + a.y * a.y + a.z * a.z + a.w * a.w;
    }
#pragma unroll
    for (int o = 16; o; o >>= 1) {
        s  += __shfl_xor_sync(~0u, s, o);
        s2 += __shfl_xor_sync(~0u, s2, o);
    }
    const float mean = s / D;
    const float inv = rsqrtf(s2 / D - mean * mean + 1e-5f);
    const float4* gg = (const float4*)g;
    const float4* bb = (const float4*)bta;
    for (int i = 0; i < cnt; i++) {
        int idx = lane + i * 32;
        float4 a = x[idx];
        if (x2) {
            float4 b = x2[idx];
            a.x += b.x; a.y += b.y; a.z += b.z; a.w += b.w;
        }
        float4 gv = gg[idx], bv = bb[idx];
        float4 o;
        o.x = (a.x - mean) * inv * gv.x + bv.x;
        o.y = (a.y - mean) * inv * gv.y + bv.y;
        o.z = (a.z - mean) * inv * gv.z + bv.z;
        o.w = (a.w - mean) * inv * gv.w + bv.w;
        ((float4*)(out1 + (long)row * D))[idx] = o;
        if (out2) ((float4*)(out2 + (long)row * D))[idx] = o;
    }
}

// ---------------- misc small kernels ----------------
__global__ void initS_k(const float* __restrict__ X, float* __restrict__ S)
{
    const int t = blockIdx.x, b = blockIdx.y, d = threadIdx.x;
    int frame;
    if (t < RTn) {
        int si = t >> 2;
        int st = (si == 15) ? 256 : (si + 1) * 16;
        frame = st + (t & 3);
    } else {
        frame = t - RTn;
    }
    S[((size_t)t * Bn + b) * Dm_ + d] = X[(size_t)b * 133120 + (size_t)frame * Dm_ + d];
}

__global__ void mems0_k(const float* __restrict__ S, float* __restrict__ M)
{
    const int s = blockIdx.x, b = blockIdx.y, d = threadIdx.x;
    size_t base = ((size_t)(RTn + s * 16) * Bn + b) * Dm_ + d;
    float acc = 0.f;
#pragma unroll
    for (int k = 0; k < 16; k++) acc += S[base + (size_t)k * Bn * Dm_];
    M[((size_t)s * Bn + b) * Dm_ + d] = acc * (1.f / 16.f);
}

__global__ void summary_k(float* __restrict__ qin)
{
    const int s = blockIdx.x, b = blockIdx.y, d = threadIdx.x;
    size_t base = ((size_t)(RTn + s * 16) * Bn + b) * Dm_ + d;
    float acc = 0.f;
#pragma unroll
    for (int k = 0; k < 16; k++) acc += qin[base + (size_t)k * Bn * Dm_];
    qin[((size_t)(SN + s) * Bn + b) * Dm_ + d] = acc * (1.f / 16.f);
}

__global__ void copy_k(const float* __restrict__ src, float* __restrict__ dst, int n)
{
    int i = blockIdx.x * blockDim.x + threadIdx.x;
    if (i < n) dst[i] = src[i];
}
__global__ void addinto_k(float* __restrict__ dst, const float* __restrict__ src, int n)
{
    int i = blockIdx.x * blockDim.x + threadIdx.x;
    if (i < n) dst[i] += src[i];
}
__global__ void tanh_k(const float* __restrict__ src, float* __restrict__ dst, int n)
{
    int i = blockIdx.x * blockDim.x + threadIdx.x;
    if (i < n) dst[i] = tanhf(src[i]);
}

// ---------------- fused masked attention (compact key list) ----------------
// grid (QN, Bn), 256 threads = 8 warps = 8 heads; one warp per (q,b,h).
__global__ __launch_bounds__(256) void attn_k(
    const float* __restrict__ Qb, const float* __restrict__ Kb,
    const float* __restrict__ Vb, const int* __restrict__ lengths,
    float* __restrict__ Att)
{
    __shared__ float sc[Hn][64];
    __shared__ short ki[Hn][64];
    const int qi = blockIdx.x, b = blockIdx.y;
    const int h = threadIdx.x >> 5, lane = threadIdx.x & 31;

    int maxlr = 0;
#pragma unroll
    for (int i = 0; i < Bn; i++) maxlr = max(maxlr, lengths[i] >> 2);
    const int lrb = lengths[b] >> 2;

    int seg; bool summ = false;
    if (qi < RTn)      seg = qi >> 2;
    else if (qi < SN)  seg = (qi - RTn) >> 4;
    else             { seg = qi - SN; summ = true; }
    const int ms  = max(seg - 4, 0);
    const int ss  = max(seg * 16 - 32, 0);
    const int se  = min(seg * 16 + 16, Un);
    const int ue  = min(se, lrb + 256 - maxlr);   // length cutoff on utt keys
    const int rcs = 15 + seg * 4;

    const int c0 = summ ? 0 : (seg - ms);   // mem keys
    const int c2 = max(ue - ss, 0);         // utt keys
    const int n  = c0 + 4 + c2;

    for (int j = lane; j < n; j += 32) {
        int k;
        if (j < c0)           k = ms + j;
        else if (j < c0 + 4)  k = rcs + (j - c0);
        else                  k = 79 + ss + (j - c0 - 4);
        ki[h][j] = (short)k;
    }
    __syncwarp();

    const float* qp = Qb + ((size_t)qi * Bn + b) * Dm_ + h * DHn;
    const float q0 = qp[2 * lane]     * 0.125f;
    const float q1 = qp[2 * lane + 1] * 0.125f;
    const float* Kbh = Kb + (size_t)b * Dm_ + h * DHn;

    for (int j = 0; j < n; j++) {
        const float* kp = Kbh + (size_t)ki[h][j] * (Bn * Dm_);
        float p = fmaf(q0, kp[2 * lane], q1 * kp[2 * lane + 1]);
#pragma unroll
        for (int o = 16; o; o >>= 1) p += __shfl_xor_sync(~0u, p, o);
        if (lane == 0) sc[h][j] = p;
    }
    __syncwarp();

    float m = -3.4e38f;
    for (int j = lane; j < n; j += 32) m = fmaxf(m, sc[h][j]);
#pragma unroll
    for (int o = 16; o; o >>= 1) m = fmaxf(m, __shfl_xor_sync(~0u, m, o));
    float sum = 0.f;
    for (int j = lane; j < n; j += 32) {
        float e = expf(sc[h][j] - m);
        sc[h][j] = e;
        sum += e;
    }
#pragma unroll
    for (int o = 16; o; o >>= 1) sum += __shfl_xor_sync(~0u, sum, o);
    __syncwarp();
    const float inv = 1.f / sum;

    float a0 = 0.f, a1 = 0.f;
    const float* Vbh = Vb + (size_t)b * Dm_ + h * DHn;
    for (int j = 0; j < n; j++) {
        float p = sc[h][j];
        const float* vp = Vbh + (size_t)ki[h][j] * (Bn * Dm_);
        a0 = fmaf(p, vp[2 * lane], a0);
        a1 = fmaf(p, vp[2 * lane + 1], a1);
    }
    float* op = Att + ((size_t)qi * Bn + b) * Dm_ + h * DHn;
    op[2 * lane]     = a0 * inv;
    op[2 * lane + 1] = a1 * inv;
}

// yt[(b*256+u), d] = S[(64+u)*8 + b, d]
__global__ void transpose_k(const float* __restrict__ S, float* __restrict__ yt)
{
    const int r = blockIdx.x, d = threadIdx.x;
    const int b = r >> 8, u = r & 255;
    yt[(size_t)r * Dm_ + d] = S[((size_t)(RTn + u) * Bn + b) * Dm_ + d];
}

__global__ void lr_k(const int* __restrict__ lengths, float* __restrict__ out)
{
    int i = threadIdx.x;
    if (i < Bn) out[i] = (float)(lengths[i] >> 2);
}

// ---------------- launch ----------------
extern "C" void kernel_launch(void* const* d_in, const int* in_sizes, int n_in,
                              void* d_out, int out_size)
{
    const float* input   = (const float*)d_in[0];
    const int*   lengths = (const int*)  d_in[1];
    const float* w_in    = (const float*)d_in[2];
    const float* ln_in_g = (const float*)d_in[3];
    const float* ln_in_b = (const float*)d_in[4];
    const float* wq = (const float*)d_in[5];
    const float* bq = (const float*)d_in[6];
    const float* wk = (const float*)d_in[7];
    const float* bk = (const float*)d_in[8];
    const float* wv = (const float*)d_in[9];
    const float* bv = (const float*)d_in[10];
    const float* wo = (const float*)d_in[11];
    const float* bo = (const float*)d_in[12];
    const float* ff_g = (const float*)d_in[13];
    const float* ff_b = (const float*)d_in[14];
    const float* w1 = (const float*)d_in[15];
    const float* b1 = (const float*)d_in[16];
    const float* w2 = (const float*)d_in[17];
    const float* b2 = (const float*)d_in[18];
    const float* lo_g = (const float*)d_in[19];
    const float* lo_b = (const float*)d_in[20];
    const float* w_out = (const float*)d_in[21];
    const float* b_out = (const float*)d_in[22];
    const float* lng = (const float*)d_in[23];
    const float* lnb = (const float*)d_in[24];
    float* out = (float*)d_out;

    float* arena = nullptr;
    cudaGetSymbolAddress((void**)&arena, g_arena);
    float* X    = arena + OFF_X;
    float* S    = arena + OFF_S;
    float* MEMS = arena + OFF_MEMS;
    float* QIN  = arena + OFF_QIN;
    float* KIN  = arena + OFF_KIN;
    float* Qb   = arena + OFF_Q;
    float* Kb   = arena + OFF_K;
    float* Vb   = arena + OFF_V;
    float* ATT  = arena + OFF_ATT;
    float* Ob   = arena + OFF_O;
    float* Hb   = arena + OFF_H;
    float* Fb   = arena + OFF_F;
    float* H2   = arena + OFF_H2;
    float* YT   = arena + OFF_YT;
    float* Yb   = arena + OFF_Y;

    const int NS = SN * Bn * Dm_;
    const int NM = 15 * Bn * Dm_;

    gemm_tc<<<dim3(1, 65), 256>>>(input, w_in, nullptr, X, 8320, 128, 80, 0);
    initS_k<<<dim3(SN, Bn), Dm_>>>(X, S);
    mems0_k<<<dim3(15, Bn), Dm_>>>(S, MEMS);

    for (int l = 0; l < Ln; l++) {
        const float* Wq = wq + (size_t)l * Dm_ * Dm_;
        const float* Wk = wk + (size_t)l * Dm_ * Dm_;
        const float* Wv = wv + (size_t)l * Dm_ * Dm_;
        const float* Wo = wo + (size_t)l * Dm_ * Dm_;
        const float* W1 = w1 + (size_t)l * Dm_ * FFNn;
        const float* W2 = w2 + (size_t)l * FFNn * Dm_;

        ln_row_k<<<SN * Bn / 8, 256>>>(S, nullptr, ln_in_g + l * Dm_, ln_in_b + l * Dm_,
                                       QIN, KIN + 15 * Bn * Dm_, SN * Bn, Dm_);
        summary_k<<<dim3(NSEG, Bn), Dm_>>>(QIN);
        copy_k<<<(NM + 255) / 256, 256>>>(MEMS, KIN, NM);

        gemm_tc<<<dim3(4, 21), 256>>>(QIN, Wq, bq + l * Dm_, Qb, QN * Bn, Dm_, Dm_, 0);
        gemm_tc<<<dim3(4, 21), 256>>>(KIN, Wk, bk + l * Dm_, Kb, KN * Bn, Dm_, Dm_, 0);
        gemm_tc<<<dim3(4, 21), 256>>>(KIN, Wv, bv + l * Dm_, Vb, KN * Bn, Dm_, Dm_, 0);

        attn_k<<<dim3(QN, Bn), 256>>>(Qb, Kb, Vb, lengths, ATT);

        gemm_tc<<<dim3(4, 21), 256>>>(ATT, Wo, bo + l * Dm_, Ob, QN * Bn, Dm_, Dm_, 0);

        addinto_k<<<(NS + 255) / 256, 256>>>(S, Ob, NS);
        tanh_k<<<(NM + 255) / 256, 256>>>(Ob + NS, MEMS, NM);

        ln_row_k<<<SN * Bn / 8, 256>>>(S, nullptr, ff_g + l * Dm_, ff_b + l * Dm_,
                                       Hb, nullptr, SN * Bn, Dm_);
        gemm_tc<<<dim3(16, 20), 256>>>(Hb, W1, b1 + l * FFNn, Fb, SN * Bn, FFNn, Dm_, 1);
        gemm_tc<<<dim3(4, 20), 256>>>(Fb, W2, b2 + l * Dm_, H2, SN * Bn, Dm_, FFNn, 0);
        ln_row_k<<<SN * Bn / 8, 256>>>(S, H2, lo_g + l * Dm_, lo_b + l * Dm_,
                                       S, nullptr, SN * Bn, Dm_);
    }

    transpose_k<<<2048, Dm_>>>(S, YT);
    gemm_tc<<<dim3(8, 16), 256>>>(YT, w_out, b_out, Yb, 2048, OUTn, Dm_, 0);
    ln_row_k<<<2048 / 8, 256>>>(Yb, nullptr, lng, lnb, out, nullptr, 2048, OUTn);

    if (out_size >= 2048 * 1024 + Bn)
        lr_k<<<1, 32>>>(lengths, out + 2048 * 1024);
}

// round 3
// speedup vs baseline: 1.9793x; 1.1030x over previous
#include <cuda_runtime.h>
#include <cuda_bf16.h>
#include <math.h>
#include <stdint.h>

typedef __nv_bfloat16 BF;
typedef __nv_bfloat162 BF2;

// ---------------- constants ----------------
#define Bn   8
#define Dm_  512
#define FFNn 2048
#define Ln   8
#define OUTn 1024
#define Hn   8
#define DHn  64
#define QN   336
#define KN   335
#define SN   320
#define RTn  64
#define Un   256
#define NSEG 16

// ------- float arena -------
#define F_X    0UL
#define F_S    (F_X + 8320UL*128UL)
#define F_MEMS (F_S + 1310720UL)
#define F_QB   (F_MEMS + 61440UL)
#define F_KV   (F_QB + 1376256UL)
#define F_OB   (F_KV + 2752512UL)
#define F_H2   (F_OB + 1376256UL)
#define F_YB   (F_H2 + 1310720UL)
#define F_BKV  (F_YB + 2097152UL)
#define F_TOTAL (F_BKV + 8192UL)
__device__ float g_arena[F_TOTAL];

// ------- bf16 arena (hi plane at base, lo plane at base+E) -------
#define EQ   262144UL      // 512*512
#define EKV  524288UL      // 1024*512
#define EW1  1048576UL     // 2048*512
#define EA   1376256UL     // 2688*512
#define EHB  1310720UL     // 2560*512
#define EFB  5242880UL     // 2560*2048
#define EYT  1048576UL     // 2048*512

#define BW_QT   0UL
#define BW_KVT  (BW_QT   + 8UL*2UL*EQ)
#define BW_OT   (BW_KVT  + 8UL*2UL*EKV)
#define BW_W1T  (BW_OT   + 8UL*2UL*EQ)
#define BW_W2T  (BW_W1T  + 8UL*2UL*EW1)
#define BW_OUTT (BW_W2T  + 8UL*2UL*EW1)
#define BA_QIN  (BW_OUTT + 2UL*EKV)
#define BA_KIN  (BA_QIN  + 2UL*EA)
#define BA_ATT  (BA_KIN  + 2UL*EA)
#define BA_HB   (BA_ATT  + 2UL*EA)
#define BA_FB   (BA_HB   + 2UL*EHB)
#define BA_YT   (BA_FB   + 2UL*EFB)
#define B_TOTAL (BA_YT   + 2UL*EYT)
__device__ BF g_bf[B_TOTAL];

__device__ __forceinline__ void split2(float x, BF& h, BF& l) {
    h = __float2bfloat16(x);
    l = __float2bfloat16(x - __bfloat162float(h));
}

// ---------------- cp.async helpers ----------------
__device__ __forceinline__ void cp16(void* dst, const void* src) {
    uint32_t d = (uint32_t)__cvta_generic_to_shared(dst);
    asm volatile("cp.async.cg.shared.global [%0], [%1], 16;\n" :: "r"(d), "l"(src));
}
#define CP_COMMIT() asm volatile("cp.async.commit_group;\n")
#define CP_WAIT1()  asm volatile("cp.async.wait_group 1;\n")
#define CP_WAIT0()  asm volatile("cp.async.wait_group 0;\n")

__device__ __forceinline__ void mma_bf16(float c[4], const uint32_t a[4],
                                         const uint32_t b[2]) {
    asm volatile(
        "mma.sync.aligned.m16n8k16.row.col.f32.bf16.bf16.f32 "
        "{%0,%1,%2,%3}, {%4,%5,%6,%7}, {%8,%9}, {%0,%1,%2,%3};\n"
        : "+f"(c[0]), "+f"(c[1]), "+f"(c[2]), "+f"(c[3])
        : "r"(a[0]), "r"(a[1]), "r"(a[2]), "r"(a[3]), "r"(b[0]), "r"(b[1]));
}

// ---------------- pipelined plane GEMM ----------------
// C = act(A @ B^T + bias).  A planes: (M,K) bf16 hi/lo. B planes: (N,K) hi/lo.
// M%128==0, N%128==0, K%32==0.  Out: fp32 C and/or bf16 planes Ch/Cl.
#define LDA 40
#define STG 20480   // bf16 elems per stage (4 planes * 128*40)

__device__ __forceinline__ void stage_ld(
    BF* s, const BF* Ah, const BF* Al, const BF* Bh, const BF* Bl,
    long arow0, long brow0, int K, int k0, int tid)
{
    const int r = tid >> 1;
    const int o = (tid & 1) * 16;
    const long ka = (arow0 + r) * (long)K + k0 + o;
    const long kb = (brow0 + r) * (long)K + k0 + o;
    BF* d = s + r * LDA + o;
    cp16(d,             Ah + ka); cp16(d + 8,             Ah + ka + 8);
    cp16(d + 5120,      Al + ka); cp16(d + 5120 + 8,      Al + ka + 8);
    cp16(d + 10240,     Bh + kb); cp16(d + 10240 + 8,     Bh + kb + 8);
    cp16(d + 15360,     Bl + kb); cp16(d + 15360 + 8,     Bl + kb + 8);
}

extern "C" __global__ __launch_bounds__(256) void gemm_tcp(
    const BF* __restrict__ Ah, const BF* __restrict__ Al,
    const BF* __restrict__ Bh, const BF* __restrict__ Bl,
    const float* __restrict__ bias, float* __restrict__ C,
    BF* __restrict__ Ch, BF* __restrict__ Cl,
    int M, int N, int K, int act)
{
    extern __shared__ __align__(16) BF sm[];
    const int tid = threadIdx.x, lane = tid & 31, wid = tid >> 5;
    const int wm = wid & 3, wn = wid >> 2;
    const int grp = lane >> 2, tig = lane & 3;
    const long row0 = (long)blockIdx.y * 128;
    const long col0 = (long)blockIdx.x * 128;

    float acc[2][8][4] = {};
    const int T = K >> 5;

    stage_ld(sm, Ah, Al, Bh, Bl, row0, col0, K, 0, tid);  CP_COMMIT();
    stage_ld(sm + STG, Ah, Al, Bh, Bl, row0, col0, K, 32, tid); CP_COMMIT();

    for (int i = 0; i < T; i++) {
        if (i < T - 1) CP_WAIT1(); else CP_WAIT0();
        __syncthreads();
        const BF* base = sm + (i & 1) * STG;
        const BF* sAh = base;
        const BF* sAl = base + 5120;
        const BF* sBh = base + 10240;
        const BF* sBl = base + 15360;
#pragma unroll
        for (int kk = 0; kk < 32; kk += 16) {
            uint32_t ah[2][4], al[2][4];
#pragma unroll
            for (int mt = 0; mt < 2; mt++) {
                int r = wm * 32 + mt * 16;
                int o  = (r + grp) * LDA + kk + tig * 2;
                int o8 = o + 8 * LDA;
                ah[mt][0] = *(const uint32_t*)&sAh[o];
                ah[mt][1] = *(const uint32_t*)&sAh[o8];
                ah[mt][2] = *(const uint32_t*)&sAh[o + 8];
                ah[mt][3] = *(const uint32_t*)&sAh[o8 + 8];
                al[mt][0] = *(const uint32_t*)&sAl[o];
                al[mt][1] = *(const uint32_t*)&sAl[o8];
                al[mt][2] = *(const uint32_t*)&sAl[o + 8];
                al[mt][3] = *(const uint32_t*)&sAl[o8 + 8];
            }
#pragma unroll
            for (int nt = 0; nt < 8; nt++) {
                int nn = wn * 64 + nt * 8 + grp;
                int o = nn * LDA + kk + tig * 2;
                uint32_t bh[2], bl[2];
                bh[0] = *(const uint32_t*)&sBh[o]; bh[1] = *(const uint32_t*)&sBh[o + 8];
                bl[0] = *(const uint32_t*)&sBl[o]; bl[1] = *(const uint32_t*)&sBl[o + 8];
#pragma unroll
                for (int mt = 0; mt < 2; mt++) {
                    mma_bf16(acc[mt][nt], ah[mt], bh);
                    mma_bf16(acc[mt][nt], al[mt], bh);
                    mma_bf16(acc[mt][nt], ah[mt], bl);
                }
            }
        }
        __syncthreads();
        if (i + 2 < T) {
            stage_ld(sm + (i & 1) * STG, Ah, Al, Bh, Bl, row0, col0, K,
                     (i + 2) * 32, tid);
            CP_COMMIT();
        }
    }

#pragma unroll
    for (int mt = 0; mt < 2; mt++) {
#pragma unroll
        for (int nt = 0; nt < 8; nt++) {
            long c = col0 + wn * 64 + nt * 8 + tig * 2;
            float b0 = bias ? bias[c] : 0.f;
            float b1 = bias ? bias[c + 1] : 0.f;
            long r = row0 + wm * 32 + mt * 16 + grp;
            float v0 = acc[mt][nt][0] + b0, v1 = acc[mt][nt][1] + b1;
            float v2 = acc[mt][nt][2] + b0, v3 = acc[mt][nt][3] + b1;
            if (act) {
                v0 = fmaxf(v0, 0.f); v1 = fmaxf(v1, 0.f);
                v2 = fmaxf(v2, 0.f); v3 = fmaxf(v3, 0.f);
            }
            if (C) {
                *(float2*)&C[r * N + c]       = make_float2(v0, v1);
                *(float2*)&C[(r + 8) * N + c] = make_float2(v2, v3);
            }
            if (Ch) {
                BF h0,l0,h1,l1;
                split2(v0,h0,l0); split2(v1,h1,l1);
                *(BF2*)&Ch[r * N + c] = BF2(h0, h1);
                *(BF2*)&Cl[r * N + c] = BF2(l0, l1);
                split2(v2,h0,l0); split2(v3,h1,l1);
                *(BF2*)&Ch[(r + 8) * N + c] = BF2(h0, h1);
                *(BF2*)&Cl[(r + 8) * N + c] = BF2(l0, l1);
            }
        }
    }
}

// ---------------- legacy in-kernel-convert GEMM (input proj, K=80) ---------
#define LLDA 40
__global__ __launch_bounds__(256) void gemm_tc(
    const float* __restrict__ A, const float* __restrict__ W,
    const float* __restrict__ bias, float* __restrict__ C,
    int M, int N, int K, int act)
{
    __shared__ BF Ahs[128 * LLDA], Als[128 * LLDA];
    __shared__ BF Bhs[128 * LLDA], Bls[128 * LLDA];
    const int tid = threadIdx.x, lane = tid & 31, wid = tid >> 5;
    const int wm = wid & 3, wn = wid >> 2;
    const int grp = lane >> 2, tig = lane & 3;
    const long row0 = (long)blockIdx.y * 128;
    const int  col0 = blockIdx.x * 128;
    float acc[2][8][4] = {};
    const int arow = tid >> 1, acol0 = (tid & 1) * 16;
    const int brow = tid >> 3, bcol0 = (tid & 7) * 16;

    for (int k0 = 0; k0 < K; k0 += 32) {
#pragma unroll
        for (int j = 0; j < 4; j++) {
            int c = acol0 + j * 4;
            float4 v = make_float4(0.f, 0.f, 0.f, 0.f);
            if (row0 + arow < M && k0 + c < K)
                v = *(const float4*)&A[(row0 + arow) * (long)K + k0 + c];
            BF h, l; int o = arow * LLDA + c;
            split2(v.x, h, l); Ahs[o]     = h; Als[o]     = l;
            split2(v.y, h, l); Ahs[o + 1] = h; Als[o + 1] = l;
            split2(v.z, h, l); Ahs[o + 2] = h; Als[o + 2] = l;
            split2(v.w, h, l); Ahs[o + 3] = h; Als[o + 3] = l;
        }
#pragma unroll
        for (int j = 0; j < 4; j++) {
            int n = bcol0 + j * 4;
            float4 v = make_float4(0.f, 0.f, 0.f, 0.f);
            if (k0 + brow < K)
                v = *(const float4*)&W[(long)(k0 + brow) * N + col0 + n];
            BF h, l;
            split2(v.x, h, l); Bhs[(n + 0) * LLDA + brow] = h; Bls[(n + 0) * LLDA + brow] = l;
            split2(v.y, h, l); Bhs[(n + 1) * LLDA + brow] = h; Bls[(n + 1) * LLDA + brow] = l;
            split2(v.z, h, l); Bhs[(n + 2) * LLDA + brow] = h; Bls[(n + 2) * LLDA + brow] = l;
            split2(v.w, h, l); Bhs[(n + 3) * LLDA + brow] = h; Bls[(n + 3) * LLDA + brow] = l;
        }
        __syncthreads();
#pragma unroll
        for (int kk = 0; kk < 32; kk += 16) {
            uint32_t ah[2][4], al[2][4];
#pragma unroll
            for (int mt = 0; mt < 2; mt++) {
                int r = wm * 32 + mt * 16;
                int o  = (r + grp) * LLDA + kk + tig * 2;
                int o8 = o + 8 * LLDA;
                ah[mt][0] = *(const uint32_t*)&Ahs[o];
                ah[mt][1] = *(const uint32_t*)&Ahs[o8];
                ah[mt][2] = *(const uint32_t*)&Ahs[o + 8];
                ah[mt][3] = *(const uint32_t*)&Ahs[o8 + 8];
                al[mt][0] = *(const uint32_t*)&Als[o];
                al[mt][1] = *(const uint32_t*)&Als[o8];
                al[mt][2] = *(const uint32_t*)&Als[o + 8];
                al[mt][3] = *(const uint32_t*)&Als[o8 + 8];
            }
#pragma unroll
            for (int nt = 0; nt < 8; nt++) {
                int nn = wn * 64 + nt * 8 + grp;
                int o = nn * LLDA + kk + tig * 2;
                uint32_t bh[2], bl[2];
                bh[0] = *(const uint32_t*)&Bhs[o]; bh[1] = *(const uint32_t*)&Bhs[o + 8];
                bl[0] = *(const uint32_t*)&Bls[o]; bl[1] = *(const uint32_t*)&Bls[o + 8];
#pragma unroll
                for (int mt = 0; mt < 2; mt++) {
                    mma_bf16(acc[mt][nt], ah[mt], bh);
                    mma_bf16(acc[mt][nt], al[mt], bh);
                    mma_bf16(acc[mt][nt], ah[mt], bl);
                }
            }
        }
        __syncthreads();
    }
#pragma unroll
    for (int mt = 0; mt < 2; mt++) {
#pragma unroll
        for (int nt = 0; nt < 8; nt++) {
            int c = col0 + wn * 64 + nt * 8 + tig * 2;
            float b0 = bias ? bias[c] : 0.f;
            float b1 = bias ? bias[c + 1] : 0.f;
            long r = row0 + wm * 32 + mt * 16 + grp;
            float v0 = acc[mt][nt][0] + b0, v1 = acc[mt][nt][1] + b1;
            float v2 = acc[mt][nt][2] + b0, v3 = acc[mt][nt][3] + b1;
            if (act) { v0=fmaxf(v0,0.f); v1=fmaxf(v1,0.f); v2=fmaxf(v2,0.f); v3=fmaxf(v3,0.f); }
            if (r < M)     *(float2*)&C[r * N + c]       = make_float2(v0, v1);
            if (r + 8 < M) *(float2*)&C[(r + 8) * N + c] = make_float2(v2, v3);
        }
    }
}

// ---------------- weight transpose+convert: out[n][k] = W[k][n] ----------
__global__ void wconv_k(const float* __restrict__ W, BF* __restrict__ oh,
                        BF* __restrict__ ol, int K, int N,
                        long inS, long outS)
{
    __shared__ float t[32][33];
    const float* w = W + (long)blockIdx.z * inS;
    BF* ph = oh + (long)blockIdx.z * outS;
    BF* pl = ol + (long)blockIdx.z * outS;
    const int n0 = blockIdx.x * 32, k0 = blockIdx.y * 32;
    const int tx = threadIdx.x & 31, ty0 = threadIdx.x >> 5;
#pragma unroll
    for (int i = 0; i < 4; i++) {
        int ky = ty0 + i * 8;
        t[ky][tx] = w[(long)(k0 + ky) * N + n0 + tx];
    }
    __syncthreads();
#pragma unroll
    for (int i = 0; i < 4; i++) {
        int ny = ty0 + i * 8;
        float v = t[tx][ny];
        BF h, l; split2(v, h, l);
        ph[(long)(n0 + ny) * K + k0 + tx] = h;
        pl[(long)(n0 + ny) * K + k0 + tx] = l;
    }
}

__global__ void bkv_k(const float* __restrict__ bk, const float* __restrict__ bv,
                      float* __restrict__ bkv)
{
    int i = blockIdx.x * blockDim.x + threadIdx.x;
    if (i < 8192) {
        int l = i >> 10, j = i & 1023;
        bkv[i] = (j < 512) ? bk[l * 512 + j] : bv[l * 512 + j - 512];
    }
}

__global__ void kinpad_k(BF* __restrict__ kh, BF* __restrict__ kl)
{
    int i = threadIdx.x + blockIdx.x * blockDim.x;  // 4096
    size_t o = 2680UL * 512UL + i;
    kh[o] = __float2bfloat16(0.f);
    kl[o] = __float2bfloat16(0.f);
}

// ---------------- LayerNorm: warp per row, flexible outputs ----------------
__global__ __launch_bounds__(256) void ln_row_k(
    const float* __restrict__ X, const float* __restrict__ X2,
    const float* __restrict__ g, const float* __restrict__ bta,
    float* __restrict__ outf,
    BF* __restrict__ oh1, BF* __restrict__ ol1,
    BF* __restrict__ oh2, BF* __restrict__ ol2,
    int rows, int D, int rowoff2)
{
    const int wid = threadIdx.x >> 5, lane = threadIdx.x & 31;
    const int row = blockIdx.x * 8 + wid;
    if (row >= rows) return;
    const float4* x  = (const float4*)(X + (long)row * D);
    const float4* x2 = X2 ? (const float4*)(X2 + (long)row * D) : nullptr;
    const int cnt = D >> 7;

    float s = 0.f, s2 = 0.f;
    for (int i = 0; i < cnt; i++) {
        float4 a = x[lane + i * 32];
        if (x2) {
            float4 b = x2[lane + i * 32];
            a.x += b.x; a.y += b.y; a.z += b.z; a.w += b.w;
        }
        s  += a.x + a.y + a.z + a.w;
        s2 += a.x * a.x + a.y * a.y + a.z * a.z + a.w * a.w;
    }
#pragma unroll
    for (int o = 16; o; o >>= 1) {
        s  += __shfl_xor_sync(~0u, s, o);
        s2 += __shfl_xor_sync(~0u, s2, o);
    }
    const float mean = s / D;
    const float inv = rsqrtf(s2 / D - mean * mean + 1e-5f);
    const float4* gg = (const float4*)g;
    const float4* bb = (const float4*)bta;
    for (int i = 0; i < cnt; i++) {
        int idx = lane + i * 32;
        float4 a = x[idx];
        if (x2) {
            float4 b = x2[idx];
            a.x += b.x; a.y += b.y; a.z += b.z; a.w += b.w;
        }
        float4 gv = gg[idx], bv = bb[idx];
        float4 o;
        o.x = (a.x - mean) * inv * gv.x + bv.x;
        o.y = (a.y - mean) * inv * gv.y + bv.y;
        o.z = (a.z - mean) * inv * gv.z + bv.z;
        o.w = (a.w - mean) * inv * gv.w + bv.w;
        if (outf) ((float4*)(outf + (long)row * D))[idx] = o;
        if (oh1) {
            BF h0,l0,h1,l1,h2,l2,h3,l3;
            split2(o.x,h0,l0); split2(o.y,h1,l1);
            split2(o.z,h2,l2); split2(o.w,h3,l3);
            long base = (long)row * D + idx * 4;
            *(BF2*)&oh1[base]     = BF2(h0,h1);
            *(BF2*)&oh1[base + 2] = BF2(h2,h3);
            *(BF2*)&ol1[base]     = BF2(l0,l1);
            *(BF2*)&ol1[base + 2] = BF2(l2,l3);
            if (oh2) {
                long b2o = (long)(row + rowoff2) * D + idx * 4;
                *(BF2*)&oh2[b2o]     = BF2(h0,h1);
                *(BF2*)&oh2[b2o + 2] = BF2(h2,h3);
                *(BF2*)&ol2[b2o]     = BF2(l0,l1);
                *(BF2*)&ol2[b2o + 2] = BF2(l2,l3);
            }
        }
    }
}

// ---------------- misc ----------------
__global__ void initS_k(const float* __restrict__ X, float* __restrict__ S)
{
    const int t = blockIdx.x, b = blockIdx.y, d = threadIdx.x;
    int frame;
    if (t < RTn) {
        int si = t >> 2;
        int st = (si == 15) ? 256 : (si + 1) * 16;
        frame = st + (t & 3);
    } else frame = t - RTn;
    S[((size_t)t * Bn + b) * Dm_ + d] = X[(size_t)b * 133120 + (size_t)frame * Dm_ + d];
}

__global__ void mems0_k(const float* __restrict__ S, float* __restrict__ M)
{
    const int s = blockIdx.x, b = blockIdx.y, d = threadIdx.x;
    size_t base = ((size_t)(RTn + s * 16) * Bn + b) * Dm_ + d;
    float acc = 0.f;
#pragma unroll
    for (int k = 0; k < 16; k++) acc += S[base + (size_t)k * Bn * Dm_];
    M[((size_t)s * Bn + b) * Dm_ + d] = acc * (1.f / 16.f);
}

// summary rows on planes: qin token 320+s = mean of tokens 64+16s..+15
__global__ void summary_pl_k(BF* __restrict__ qh, BF* __restrict__ ql)
{
    const int s = blockIdx.x, b = blockIdx.y, d = threadIdx.x;
    size_t base = ((size_t)(RTn + s * 16) * Bn + b) * Dm_ + d;
    float acc = 0.f;
#pragma unroll
    for (int k = 0; k < 16; k++) {
        size_t o = base + (size_t)k * Bn * Dm_;
        acc += __bfloat162float(qh[o]) + __bfloat162float(ql[o]);
    }
    acc *= (1.f / 16.f);
    BF h, l; split2(acc, h, l);
    size_t o = ((size_t)(SN + s) * Bn + b) * Dm_ + d;
    qh[o] = h; ql[o] = l;
}

__global__ void mems2pl_k(const float* __restrict__ M, BF* __restrict__ kh,
                          BF* __restrict__ kl, int n)
{
    int i = blockIdx.x * blockDim.x + threadIdx.x;
    if (i < n) { BF h, l; split2(M[i], h, l); kh[i] = h; kl[i] = l; }
}

__global__ void addinto_k(float* __restrict__ dst, const float* __restrict__ src, int n)
{
    int i = blockIdx.x * blockDim.x + threadIdx.x;
    if (i < n) dst[i] += src[i];
}
__global__ void tanh_k(const float* __restrict__ src, float* __restrict__ dst, int n)
{
    int i = blockIdx.x * blockDim.x + threadIdx.x;
    if (i < n) dst[i] = tanhf(src[i]);
}

// ---------------- attention (fp32 Q/KV in, bf16 planes out) ----------------
__global__ __launch_bounds__(256) void attn_k(
    const float* __restrict__ Qb, const float* __restrict__ KVf,
    const int* __restrict__ lengths, BF* __restrict__ Ah, BF* __restrict__ Al)
{
    __shared__ float sc[Hn][64];
    __shared__ short ki[Hn][64];
    const int qi = blockIdx.x, b = blockIdx.y;
    const int h = threadIdx.x >> 5, lane = threadIdx.x & 31;

    int maxlr = 0;
#pragma unroll
    for (int i = 0; i < Bn; i++) maxlr = max(maxlr, lengths[i] >> 2);
    const int lrb = lengths[b] >> 2;

    int seg; bool summ = false;
    if (qi < RTn)      seg = qi >> 2;
    else if (qi < SN)  seg = (qi - RTn) >> 4;
    else             { seg = qi - SN; summ = true; }
    const int ms  = max(seg - 4, 0);
    const int ss  = max(seg * 16 - 32, 0);
    const int se  = min(seg * 16 + 16, Un);
    const int ue  = min(se, lrb + 256 - maxlr);
    const int rcs = 15 + seg * 4;

    const int c0 = summ ? 0 : (seg - ms);
    const int c2 = max(ue - ss, 0);
    const int n  = c0 + 4 + c2;

    for (int j = lane; j < n; j += 32) {
        int k;
        if (j < c0)          k = ms + j;
        else if (j < c0 + 4) k = rcs + (j - c0);
        else                 k = 79 + ss + (j - c0 - 4);
        ki[h][j] = (short)k;
    }
    __syncwarp();

    const float* qp = Qb + ((size_t)qi * Bn + b) * Dm_ + h * DHn;
    const float q0 = qp[2 * lane]     * 0.125f;
    const float q1 = qp[2 * lane + 1] * 0.125f;
    const float* Kbh = KVf + (size_t)b * 1024 + h * DHn;          // K at +0
    const float* Vbh = Kbh + 512;                                  // V at +512

    for (int j = 0; j < n; j++) {
        const float* kp = Kbh + (size_t)ki[h][j] * (Bn * 1024);
        float p = fmaf(q0, kp[2 * lane], q1 * kp[2 * lane + 1]);
#pragma unroll
        for (int o = 16; o; o >>= 1) p += __shfl_xor_sync(~0u, p, o);
        if (lane == 0) sc[h][j] = p;
    }
    __syncwarp();

    float m = -3.4e38f;
    for (int j = lane; j < n; j += 32) m = fmaxf(m, sc[h][j]);
#pragma unroll
    for (int o = 16; o; o >>= 1) m = fmaxf(m, __shfl_xor_sync(~0u, m, o));
    float sum = 0.f;
    for (int j = lane; j < n; j += 32) {
        float e = expf(sc[h][j] - m);
        sc[h][j] = e;
        sum += e;
    }
#pragma unroll
    for (int o = 16; o; o >>= 1) sum += __shfl_xor_sync(~0u, sum, o);
    __syncwarp();
    const float inv = 1.f / sum;

    float a0 = 0.f, a1 = 0.f;
    for (int j = 0; j < n; j++) {
        float p = sc[h][j];
        const float* vp = Vbh + (size_t)ki[h][j] * (Bn * 1024);
        a0 = fmaf(p, vp[2 * lane], a0);
        a1 = fmaf(p, vp[2 * lane + 1], a1);
    }
    a0 *= inv; a1 *= inv;
    BF h0, l0, h1, l1;
    split2(a0, h0, l0); split2(a1, h1, l1);
    size_t op = ((size_t)qi * Bn + b) * Dm_ + h * DHn + 2 * lane;
    *(BF2*)&Ah[op] = BF2(h0, h1);
    *(BF2*)&Al[op] = BF2(l0, l1);
}

// yt planes[(b*256+u), d] = S[(64+u)*8 + b, d]
__global__ void transpose_pl_k(const float* __restrict__ S, BF* __restrict__ yh,
                               BF* __restrict__ yl)
{
    const int r = blockIdx.x, d = threadIdx.x;
    const int b = r >> 8, u = r & 255;
    float v = S[((size_t)(RTn + u) * Bn + b) * Dm_ + d];
    BF h, l; split2(v, h, l);
    yh[(size_t)r * Dm_ + d] = h;
    yl[(size_t)r * Dm_ + d] = l;
}

__global__ void lr_k(const int* __restrict__ lengths, float* __restrict__ out)
{
    int i = threadIdx.x;
    if (i < Bn) out[i] = (float)(lengths[i] >> 2);
}

// ---------------- launch ----------------
extern "C" void kernel_launch(void* const* d_in, const int* in_sizes, int n_in,
                              void* d_out, int out_size)
{
    const float* input   = (const float*)d_in[0];
    const int*   lengths = (const int*)  d_in[1];
    const float* w_in    = (const float*)d_in[2];
    const float* ln_in_g = (const float*)d_in[3];
    const float* ln_in_b = (const float*)d_in[4];
    const float* wq = (const float*)d_in[5];
    const float* bq = (const float*)d_in[6];
    const float* wk = (const float*)d_in[7];
    const float* bk = (const float*)d_in[8];
    const float* wv = (const float*)d_in[9];
    const float* bv = (const float*)d_in[10];
    const float* wo = (const float*)d_in[11];
    const float* bo = (const float*)d_in[12];
    const float* ff_g = (const float*)d_in[13];
    const float* ff_b = (const float*)d_in[14];
    const float* w1 = (const float*)d_in[15];
    const float* b1 = (const float*)d_in[16];
    const float* w2 = (const float*)d_in[17];
    const float* b2 = (const float*)d_in[18];
    const float* lo_g = (const float*)d_in[19];
    const float* lo_b = (const float*)d_in[20];
    const float* w_out = (const float*)d_in[21];
    const float* b_out = (const float*)d_in[22];
    const float* lng = (const float*)d_in[23];
    const float* lnb = (const float*)d_in[24];
    float* out = (float*)d_out;

    float* fa = nullptr; BF* bf = nullptr;
    cudaGetSymbolAddress((void**)&fa, g_arena);
    cudaGetSymbolAddress((void**)&bf, g_bf);

    cudaFuncSetAttribute(gemm_tcp, cudaFuncAttributeMaxDynamicSharedMemorySize,
                         2 * STG * (int)sizeof(BF));
    const int SMEMB = 2 * STG * (int)sizeof(BF);

    float* X    = fa + F_X;
    float* S    = fa + F_S;
    float* MEMS = fa + F_MEMS;
    float* Qb   = fa + F_QB;
    float* KVf  = fa + F_KV;
    float* Ob   = fa + F_OB;
    float* H2   = fa + F_H2;
    float* Yb   = fa + F_YB;
    float* BKV  = fa + F_BKV;

    BF* QINh = bf + BA_QIN; BF* QINl = QINh + EA;
    BF* KINh = bf + BA_KIN; BF* KINl = KINh + EA;
    BF* ATTh = bf + BA_ATT; BF* ATTl = ATTh + EA;
    BF* HBh  = bf + BA_HB;  BF* HBl  = HBh + EHB;
    BF* FBh  = bf + BA_FB;  BF* FBl  = FBh + EFB;
    BF* YTh  = bf + BA_YT;  BF* YTl  = YTh + EYT;

    const int NS = SN * Bn * Dm_;     // 1,310,720
    const int NM = 15 * Bn * Dm_;     // 61,440

    // ---- per-replay preprocessing ----
    gemm_tc<<<dim3(1, 65), 256>>>(input, w_in, nullptr, X, 8320, 128, 80, 0);
    initS_k<<<dim3(SN, Bn), Dm_>>>(X, S);
    mems0_k<<<dim3(15, Bn), Dm_>>>(S, MEMS);

    wconv_k<<<dim3(16, 16, 8), 256>>>(wq, bf + BW_QT, bf + BW_QT + EQ, 512, 512, EQ, 2 * EQ);
    wconv_k<<<dim3(16, 16, 8), 256>>>(wk, bf + BW_KVT, bf + BW_KVT + EKV, 512, 512, EQ, 2 * EKV);
    wconv_k<<<dim3(16, 16, 8), 256>>>(wv, bf + BW_KVT + 262144, bf + BW_KVT + EKV + 262144,
                                      512, 512, EQ, 2 * EKV);
    wconv_k<<<dim3(16, 16, 8), 256>>>(wo, bf + BW_OT, bf + BW_OT + EQ, 512, 512, EQ, 2 * EQ);
    wconv_k<<<dim3(64, 16, 8), 256>>>(w1, bf + BW_W1T, bf + BW_W1T + EW1, 512, 2048, EW1, 2 * EW1);
    wconv_k<<<dim3(16, 64, 8), 256>>>(w2, bf + BW_W2T, bf + BW_W2T + EW1, 2048, 512, EW1, 2 * EW1);
    wconv_k<<<dim3(32, 16, 1), 256>>>(w_out, bf + BW_OUTT, bf + BW_OUTT + EKV, 512, 1024, 0, 0);
    bkv_k<<<32, 256>>>(bk, bv, BKV);
    kinpad_k<<<16, 256>>>(KINh, KINl);

    for (int l = 0; l < Ln; l++) {
        BF* WQTh  = bf + BW_QT  + (size_t)l * 2 * EQ;
        BF* WKVTh = bf + BW_KVT + (size_t)l * 2 * EKV;
        BF* WOTh  = bf + BW_OT  + (size_t)l * 2 * EQ;
        BF* W1Th  = bf + BW_W1T + (size_t)l * 2 * EW1;
        BF* W2Th  = bf + BW_W2T + (size_t)l * 2 * EW1;

        ln_row_k<<<SN * Bn / 8, 256>>>(S, nullptr, ln_in_g + l * Dm_, ln_in_b + l * Dm_,
                                       nullptr, QINh, QINl, KINh, KINl,
                                       SN * Bn, Dm_, 120);
        summary_pl_k<<<dim3(NSEG, Bn), Dm_>>>(QINh, QINl);
        mems2pl_k<<<(NM + 255) / 256, 256>>>(MEMS, KINh, KINl, NM);

        gemm_tcp<<<dim3(4, 21), 256, SMEMB>>>(QINh, QINl, WQTh, WQTh + EQ,
                                              bq + l * Dm_, Qb, nullptr, nullptr,
                                              2688, 512, 512, 0);
        gemm_tcp<<<dim3(8, 21), 256, SMEMB>>>(KINh, KINl, WKVTh, WKVTh + EKV,
                                              BKV + l * 1024, KVf, nullptr, nullptr,
                                              2688, 1024, 512, 0);

        attn_k<<<dim3(QN, Bn), 256>>>(Qb, KVf, lengths, ATTh, ATTl);

        gemm_tcp<<<dim3(4, 21), 256, SMEMB>>>(ATTh, ATTl, WOTh, WOTh + EQ,
                                              bo + l * Dm_, Ob, nullptr, nullptr,
                                              2688, 512, 512, 0);

        addinto_k<<<(NS + 255) / 256, 256>>>(S, Ob, NS);
        tanh_k<<<(NM + 255) / 256, 256>>>(Ob + NS, MEMS, NM);

        ln_row_k<<<SN * Bn / 8, 256>>>(S, nullptr, ff_g + l * Dm_, ff_b + l * Dm_,
                                       nullptr, HBh, HBl, nullptr, nullptr,
                                       SN * Bn, Dm_, 0);
        gemm_tcp<<<dim3(16, 20), 256, SMEMB>>>(HBh, HBl, W1Th, W1Th + EW1,
                                               b1 + l * FFNn, nullptr, FBh, FBl,
                                               2560, 2048, 512, 1);
        gemm_tcp<<<dim3(4, 20), 256, SMEMB>>>(FBh, FBl, W2Th, W2Th + EW1,
                                              b2 + l * Dm_, H2, nullptr, nullptr,
                                              2560, 512, 2048, 0);
        ln_row_k<<<SN * Bn / 8, 256>>>(S, H2, lo_g + l * Dm_, lo_b + l * Dm_,
                                       S, nullptr, nullptr, nullptr, nullptr,
                                       SN * Bn, Dm_, 0);
    }

    transpose_pl_k<<<2048, Dm_>>>(S, YTh, YTl);
    gemm_tcp<<<dim3(8, 16), 256, SMEMB>>>(YTh, YTl, bf + BW_OUTT, bf + BW_OUTT + EKV,
                                          b_out, Yb, nullptr, nullptr,
                                          2048, 1024, 512, 0);
    ln_row_k<<<2048 / 8, 256>>>(Yb, nullptr, lng, lnb, out,
                                nullptr, nullptr, nullptr, nullptr, 2048, OUTn, 0);

    if (out_size >= 2048 * 1024 + Bn)
        lr_k<<<1, 32>>>(lengths, out + 2048 * 1024);
}

// round 6
// speedup vs baseline: 4.0411x; 2.0417x over previous
#include <cuda_runtime.h>
#include <cuda_bf16.h>
#include <cuda.h>
#include <math.h>
#include <stdint.h>

typedef __nv_bfloat16 BF;
typedef __nv_bfloat162 BF2;

// ---------------- constants ----------------
#define Bn   8
#define Dm_  512
#define FFNn 2048
#define Ln   8
#define OUTn 1024
#define Hn   8
#define DHn  64
#define QN   336
#define KN   335
#define SN   320
#define RTn  64
#define Un   256
#define NSEG 16

// ------- float arena -------
#define F_X    0UL
#define F_S    (F_X + 8320UL*128UL)
#define F_MEMS (F_S + 1310720UL)
#define F_QB   (F_MEMS + 61440UL)
#define F_KV   (F_QB + 1376256UL)
#define F_OB   (F_KV + 2752512UL)
#define F_H2   (F_OB + 1376256UL)
#define F_YB   (F_H2 + 1310720UL)
#define F_BKV  (F_YB + 2097152UL)
#define F_TOTAL (F_BKV + 8192UL)
__device__ __align__(1024) float g_arena[F_TOTAL];

// ------- bf16 arena (hi plane at base, lo plane at base+E) -------
#define EQ   262144UL
#define EKV  524288UL
#define EW1  1048576UL
#define EA   1376256UL     // 2688*512
#define EHB  1310720UL     // 2560*512
#define EFB  5242880UL     // 2560*2048
#define EYT  1048576UL     // 2048*512

#define BW_QT   0UL
#define BW_KVT  (BW_QT   + 8UL*2UL*EQ)
#define BW_OT   (BW_KVT  + 8UL*2UL*EKV)
#define BW_W1T  (BW_OT   + 8UL*2UL*EQ)
#define BW_W2T  (BW_W1T  + 8UL*2UL*EW1)
#define BW_OUTT (BW_W2T  + 8UL*2UL*EW1)
#define BA_QIN  (BW_OUTT + 2UL*EKV)
#define BA_KIN  (BA_QIN  + 2UL*EA)
#define BA_ATT  (BA_KIN  + 2UL*EA)
#define BA_HB   (BA_ATT  + 2UL*EA)
#define BA_FB   (BA_HB   + 2UL*EHB)
#define BA_YT   (BA_FB   + 2UL*EFB)
#define B_TOTAL (BA_YT   + 2UL*EYT)
__device__ __align__(1024) BF g_bf[B_TOTAL];

__device__ __forceinline__ void split2(float x, BF& h, BF& l) {
    h = __float2bfloat16(x);
    l = __float2bfloat16(x - __bfloat162float(h));
}

// ============ TMA / mbarrier primitives ============
__device__ __forceinline__ uint32_t smem_u32(const void* p) {
    return (uint32_t)__cvta_generic_to_shared(p);
}
__device__ __forceinline__ void mbar_init(uint32_t a, uint32_t cnt) {
    asm volatile("mbarrier.init.shared::cta.b64 [%0], %1;" :: "r"(a), "r"(cnt) : "memory");
}
__device__ __forceinline__ void mbar_expect(uint32_t a, uint32_t tx) {
    asm volatile("mbarrier.arrive.expect_tx.shared::cta.b64 _, [%0], %1;"
                 :: "r"(a), "r"(tx) : "memory");
}
__device__ __forceinline__ void mbar_arrive(uint32_t a) {
    asm volatile("mbarrier.arrive.shared::cta.b64 _, [%0];" :: "r"(a) : "memory");
}
__device__ __forceinline__ void mbar_wait(uint32_t a, uint32_t ph) {
    uint32_t done = 0;
    while (!done) {
        asm volatile(
            "{\n\t.reg .pred p;\n\t"
            "mbarrier.try_wait.parity.acquire.cta.shared::cta.b64 p, [%1], %2, 0x989680;\n\t"
            "selp.b32 %0, 1, 0, p;\n\t}"
            : "=r"(done) : "r"(a), "r"(ph) : "memory");
    }
}
__device__ __forceinline__ void tma3d(uint32_t dst, const void* map,
                                      int cx, int cy, int cz, uint32_t mbar) {
    asm volatile(
        "cp.async.bulk.tensor.3d.shared::cta.global.tile.mbarrier::complete_tx::bytes "
        "[%0], [%1, {%2, %3, %4}], [%5];"
        :: "r"(dst), "l"(map), "r"(cx), "r"(cy), "r"(cz), "r"(mbar) : "memory");
}
__device__ __forceinline__ void mma2(float c[4], const uint32_t a[4],
                                     uint32_t b0, uint32_t b1) {
    asm volatile(
        "mma.sync.aligned.m16n8k16.row.col.f32.bf16.bf16.f32 "
        "{%0,%1,%2,%3}, {%4,%5,%6,%7}, {%8,%9}, {%0,%1,%2,%3};\n"
        : "+f"(c[0]), "+f"(c[1]), "+f"(c[2]), "+f"(c[3])
        : "r"(a[0]), "r"(a[1]), "r"(a[2]), "r"(a[3]), "r"(b0), "r"(b1));
}
#define LDSM4(r, a) \
    asm volatile("ldmatrix.sync.aligned.m8n8.x4.shared.b16 {%0,%1,%2,%3}, [%4];" \
        : "=r"((r)[0]), "=r"((r)[1]), "=r"((r)[2]), "=r"((r)[3]) : "r"(a))

// ============ TMA-staged mma.sync GEMM ============
// C = act(A @ B^T + bias). A:(M,K) bf16 hi/lo planes, B:(N,K) planes (tensormaps,
// SWIZZLE_128B, box 64x128). grid (N/128, M/128). 256 thr. K%64==0, M%128==0.
#define NST 3
#define STB 65536
#define SM6_TOTAL (2048 + NST * STB)

__global__ __launch_bounds__(256) void gemm6(
    const __grid_constant__ CUtensorMap tmA,
    const __grid_constant__ CUtensorMap tmB,
    const float* __restrict__ bias, float* __restrict__ Cf,
    BF* __restrict__ Ch, BF* __restrict__ Cl,
    int N, int K, int act)
{
    extern __shared__ __align__(1024) char smx[];
    const uint32_t sb = smem_u32(smx);
    const uint32_t db = (sb + 1023) & ~1023u;     // 1024-aligned data base
    const int tid = threadIdx.x, lane = tid & 31, wid = tid >> 5;
    const int wm = wid & 3, wn = wid >> 2;
    const int grp = lane >> 2, tig = lane & 3;
    const int row0 = blockIdx.y * 128, col0 = blockIdx.x * 128;
    const int T = K >> 6;

    // barriers live in the pad below db? db may equal sb; put barriers at db + NST*STB
    const uint32_t barb = db + NST * STB;
    if (tid == 0) {
        for (int s = 0; s < NST; s++) {
            mbar_init(barb + s * 8, 1);          // full (tx)
            mbar_init(barb + 64 + s * 8, 256);   // empty (all threads)
        }
    }
    __syncthreads();

    if (tid == 0) {
        for (int s = 0; s < NST; s++) {
            uint32_t st = db + s * STB, fb = barb + s * 8;
            mbar_expect(fb, STB);
            tma3d(st,         &tmA, s * 64, row0, 0, fb);
            tma3d(st + 16384, &tmA, s * 64, row0, 1, fb);
            tma3d(st + 32768, &tmB, s * 64, col0, 0, fb);
            tma3d(st + 49152, &tmB, s * 64, col0, 1, fb);
        }
    }

    float acc[2][8][4] = {};
    // ldmatrix lane geometry
    const int lrow = (lane & 7) + (((lane >> 3) & 1) << 3);
    const int kofs = ((lane >> 4) & 1) * 8;
    const uint32_t msk = (uint32_t)(lane & 7) << 4;
    uint32_t arow_off[2], brow_off[4];
#pragma unroll
    for (int mt = 0; mt < 2; mt++) arow_off[mt] = (uint32_t)(wm * 32 + mt * 16 + lrow) * 128;
#pragma unroll
    for (int p = 0; p < 4; p++)    brow_off[p]  = (uint32_t)(wn * 64 + p * 16 + lrow) * 128;

    uint32_t pfm = 0, pem = 0;
    for (int i = 0; i < T; i++) {
        const int bslot = i % NST;
        const uint32_t fb = barb + bslot * 8, eb = barb + 64 + bslot * 8;
        mbar_wait(fb, (pfm >> bslot) & 1); pfm ^= (1u << bslot);
        const uint32_t sA = db + bslot * STB, sB = sA + 32768;
#pragma unroll
        for (int kk = 0; kk < 4; kk++) {
            const uint32_t csw = ((uint32_t)((kk * 16 + kofs) * 2)) ^ msk;
            uint32_t ah[2][4], al_[2][4], bh[4][4], bl_[4][4];
#pragma unroll
            for (int mt = 0; mt < 2; mt++) {
                uint32_t ad = sA + arow_off[mt] + csw;
                LDSM4(ah[mt], ad);
                LDSM4(al_[mt], ad + 16384);
            }
#pragma unroll
            for (int p = 0; p < 4; p++) {
                uint32_t bd = sB + brow_off[p] + csw;
                LDSM4(bh[p], bd);
                LDSM4(bl_[p], bd + 16384);
            }
#pragma unroll
            for (int nt = 0; nt < 8; nt++) {
                const int p = nt >> 1, s1 = nt & 1;
                mma2(acc[0][nt], ah[0], bh[p][s1], bh[p][2 + s1]);
                mma2(acc[1][nt], ah[1], bh[p][s1], bh[p][2 + s1]);
                mma2(acc[0][nt], al_[0], bh[p][s1], bh[p][2 + s1]);
                mma2(acc[1][nt], al_[1], bh[p][s1], bh[p][2 + s1]);
                mma2(acc[0][nt], ah[0], bl_[p][s1], bl_[p][2 + s1]);
                mma2(acc[1][nt], ah[1], bl_[p][s1], bl_[p][2 + s1]);
            }
        }
        mbar_arrive(eb);
        if (tid == 0 && i + NST < T) {
            mbar_wait(eb, (pem >> bslot) & 1); pem ^= (1u << bslot);
            uint32_t st = db + bslot * STB;
            mbar_expect(fb, STB);
            int k0 = (i + NST) * 64;
            tma3d(st,         &tmA, k0, row0, 0, fb);
            tma3d(st + 16384, &tmA, k0, row0, 1, fb);
            tma3d(st + 32768, &tmB, k0, col0, 0, fb);
            tma3d(st + 49152, &tmB, k0, col0, 1, fb);
        }
    }

    // ---- epilogue ----
#pragma unroll
    for (int mt = 0; mt < 2; mt++) {
        const long r = row0 + wm * 32 + mt * 16 + grp;
#pragma unroll
        for (int nt = 0; nt < 8; nt++) {
            const long c = col0 + wn * 64 + nt * 8 + tig * 2;
            float bb0 = bias ? bias[c] : 0.f, bb1 = bias ? bias[c + 1] : 0.f;
            float v0 = acc[mt][nt][0] + bb0, v1 = acc[mt][nt][1] + bb1;
            float v2 = acc[mt][nt][2] + bb0, v3 = acc[mt][nt][3] + bb1;
            if (act) {
                v0 = fmaxf(v0, 0.f); v1 = fmaxf(v1, 0.f);
                v2 = fmaxf(v2, 0.f); v3 = fmaxf(v3, 0.f);
            }
            if (Cf) {
                *(float2*)&Cf[r * N + c]       = make_float2(v0, v1);
                *(float2*)&Cf[(r + 8) * N + c] = make_float2(v2, v3);
            }
            if (Ch) {
                BF h0, l0, h1, l1;
                split2(v0, h0, l0); split2(v1, h1, l1);
                *(BF2*)&Ch[r * N + c] = BF2(h0, h1);
                *(BF2*)&Cl[r * N + c] = BF2(l0, l1);
                split2(v2, h0, l0); split2(v3, h1, l1);
                *(BF2*)&Ch[(r + 8) * N + c] = BF2(h0, h1);
                *(BF2*)&Cl[(r + 8) * N + c] = BF2(l0, l1);
            }
        }
    }
}

// ---------------- legacy in-kernel-convert GEMM (input proj, K=80) ---------
#define LLDA 40
__global__ __launch_bounds__(256) void gemm_tc(
    const float* __restrict__ A, const float* __restrict__ W,
    const float* __restrict__ bias, float* __restrict__ C,
    int M, int N, int K, int act)
{
    __shared__ BF Ahs[128 * LLDA], Als[128 * LLDA];
    __shared__ BF Bhs[128 * LLDA], Bls[128 * LLDA];
    const int tid = threadIdx.x, lane = tid & 31, wid = tid >> 5;
    const int wm = wid & 3, wn = wid >> 2;
    const int grp = lane >> 2, tig = lane & 3;
    const long row0 = (long)blockIdx.y * 128;
    const int  col0 = blockIdx.x * 128;
    float acc[2][8][4] = {};
    const int arow = tid >> 1, acol0 = (tid & 1) * 16;
    const int brow = tid >> 3, bcol0 = (tid & 7) * 16;

    for (int k0 = 0; k0 < K; k0 += 32) {
#pragma unroll
        for (int j = 0; j < 4; j++) {
            int c = acol0 + j * 4;
            float4 v = make_float4(0.f, 0.f, 0.f, 0.f);
            if (row0 + arow < M && k0 + c < K)
                v = *(const float4*)&A[(row0 + arow) * (long)K + k0 + c];
            BF h, l; int o = arow * LLDA + c;
            split2(v.x, h, l); Ahs[o]     = h; Als[o]     = l;
            split2(v.y, h, l); Ahs[o + 1] = h; Als[o + 1] = l;
            split2(v.z, h, l); Ahs[o + 2] = h; Als[o + 2] = l;
            split2(v.w, h, l); Ahs[o + 3] = h; Als[o + 3] = l;
        }
#pragma unroll
        for (int j = 0; j < 4; j++) {
            int n = bcol0 + j * 4;
            float4 v = make_float4(0.f, 0.f, 0.f, 0.f);
            if (k0 + brow < K)
                v = *(const float4*)&W[(long)(k0 + brow) * N + col0 + n];
            BF h, l;
            split2(v.x, h, l); Bhs[(n + 0) * LLDA + brow] = h; Bls[(n + 0) * LLDA + brow] = l;
            split2(v.y, h, l); Bhs[(n + 1) * LLDA + brow] = h; Bls[(n + 1) * LLDA + brow] = l;
            split2(v.z, h, l); Bhs[(n + 2) * LLDA + brow] = h; Bls[(n + 2) * LLDA + brow] = l;
            split2(v.w, h, l); Bhs[(n + 3) * LLDA + brow] = h; Bls[(n + 3) * LLDA + brow] = l;
        }
        __syncthreads();
#pragma unroll
        for (int kk = 0; kk < 32; kk += 16) {
            uint32_t ah[2][4], al[2][4];
#pragma unroll
            for (int mt = 0; mt < 2; mt++) {
                int r = wm * 32 + mt * 16;
                int o  = (r + grp) * LLDA + kk + tig * 2;
                int o8 = o + 8 * LLDA;
                ah[mt][0] = *(const uint32_t*)&Ahs[o];
                ah[mt][1] = *(const uint32_t*)&Ahs[o8];
                ah[mt][2] = *(const uint32_t*)&Ahs[o + 8];
                ah[mt][3] = *(const uint32_t*)&Ahs[o8 + 8];
                al[mt][0] = *(const uint32_t*)&Als[o];
                al[mt][1] = *(const uint32_t*)&Als[o8];
                al[mt][2] = *(const uint32_t*)&Als[o + 8];
                al[mt][3] = *(const uint32_t*)&Als[o8 + 8];
            }
#pragma unroll
            for (int nt = 0; nt < 8; nt++) {
                int nn = wn * 64 + nt * 8 + grp;
                int o = nn * LLDA + kk + tig * 2;
                uint32_t b0 = *(const uint32_t*)&Bhs[o], b1 = *(const uint32_t*)&Bhs[o + 8];
                uint32_t c0 = *(const uint32_t*)&Bls[o], c1 = *(const uint32_t*)&Bls[o + 8];
#pragma unroll
                for (int mt = 0; mt < 2; mt++) {
                    mma2(acc[mt][nt], ah[mt], b0, b1);
                    mma2(acc[mt][nt], al[mt], b0, b1);
                    mma2(acc[mt][nt], ah[mt], c0, c1);
                }
            }
        }
        __syncthreads();
    }
#pragma unroll
    for (int mt = 0; mt < 2; mt++) {
#pragma unroll
        for (int nt = 0; nt < 8; nt++) {
            int c = col0 + wn * 64 + nt * 8 + tig * 2;
            float b0 = bias ? bias[c] : 0.f;
            float b1 = bias ? bias[c + 1] : 0.f;
            long r = row0 + wm * 32 + mt * 16 + grp;
            float v0 = acc[mt][nt][0] + b0, v1 = acc[mt][nt][1] + b1;
            float v2 = acc[mt][nt][2] + b0, v3 = acc[mt][nt][3] + b1;
            if (act) { v0=fmaxf(v0,0.f); v1=fmaxf(v1,0.f); v2=fmaxf(v2,0.f); v3=fmaxf(v3,0.f); }
            if (r < M)     *(float2*)&C[r * N + c]       = make_float2(v0, v1);
            if (r + 8 < M) *(float2*)&C[(r + 8) * N + c] = make_float2(v2, v3);
        }
    }
}

// ---------------- weight transpose+convert: out[n][k] = W[k][n] ----------
__global__ void wconv_k(const float* __restrict__ W, BF* __restrict__ oh,
                        BF* __restrict__ ol, int K, int N, long inS, long outS)
{
    __shared__ float t[32][33];
    const float* w = W + (long)blockIdx.z * inS;
    BF* ph = oh + (long)blockIdx.z * outS;
    BF* pl = ol + (long)blockIdx.z * outS;
    const int n0 = blockIdx.x * 32, k0 = blockIdx.y * 32;
    const int tx = threadIdx.x & 31, ty0 = threadIdx.x >> 5;
#pragma unroll
    for (int i = 0; i < 4; i++) {
        int ky = ty0 + i * 8;
        t[ky][tx] = w[(long)(k0 + ky) * N + n0 + tx];
    }
    __syncthreads();
#pragma unroll
    for (int i = 0; i < 4; i++) {
        int ny = ty0 + i * 8;
        float v = t[tx][ny];
        BF h, l; split2(v, h, l);
        ph[(long)(n0 + ny) * K + k0 + tx] = h;
        pl[(long)(n0 + ny) * K + k0 + tx] = l;
    }
}

__global__ void bkv_k(const float* __restrict__ bk, const float* __restrict__ bv,
                      float* __restrict__ bkv)
{
    int i = blockIdx.x * blockDim.x + threadIdx.x;
    if (i < 8192) {
        int l = i >> 10, j = i & 1023;
        bkv[i] = (j < 512) ? bk[l * 512 + j] : bv[l * 512 + j - 512];
    }
}

__global__ void kinpad_k(BF* __restrict__ kh, BF* __restrict__ kl)
{
    int i = threadIdx.x + blockIdx.x * blockDim.x;  // 4096
    size_t o = 2680UL * 512UL + i;
    kh[o] = __float2bfloat16(0.f);
    kl[o] = __float2bfloat16(0.f);
}

// ---------------- LayerNorm: warp per row ----------------
__global__ __launch_bounds__(256) void ln_row_k(
    const float* __restrict__ X, const float* __restrict__ X2,
    const float* __restrict__ g, const float* __restrict__ bta,
    float* __restrict__ outf,
    BF* __restrict__ oh1, BF* __restrict__ ol1,
    BF* __restrict__ oh2, BF* __restrict__ ol2,
    int rows, int D, int rowoff2)
{
    const int wid = threadIdx.x >> 5, lane = threadIdx.x & 31;
    const int row = blockIdx.x * 8 + wid;
    if (row >= rows) return;
    const float4* x  = (const float4*)(X + (long)row * D);
    const float4* x2 = X2 ? (const float4*)(X2 + (long)row * D) : nullptr;
    const int cnt = D >> 7;

    float s = 0.f, s2 = 0.f;
    for (int i = 0; i < cnt; i++) {
        float4 a = x[lane + i * 32];
        if (x2) {
            float4 b = x2[lane + i * 32];
            a.x += b.x; a.y += b.y; a.z += b.z; a.w += b.w;
        }
        s  += a.x + a.y + a.z + a.w;
        s2 += a.x * a.x + a.y * a.y + a.z * a.z + a.w * a.w;
    }
#pragma unroll
    for (int o = 16; o; o >>= 1) {
        s  += __shfl_xor_sync(~0u, s, o);
        s2 += __shfl_xor_sync(~0u, s2, o);
    }
    const float mean = s / D;
    const float inv = rsqrtf(s2 / D - mean * mean + 1e-5f);
    const float4* gg = (const float4*)g;
    const float4* bb = (const float4*)bta;
    for (int i = 0; i < cnt; i++) {
        int idx = lane + i * 32;
        float4 a = x[idx];
        if (x2) {
            float4 b = x2[idx];
            a.x += b.x; a.y += b.y; a.z += b.z; a.w += b.w;
        }
        float4 gv = gg[idx], bv = bb[idx];
        float4 o;
        o.x = (a.x - mean) * inv * gv.x + bv.x;
        o.y = (a.y - mean) * inv * gv.y + bv.y;
        o.z = (a.z - mean) * inv * gv.z + bv.z;
        o.w = (a.w - mean) * inv * gv.w + bv.w;
        if (outf) ((float4*)(outf + (long)row * D))[idx] = o;
        if (oh1) {
            BF h0,l0,h1,l1,h2,l2,h3,l3;
            split2(o.x,h0,l0); split2(o.y,h1,l1);
            split2(o.z,h2,l2); split2(o.w,h3,l3);
            long base = (long)row * D + idx * 4;
            *(BF2*)&oh1[base]     = BF2(h0,h1);
            *(BF2*)&oh1[base + 2] = BF2(h2,h3);
            *(BF2*)&ol1[base]     = BF2(l0,l1);
            *(BF2*)&ol1[base + 2] = BF2(l2,l3);
            if (oh2) {
                long b2o = (long)(row + rowoff2) * D + idx * 4;
                *(BF2*)&oh2[b2o]     = BF2(h0,h1);
                *(BF2*)&oh2[b2o + 2] = BF2(h2,h3);
                *(BF2*)&ol2[b2o]     = BF2(l0,l1);
                *(BF2*)&ol2[b2o + 2] = BF2(l2,l3);
            }
        }
    }
}

// ---------------- misc ----------------
__global__ void initS_k(const float* __restrict__ X, float* __restrict__ S)
{
    const int t = blockIdx.x, b = blockIdx.y, d = threadIdx.x;
    int frame;
    if (t < RTn) {
        int si = t >> 2;
        int st = (si == 15) ? 256 : (si + 1) * 16;
        frame = st + (t & 3);
    } else frame = t - RTn;
    S[((size_t)t * Bn + b) * Dm_ + d] = X[(size_t)b * 133120 + (size_t)frame * Dm_ + d];
}

__global__ void mems0_k(const float* __restrict__ S, float* __restrict__ M)
{
    const int s = blockIdx.x, b = blockIdx.y, d = threadIdx.x;
    size_t base = ((size_t)(RTn + s * 16) * Bn + b) * Dm_ + d;
    float acc = 0.f;
#pragma unroll
    for (int k = 0; k < 16; k++) acc += S[base + (size_t)k * Bn * Dm_];
    M[((size_t)s * Bn + b) * Dm_ + d] = acc * (1.f / 16.f);
}

__global__ void summary_pl_k(BF* __restrict__ qh, BF* __restrict__ ql)
{
    const int s = blockIdx.x, b = blockIdx.y, d = threadIdx.x;
    size_t base = ((size_t)(RTn + s * 16) * Bn + b) * Dm_ + d;
    float acc = 0.f;
#pragma unroll
    for (int k = 0; k < 16; k++) {
        size_t o = base + (size_t)k * Bn * Dm_;
        acc += __bfloat162float(qh[o]) + __bfloat162float(ql[o]);
    }
    acc *= (1.f / 16.f);
    BF h, l; split2(acc, h, l);
    size_t o = ((size_t)(SN + s) * Bn + b) * Dm_ + d;
    qh[o] = h; ql[o] = l;
}

__global__ void mems2pl_k(const float* __restrict__ M, BF* __restrict__ kh,
                          BF* __restrict__ kl, int n)
{
    int i = blockIdx.x * blockDim.x + threadIdx.x;
    if (i < n) { BF h, l; split2(M[i], h, l); kh[i] = h; kl[i] = l; }
}

__global__ void addinto_k(float* __restrict__ dst, const float* __restrict__ src, int n)
{
    int i = blockIdx.x * blockDim.x + threadIdx.x;
    if (i < n) dst[i] += src[i];
}
__global__ void tanh_k(const float* __restrict__ src, float* __restrict__ dst, int n)
{
    int i = blockIdx.x * blockDim.x + threadIdx.x;
    if (i < n) dst[i] = tanhf(src[i]);
}

// ---------------- attention ----------------
__global__ __launch_bounds__(256) void attn_k(
    const float* __restrict__ Qb, const float* __restrict__ KVf,
    const int* __restrict__ lengths, BF* __restrict__ Ah, BF* __restrict__ Al)
{
    __shared__ float sc[Hn][64];
    __shared__ short ki[Hn][64];
    const int qi = blockIdx.x, b = blockIdx.y;
    const int h = threadIdx.x >> 5, lane = threadIdx.x & 31;

    int maxlr = 0;
#pragma unroll
    for (int i = 0; i < Bn; i++) maxlr = max(maxlr, lengths[i] >> 2);
    const int lrb = lengths[b] >> 2;

    int seg; bool summ = false;
    if (qi < RTn)      seg = qi >> 2;
    else if (qi < SN)  seg = (qi - RTn) >> 4;
    else             { seg = qi - SN; summ = true; }
    const int ms  = max(seg - 4, 0);
    const int ss  = max(seg * 16 - 32, 0);
    const int se  = min(seg * 16 + 16, Un);
    const int ue  = min(se, lrb + 256 - maxlr);
    const int rcs = 15 + seg * 4;

    const int c0 = summ ? 0 : (seg - ms);
    const int c2 = max(ue - ss, 0);
    const int n  = c0 + 4 + c2;

    for (int j = lane; j < n; j += 32) {
        int k;
        if (j < c0)          k = ms + j;
        else if (j < c0 + 4) k = rcs + (j - c0);
        else                 k = 79 + ss + (j - c0 - 4);
        ki[h][j] = (short)k;
    }
    __syncwarp();

    const float* qp = Qb + ((size_t)qi * Bn + b) * Dm_ + h * DHn;
    const float q0 = qp[2 * lane]     * 0.125f;
    const float q1 = qp[2 * lane + 1] * 0.125f;
    const float* Kbh = KVf + (size_t)b * 1024 + h * DHn;
    const float* Vbh = Kbh + 512;

    for (int j = 0; j < n; j++) {
        const float* kp = Kbh + (size_t)ki[h][j] * (Bn * 1024);
        float p = fmaf(q0, kp[2 * lane], q1 * kp[2 * lane + 1]);
#pragma unroll
        for (int o = 16; o; o >>= 1) p += __shfl_xor_sync(~0u, p, o);
        if (lane == 0) sc[h][j] = p;
    }
    __syncwarp();

    float m = -3.4e38f;
    for (int j = lane; j < n; j += 32) m = fmaxf(m, sc[h][j]);
#pragma unroll
    for (int o = 16; o; o >>= 1) m = fmaxf(m, __shfl_xor_sync(~0u, m, o));
    float sum = 0.f;
    for (int j = lane; j < n; j += 32) {
        float e = expf(sc[h][j] - m);
        sc[h][j] = e;
        sum += e;
    }
#pragma unroll
    for (int o = 16; o; o >>= 1) sum += __shfl_xor_sync(~0u, sum, o);
    __syncwarp();
    const float inv = 1.f / sum;

    float a0 = 0.f, a1 = 0.f;
    for (int j = 0; j < n; j++) {
        float p = sc[h][j];
        const float* vp = Vbh + (size_t)ki[h][j] * (Bn * 1024);
        a0 = fmaf(p, vp[2 * lane], a0);
        a1 = fmaf(p, vp[2 * lane + 1], a1);
    }
    a0 *= inv; a1 *= inv;
    BF h0, l0, h1, l1;
    split2(a0, h0, l0); split2(a1, h1, l1);
    size_t op = ((size_t)qi * Bn + b) * Dm_ + h * DHn + 2 * lane;
    *(BF2*)&Ah[op] = BF2(h0, h1);
    *(BF2*)&Al[op] = BF2(l0, l1);
}

__global__ void transpose_pl_k(const float* __restrict__ S, BF* __restrict__ yh,
                               BF* __restrict__ yl)
{
    const int r = blockIdx.x, d = threadIdx.x;
    const int b = r >> 8, u = r & 255;
    float v = S[((size_t)(RTn + u) * Bn + b) * Dm_ + d];
    BF h, l; split2(v, h, l);
    yh[(size_t)r * Dm_ + d] = h;
    yl[(size_t)r * Dm_ + d] = l;
}

__global__ void lr_k(const int* __restrict__ lengths, float* __restrict__ out)
{
    int i = threadIdx.x;
    if (i < Bn) out[i] = (float)(lengths[i] >> 2);
}

// ---------------- host: tensormap plumbing ----------------
typedef CUresult (*EncFn)(CUtensorMap*, CUtensorMapDataType, cuuint32_t, void*,
                          const cuuint64_t*, const cuuint64_t*, const cuuint32_t*,
                          const cuuint32_t*, CUtensorMapInterleave, CUtensorMapSwizzle,
                          CUtensorMapL2promotion, CUtensorMapFloatOOBfill);

static EncFn get_enc() {
    void* p = nullptr;
    cudaDriverEntryPointQueryResult qr;
#if CUDART_VERSION >= 12050
    if (cudaGetDriverEntryPointByVersion("cuTensorMapEncodeTiled", &p, 12000,
                                         cudaEnableDefault, &qr) == cudaSuccess && p)
        return (EncFn)p;
    p = nullptr;
#endif
    cudaGetDriverEntryPoint("cuTensorMapEncodeTiled", &p, cudaEnableDefault, &qr);
    return (EncFn)p;
}

static CUtensorMap mkmap(EncFn enc, const BF* base, long K, long M, long planeStride) {
    CUtensorMap m;
    cuuint64_t dims[3]    = {(cuuint64_t)K, (cuuint64_t)M, 2};
    cuuint64_t strides[2] = {(cuuint64_t)K * 2, (cuuint64_t)planeStride * 2};
    cuuint32_t box[3]     = {64, 128, 1};
    cuuint32_t es[3]      = {1, 1, 1};
    enc(&m, CU_TENSOR_MAP_DATA_TYPE_BFLOAT16, 3, (void*)base, dims, strides, box, es,
        CU_TENSOR_MAP_INTERLEAVE_NONE, CU_TENSOR_MAP_SWIZZLE_128B,
        CU_TENSOR_MAP_L2_PROMOTION_L2_128B, CU_TENSOR_MAP_FLOAT_OOB_FILL_NONE);
    return m;
}

// ---------------- launch ----------------
extern "C" void kernel_launch(void* const* d_in, const int* in_sizes, int n_in,
                              void* d_out, int out_size)
{
    const float* input   = (const float*)d_in[0];
    const int*   lengths = (const int*)  d_in[1];
    const float* w_in    = (const float*)d_in[2];
    const float* ln_in_g = (const float*)d_in[3];
    const float* ln_in_b = (const float*)d_in[4];
    const float* wq = (const float*)d_in[5];
    const float* bq = (const float*)d_in[6];
    const float* wk = (const float*)d_in[7];
    const float* bk = (const float*)d_in[8];
    const float* wv = (const float*)d_in[9];
    const float* bv = (const float*)d_in[10];
    const float* wo = (const float*)d_in[11];
    const float* bo = (const float*)d_in[12];
    const float* ff_g = (const float*)d_in[13];
    const float* ff_b = (const float*)d_in[14];
    const float* w1 = (const float*)d_in[15];
    const float* b1 = (const float*)d_in[16];
    const float* w2 = (const float*)d_in[17];
    const float* b2 = (const float*)d_in[18];
    const float* lo_g = (const float*)d_in[19];
    const float* lo_b = (const float*)d_in[20];
    const float* w_out = (const float*)d_in[21];
    const float* b_out = (const float*)d_in[22];
    const float* lng = (const float*)d_in[23];
    const float* lnb = (const float*)d_in[24];
    float* out = (float*)d_out;

    float* fa = nullptr; BF* bf = nullptr;
    cudaGetSymbolAddress((void**)&fa, g_arena);
    cudaGetSymbolAddress((void**)&bf, g_bf);

    cudaFuncSetAttribute(gemm6, cudaFuncAttributeMaxDynamicSharedMemorySize, SM6_TOTAL);

    float* X    = fa + F_X;
    float* S    = fa + F_S;
    float* MEMS = fa + F_MEMS;
    float* Qb   = fa + F_QB;
    float* KVf  = fa + F_KV;
    float* Ob   = fa + F_OB;
    float* H2   = fa + F_H2;
    float* Yb   = fa + F_YB;
    float* BKV  = fa + F_BKV;

    BF* QINh = bf + BA_QIN; BF* QINl = QINh + EA;
    BF* KINh = bf + BA_KIN; BF* KINl = KINh + EA;
    BF* ATTh = bf + BA_ATT; BF* ATTl = ATTh + EA;
    BF* HBh  = bf + BA_HB;  BF* HBl  = HBh + EHB;
    BF* FBh  = bf + BA_FB;  BF* FBl  = FBh + EFB;
    BF* YTh  = bf + BA_YT;  BF* YTl  = YTh + EYT;

    EncFn enc = get_enc();
    CUtensorMap mQIN = mkmap(enc, QINh, 512, 2688, EA);
    CUtensorMap mKIN = mkmap(enc, KINh, 512, 2688, EA);
    CUtensorMap mATT = mkmap(enc, ATTh, 512, 2688, EA);
    CUtensorMap mHB  = mkmap(enc, HBh,  512, 2560, EHB);
    CUtensorMap mFB  = mkmap(enc, FBh, 2048, 2560, EFB);
    CUtensorMap mYT  = mkmap(enc, YTh,  512, 2048, EYT);
    CUtensorMap mOUT = mkmap(enc, bf + BW_OUTT, 512, 1024, EKV);
    CUtensorMap mWQ[Ln], mWKV[Ln], mWO[Ln], mW1[Ln], mW2[Ln];
    for (int l = 0; l < Ln; l++) {
        mWQ[l]  = mkmap(enc, bf + BW_QT  + (size_t)l * 2 * EQ,  512,  512, EQ);
        mWKV[l] = mkmap(enc, bf + BW_KVT + (size_t)l * 2 * EKV, 512, 1024, EKV);
        mWO[l]  = mkmap(enc, bf + BW_OT  + (size_t)l * 2 * EQ,  512,  512, EQ);
        mW1[l]  = mkmap(enc, bf + BW_W1T + (size_t)l * 2 * EW1, 512, 2048, EW1);
        mW2[l]  = mkmap(enc, bf + BW_W2T + (size_t)l * 2 * EW1, 2048, 512, EW1);
    }

    const int NS = SN * Bn * Dm_;
    const int NM = 15 * Bn * Dm_;

    // ---- per-replay preprocessing ----
    gemm_tc<<<dim3(1, 65), 256>>>(input, w_in, nullptr, X, 8320, 128, 80, 0);
    initS_k<<<dim3(SN, Bn), Dm_>>>(X, S);
    mems0_k<<<dim3(15, Bn), Dm_>>>(S, MEMS);

    wconv_k<<<dim3(16, 16, 8), 256>>>(wq, bf + BW_QT, bf + BW_QT + EQ, 512, 512, EQ, 2 * EQ);
    wconv_k<<<dim3(16, 16, 8), 256>>>(wk, bf + BW_KVT, bf + BW_KVT + EKV, 512, 512, EQ, 2 * EKV);
    wconv_k<<<dim3(16, 16, 8), 256>>>(wv, bf + BW_KVT + 262144, bf + BW_KVT + EKV + 262144,
                                      512, 512, EQ, 2 * EKV);
    wconv_k<<<dim3(16, 16, 8), 256>>>(wo, bf + BW_OT, bf + BW_OT + EQ, 512, 512, EQ, 2 * EQ);
    wconv_k<<<dim3(64, 16, 8), 256>>>(w1, bf + BW_W1T, bf + BW_W1T + EW1, 512, 2048, EW1, 2 * EW1);
    wconv_k<<<dim3(16, 64, 8), 256>>>(w2, bf + BW_W2T, bf + BW_W2T + EW1, 2048, 512, EW1, 2 * EW1);
    wconv_k<<<dim3(32, 16, 1), 256>>>(w_out, bf + BW_OUTT, bf + BW_OUTT + EKV, 512, 1024, 0, 0);
    bkv_k<<<32, 256>>>(bk, bv, BKV);
    kinpad_k<<<16, 256>>>(KINh, KINl);

    for (int l = 0; l < Ln; l++) {
        ln_row_k<<<SN * Bn / 8, 256>>>(S, nullptr, ln_in_g + l * Dm_, ln_in_b + l * Dm_,
                                       nullptr, QINh, QINl, KINh, KINl,
                                       SN * Bn, Dm_, 120);
        summary_pl_k<<<dim3(NSEG, Bn), Dm_>>>(QINh, QINl);
        mems2pl_k<<<(NM + 255) / 256, 256>>>(MEMS, KINh, KINl, NM);

        gemm6<<<dim3(4, 21), 256, SM6_TOTAL>>>(mQIN, mWQ[l], bq + l * Dm_,
                                               Qb, nullptr, nullptr, 512, 512, 0);
        gemm6<<<dim3(8, 21), 256, SM6_TOTAL>>>(mKIN, mWKV[l], BKV + l * 1024,
                                               KVf, nullptr, nullptr, 1024, 512, 0);

        attn_k<<<dim3(QN, Bn), 256>>>(Qb, KVf, lengths, ATTh, ATTl);

        gemm6<<<dim3(4, 21), 256, SM6_TOTAL>>>(mATT, mWO[l], bo + l * Dm_,
                                               Ob, nullptr, nullptr, 512, 512, 0);

        addinto_k<<<(NS + 255) / 256, 256>>>(S, Ob, NS);
        tanh_k<<<(NM + 255) / 256, 256>>>(Ob + NS, MEMS, NM);

        ln_row_k<<<SN * Bn / 8, 256>>>(S, nullptr, ff_g + l * Dm_, ff_b + l * Dm_,
                                       nullptr, HBh, HBl, nullptr, nullptr,
                                       SN * Bn, Dm_, 0);
        gemm6<<<dim3(16, 20), 256, SM6_TOTAL>>>(mHB, mW1[l], b1 + l * FFNn,
                                                nullptr, FBh, FBl, 2048, 512, 1);
        gemm6<<<dim3(4, 20), 256, SM6_TOTAL>>>(mFB, mW2[l], b2 + l * Dm_,
                                               H2, nullptr, nullptr, 512, 2048, 0);
        ln_row_k<<<SN * Bn / 8, 256>>>(S, H2, lo_g + l * Dm_, lo_b + l * Dm_,
                                       S, nullptr, nullptr, nullptr, nullptr,
                                       SN * Bn, Dm_, 0);
    }

    transpose_pl_k<<<2048, Dm_>>>(S, YTh, YTl);
    gemm6<<<dim3(8, 16), 256, SM6_TOTAL>>>(mYT, mOUT, b_out, Yb, nullptr, nullptr,
                                           1024, 512, 0);
    ln_row_k<<<2048 / 8, 256>>>(Yb, nullptr, lng, lnb, out,
                                nullptr, nullptr, nullptr, nullptr, 2048, OUTn, 0);

    if (out_size >= 2048 * 1024 + Bn)
        lr_k<<<1, 32>>>(lengths, out + 2048 * 1024);
}

// round 7
// speedup vs baseline: 4.3385x; 1.0736x over previous
#include <cuda_runtime.h>
#include <cuda_bf16.h>
#include <cuda.h>
#include <math.h>
#include <stdint.h>

typedef __nv_bfloat16 BF;
typedef __nv_bfloat162 BF2;

// ---------------- constants ----------------
#define Bn   8
#define Dm_  512
#define FFNn 2048
#define Ln   8
#define OUTn 1024
#define Hn   8
#define DHn  64
#define QN   336
#define SN   320
#define RTn  64
#define Un   256
#define NSEG 16

// token space: 0..14 mems | 15..78 rc | 79..334 utt | 335..350 summary | 351 pad
// row = token*8 + b;  M_UIN = 2816

// ------- float arena -------
#define F_X    0UL
#define F_S    (F_X + 1064960UL)
#define F_QKV  (F_S + 1310720UL)
#define F_H2A  (F_QKV + 4325376UL)
#define F_H2B  (F_H2A + 1310720UL)
#define F_YB   (F_H2B + 1310720UL)
#define F_BQKV (F_YB + 2097152UL)
#define F_TOT  (F_BQKV + 12288UL)
__device__ __align__(1024) float g_arena[F_TOT];

// ------- bf16 arena -------
#define EQ    262144UL
#define EQKV  786432UL     // 1536*512
#define EW1   1048576UL
#define EOUT  524288UL
#define EU    1441792UL    // 2816*512
#define EAT   1376256UL    // 2688*512
#define EHB   1310720UL    // 2560*512
#define EFB   5242880UL    // 2560*2048
#define EYT   1048576UL    // 2048*512

#define BW_QKV 0UL
#define BW_O   (BW_QKV + 8UL*2UL*EQKV)
#define BW_1   (BW_O   + 8UL*2UL*EQ)
#define BW_2   (BW_1   + 8UL*2UL*EW1)
#define BW_OUT (BW_2   + 8UL*2UL*EW1)
#define BA_U   (BW_OUT + 2UL*EOUT)
#define BA_AT  (BA_U   + 2UL*EU)
#define BA_HB  (BA_AT  + 2UL*EAT)
#define BA_FB  (BA_HB  + 2UL*EHB)
#define BA_YT  (BA_FB  + 2UL*EFB)
#define B_TOT  (BA_YT  + 2UL*EYT)
__device__ __align__(1024) BF g_bf[B_TOT];

__device__ __forceinline__ void split2(float x, BF& h, BF& l) {
    h = __float2bfloat16(x);
    l = __float2bfloat16(x - __bfloat162float(h));
}

// ============ TMA / mbarrier primitives ============
__device__ __forceinline__ uint32_t smem_u32(const void* p) {
    return (uint32_t)__cvta_generic_to_shared(p);
}
__device__ __forceinline__ void mbar_init(uint32_t a, uint32_t cnt) {
    asm volatile("mbarrier.init.shared::cta.b64 [%0], %1;" :: "r"(a), "r"(cnt) : "memory");
}
__device__ __forceinline__ void mbar_expect(uint32_t a, uint32_t tx) {
    asm volatile("mbarrier.arrive.expect_tx.shared::cta.b64 _, [%0], %1;"
                 :: "r"(a), "r"(tx) : "memory");
}
__device__ __forceinline__ void mbar_arrive(uint32_t a) {
    asm volatile("mbarrier.arrive.shared::cta.b64 _, [%0];" :: "r"(a) : "memory");
}
__device__ __forceinline__ void mbar_wait(uint32_t a, uint32_t ph) {
    uint32_t done = 0;
    while (!done) {
        asm volatile(
            "{\n\t.reg .pred p;\n\t"
            "mbarrier.try_wait.parity.acquire.cta.shared::cta.b64 p, [%1], %2, 0x989680;\n\t"
            "selp.b32 %0, 1, 0, p;\n\t}"
            : "=r"(done) : "r"(a), "r"(ph) : "memory");
    }
}
__device__ __forceinline__ void tma3d(uint32_t dst, const void* map,
                                      int cx, int cy, int cz, uint32_t mbar) {
    asm volatile(
        "cp.async.bulk.tensor.3d.shared::cta.global.tile.mbarrier::complete_tx::bytes "
        "[%0], [%1, {%2, %3, %4}], [%5];"
        :: "r"(dst), "l"(map), "r"(cx), "r"(cy), "r"(cz), "r"(mbar) : "memory");
}
__device__ __forceinline__ void mma2(float c[4], const uint32_t a[4],
                                     uint32_t b0, uint32_t b1) {
    asm volatile(
        "mma.sync.aligned.m16n8k16.row.col.f32.bf16.bf16.f32 "
        "{%0,%1,%2,%3}, {%4,%5,%6,%7}, {%8,%9}, {%0,%1,%2,%3};\n"
        : "+f"(c[0]), "+f"(c[1]), "+f"(c[2]), "+f"(c[3])
        : "r"(a[0]), "r"(a[1]), "r"(a[2]), "r"(a[3]), "r"(b0), "r"(b1));
}
#define LDSM4(r, a) \
    asm volatile("ldmatrix.sync.aligned.m8n8.x4.shared.b16 {%0,%1,%2,%3}, [%4];" \
        : "=r"((r)[0]), "=r"((r)[1]), "=r"((r)[2]), "=r"((r)[3]) : "r"(a))

// ============ TMA-staged mma.sync GEMM ============
// C = act(A @ B^T + bias). grid (N/128, M/128, splitZ).
// mode 0: fp32 Cf (+ z*czstride). mode 1: bf16 planes Ch/Cl.
// mode 2: fused O epilogue: rows<2560 S+=v; rows 2560..2679 planes=tanh(v).
#define NST 3
#define STB 65536
#define SM6_TOTAL (2048 + NST * STB)

__global__ __launch_bounds__(256) void gemm6(
    const __grid_constant__ CUtensorMap tmA,
    const __grid_constant__ CUtensorMap tmB,
    const float* __restrict__ bias, float* __restrict__ Cf, long czstride,
    BF* __restrict__ Ch, BF* __restrict__ Cl,
    int N, int K, int act, int mode)
{
    extern __shared__ __align__(1024) char smx[];
    const uint32_t sb = smem_u32(smx);
    const uint32_t db = (sb + 1023) & ~1023u;
    const int tid = threadIdx.x, lane = tid & 31, wid = tid >> 5;
    const int wm = wid & 3, wn = wid >> 2;
    const int grp = lane >> 2, tig = lane & 3;
    const int row0 = blockIdx.y * 128, col0 = blockIdx.x * 128;
    const int kstart = blockIdx.z * K;
    if (Cf && mode == 0) Cf += (long)blockIdx.z * czstride;
    const float* bi = (bias && kstart == 0) ? bias : nullptr;
    const int T = K >> 6;

    const uint32_t barb = db + NST * STB;
    if (tid == 0) {
        for (int s = 0; s < NST; s++) {
            mbar_init(barb + s * 8, 1);
            mbar_init(barb + 64 + s * 8, 256);
        }
    }
    __syncthreads();

    if (tid == 0) {
        for (int s = 0; s < NST; s++) {
            uint32_t st = db + s * STB, fb = barb + s * 8;
            mbar_expect(fb, STB);
            tma3d(st,         &tmA, kstart + s * 64, row0, 0, fb);
            tma3d(st + 16384, &tmA, kstart + s * 64, row0, 1, fb);
            tma3d(st + 32768, &tmB, kstart + s * 64, col0, 0, fb);
            tma3d(st + 49152, &tmB, kstart + s * 64, col0, 1, fb);
        }
    }

    float acc[2][8][4] = {};
    const int lrow = (lane & 7) + (((lane >> 3) & 1) << 3);
    const int kofs = ((lane >> 4) & 1) * 8;
    const uint32_t msk = (uint32_t)(lane & 7) << 4;
    uint32_t arow_off[2], brow_off[4];
#pragma unroll
    for (int mt = 0; mt < 2; mt++) arow_off[mt] = (uint32_t)(wm * 32 + mt * 16 + lrow) * 128;
#pragma unroll
    for (int p = 0; p < 4; p++)    brow_off[p]  = (uint32_t)(wn * 64 + p * 16 + lrow) * 128;

    uint32_t pfm = 0, pem = 0;
    for (int i = 0; i < T; i++) {
        const int bslot = i % NST;
        const uint32_t fb = barb + bslot * 8, eb = barb + 64 + bslot * 8;
        mbar_wait(fb, (pfm >> bslot) & 1); pfm ^= (1u << bslot);
        const uint32_t sA = db + bslot * STB, sB = sA + 32768;
#pragma unroll
        for (int kk = 0; kk < 4; kk++) {
            const uint32_t csw = ((uint32_t)((kk * 16 + kofs) * 2)) ^ msk;
            uint32_t ah[2][4], al_[2][4], bh[4][4], bl_[4][4];
#pragma unroll
            for (int mt = 0; mt < 2; mt++) {
                uint32_t ad = sA + arow_off[mt] + csw;
                LDSM4(ah[mt], ad);
                LDSM4(al_[mt], ad + 16384);
            }
#pragma unroll
            for (int p = 0; p < 4; p++) {
                uint32_t bd = sB + brow_off[p] + csw;
                LDSM4(bh[p], bd);
                LDSM4(bl_[p], bd + 16384);
            }
#pragma unroll
            for (int nt = 0; nt < 8; nt++) {
                const int p = nt >> 1, s1 = nt & 1;
                mma2(acc[0][nt], ah[0], bh[p][s1], bh[p][2 + s1]);
                mma2(acc[1][nt], ah[1], bh[p][s1], bh[p][2 + s1]);
                mma2(acc[0][nt], al_[0], bh[p][s1], bh[p][2 + s1]);
                mma2(acc[1][nt], al_[1], bh[p][s1], bh[p][2 + s1]);
                mma2(acc[0][nt], ah[0], bl_[p][s1], bl_[p][2 + s1]);
                mma2(acc[1][nt], ah[1], bl_[p][s1], bl_[p][2 + s1]);
            }
        }
        mbar_arrive(eb);
        if (tid == 0 && i + NST < T) {
            mbar_wait(eb, (pem >> bslot) & 1); pem ^= (1u << bslot);
            uint32_t st = db + bslot * STB;
            mbar_expect(fb, STB);
            int k0 = kstart + (i + NST) * 64;
            tma3d(st,         &tmA, k0, row0, 0, fb);
            tma3d(st + 16384, &tmA, k0, row0, 1, fb);
            tma3d(st + 32768, &tmB, k0, col0, 0, fb);
            tma3d(st + 49152, &tmB, k0, col0, 1, fb);
        }
    }

#pragma unroll
    for (int mt = 0; mt < 2; mt++) {
        const long r = row0 + wm * 32 + mt * 16 + grp;
#pragma unroll
        for (int nt = 0; nt < 8; nt++) {
            const long c = col0 + wn * 64 + nt * 8 + tig * 2;
            float bb0 = bi ? bi[c] : 0.f, bb1 = bi ? bi[c + 1] : 0.f;
            float v0 = acc[mt][nt][0] + bb0, v1 = acc[mt][nt][1] + bb1;
            float v2 = acc[mt][nt][2] + bb0, v3 = acc[mt][nt][3] + bb1;
            if (act) {
                v0 = fmaxf(v0, 0.f); v1 = fmaxf(v1, 0.f);
                v2 = fmaxf(v2, 0.f); v3 = fmaxf(v3, 0.f);
            }
            if (mode == 0) {
                *(float2*)&Cf[r * N + c]       = make_float2(v0, v1);
                *(float2*)&Cf[(r + 8) * N + c] = make_float2(v2, v3);
            } else if (mode == 1) {
                BF h0, l0, h1, l1;
                split2(v0, h0, l0); split2(v1, h1, l1);
                *(BF2*)&Ch[r * N + c] = BF2(h0, h1);
                *(BF2*)&Cl[r * N + c] = BF2(l0, l1);
                split2(v2, h0, l0); split2(v3, h1, l1);
                *(BF2*)&Ch[(r + 8) * N + c] = BF2(h0, h1);
                *(BF2*)&Cl[(r + 8) * N + c] = BF2(l0, l1);
            } else {
#pragma unroll
                for (int rr = 0; rr < 2; rr++) {
                    long r2 = r + rr * 8;
                    float u0 = rr ? v2 : v0, u1 = rr ? v3 : v1;
                    if (r2 < 2560) {
                        float2 s = *(float2*)&Cf[r2 * 512 + c];
                        *(float2*)&Cf[r2 * 512 + c] = make_float2(s.x + u0, s.y + u1);
                    } else if (r2 < 2680) {
                        float t0 = tanhf(u0), t1 = tanhf(u1);
                        BF h0, l0, h1, l1;
                        split2(t0, h0, l0); split2(t1, h1, l1);
                        long o = (r2 - 2560) * 512 + c;
                        *(BF2*)&Ch[o] = BF2(h0, h1);
                        *(BF2*)&Cl[o] = BF2(l0, l1);
                    }
                }
            }
        }
    }
}

// ---------------- legacy in-kernel-convert GEMM (input proj, K=80) ---------
#define LLDA 40
__global__ __launch_bounds__(256) void gemm_tc(
    const float* __restrict__ A, const float* __restrict__ W,
    const float* __restrict__ bias, float* __restrict__ C,
    int M, int N, int K, int act)
{
    __shared__ BF Ahs[128 * LLDA], Als[128 * LLDA];
    __shared__ BF Bhs[128 * LLDA], Bls[128 * LLDA];
    const int tid = threadIdx.x, lane = tid & 31, wid = tid >> 5;
    const int wm = wid & 3, wn = wid >> 2;
    const int grp = lane >> 2, tig = lane & 3;
    const long row0 = (long)blockIdx.y * 128;
    const int  col0 = blockIdx.x * 128;
    float acc[2][8][4] = {};
    const int arow = tid >> 1, acol0 = (tid & 1) * 16;
    const int brow = tid >> 3, bcol0 = (tid & 7) * 16;

    for (int k0 = 0; k0 < K; k0 += 32) {
#pragma unroll
        for (int j = 0; j < 4; j++) {
            int c = acol0 + j * 4;
            float4 v = make_float4(0.f, 0.f, 0.f, 0.f);
            if (row0 + arow < M && k0 + c < K)
                v = *(const float4*)&A[(row0 + arow) * (long)K + k0 + c];
            BF h, l; int o = arow * LLDA + c;
            split2(v.x, h, l); Ahs[o]     = h; Als[o]     = l;
            split2(v.y, h, l); Ahs[o + 1] = h; Als[o + 1] = l;
            split2(v.z, h, l); Ahs[o + 2] = h; Als[o + 2] = l;
            split2(v.w, h, l); Ahs[o + 3] = h; Als[o + 3] = l;
        }
#pragma unroll
        for (int j = 0; j < 4; j++) {
            int n = bcol0 + j * 4;
            float4 v = make_float4(0.f, 0.f, 0.f, 0.f);
            if (k0 + brow < K)
                v = *(const float4*)&W[(long)(k0 + brow) * N + col0 + n];
            BF h, l;
            split2(v.x, h, l); Bhs[(n + 0) * LLDA + brow] = h; Bls[(n + 0) * LLDA + brow] = l;
            split2(v.y, h, l); Bhs[(n + 1) * LLDA + brow] = h; Bls[(n + 1) * LLDA + brow] = l;
            split2(v.z, h, l); Bhs[(n + 2) * LLDA + brow] = h; Bls[(n + 2) * LLDA + brow] = l;
            split2(v.w, h, l); Bhs[(n + 3) * LLDA + brow] = h; Bls[(n + 3) * LLDA + brow] = l;
        }
        __syncthreads();
#pragma unroll
        for (int kk = 0; kk < 32; kk += 16) {
            uint32_t ah[2][4], al[2][4];
#pragma unroll
            for (int mt = 0; mt < 2; mt++) {
                int r = wm * 32 + mt * 16;
                int o  = (r + grp) * LLDA + kk + tig * 2;
                int o8 = o + 8 * LLDA;
                ah[mt][0] = *(const uint32_t*)&Ahs[o];
                ah[mt][1] = *(const uint32_t*)&Ahs[o8];
                ah[mt][2] = *(const uint32_t*)&Ahs[o + 8];
                ah[mt][3] = *(const uint32_t*)&Ahs[o8 + 8];
                al[mt][0] = *(const uint32_t*)&Als[o];
                al[mt][1] = *(const uint32_t*)&Als[o8];
                al[mt][2] = *(const uint32_t*)&Als[o + 8];
                al[mt][3] = *(const uint32_t*)&Als[o8 + 8];
            }
#pragma unroll
            for (int nt = 0; nt < 8; nt++) {
                int nn = wn * 64 + nt * 8 + grp;
                int o = nn * LLDA + kk + tig * 2;
                uint32_t b0 = *(const uint32_t*)&Bhs[o], b1 = *(const uint32_t*)&Bhs[o + 8];
                uint32_t c0 = *(const uint32_t*)&Bls[o], c1 = *(const uint32_t*)&Bls[o + 8];
#pragma unroll
                for (int mt = 0; mt < 2; mt++) {
                    mma2(acc[mt][nt], ah[mt], b0, b1);
                    mma2(acc[mt][nt], al[mt], b0, b1);
                    mma2(acc[mt][nt], ah[mt], c0, c1);
                }
            }
        }
        __syncthreads();
    }
#pragma unroll
    for (int mt = 0; mt < 2; mt++) {
#pragma unroll
        for (int nt = 0; nt < 8; nt++) {
            int c = col0 + wn * 64 + nt * 8 + tig * 2;
            float b0 = bias ? bias[c] : 0.f;
            float b1 = bias ? bias[c + 1] : 0.f;
            long r = row0 + wm * 32 + mt * 16 + grp;
            float v0 = acc[mt][nt][0] + b0, v1 = acc[mt][nt][1] + b1;
            float v2 = acc[mt][nt][2] + b0, v3 = acc[mt][nt][3] + b1;
            if (act) { v0=fmaxf(v0,0.f); v1=fmaxf(v1,0.f); v2=fmaxf(v2,0.f); v3=fmaxf(v3,0.f); }
            if (r < M)     *(float2*)&C[r * N + c]       = make_float2(v0, v1);
            if (r + 8 < M) *(float2*)&C[(r + 8) * N + c] = make_float2(v2, v3);
        }
    }
}

// ---------------- weight transpose+convert ----------
__global__ void wconv_k(const float* __restrict__ W, BF* __restrict__ oh,
                        BF* __restrict__ ol, int K, int N, long inS, long outS)
{
    __shared__ float t[32][33];
    const float* w = W + (long)blockIdx.z * inS;
    BF* ph = oh + (long)blockIdx.z * outS;
    BF* pl = ol + (long)blockIdx.z * outS;
    const int n0 = blockIdx.x * 32, k0 = blockIdx.y * 32;
    const int tx = threadIdx.x & 31, ty0 = threadIdx.x >> 5;
#pragma unroll
    for (int i = 0; i < 4; i++) {
        int ky = ty0 + i * 8;
        t[ky][tx] = w[(long)(k0 + ky) * N + n0 + tx];
    }
    __syncthreads();
#pragma unroll
    for (int i = 0; i < 4; i++) {
        int ny = ty0 + i * 8;
        float v = t[tx][ny];
        BF h, l; split2(v, h, l);
        ph[(long)(n0 + ny) * K + k0 + tx] = h;
        pl[(long)(n0 + ny) * K + k0 + tx] = l;
    }
}

__global__ void bqkv_k(const float* __restrict__ bq, const float* __restrict__ bk,
                       const float* __restrict__ bv, float* __restrict__ o)
{
    int i = blockIdx.x * blockDim.x + threadIdx.x;
    if (i < 12288) {
        int l = i / 1536, j = i % 1536;
        float v;
        if (j < 512)       v = bq[l * 512 + j];
        else if (j < 1024) v = bk[l * 512 + j - 512];
        else               v = bv[l * 512 + j - 1024];
        o[i] = v;
    }
}

__global__ void padU_k(BF* __restrict__ uh, BF* __restrict__ ul)
{
    int i = threadIdx.x + blockIdx.x * blockDim.x;  // 4096
    size_t o = 2808UL * 512UL + i;
    uh[o] = __float2bfloat16(0.f);
    ul[o] = __float2bfloat16(0.f);
}

// ---------------- LayerNorm: warp per row ----------------
__global__ __launch_bounds__(256) void ln_row_k(
    const float* __restrict__ X, const float* __restrict__ g, const float* __restrict__ bta,
    float* __restrict__ outf, BF* __restrict__ oh, BF* __restrict__ ol, int D)
{
    const int wid = threadIdx.x >> 5, lane = threadIdx.x & 31;
    const int row = blockIdx.x * 8 + wid;
    const float4* x = (const float4*)(X + (long)row * D);
    const int cnt = D >> 7;
    float s = 0.f, s2 = 0.f;
    for (int i = 0; i < cnt; i++) {
        float4 a = x[lane + i * 32];
        s  += a.x + a.y + a.z + a.w;
        s2 += a.x * a.x + a.y * a.y + a.z * a.z + a.w * a.w;
    }
#pragma unroll
    for (int o = 16; o; o >>= 1) {
        s  += __shfl_xor_sync(~0u, s, o);
        s2 += __shfl_xor_sync(~0u, s2, o);
    }
    const float mean = s / D;
    const float inv = rsqrtf(s2 / D - mean * mean + 1e-5f);
    const float4* gg = (const float4*)g;
    const float4* bb = (const float4*)bta;
    for (int i = 0; i < cnt; i++) {
        int idx = lane + i * 32;
        float4 a = x[idx], gv = gg[idx], bv = bb[idx], o;
        o.x = (a.x - mean) * inv * gv.x + bv.x;
        o.y = (a.y - mean) * inv * gv.y + bv.y;
        o.z = (a.z - mean) * inv * gv.z + bv.z;
        o.w = (a.w - mean) * inv * gv.w + bv.w;
        if (outf) ((float4*)(outf + (long)row * D))[idx] = o;
        if (oh) {
            BF h0,l0,h1,l1,h2,l2,h3,l3;
            split2(o.x,h0,l0); split2(o.y,h1,l1);
            split2(o.z,h2,l2); split2(o.w,h3,l3);
            long base = (long)row * D + idx * 4;
            *(BF2*)&oh[base]     = BF2(h0,h1);
            *(BF2*)&oh[base + 2] = BF2(h2,h3);
            *(BF2*)&ol[base]     = BF2(l0,l1);
            *(BF2*)&ol[base + 2] = BF2(l2,l3);
        }
    }
}

// ---------------- double LN: res=S+HA+HB; S=LN1(res); planes=LN2(S) --------
__global__ __launch_bounds__(256) void ln2_k(
    const float* __restrict__ S, const float* __restrict__ HA, const float* __restrict__ HB_,
    const float* __restrict__ g1, const float* __restrict__ be1,
    const float* __restrict__ g2, const float* __restrict__ be2,
    float* __restrict__ Sout, BF* __restrict__ oh, BF* __restrict__ ol)
{
    const int wid = threadIdx.x >> 5, lane = threadIdx.x & 31;
    const int row = blockIdx.x * 8 + wid;   // 0..2559
    const float4* xs = (const float4*)(S   + (long)row * 512);
    const float4* xa = (const float4*)(HA  + (long)row * 512);
    const float4* xb = (const float4*)(HB_ + (long)row * 512);
    float4 R[4];
    float s = 0.f, s2 = 0.f;
#pragma unroll
    for (int i = 0; i < 4; i++) {
        int idx = lane + i * 32;
        float4 a = xs[idx], c = xa[idx], d = xb[idx];
        a.x += c.x + d.x; a.y += c.y + d.y; a.z += c.z + d.z; a.w += c.w + d.w;
        R[i] = a;
        s  += a.x + a.y + a.z + a.w;
        s2 += a.x * a.x + a.y * a.y + a.z * a.z + a.w * a.w;
    }
#pragma unroll
    for (int o = 16; o; o >>= 1) {
        s  += __shfl_xor_sync(~0u, s, o);
        s2 += __shfl_xor_sync(~0u, s2, o);
    }
    float mean = s * (1.f / 512.f);
    float inv = rsqrtf(s2 * (1.f / 512.f) - mean * mean + 1e-5f);
    const float4* g1v = (const float4*)g1; const float4* b1v = (const float4*)be1;
    float t = 0.f, t2 = 0.f;
#pragma unroll
    for (int i = 0; i < 4; i++) {
        int idx = lane + i * 32;
        float4 gv = g1v[idx], bv = b1v[idx], y;
        y.x = (R[i].x - mean) * inv * gv.x + bv.x;
        y.y = (R[i].y - mean) * inv * gv.y + bv.y;
        y.z = (R[i].z - mean) * inv * gv.z + bv.z;
        y.w = (R[i].w - mean) * inv * gv.w + bv.w;
        R[i] = y;
        ((float4*)(Sout + (long)row * 512))[idx] = y;
        t  += y.x + y.y + y.z + y.w;
        t2 += y.x * y.x + y.y * y.y + y.z * y.z + y.w * y.w;
    }
    if (!g2) return;
#pragma unroll
    for (int o = 16; o; o >>= 1) {
        t  += __shfl_xor_sync(~0u, t, o);
        t2 += __shfl_xor_sync(~0u, t2, o);
    }
    float mean2 = t * (1.f / 512.f);
    float inv2 = rsqrtf(t2 * (1.f / 512.f) - mean2 * mean2 + 1e-5f);
    const float4* g2v = (const float4*)g2; const float4* b2v = (const float4*)be2;
#pragma unroll
    for (int i = 0; i < 4; i++) {
        int idx = lane + i * 32;
        float4 gv = g2v[idx], bv = b2v[idx], z;
        z.x = (R[i].x - mean2) * inv2 * gv.x + bv.x;
        z.y = (R[i].y - mean2) * inv2 * gv.y + bv.y;
        z.z = (R[i].z - mean2) * inv2 * gv.z + bv.z;
        z.w = (R[i].w - mean2) * inv2 * gv.w + bv.w;
        BF h0,l0,h1,l1,h2,l2,h3,l3;
        split2(z.x,h0,l0); split2(z.y,h1,l1);
        split2(z.z,h2,l2); split2(z.w,h3,l3);
        long base = (long)row * 512 + idx * 4;
        *(BF2*)&oh[base]     = BF2(h0,h1);
        *(BF2*)&oh[base + 2] = BF2(h2,h3);
        *(BF2*)&ol[base]     = BF2(l0,l1);
        *(BF2*)&ol[base + 2] = BF2(l2,l3);
    }
}

// ---------------- misc ----------------
__global__ void initS_k(const float* __restrict__ X, float* __restrict__ S)
{
    const int t = blockIdx.x, b = blockIdx.y, d = threadIdx.x;
    int frame;
    if (t < RTn) {
        int si = t >> 2;
        int st = (si == 15) ? 256 : (si + 1) * 16;
        frame = st + (t & 3);
    } else frame = t - RTn;
    S[((size_t)t * Bn + b) * Dm_ + d] = X[(size_t)b * 133120 + (size_t)frame * Dm_ + d];
}

// mems0 planes -> UIN rows 0..119
__global__ void mems0_k(const float* __restrict__ S, BF* __restrict__ uh,
                        BF* __restrict__ ul)
{
    const int s = blockIdx.x, b = blockIdx.y, d = threadIdx.x;
    size_t base = ((size_t)(RTn + s * 16) * Bn + b) * Dm_ + d;
    float acc = 0.f;
#pragma unroll
    for (int k = 0; k < 16; k++) acc += S[base + (size_t)k * Bn * Dm_];
    acc *= (1.f / 16.f);
    BF h, l; split2(acc, h, l);
    size_t o = ((size_t)s * Bn + b) * Dm_ + d;
    uh[o] = h; ul[o] = l;
}

// summary tokens 335+s from UIN utt tokens 79+16s..+15
__global__ void summary_pl_k(BF* __restrict__ uh, BF* __restrict__ ul)
{
    const int s = blockIdx.x, b = blockIdx.y, d = threadIdx.x;
    size_t base = ((size_t)((79 + s * 16) * Bn) + b) * Dm_ + d;
    float acc = 0.f;
#pragma unroll
    for (int k = 0; k < 16; k++) {
        size_t o = base + (size_t)k * Bn * Dm_;
        acc += __bfloat162float(uh[o]) + __bfloat162float(ul[o]);
    }
    acc *= (1.f / 16.f);
    BF h, l; split2(acc, h, l);
    size_t o = ((size_t)((335 + s) * Bn) + b) * Dm_ + d;
    uh[o] = h; ul[o] = l;
}

// ---------------- attention (QKV packed fp32 in, planes out) ----------------
__global__ __launch_bounds__(256) void attn_k(
    const float* __restrict__ QKV, const int* __restrict__ lengths,
    BF* __restrict__ Ah, BF* __restrict__ Al)
{
    __shared__ float sc[Hn][64];
    __shared__ short ki[Hn][64];
    const int qi = blockIdx.x, b = blockIdx.y;
    const int h = threadIdx.x >> 5, lane = threadIdx.x & 31;

    int maxlr = 0;
#pragma unroll
    for (int i = 0; i < Bn; i++) maxlr = max(maxlr, lengths[i] >> 2);
    const int lrb = lengths[b] >> 2;

    int seg; bool summ = false;
    if (qi < RTn)      seg = qi >> 2;
    else if (qi < SN)  seg = (qi - RTn) >> 4;
    else             { seg = qi - SN; summ = true; }
    const int ms  = max(seg - 4, 0);
    const int ss  = max(seg * 16 - 32, 0);
    const int se  = min(seg * 16 + 16, Un);
    const int ue  = min(se, lrb + 256 - maxlr);
    const int rcs = 15 + seg * 4;

    const int c0 = summ ? 0 : (seg - ms);
    const int c2 = max(ue - ss, 0);
    const int n  = c0 + 4 + c2;

    for (int j = lane; j < n; j += 32) {
        int k;
        if (j < c0)          k = ms + j;
        else if (j < c0 + 4) k = rcs + (j - c0);
        else                 k = 79 + ss + (j - c0 - 4);
        ki[h][j] = (short)k;
    }
    __syncwarp();

    const float* qp = QKV + ((size_t)(15 + qi) * Bn + b) * 1536 + h * DHn;
    const float q0 = qp[2 * lane]     * 0.125f;
    const float q1 = qp[2 * lane + 1] * 0.125f;
    const float* Kb = QKV + (size_t)b * 1536 + 512 + h * DHn;

    for (int j = 0; j < n; j++) {
        const float* kp = Kb + (size_t)ki[h][j] * (Bn * 1536);
        float p = fmaf(q0, kp[2 * lane], q1 * kp[2 * lane + 1]);
#pragma unroll
        for (int o = 16; o; o >>= 1) p += __shfl_xor_sync(~0u, p, o);
        if (lane == 0) sc[h][j] = p;
    }
    __syncwarp();

    float m = -3.4e38f;
    for (int j = lane; j < n; j += 32) m = fmaxf(m, sc[h][j]);
#pragma unroll
    for (int o = 16; o; o >>= 1) m = fmaxf(m, __shfl_xor_sync(~0u, m, o));
    float sum = 0.f;
    for (int j = lane; j < n; j += 32) {
        float e = expf(sc[h][j] - m);
        sc[h][j] = e;
        sum += e;
    }
#pragma unroll
    for (int o = 16; o; o >>= 1) sum += __shfl_xor_sync(~0u, sum, o);
    __syncwarp();
    const float inv = 1.f / sum;

    float a0 = 0.f, a1 = 0.f;
    for (int j = 0; j < n; j++) {
        float p = sc[h][j];
        const float* vp = Kb + 512 + (size_t)ki[h][j] * (Bn * 1536);
        a0 = fmaf(p, vp[2 * lane], a0);
        a1 = fmaf(p, vp[2 * lane + 1], a1);
    }
    a0 *= inv; a1 *= inv;
    BF h0, l0, h1, l1;
    split2(a0, h0, l0); split2(a1, h1, l1);
    size_t op = ((size_t)qi * Bn + b) * Dm_ + h * DHn + 2 * lane;
    *(BF2*)&Ah[op] = BF2(h0, h1);
    *(BF2*)&Al[op] = BF2(l0, l1);
}

__global__ void transpose_pl_k(const float* __restrict__ S, BF* __restrict__ yh,
                               BF* __restrict__ yl)
{
    const int r = blockIdx.x, d = threadIdx.x;
    const int b = r >> 8, u = r & 255;
    float v = S[((size_t)(RTn + u) * Bn + b) * Dm_ + d];
    BF h, l; split2(v, h, l);
    yh[(size_t)r * Dm_ + d] = h;
    yl[(size_t)r * Dm_ + d] = l;
}

__global__ void lr_k(const int* __restrict__ lengths, float* __restrict__ out)
{
    int i = threadIdx.x;
    if (i < Bn) out[i] = (float)(lengths[i] >> 2);
}

// ---------------- host: tensormap plumbing ----------------
typedef CUresult (*EncFn)(CUtensorMap*, CUtensorMapDataType, cuuint32_t, void*,
                          const cuuint64_t*, const cuuint64_t*, const cuuint32_t*,
                          const cuuint32_t*, CUtensorMapInterleave, CUtensorMapSwizzle,
                          CUtensorMapL2promotion, CUtensorMapFloatOOBfill);

static EncFn get_enc() {
    void* p = nullptr;
    cudaDriverEntryPointQueryResult qr;
#if CUDART_VERSION >= 12050
    if (cudaGetDriverEntryPointByVersion("cuTensorMapEncodeTiled", &p, 12000,
                                         cudaEnableDefault, &qr) == cudaSuccess && p)
        return (EncFn)p;
    p = nullptr;
#endif
    cudaGetDriverEntryPoint("cuTensorMapEncodeTiled", &p, cudaEnableDefault, &qr);
    return (EncFn)p;
}

static CUtensorMap mkmap(EncFn enc, const BF* base, long K, long M, long planeStride) {
    CUtensorMap m;
    cuuint64_t dims[3]    = {(cuuint64_t)K, (cuuint64_t)M, 2};
    cuuint64_t strides[2] = {(cuuint64_t)K * 2, (cuuint64_t)planeStride * 2};
    cuuint32_t box[3]     = {64, 128, 1};
    cuuint32_t es[3]      = {1, 1, 1};
    enc(&m, CU_TENSOR_MAP_DATA_TYPE_BFLOAT16, 3, (void*)base, dims, strides, box, es,
        CU_TENSOR_MAP_INTERLEAVE_NONE, CU_TENSOR_MAP_SWIZZLE_128B,
        CU_TENSOR_MAP_L2_PROMOTION_L2_128B, CU_TENSOR_MAP_FLOAT_OOB_FILL_NONE);
    return m;
}

// ---------------- launch ----------------
extern "C" void kernel_launch(void* const* d_in, const int* in_sizes, int n_in,
                              void* d_out, int out_size)
{
    const float* input   = (const float*)d_in[0];
    const int*   lengths = (const int*)  d_in[1];
    const float* w_in    = (const float*)d_in[2];
    const float* ln_in_g = (const float*)d_in[3];
    const float* ln_in_b = (const float*)d_in[4];
    const float* wq = (const float*)d_in[5];
    const float* bq = (const float*)d_in[6];
    const float* wk = (const float*)d_in[7];
    const float* bk = (const float*)d_in[8];
    const float* wv = (const float*)d_in[9];
    const float* bv = (const float*)d_in[10];
    const float* wo = (const float*)d_in[11];
    const float* bo = (const float*)d_in[12];
    const float* ff_g = (const float*)d_in[13];
    const float* ff_b = (const float*)d_in[14];
    const float* w1 = (const float*)d_in[15];
    const float* b1 = (const float*)d_in[16];
    const float* w2 = (const float*)d_in[17];
    const float* b2 = (const float*)d_in[18];
    const float* lo_g = (const float*)d_in[19];
    const float* lo_b = (const float*)d_in[20];
    const float* w_out = (const float*)d_in[21];
    const float* b_out = (const float*)d_in[22];
    const float* lng = (const float*)d_in[23];
    const float* lnb = (const float*)d_in[24];
    float* out = (float*)d_out;

    float* fa = nullptr; BF* bf = nullptr;
    cudaGetSymbolAddress((void**)&fa, g_arena);
    cudaGetSymbolAddress((void**)&bf, g_bf);

    cudaFuncSetAttribute(gemm6, cudaFuncAttributeMaxDynamicSharedMemorySize, SM6_TOTAL);

    float* X    = fa + F_X;
    float* S    = fa + F_S;
    float* QKVf = fa + F_QKV;
    float* H2A  = fa + F_H2A;
    float* Yb   = fa + F_YB;
    float* BQKV = fa + F_BQKV;

    BF* UINh = bf + BA_U;   BF* UINl = UINh + EU;
    BF* ATTh = bf + BA_AT;  BF* ATTl = ATTh + EAT;
    BF* HBh  = bf + BA_HB;  BF* HBl  = HBh + EHB;
    BF* FBh  = bf + BA_FB;  BF* FBl  = FBh + EFB;
    BF* YTh  = bf + BA_YT;  BF* YTl  = YTh + EYT;

    EncFn enc = get_enc();
    CUtensorMap mUIN = mkmap(enc, UINh, 512, 2816, EU);
    CUtensorMap mATT = mkmap(enc, ATTh, 512, 2688, EAT);
    CUtensorMap mHB  = mkmap(enc, HBh,  512, 2560, EHB);
    CUtensorMap mFB  = mkmap(enc, FBh, 2048, 2560, EFB);
    CUtensorMap mYT  = mkmap(enc, YTh,  512, 2048, EYT);
    CUtensorMap mOUT = mkmap(enc, bf + BW_OUT, 512, 1024, EOUT);
    CUtensorMap mWQKV[Ln], mWO[Ln], mW1[Ln], mW2[Ln];
    for (int l = 0; l < Ln; l++) {
        mWQKV[l] = mkmap(enc, bf + BW_QKV + (size_t)l * 2 * EQKV, 512, 1536, EQKV);
        mWO[l]   = mkmap(enc, bf + BW_O   + (size_t)l * 2 * EQ,   512,  512, EQ);
        mW1[l]   = mkmap(enc, bf + BW_1   + (size_t)l * 2 * EW1,  512, 2048, EW1);
        mW2[l]   = mkmap(enc, bf + BW_2   + (size_t)l * 2 * EW1, 2048,  512, EW1);
    }

    // ---- per-replay preprocessing ----
    gemm_tc<<<dim3(1, 65), 256>>>(input, w_in, nullptr, X, 8320, 128, 80, 0);
    initS_k<<<dim3(SN, Bn), Dm_>>>(X, S);
    mems0_k<<<dim3(15, Bn), Dm_>>>(S, UINh, UINl);

    wconv_k<<<dim3(16, 16, 8), 256>>>(wq, bf + BW_QKV,
                                      bf + BW_QKV + EQKV, 512, 512, EQ, 2 * EQKV);
    wconv_k<<<dim3(16, 16, 8), 256>>>(wk, bf + BW_QKV + 262144,
                                      bf + BW_QKV + EQKV + 262144, 512, 512, EQ, 2 * EQKV);
    wconv_k<<<dim3(16, 16, 8), 256>>>(wv, bf + BW_QKV + 524288,
                                      bf + BW_QKV + EQKV + 524288, 512, 512, EQ, 2 * EQKV);
    wconv_k<<<dim3(16, 16, 8), 256>>>(wo, bf + BW_O, bf + BW_O + EQ, 512, 512, EQ, 2 * EQ);
    wconv_k<<<dim3(64, 16, 8), 256>>>(w1, bf + BW_1, bf + BW_1 + EW1, 512, 2048, EW1, 2 * EW1);
    wconv_k<<<dim3(16, 64, 8), 256>>>(w2, bf + BW_2, bf + BW_2 + EW1, 2048, 512, EW1, 2 * EW1);
    wconv_k<<<dim3(32, 16, 1), 256>>>(w_out, bf + BW_OUT, bf + BW_OUT + EOUT, 512, 1024, 0, 0);
    bqkv_k<<<48, 256>>>(bq, bk, bv, BQKV);
    padU_k<<<16, 256>>>(UINh, UINl);

    // layer-0 LN1: S -> UIN state planes (rows 120..2679)
    ln_row_k<<<SN * Bn / 8, 256>>>(S, ln_in_g, ln_in_b, nullptr,
                                   UINh + 120 * 512, UINl + 120 * 512, Dm_);

    for (int l = 0; l < Ln; l++) {
        summary_pl_k<<<dim3(NSEG, Bn), Dm_>>>(UINh, UINl);

        gemm6<<<dim3(12, 22, 1), 256, SM6_TOTAL>>>(mUIN, mWQKV[l], BQKV + l * 1536,
                                                   QKVf, 0, nullptr, nullptr,
                                                   1536, 512, 0, 0);

        attn_k<<<dim3(QN, Bn), 256>>>(QKVf, lengths, ATTh, ATTl);

        // O-proj fused: S += out (state rows); UIN mems planes = tanh (summary rows)
        gemm6<<<dim3(4, 21, 1), 256, SM6_TOTAL>>>(mATT, mWO[l], bo + l * Dm_,
                                                  S, 0, UINh, UINl,
                                                  512, 512, 0, 2);

        ln_row_k<<<SN * Bn / 8, 256>>>(S, ff_g + l * Dm_, ff_b + l * Dm_,
                                       nullptr, HBh, HBl, Dm_);
        gemm6<<<dim3(16, 20, 1), 256, SM6_TOTAL>>>(mHB, mW1[l], b1 + l * FFNn,
                                                   nullptr, 0, FBh, FBl,
                                                   2048, 512, 1, 1);
        gemm6<<<dim3(4, 20, 2), 256, SM6_TOTAL>>>(mFB, mW2[l], b2 + l * Dm_,
                                                  H2A, 1310720, nullptr, nullptr,
                                                  512, 1024, 0, 0);

        const float* g2 = (l + 1 < Ln) ? (ln_in_g + (l + 1) * Dm_) : nullptr;
        const float* b2n = (l + 1 < Ln) ? (ln_in_b + (l + 1) * Dm_) : nullptr;
        ln2_k<<<SN * Bn / 8, 256>>>(S, H2A, H2A + 1310720,
                                    lo_g + l * Dm_, lo_b + l * Dm_, g2, b2n,
                                    S, UINh + 120 * 512, UINl + 120 * 512);
    }

    transpose_pl_k<<<2048, Dm_>>>(S, YTh, YTl);
    gemm6<<<dim3(8, 16, 1), 256, SM6_TOTAL>>>(mYT, mOUT, b_out,
                                              Yb, 0, nullptr, nullptr,
                                              1024, 512, 0, 0);
    ln_row_k<<<2048 / 8, 256>>>(Yb, lng, lnb, out, nullptr, nullptr, OUTn);

    if (out_size >= 2048 * 1024 + Bn)
        lr_k<<<1, 32>>>(lengths, out + 2048 * 1024);
}

// round 8
// speedup vs baseline: 4.8863x; 1.1263x over previous
#include <cuda_runtime.h>
#include <cuda_bf16.h>
#include <cuda.h>
#include <math.h>
#include <stdint.h>

typedef __nv_bfloat16 BF;
typedef __nv_bfloat162 BF2;

// ---------------- constants ----------------
#define Bn   8
#define Dm_  512
#define FFNn 2048
#define Ln   8
#define OUTn 1024
#define Hn   8
#define DHn  64
#define QN   336
#define SN   320
#define RTn  64
#define Un   256
#define NSEG 16

// token space: 0..14 mems | 15..78 rc | 79..334 utt | 335..350 summary | 351 pad
// row = token*8 + b;  M_UIN = 2816

// ------- float arena -------
#define F_X    0UL
#define F_S    (F_X + 1064960UL)
#define F_QKV  (F_S + 1310720UL)
#define F_H2A  (F_QKV + 4325376UL)
#define F_H2B  (F_H2A + 1310720UL)
#define F_YB   (F_H2B + 1310720UL)
#define F_BQKV (F_YB + 2097152UL)
#define F_TOT  (F_BQKV + 12288UL)
__device__ __align__(1024) float g_arena[F_TOT];

// ------- bf16 arena -------
#define EQ    262144UL
#define EQKV  786432UL     // 1536*512
#define EW1   1048576UL
#define EOUT  524288UL
#define EU    1441792UL    // 2816*512
#define EAT   1376256UL    // 2688*512
#define EHB   1310720UL    // 2560*512
#define EFB   5242880UL    // 2560*2048
#define EYT   1048576UL    // 2048*512

#define BW_QKV 0UL
#define BW_O   (BW_QKV + 8UL*2UL*EQKV)
#define BW_1   (BW_O   + 8UL*2UL*EQ)
#define BW_2   (BW_1   + 8UL*2UL*EW1)
#define BW_OUT (BW_2   + 8UL*2UL*EW1)
#define BA_U   (BW_OUT + 2UL*EOUT)
#define BA_AT  (BA_U   + 2UL*EU)
#define BA_HB  (BA_AT  + 2UL*EAT)
#define BA_FB  (BA_HB  + 2UL*EHB)
#define BA_YT  (BA_FB  + 2UL*EFB)
#define B_TOT  (BA_YT  + 2UL*EYT)
__device__ __align__(1024) BF g_bf[B_TOT];

__device__ __forceinline__ void split2(float x, BF& h, BF& l) {
    h = __float2bfloat16(x);
    l = __float2bfloat16(x - __bfloat162float(h));
}

// ============ TMA / mbarrier primitives ============
__device__ __forceinline__ uint32_t smem_u32(const void* p) {
    return (uint32_t)__cvta_generic_to_shared(p);
}
__device__ __forceinline__ void mbar_init(uint32_t a, uint32_t cnt) {
    asm volatile("mbarrier.init.shared::cta.b64 [%0], %1;" :: "r"(a), "r"(cnt) : "memory");
}
__device__ __forceinline__ void mbar_expect(uint32_t a, uint32_t tx) {
    asm volatile("mbarrier.arrive.expect_tx.shared::cta.b64 _, [%0], %1;"
                 :: "r"(a), "r"(tx) : "memory");
}
__device__ __forceinline__ void mbar_arrive(uint32_t a) {
    asm volatile("mbarrier.arrive.shared::cta.b64 _, [%0];" :: "r"(a) : "memory");
}
__device__ __forceinline__ void mbar_wait(uint32_t a, uint32_t ph) {
    uint32_t done = 0;
    while (!done) {
        asm volatile(
            "{\n\t.reg .pred p;\n\t"
            "mbarrier.try_wait.parity.acquire.cta.shared::cta.b64 p, [%1], %2, 0x989680;\n\t"
            "selp.b32 %0, 1, 0, p;\n\t}"
            : "=r"(done) : "r"(a), "r"(ph) : "memory");
    }
}
__device__ __forceinline__ void tma3d(uint32_t dst, const void* map,
                                      int cx, int cy, int cz, uint32_t mbar) {
    asm volatile(
        "cp.async.bulk.tensor.3d.shared::cta.global.tile.mbarrier::complete_tx::bytes "
        "[%0], [%1, {%2, %3, %4}], [%5];"
        :: "r"(dst), "l"(map), "r"(cx), "r"(cy), "r"(cz), "r"(mbar) : "memory");
}
__device__ __forceinline__ void mma2(float c[4], const uint32_t a[4],
                                     uint32_t b0, uint32_t b1) {
    asm volatile(
        "mma.sync.aligned.m16n8k16.row.col.f32.bf16.bf16.f32 "
        "{%0,%1,%2,%3}, {%4,%5,%6,%7}, {%8,%9}, {%0,%1,%2,%3};\n"
        : "+f"(c[0]), "+f"(c[1]), "+f"(c[2]), "+f"(c[3])
        : "r"(a[0]), "r"(a[1]), "r"(a[2]), "r"(a[3]), "r"(b0), "r"(b1));
}
#define LDSM4(r, a) \
    asm volatile("ldmatrix.sync.aligned.m8n8.x4.shared.b16 {%0,%1,%2,%3}, [%4];" \
        : "=r"((r)[0]), "=r"((r)[1]), "=r"((r)[2]), "=r"((r)[3]) : "r"(a))

// ============ TMA-staged mma.sync GEMM (SW64, 32-K stages, 2 CTA/SM) ========
// C = act(A @ B^T + bias). grid (N/128, M/128, splitZ). K%32==0, M%128==0.
// mode 0: fp32 Cf (+ z*czstride). mode 1: bf16 planes Ch/Cl.
// mode 2: fused O epilogue: rows<2560 S+=v; rows 2560..2679 planes=tanh(v).
#define NST 3
#define STB 32768
#define SM6_TOTAL (1024 + NST * STB + 128)

__global__ __launch_bounds__(256, 2) void gemm6(
    const __grid_constant__ CUtensorMap tmA,
    const __grid_constant__ CUtensorMap tmB,
    const float* __restrict__ bias, float* __restrict__ Cf, long czstride,
    BF* __restrict__ Ch, BF* __restrict__ Cl,
    int N, int K, int act, int mode)
{
    extern __shared__ __align__(16) char smx[];
    const uint32_t sb = smem_u32(smx);
    const uint32_t db = (sb + 1023) & ~1023u;
    const int tid = threadIdx.x, lane = tid & 31, wid = tid >> 5;
    const int wm = wid & 3, wn = wid >> 2;
    const int grp = lane >> 2, tig = lane & 3;
    const int row0 = blockIdx.y * 128, col0 = blockIdx.x * 128;
    const int kstart = blockIdx.z * K;
    if (Cf && mode == 0) Cf += (long)blockIdx.z * czstride;
    const float* bi = (bias && kstart == 0) ? bias : nullptr;
    const int T = K >> 5;

    const uint32_t barb = db + NST * STB;
    if (tid == 0) {
        for (int s = 0; s < NST; s++) {
            mbar_init(barb + s * 8, 1);
            mbar_init(barb + 64 + s * 8, 256);
        }
    }
    __syncthreads();

    if (tid == 0) {
        for (int s = 0; s < NST; s++) {
            uint32_t st = db + s * STB, fb = barb + s * 8;
            mbar_expect(fb, STB);
            tma3d(st,         &tmA, kstart + s * 32, row0, 0, fb);
            tma3d(st + 8192,  &tmA, kstart + s * 32, row0, 1, fb);
            tma3d(st + 16384, &tmB, kstart + s * 32, col0, 0, fb);
            tma3d(st + 24576, &tmB, kstart + s * 32, col0, 1, fb);
        }
    }

    float acc[2][8][4] = {};
    // ldmatrix lane geometry (SW64: 64B rows; xor = ((row>>1)&3)<<4)
    const int lrow = (lane & 7) + (((lane >> 3) & 1) << 3);
    const int kofs = ((lane >> 4) & 1) * 8;
    const uint32_t msk = (uint32_t)((lrow >> 1) & 3) << 4;
    uint32_t arow_off[2], brow_off[4];
#pragma unroll
    for (int mt = 0; mt < 2; mt++) arow_off[mt] = (uint32_t)(wm * 32 + mt * 16 + lrow) * 64;
#pragma unroll
    for (int p = 0; p < 4; p++)    brow_off[p]  = (uint32_t)(wn * 64 + p * 16 + lrow) * 64;

    uint32_t pfm = 0, pem = 0;
    for (int i = 0; i < T; i++) {
        const int bslot = i % NST;
        const uint32_t fb = barb + bslot * 8, eb = barb + 64 + bslot * 8;
        mbar_wait(fb, (pfm >> bslot) & 1); pfm ^= (1u << bslot);
        const uint32_t sA = db + bslot * STB, sB = sA + 16384;
#pragma unroll
        for (int kk = 0; kk < 32; kk += 16) {
            const uint32_t csw = ((uint32_t)((kk + kofs) * 2)) ^ msk;
            uint32_t ah[2][4], al_[2][4], bh[4][4], bl_[4][4];
#pragma unroll
            for (int mt = 0; mt < 2; mt++) {
                uint32_t ad = sA + arow_off[mt] + csw;
                LDSM4(ah[mt], ad);
                LDSM4(al_[mt], ad + 8192);
            }
#pragma unroll
            for (int p = 0; p < 4; p++) {
                uint32_t bd = sB + brow_off[p] + csw;
                LDSM4(bh[p], bd);
                LDSM4(bl_[p], bd + 8192);
            }
#pragma unroll
            for (int nt = 0; nt < 8; nt++) {
                const int p = nt >> 1, s1 = nt & 1;
                mma2(acc[0][nt], ah[0], bh[p][s1], bh[p][2 + s1]);
                mma2(acc[1][nt], ah[1], bh[p][s1], bh[p][2 + s1]);
                mma2(acc[0][nt], al_[0], bh[p][s1], bh[p][2 + s1]);
                mma2(acc[1][nt], al_[1], bh[p][s1], bh[p][2 + s1]);
                mma2(acc[0][nt], ah[0], bl_[p][s1], bl_[p][2 + s1]);
                mma2(acc[1][nt], ah[1], bl_[p][s1], bl_[p][2 + s1]);
            }
        }
        mbar_arrive(eb);
        if (tid == 0 && i + NST < T) {
            mbar_wait(eb, (pem >> bslot) & 1); pem ^= (1u << bslot);
            uint32_t st = db + bslot * STB;
            mbar_expect(fb, STB);
            int k0 = kstart + (i + NST) * 32;
            tma3d(st,         &tmA, k0, row0, 0, fb);
            tma3d(st + 8192,  &tmA, k0, row0, 1, fb);
            tma3d(st + 16384, &tmB, k0, col0, 0, fb);
            tma3d(st + 24576, &tmB, k0, col0, 1, fb);
        }
    }

#pragma unroll
    for (int mt = 0; mt < 2; mt++) {
        const long r = row0 + wm * 32 + mt * 16 + grp;
#pragma unroll
        for (int nt = 0; nt < 8; nt++) {
            const long c = col0 + wn * 64 + nt * 8 + tig * 2;
            float bb0 = bi ? bi[c] : 0.f, bb1 = bi ? bi[c + 1] : 0.f;
            float v0 = acc[mt][nt][0] + bb0, v1 = acc[mt][nt][1] + bb1;
            float v2 = acc[mt][nt][2] + bb0, v3 = acc[mt][nt][3] + bb1;
            if (act) {
                v0 = fmaxf(v0, 0.f); v1 = fmaxf(v1, 0.f);
                v2 = fmaxf(v2, 0.f); v3 = fmaxf(v3, 0.f);
            }
            if (mode == 0) {
                *(float2*)&Cf[r * N + c]       = make_float2(v0, v1);
                *(float2*)&Cf[(r + 8) * N + c] = make_float2(v2, v3);
            } else if (mode == 1) {
                BF h0, l0, h1, l1;
                split2(v0, h0, l0); split2(v1, h1, l1);
                *(BF2*)&Ch[r * N + c] = BF2(h0, h1);
                *(BF2*)&Cl[r * N + c] = BF2(l0, l1);
                split2(v2, h0, l0); split2(v3, h1, l1);
                *(BF2*)&Ch[(r + 8) * N + c] = BF2(h0, h1);
                *(BF2*)&Cl[(r + 8) * N + c] = BF2(l0, l1);
            } else {
#pragma unroll
                for (int rr = 0; rr < 2; rr++) {
                    long r2 = r + rr * 8;
                    float u0 = rr ? v2 : v0, u1 = rr ? v3 : v1;
                    if (r2 < 2560) {
                        float2 s = *(float2*)&Cf[r2 * 512 + c];
                        *(float2*)&Cf[r2 * 512 + c] = make_float2(s.x + u0, s.y + u1);
                    } else if (r2 < 2680) {
                        float t0 = tanhf(u0), t1 = tanhf(u1);
                        BF h0, l0, h1, l1;
                        split2(t0, h0, l0); split2(t1, h1, l1);
                        long o = (r2 - 2560) * 512 + c;
                        *(BF2*)&Ch[o] = BF2(h0, h1);
                        *(BF2*)&Cl[o] = BF2(l0, l1);
                    }
                }
            }
        }
    }
}

// ---------------- legacy in-kernel-convert GEMM (input proj, K=80) ---------
#define LLDA 40
__global__ __launch_bounds__(256) void gemm_tc(
    const float* __restrict__ A, const float* __restrict__ W,
    const float* __restrict__ bias, float* __restrict__ C,
    int M, int N, int K, int act)
{
    __shared__ BF Ahs[128 * LLDA], Als[128 * LLDA];
    __shared__ BF Bhs[128 * LLDA], Bls[128 * LLDA];
    const int tid = threadIdx.x, lane = tid & 31, wid = tid >> 5;
    const int wm = wid & 3, wn = wid >> 2;
    const int grp = lane >> 2, tig = lane & 3;
    const long row0 = (long)blockIdx.y * 128;
    const int  col0 = blockIdx.x * 128;
    float acc[2][8][4] = {};
    const int arow = tid >> 1, acol0 = (tid & 1) * 16;
    const int brow = tid >> 3, bcol0 = (tid & 7) * 16;

    for (int k0 = 0; k0 < K; k0 += 32) {
#pragma unroll
        for (int j = 0; j < 4; j++) {
            int c = acol0 + j * 4;
            float4 v = make_float4(0.f, 0.f, 0.f, 0.f);
            if (row0 + arow < M && k0 + c < K)
                v = *(const float4*)&A[(row0 + arow) * (long)K + k0 + c];
            BF h, l; int o = arow * LLDA + c;
            split2(v.x, h, l); Ahs[o]     = h; Als[o]     = l;
            split2(v.y, h, l); Ahs[o + 1] = h; Als[o + 1] = l;
            split2(v.z, h, l); Ahs[o + 2] = h; Als[o + 2] = l;
            split2(v.w, h, l); Ahs[o + 3] = h; Als[o + 3] = l;
        }
#pragma unroll
        for (int j = 0; j < 4; j++) {
            int n = bcol0 + j * 4;
            float4 v = make_float4(0.f, 0.f, 0.f, 0.f);
            if (k0 + brow < K)
                v = *(const float4*)&W[(long)(k0 + brow) * N + col0 + n];
            BF h, l;
            split2(v.x, h, l); Bhs[(n + 0) * LLDA + brow] = h; Bls[(n + 0) * LLDA + brow] = l;
            split2(v.y, h, l); Bhs[(n + 1) * LLDA + brow] = h; Bls[(n + 1) * LLDA + brow] = l;
            split2(v.z, h, l); Bhs[(n + 2) * LLDA + brow] = h; Bls[(n + 2) * LLDA + brow] = l;
            split2(v.w, h, l); Bhs[(n + 3) * LLDA + brow] = h; Bls[(n + 3) * LLDA + brow] = l;
        }
        __syncthreads();
#pragma unroll
        for (int kk = 0; kk < 32; kk += 16) {
            uint32_t ah[2][4], al[2][4];
#pragma unroll
            for (int mt = 0; mt < 2; mt++) {
                int r = wm * 32 + mt * 16;
                int o  = (r + grp) * LLDA + kk + tig * 2;
                int o8 = o + 8 * LLDA;
                ah[mt][0] = *(const uint32_t*)&Ahs[o];
                ah[mt][1] = *(const uint32_t*)&Ahs[o8];
                ah[mt][2] = *(const uint32_t*)&Ahs[o + 8];
                ah[mt][3] = *(const uint32_t*)&Ahs[o8 + 8];
                al[mt][0] = *(const uint32_t*)&Als[o];
                al[mt][1] = *(const uint32_t*)&Als[o8];
                al[mt][2] = *(const uint32_t*)&Als[o + 8];
                al[mt][3] = *(const uint32_t*)&Als[o8 + 8];
            }
#pragma unroll
            for (int nt = 0; nt < 8; nt++) {
                int nn = wn * 64 + nt * 8 + grp;
                int o = nn * LLDA + kk + tig * 2;
                uint32_t b0 = *(const uint32_t*)&Bhs[o], b1 = *(const uint32_t*)&Bhs[o + 8];
                uint32_t c0 = *(const uint32_t*)&Bls[o], c1 = *(const uint32_t*)&Bls[o + 8];
#pragma unroll
                for (int mt = 0; mt < 2; mt++) {
                    mma2(acc[mt][nt], ah[mt], b0, b1);
                    mma2(acc[mt][nt], al[mt], b0, b1);
                    mma2(acc[mt][nt], ah[mt], c0, c1);
                }
            }
        }
        __syncthreads();
    }
#pragma unroll
    for (int mt = 0; mt < 2; mt++) {
#pragma unroll
        for (int nt = 0; nt < 8; nt++) {
            int c = col0 + wn * 64 + nt * 8 + tig * 2;
            float b0 = bias ? bias[c] : 0.f;
            float b1 = bias ? bias[c + 1] : 0.f;
            long r = row0 + wm * 32 + mt * 16 + grp;
            float v0 = acc[mt][nt][0] + b0, v1 = acc[mt][nt][1] + b1;
            float v2 = acc[mt][nt][2] + b0, v3 = acc[mt][nt][3] + b1;
            if (act) { v0=fmaxf(v0,0.f); v1=fmaxf(v1,0.f); v2=fmaxf(v2,0.f); v3=fmaxf(v3,0.f); }
            if (r < M)     *(float2*)&C[r * N + c]       = make_float2(v0, v1);
            if (r + 8 < M) *(float2*)&C[(r + 8) * N + c] = make_float2(v2, v3);
        }
    }
}

// ---------------- weight transpose+convert: out[n][k] = W[k][n] ----------
__global__ __launch_bounds__(256) void wconv_k(
    const float* __restrict__ W, BF* __restrict__ oh, BF* __restrict__ ol,
    int K, int N, long inS, long outS)
{
    __shared__ float t[32][33];
    const float* w = W + (long)blockIdx.z * inS;
    BF* ph = oh + (long)blockIdx.z * outS;
    BF* pl = ol + (long)blockIdx.z * outS;
    const int n0 = blockIdx.x * 32, k0 = blockIdx.y * 32;
    const int tx = threadIdx.x & 7, ty = threadIdx.x >> 3;   // ty 0..31
    float4 v = *(const float4*)&w[(long)(k0 + ty) * N + n0 + tx * 4];
    t[ty][tx * 4 + 0] = v.x; t[ty][tx * 4 + 1] = v.y;
    t[ty][tx * 4 + 2] = v.z; t[ty][tx * 4 + 3] = v.w;
    __syncthreads();
    float a0 = t[tx * 4 + 0][ty], a1 = t[tx * 4 + 1][ty];
    float a2 = t[tx * 4 + 2][ty], a3 = t[tx * 4 + 3][ty];
    BF h0, l0, h1, l1, h2, l2, h3, l3;
    split2(a0, h0, l0); split2(a1, h1, l1);
    split2(a2, h2, l2); split2(a3, h3, l3);
    long o = (long)(n0 + ty) * K + k0 + tx * 4;
    *(BF2*)&ph[o]     = BF2(h0, h1);
    *(BF2*)&ph[o + 2] = BF2(h2, h3);
    *(BF2*)&pl[o]     = BF2(l0, l1);
    *(BF2*)&pl[o + 2] = BF2(l2, l3);
}

// merged bias pack + UIN pad
__global__ void prep_k(const float* __restrict__ bq, const float* __restrict__ bk,
                       const float* __restrict__ bv, float* __restrict__ o,
                       BF* __restrict__ uh, BF* __restrict__ ul)
{
    int i = blockIdx.x * blockDim.x + threadIdx.x;
    if (i < 12288) {
        int l = i / 1536, j = i % 1536;
        float v;
        if (j < 512)       v = bq[l * 512 + j];
        else if (j < 1024) v = bk[l * 512 + j - 512];
        else               v = bv[l * 512 + j - 1024];
        o[i] = v;
    }
    if (i < 4096) {
        size_t p = 2808UL * 512UL + i;
        uh[p] = __float2bfloat16(0.f);
        ul[p] = __float2bfloat16(0.f);
    }
}

// ---------------- LayerNorm: warp per row ----------------
__global__ __launch_bounds__(256) void ln_row_k(
    const float* __restrict__ X, const float* __restrict__ g, const float* __restrict__ bta,
    float* __restrict__ outf, BF* __restrict__ oh, BF* __restrict__ ol, int D)
{
    const int wid = threadIdx.x >> 5, lane = threadIdx.x & 31;
    const int row = blockIdx.x * 8 + wid;
    const float4* x = (const float4*)(X + (long)row * D);
    const int cnt = D >> 7;
    float s = 0.f, s2 = 0.f;
    for (int i = 0; i < cnt; i++) {
        float4 a = x[lane + i * 32];
        s  += a.x + a.y + a.z + a.w;
        s2 += a.x * a.x + a.y * a.y + a.z * a.z + a.w * a.w;
    }
#pragma unroll
    for (int o = 16; o; o >>= 1) {
        s  += __shfl_xor_sync(~0u, s, o);
        s2 += __shfl_xor_sync(~0u, s2, o);
    }
    const float mean = s / D;
    const float inv = rsqrtf(s2 / D - mean * mean + 1e-5f);
    const float4* gg = (const float4*)g;
    const float4* bb = (const float4*)bta;
    for (int i = 0; i < cnt; i++) {
        int idx = lane + i * 32;
        float4 a = x[idx], gv = gg[idx], bv = bb[idx], o;
        o.x = (a.x - mean) * inv * gv.x + bv.x;
        o.y = (a.y - mean) * inv * gv.y + bv.y;
        o.z = (a.z - mean) * inv * gv.z + bv.z;
        o.w = (a.w - mean) * inv * gv.w + bv.w;
        if (outf) ((float4*)(outf + (long)row * D))[idx] = o;
        if (oh) {
            BF h0,l0,h1,l1,h2,l2,h3,l3;
            split2(o.x,h0,l0); split2(o.y,h1,l1);
            split2(o.z,h2,l2); split2(o.w,h3,l3);
            long base = (long)row * D + idx * 4;
            *(BF2*)&oh[base]     = BF2(h0,h1);
            *(BF2*)&oh[base + 2] = BF2(h2,h3);
            *(BF2*)&ol[base]     = BF2(l0,l1);
            *(BF2*)&ol[base + 2] = BF2(l2,l3);
        }
    }
}

// ---------------- double LN: res=S+HA+HB; S=LN1(res); planes=LN2(S) --------
__global__ __launch_bounds__(256) void ln2_k(
    const float* __restrict__ S, const float* __restrict__ HA, const float* __restrict__ HB_,
    const float* __restrict__ g1, const float* __restrict__ be1,
    const float* __restrict__ g2, const float* __restrict__ be2,
    float* __restrict__ Sout, BF* __restrict__ oh, BF* __restrict__ ol)
{
    const int wid = threadIdx.x >> 5, lane = threadIdx.x & 31;
    const int row = blockIdx.x * 8 + wid;   // 0..2559
    const float4* xs = (const float4*)(S   + (long)row * 512);
    const float4* xa = (const float4*)(HA  + (long)row * 512);
    const float4* xb = (const float4*)(HB_ + (long)row * 512);
    float4 R[4];
    float s = 0.f, s2 = 0.f;
#pragma unroll
    for (int i = 0; i < 4; i++) {
        int idx = lane + i * 32;
        float4 a = xs[idx], c = xa[idx], d = xb[idx];
        a.x += c.x + d.x; a.y += c.y + d.y; a.z += c.z + d.z; a.w += c.w + d.w;
        R[i] = a;
        s  += a.x + a.y + a.z + a.w;
        s2 += a.x * a.x + a.y * a.y + a.z * a.z + a.w * a.w;
    }
#pragma unroll
    for (int o = 16; o; o >>= 1) {
        s  += __shfl_xor_sync(~0u, s, o);
        s2 += __shfl_xor_sync(~0u, s2, o);
    }
    float mean = s * (1.f / 512.f);
    float inv = rsqrtf(s2 * (1.f / 512.f) - mean * mean + 1e-5f);
    const float4* g1v = (const float4*)g1; const float4* b1v = (const float4*)be1;
    float t = 0.f, t2 = 0.f;
#pragma unroll
    for (int i = 0; i < 4; i++) {
        int idx = lane + i * 32;
        float4 gv = g1v[idx], bv = b1v[idx], y;
        y.x = (R[i].x - mean) * inv * gv.x + bv.x;
        y.y = (R[i].y - mean) * inv * gv.y + bv.y;
        y.z = (R[i].z - mean) * inv * gv.z + bv.z;
        y.w = (R[i].w - mean) * inv * gv.w + bv.w;
        R[i] = y;
        ((float4*)(Sout + (long)row * 512))[idx] = y;
        t  += y.x + y.y + y.z + y.w;
        t2 += y.x * y.x + y.y * y.y + y.z * y.z + y.w * y.w;
    }
    if (!g2) return;
#pragma unroll
    for (int o = 16; o; o >>= 1) {
        t  += __shfl_xor_sync(~0u, t, o);
        t2 += __shfl_xor_sync(~0u, t2, o);
    }
    float mean2 = t * (1.f / 512.f);
    float inv2 = rsqrtf(t2 * (1.f / 512.f) - mean2 * mean2 + 1e-5f);
    const float4* g2v = (const float4*)g2; const float4* b2v = (const float4*)be2;
#pragma unroll
    for (int i = 0; i < 4; i++) {
        int idx = lane + i * 32;
        float4 gv = g2v[idx], bv = b2v[idx], z;
        z.x = (R[i].x - mean2) * inv2 * gv.x + bv.x;
        z.y = (R[i].y - mean2) * inv2 * gv.y + bv.y;
        z.z = (R[i].z - mean2) * inv2 * gv.z + bv.z;
        z.w = (R[i].w - mean2) * inv2 * gv.w + bv.w;
        BF h0,l0,h1,l1,h2,l2,h3,l3;
        split2(z.x,h0,l0); split2(z.y,h1,l1);
        split2(z.z,h2,l2); split2(z.w,h3,l3);
        long base = (long)row * 512 + idx * 4;
        *(BF2*)&oh[base]     = BF2(h0,h1);
        *(BF2*)&oh[base + 2] = BF2(h2,h3);
        *(BF2*)&ol[base]     = BF2(l0,l1);
        *(BF2*)&ol[base + 2] = BF2(l2,l3);
    }
}

// ---------------- misc ----------------
__global__ void initS_k(const float* __restrict__ X, float* __restrict__ S)
{
    const int t = blockIdx.x, b = blockIdx.y, d = threadIdx.x;
    int frame;
    if (t < RTn) {
        int si = t >> 2;
        int st = (si == 15) ? 256 : (si + 1) * 16;
        frame = st + (t & 3);
    } else frame = t - RTn;
    S[((size_t)t * Bn + b) * Dm_ + d] = X[(size_t)b * 133120 + (size_t)frame * Dm_ + d];
}

__global__ void mems0_k(const float* __restrict__ S, BF* __restrict__ uh,
                        BF* __restrict__ ul)
{
    const int s = blockIdx.x, b = blockIdx.y, d = threadIdx.x;
    size_t base = ((size_t)(RTn + s * 16) * Bn + b) * Dm_ + d;
    float acc = 0.f;
#pragma unroll
    for (int k = 0; k < 16; k++) acc += S[base + (size_t)k * Bn * Dm_];
    acc *= (1.f / 16.f);
    BF h, l; split2(acc, h, l);
    size_t o = ((size_t)s * Bn + b) * Dm_ + d;
    uh[o] = h; ul[o] = l;
}

__global__ void summary_pl_k(BF* __restrict__ uh, BF* __restrict__ ul)
{
    const int s = blockIdx.x, b = blockIdx.y, d = threadIdx.x;
    size_t base = ((size_t)((79 + s * 16) * Bn) + b) * Dm_ + d;
    float acc = 0.f;
#pragma unroll
    for (int k = 0; k < 16; k++) {
        size_t o = base + (size_t)k * Bn * Dm_;
        acc += __bfloat162float(uh[o]) + __bfloat162float(ul[o]);
    }
    acc *= (1.f / 16.f);
    BF h, l; split2(acc, h, l);
    size_t o = ((size_t)((335 + s) * Bn) + b) * Dm_ + d;
    uh[o] = h; ul[o] = l;
}

// ---------------- attention (QKV packed fp32 in, planes out) ----------------
__global__ __launch_bounds__(256) void attn_k(
    const float* __restrict__ QKV, const int* __restrict__ lengths,
    BF* __restrict__ Ah, BF* __restrict__ Al)
{
    __shared__ float sc[Hn][64];
    __shared__ short ki[Hn][64];
    const int qi = blockIdx.x, b = blockIdx.y;
    const int h = threadIdx.x >> 5, lane = threadIdx.x & 31;

    int maxlr = 0;
#pragma unroll
    for (int i = 0; i < Bn; i++) maxlr = max(maxlr, lengths[i] >> 2);
    const int lrb = lengths[b] >> 2;

    int seg; bool summ = false;
    if (qi < RTn)      seg = qi >> 2;
    else if (qi < SN)  seg = (qi - RTn) >> 4;
    else             { seg = qi - SN; summ = true; }
    const int ms  = max(seg - 4, 0);
    const int ss  = max(seg * 16 - 32, 0);
    const int se  = min(seg * 16 + 16, Un);
    const int ue  = min(se, lrb + 256 - maxlr);
    const int rcs = 15 + seg * 4;

    const int c0 = summ ? 0 : (seg - ms);
    const int c2 = max(ue - ss, 0);
    const int n  = c0 + 4 + c2;

    for (int j = lane; j < n; j += 32) {
        int k;
        if (j < c0)          k = ms + j;
        else if (j < c0 + 4) k = rcs + (j - c0);
        else                 k = 79 + ss + (j - c0 - 4);
        ki[h][j] = (short)k;
    }
    __syncwarp();

    // score phase: 4 keys/iteration, 8 lanes per key (8 floats each)
    const int g = lane >> 3, e = lane & 7;
    const float4* qv = (const float4*)(QKV + ((size_t)(15 + qi) * Bn + b) * 1536 + h * DHn);
    float4 q0 = qv[e * 2], q1 = qv[e * 2 + 1];
    q0.x *= 0.125f; q0.y *= 0.125f; q0.z *= 0.125f; q0.w *= 0.125f;
    q1.x *= 0.125f; q1.y *= 0.125f; q1.z *= 0.125f; q1.w *= 0.125f;
    const float* Kb = QKV + (size_t)b * 1536 + 512 + h * DHn;

    for (int j0 = 0; j0 < n; j0 += 4) {
        int j = j0 + g;
        float p = 0.f;
        if (j < n) {
            const float4* kp = (const float4*)(Kb + (size_t)ki[h][j] * (Bn * 1536));
            float4 k0 = kp[e * 2], k1 = kp[e * 2 + 1];
            p = q0.x * k0.x + q0.y * k0.y + q0.z * k0.z + q0.w * k0.w
              + q1.x * k1.x + q1.y * k1.y + q1.z * k1.z + q1.w * k1.w;
        }
        p += __shfl_xor_sync(~0u, p, 4);
        p += __shfl_xor_sync(~0u, p, 2);
        p += __shfl_xor_sync(~0u, p, 1);
        if (e == 0 && j < n) sc[h][j] = p;
    }
    __syncwarp();

    float m = -3.4e38f;
    for (int j = lane; j < n; j += 32) m = fmaxf(m, sc[h][j]);
#pragma unroll
    for (int o = 16; o; o >>= 1) m = fmaxf(m, __shfl_xor_sync(~0u, m, o));
    float sum = 0.f;
    for (int j = lane; j < n; j += 32) {
        float e2 = expf(sc[h][j] - m);
        sc[h][j] = e2;
        sum += e2;
    }
#pragma unroll
    for (int o = 16; o; o >>= 1) sum += __shfl_xor_sync(~0u, sum, o);
    __syncwarp();
    const float inv = 1.f / sum;

    float a0 = 0.f, a1 = 0.f;
    const float* Vb = Kb + 512;
    for (int j = 0; j < n; j++) {
        float p = sc[h][j];
        const float2 vp = *(const float2*)(Vb + (size_t)ki[h][j] * (Bn * 1536) + 2 * lane);
        a0 = fmaf(p, vp.x, a0);
        a1 = fmaf(p, vp.y, a1);
    }
    a0 *= inv; a1 *= inv;
    BF h0, l0, h1, l1;
    split2(a0, h0, l0); split2(a1, h1, l1);
    size_t op = ((size_t)qi * Bn + b) * Dm_ + h * DHn + 2 * lane;
    *(BF2*)&Ah[op] = BF2(h0, h1);
    *(BF2*)&Al[op] = BF2(l0, l1);
}

__global__ void transpose_pl_k(const float* __restrict__ S, BF* __restrict__ yh,
                               BF* __restrict__ yl)
{
    const int r = blockIdx.x, d = threadIdx.x;
    const int b = r >> 8, u = r & 255;
    float v = S[((size_t)(RTn + u) * Bn + b) * Dm_ + d];
    BF h, l; split2(v, h, l);
    yh[(size_t)r * Dm_ + d] = h;
    yl[(size_t)r * Dm_ + d] = l;
}

__global__ void lr_k(const int* __restrict__ lengths, float* __restrict__ out)
{
    int i = threadIdx.x;
    if (i < Bn) out[i] = (float)(lengths[i] >> 2);
}

// ---------------- host: tensormap plumbing ----------------
typedef CUresult (*EncFn)(CUtensorMap*, CUtensorMapDataType, cuuint32_t, void*,
                          const cuuint64_t*, const cuuint64_t*, const cuuint32_t*,
                          const cuuint32_t*, CUtensorMapInterleave, CUtensorMapSwizzle,
                          CUtensorMapL2promotion, CUtensorMapFloatOOBfill);

static EncFn get_enc() {
    void* p = nullptr;
    cudaDriverEntryPointQueryResult qr;
#if CUDART_VERSION >= 12050
    if (cudaGetDriverEntryPointByVersion("cuTensorMapEncodeTiled", &p, 12000,
                                         cudaEnableDefault, &qr) == cudaSuccess && p)
        return (EncFn)p;
    p = nullptr;
#endif
    cudaGetDriverEntryPoint("cuTensorMapEncodeTiled", &p, cudaEnableDefault, &qr);
    return (EncFn)p;
}

static CUtensorMap mkmap(EncFn enc, const BF* base, long K, long M, long planeStride) {
    CUtensorMap m;
    cuuint64_t dims[3]    = {(cuuint64_t)K, (cuuint64_t)M, 2};
    cuuint64_t strides[2] = {(cuuint64_t)K * 2, (cuuint64_t)planeStride * 2};
    cuuint32_t box[3]     = {32, 128, 1};
    cuuint32_t es[3]      = {1, 1, 1};
    enc(&m, CU_TENSOR_MAP_DATA_TYPE_BFLOAT16, 3, (void*)base, dims, strides, box, es,
        CU_TENSOR_MAP_INTERLEAVE_NONE, CU_TENSOR_MAP_SWIZZLE_64B,
        CU_TENSOR_MAP_L2_PROMOTION_L2_128B, CU_TENSOR_MAP_FLOAT_OOB_FILL_NONE);
    return m;
}

// ---------------- launch ----------------
extern "C" void kernel_launch(void* const* d_in, const int* in_sizes, int n_in,
                              void* d_out, int out_size)
{
    const float* input   = (const float*)d_in[0];
    const int*   lengths = (const int*)  d_in[1];
    const float* w_in    = (const float*)d_in[2];
    const float* ln_in_g = (const float*)d_in[3];
    const float* ln_in_b = (const float*)d_in[4];
    const float* wq = (const float*)d_in[5];
    const float* bq = (const float*)d_in[6];
    const float* wk = (const float*)d_in[7];
    const float* bk = (const float*)d_in[8];
    const float* wv = (const float*)d_in[9];
    const float* bv = (const float*)d_in[10];
    const float* wo = (const float*)d_in[11];
    const float* bo = (const float*)d_in[12];
    const float* ff_g = (const float*)d_in[13];
    const float* ff_b = (const float*)d_in[14];
    const float* w1 = (const float*)d_in[15];
    const float* b1 = (const float*)d_in[16];
    const float* w2 = (const float*)d_in[17];
    const float* b2 = (const float*)d_in[18];
    const float* lo_g = (const float*)d_in[19];
    const float* lo_b = (const float*)d_in[20];
    const float* w_out = (const float*)d_in[21];
    const float* b_out = (const float*)d_in[22];
    const float* lng = (const float*)d_in[23];
    const float* lnb = (const float*)d_in[24];
    float* out = (float*)d_out;

    float* fa = nullptr; BF* bf = nullptr;
    cudaGetSymbolAddress((void**)&fa, g_arena);
    cudaGetSymbolAddress((void**)&bf, g_bf);

    cudaFuncSetAttribute(gemm6, cudaFuncAttributeMaxDynamicSharedMemorySize, SM6_TOTAL);

    float* X    = fa + F_X;
    float* S    = fa + F_S;
    float* QKVf = fa + F_QKV;
    float* H2A  = fa + F_H2A;
    float* Yb   = fa + F_YB;
    float* BQKV = fa + F_BQKV;

    BF* UINh = bf + BA_U;   BF* UINl = UINh + EU;
    BF* ATTh = bf + BA_AT;  BF* ATTl = ATTh + EAT;
    BF* HBh  = bf + BA_HB;  BF* HBl  = HBh + EHB;
    BF* FBh  = bf + BA_FB;  BF* FBl  = FBh + EFB;
    BF* YTh  = bf + BA_YT;  BF* YTl  = YTh + EYT;

    EncFn enc = get_enc();
    CUtensorMap mUIN = mkmap(enc, UINh, 512, 2816, EU);
    CUtensorMap mATT = mkmap(enc, ATTh, 512, 2688, EAT);
    CUtensorMap mHB  = mkmap(enc, HBh,  512, 2560, EHB);
    CUtensorMap mFB  = mkmap(enc, FBh, 2048, 2560, EFB);
    CUtensorMap mYT  = mkmap(enc, YTh,  512, 2048, EYT);
    CUtensorMap mOUT = mkmap(enc, bf + BW_OUT, 512, 1024, EOUT);
    CUtensorMap mWQKV[Ln], mWO[Ln], mW1[Ln], mW2[Ln];
    for (int l = 0; l < Ln; l++) {
        mWQKV[l] = mkmap(enc, bf + BW_QKV + (size_t)l * 2 * EQKV, 512, 1536, EQKV);
        mWO[l]   = mkmap(enc, bf + BW_O   + (size_t)l * 2 * EQ,   512,  512, EQ);
        mW1[l]   = mkmap(enc, bf + BW_1   + (size_t)l * 2 * EW1,  512, 2048, EW1);
        mW2[l]   = mkmap(enc, bf + BW_2   + (size_t)l * 2 * EW1, 2048,  512, EW1);
    }

    // ---- per-replay preprocessing ----
    gemm_tc<<<dim3(1, 65), 256>>>(input, w_in, nullptr, X, 8320, 128, 80, 0);
    initS_k<<<dim3(SN, Bn), Dm_>>>(X, S);
    mems0_k<<<dim3(15, Bn), Dm_>>>(S, UINh, UINl);

    wconv_k<<<dim3(16, 16, 8), 256>>>(wq, bf + BW_QKV,
                                      bf + BW_QKV + EQKV, 512, 512, EQ, 2 * EQKV);
    wconv_k<<<dim3(16, 16, 8), 256>>>(wk, bf + BW_QKV + 262144,
                                      bf + BW_QKV + EQKV + 262144, 512, 512, EQ, 2 * EQKV);
    wconv_k<<<dim3(16, 16, 8), 256>>>(wv, bf + BW_QKV + 524288,
                                      bf + BW_QKV + EQKV + 524288, 512, 512, EQ, 2 * EQKV);
    wconv_k<<<dim3(16, 16, 8), 256>>>(wo, bf + BW_O, bf + BW_O + EQ, 512, 512, EQ, 2 * EQ);
    wconv_k<<<dim3(64, 16, 8), 256>>>(w1, bf + BW_1, bf + BW_1 + EW1, 512, 2048, EW1, 2 * EW1);
    wconv_k<<<dim3(16, 64, 8), 256>>>(w2, bf + BW_2, bf + BW_2 + EW1, 2048, 512, EW1, 2 * EW1);
    wconv_k<<<dim3(32, 16, 1), 256>>>(w_out, bf + BW_OUT, bf + BW_OUT + EOUT, 512, 1024, 0, 0);
    prep_k<<<48, 256>>>(bq, bk, bv, BQKV, UINh, UINl);

    // layer-0 LN1: S -> UIN state planes (rows 120..2679)
    ln_row_k<<<SN * Bn / 8, 256>>>(S, ln_in_g, ln_in_b, nullptr,
                                   UINh + 120 * 512, UINl + 120 * 512, Dm_);

    for (int l = 0; l < Ln; l++) {
        summary_pl_k<<<dim3(NSEG, Bn), Dm_>>>(UINh, UINl);

        gemm6<<<dim3(12, 22, 1), 256, SM6_TOTAL>>>(mUIN, mWQKV[l], BQKV + l * 1536,
                                                   QKVf, 0, nullptr, nullptr,
                                                   1536, 512, 0, 0);

        attn_k<<<dim3(QN, Bn), 256>>>(QKVf, lengths, ATTh, ATTl);

        gemm6<<<dim3(4, 21, 1), 256, SM6_TOTAL>>>(mATT, mWO[l], bo + l * Dm_,
                                                  S, 0, UINh, UINl,
                                                  512, 512, 0, 2);

        ln_row_k<<<SN * Bn / 8, 256>>>(S, ff_g + l * Dm_, ff_b + l * Dm_,
                                       nullptr, HBh, HBl, Dm_);
        gemm6<<<dim3(16, 20, 1), 256, SM6_TOTAL>>>(mHB, mW1[l], b1 + l * FFNn,
                                                   nullptr, 0, FBh, FBl,
                                                   2048, 512, 1, 1);
        gemm6<<<dim3(4, 20, 2), 256, SM6_TOTAL>>>(mFB, mW2[l], b2 + l * Dm_,
                                                  H2A, 1310720, nullptr, nullptr,
                                                  512, 1024, 0, 0);

        const float* g2 = (l + 1 < Ln) ? (ln_in_g + (l + 1) * Dm_) : nullptr;
        const float* b2n = (l + 1 < Ln) ? (ln_in_b + (l + 1) * Dm_) : nullptr;
        ln2_k<<<SN * Bn / 8, 256>>>(S, H2A, H2A + 1310720,
                                    lo_g + l * Dm_, lo_b + l * Dm_, g2, b2n,
                                    S, UINh + 120 * 512, UINl + 120 * 512);
    }

    transpose_pl_k<<<2048, Dm_>>>(S, YTh, YTl);
    gemm6<<<dim3(8, 16, 1), 256, SM6_TOTAL>>>(mYT, mOUT, b_out,
                                              Yb, 0, nullptr, nullptr,
                                              1024, 512, 0, 0);
    ln_row_k<<<2048 / 8, 256>>>(Yb, lng, lnb, out, nullptr, nullptr, OUTn);

    if (out_size >= 2048 * 1024 + Bn)
        lr_k<<<1, 32>>>(lengths, out + 2048 * 1024);
}

// round 9
// speedup vs baseline: 5.1676x; 1.0575x over previous
#include <cuda_runtime.h>
#include <cuda_bf16.h>
#include <cuda.h>
#include <math.h>
#include <stdint.h>

typedef __nv_bfloat16 BF;
typedef __nv_bfloat162 BF2;

// ---------------- constants ----------------
#define Bn   8
#define Dm_  512
#define FFNn 2048
#define Ln   8
#define OUTn 1024
#define Hn   8
#define DHn  64
#define QN   336
#define SN   320
#define RTn  64
#define Un   256
#define NSEG 16

// token space: 0..14 mems | 15..78 rc | 79..334 utt | 335..350 summary | 351 pad
// row = token*8 + b;  M_UIN = 2816

// ------- float arena -------
#define F_X    0UL
#define F_S    (F_X + 1064960UL)
#define F_QKV  (F_S + 1310720UL)
#define F_H2A  (F_QKV + 4325376UL)
#define F_H2B  (F_H2A + 1310720UL)
#define F_H2C  (F_H2B + 1310720UL)
#define F_YB   (F_H2C + 1310720UL)
#define F_BQKV (F_YB + 2097152UL)
#define F_TOT  (F_BQKV + 12288UL)
__device__ __align__(1024) float g_arena[F_TOT];

// ------- bf16 arena -------
#define EQ    262144UL
#define EQKV  786432UL     // 1536*512
#define EW1   1048576UL
#define EOUT  524288UL
#define EU    1441792UL    // 2816*512
#define EAT   1376256UL    // 2688*512
#define EHB   1310720UL    // 2560*512
#define EFB   5242880UL    // 2560*2048
#define EYT   1048576UL    // 2048*512

#define BW_QKV 0UL
#define BW_O   (BW_QKV + 8UL*2UL*EQKV)
#define BW_1   (BW_O   + 8UL*2UL*EQ)
#define BW_2   (BW_1   + 8UL*2UL*EW1)
#define BW_OUT (BW_2   + 8UL*2UL*EW1)
#define BA_U   (BW_OUT + 2UL*EOUT)
#define BA_AT  (BA_U   + 2UL*EU)
#define BA_HB  (BA_AT  + 2UL*EAT)
#define BA_FB  (BA_HB  + 2UL*EHB)
#define BA_YT  (BA_FB  + 2UL*EFB)
#define B_TOT  (BA_YT  + 2UL*EYT)
__device__ __align__(1024) BF g_bf[B_TOT];

__device__ __forceinline__ void split2(float x, BF& h, BF& l) {
    h = __float2bfloat16(x);
    l = __float2bfloat16(x - __bfloat162float(h));
}

// ============ TMA / mbarrier primitives ============
__device__ __forceinline__ uint32_t smem_u32(const void* p) {
    return (uint32_t)__cvta_generic_to_shared(p);
}
__device__ __forceinline__ void mbar_init(uint32_t a, uint32_t cnt) {
    asm volatile("mbarrier.init.shared::cta.b64 [%0], %1;" :: "r"(a), "r"(cnt) : "memory");
}
__device__ __forceinline__ void mbar_expect(uint32_t a, uint32_t tx) {
    asm volatile("mbarrier.arrive.expect_tx.shared::cta.b64 _, [%0], %1;"
                 :: "r"(a), "r"(tx) : "memory");
}
__device__ __forceinline__ void mbar_arrive(uint32_t a) {
    asm volatile("mbarrier.arrive.shared::cta.b64 _, [%0];" :: "r"(a) : "memory");
}
__device__ __forceinline__ void mbar_wait(uint32_t a, uint32_t ph) {
    uint32_t done = 0;
    while (!done) {
        asm volatile(
            "{\n\t.reg .pred p;\n\t"
            "mbarrier.try_wait.parity.acquire.cta.shared::cta.b64 p, [%1], %2, 0x989680;\n\t"
            "selp.b32 %0, 1, 0, p;\n\t}"
            : "=r"(done) : "r"(a), "r"(ph) : "memory");
    }
}
__device__ __forceinline__ void tma3d(uint32_t dst, const void* map,
                                      int cx, int cy, int cz, uint32_t mbar) {
    asm volatile(
        "cp.async.bulk.tensor.3d.shared::cta.global.tile.mbarrier::complete_tx::bytes "
        "[%0], [%1, {%2, %3, %4}], [%5];"
        :: "r"(dst), "l"(map), "r"(cx), "r"(cy), "r"(cz), "r"(mbar) : "memory");
}
__device__ __forceinline__ void mma2(float c[4], const uint32_t a[4],
                                     uint32_t b0, uint32_t b1) {
    asm volatile(
        "mma.sync.aligned.m16n8k16.row.col.f32.bf16.bf16.f32 "
        "{%0,%1,%2,%3}, {%4,%5,%6,%7}, {%8,%9}, {%0,%1,%2,%3};\n"
        : "+f"(c[0]), "+f"(c[1]), "+f"(c[2]), "+f"(c[3])
        : "r"(a[0]), "r"(a[1]), "r"(a[2]), "r"(a[3]), "r"(b0), "r"(b1));
}
#define LDSM4(r, a) \
    asm volatile("ldmatrix.sync.aligned.m8n8.x4.shared.b16 {%0,%1,%2,%3}, [%4];" \
        : "=r"((r)[0]), "=r"((r)[1]), "=r"((r)[2]), "=r"((r)[3]) : "r"(a))

// ============ TMA-staged mma.sync GEMM (SW64, 32-K stages) ============
// C = act(A @ B^T + bias). grid (N/128, M/MT, splitZ). K%32==0 (logical; TMA
// zero-fills OOB K so ragged split-K chunks are safe). MT in {64,128}.
// mode 0: fp32 Cf (+ z*czstride). mode 1: bf16 planes Ch/Cl.
// mode 2: fused O epilogue: rows<2560 S+=v; rows 2560..2679 planes=tanh(v).
#define NST 3

template <int MT>
__global__ __launch_bounds__(256, 2) void gemm6(
    const __grid_constant__ CUtensorMap tmA,
    const __grid_constant__ CUtensorMap tmB,
    const float* __restrict__ bias, float* __restrict__ Cf, long czstride,
    BF* __restrict__ Ch, BF* __restrict__ Cl,
    int N, int K, int act, int mode)
{
    constexpr int MTM = MT / 64;             // m16 tiles per warp
    constexpr int APL = MT * 64;             // A plane bytes per stage
    constexpr int STB = MT * 128 + 16384;    // stage bytes
    extern __shared__ __align__(16) char smx[];
    const uint32_t sb = smem_u32(smx);
    const uint32_t db = (sb + 1023) & ~1023u;
    const int tid = threadIdx.x, lane = tid & 31, wid = tid >> 5;
    const int wm = wid & 3, wn = wid >> 2;
    const int grp = lane >> 2, tig = lane & 3;
    const int row0 = blockIdx.y * MT, col0 = blockIdx.x * 128;
    const int kstart = blockIdx.z * K;
    if (Cf && mode == 0) Cf += (long)blockIdx.z * czstride;
    const float* bi = (bias && kstart == 0) ? bias : nullptr;
    const int T = K >> 5;

    const uint32_t barb = db + NST * STB;
    if (tid == 0) {
        for (int s = 0; s < NST; s++) {
            mbar_init(barb + s * 8, 1);
            mbar_init(barb + 64 + s * 8, 256);
        }
    }
    __syncthreads();

    if (tid == 0) {
        for (int s = 0; s < NST; s++) {
            uint32_t st = db + s * STB, fb = barb + s * 8;
            mbar_expect(fb, STB);
            tma3d(st,               &tmA, kstart + s * 32, row0, 0, fb);
            tma3d(st + APL,         &tmA, kstart + s * 32, row0, 1, fb);
            tma3d(st + 2 * APL,        &tmB, kstart + s * 32, col0, 0, fb);
            tma3d(st + 2 * APL + 8192, &tmB, kstart + s * 32, col0, 1, fb);
        }
    }

    float acc[MTM][8][4] = {};
    // ldmatrix lane geometry (SW64: 64B rows; xor = ((row>>1)&3)<<4)
    const int lrow = (lane & 7) + (((lane >> 3) & 1) << 3);
    const int kofs = ((lane >> 4) & 1) * 8;
    const uint32_t msk = (uint32_t)((lrow >> 1) & 3) << 4;
    uint32_t arow_off[MTM], brow_off[4];
#pragma unroll
    for (int mt = 0; mt < MTM; mt++)
        arow_off[mt] = (uint32_t)(wm * (MT / 4) + mt * 16 + lrow) * 64;
#pragma unroll
    for (int p = 0; p < 4; p++) brow_off[p] = (uint32_t)(wn * 64 + p * 16 + lrow) * 64;

    uint32_t pfm = 0, pem = 0;
    for (int i = 0; i < T; i++) {
        const int bslot = i % NST;
        const uint32_t fb = barb + bslot * 8, eb = barb + 64 + bslot * 8;
        mbar_wait(fb, (pfm >> bslot) & 1); pfm ^= (1u << bslot);
        const uint32_t sA = db + bslot * STB, sB = sA + 2 * APL;
#pragma unroll
        for (int kk = 0; kk < 32; kk += 16) {
            const uint32_t csw = ((uint32_t)((kk + kofs) * 2)) ^ msk;
            uint32_t ah[MTM][4], al_[MTM][4], bh[4][4], bl_[4][4];
#pragma unroll
            for (int mt = 0; mt < MTM; mt++) {
                uint32_t ad = sA + arow_off[mt] + csw;
                LDSM4(ah[mt], ad);
                LDSM4(al_[mt], ad + APL);
            }
#pragma unroll
            for (int p = 0; p < 4; p++) {
                uint32_t bd = sB + brow_off[p] + csw;
                LDSM4(bh[p], bd);
                LDSM4(bl_[p], bd + 8192);
            }
#pragma unroll
            for (int nt = 0; nt < 8; nt++) {
                const int p = nt >> 1, s1 = nt & 1;
#pragma unroll
                for (int mt = 0; mt < MTM; mt++) {
                    mma2(acc[mt][nt], ah[mt],  bh[p][s1],  bh[p][2 + s1]);
                    mma2(acc[mt][nt], al_[mt], bh[p][s1],  bh[p][2 + s1]);
                    mma2(acc[mt][nt], ah[mt],  bl_[p][s1], bl_[p][2 + s1]);
                }
            }
        }
        mbar_arrive(eb);
        if (tid == 0 && i + NST < T) {
            mbar_wait(eb, (pem >> bslot) & 1); pem ^= (1u << bslot);
            uint32_t st = db + bslot * STB;
            mbar_expect(fb, STB);
            int k0 = kstart + (i + NST) * 32;
            tma3d(st,               &tmA, k0, row0, 0, fb);
            tma3d(st + APL,         &tmA, k0, row0, 1, fb);
            tma3d(st + 2 * APL,        &tmB, k0, col0, 0, fb);
            tma3d(st + 2 * APL + 8192, &tmB, k0, col0, 1, fb);
        }
    }

#pragma unroll
    for (int mt = 0; mt < MTM; mt++) {
        const long r = row0 + wm * (MT / 4) + mt * 16 + grp;
#pragma unroll
        for (int nt = 0; nt < 8; nt++) {
            const long c = col0 + wn * 64 + nt * 8 + tig * 2;
            float bb0 = bi ? bi[c] : 0.f, bb1 = bi ? bi[c + 1] : 0.f;
            float v0 = acc[mt][nt][0] + bb0, v1 = acc[mt][nt][1] + bb1;
            float v2 = acc[mt][nt][2] + bb0, v3 = acc[mt][nt][3] + bb1;
            if (act) {
                v0 = fmaxf(v0, 0.f); v1 = fmaxf(v1, 0.f);
                v2 = fmaxf(v2, 0.f); v3 = fmaxf(v3, 0.f);
            }
            if (mode == 0) {
                *(float2*)&Cf[r * N + c]       = make_float2(v0, v1);
                *(float2*)&Cf[(r + 8) * N + c] = make_float2(v2, v3);
            } else if (mode == 1) {
                BF h0, l0, h1, l1;
                split2(v0, h0, l0); split2(v1, h1, l1);
                *(BF2*)&Ch[r * N + c] = BF2(h0, h1);
                *(BF2*)&Cl[r * N + c] = BF2(l0, l1);
                split2(v2, h0, l0); split2(v3, h1, l1);
                *(BF2*)&Ch[(r + 8) * N + c] = BF2(h0, h1);
                *(BF2*)&Cl[(r + 8) * N + c] = BF2(l0, l1);
            } else {
#pragma unroll
                for (int rr = 0; rr < 2; rr++) {
                    long r2 = r + rr * 8;
                    float u0 = rr ? v2 : v0, u1 = rr ? v3 : v1;
                    if (r2 < 2560) {
                        float2 s = *(float2*)&Cf[r2 * 512 + c];
                        *(float2*)&Cf[r2 * 512 + c] = make_float2(s.x + u0, s.y + u1);
                    } else if (r2 < 2680) {
                        float t0 = tanhf(u0), t1 = tanhf(u1);
                        BF h0, l0, h1, l1;
                        split2(t0, h0, l0); split2(t1, h1, l1);
                        long o = (r2 - 2560) * 512 + c;
                        *(BF2*)&Ch[o] = BF2(h0, h1);
                        *(BF2*)&Cl[o] = BF2(l0, l1);
                    }
                }
            }
        }
    }
}

// ---------------- legacy in-kernel-convert GEMM (input proj, K=80) ---------
#define LLDA 40
__global__ __launch_bounds__(256) void gemm_tc(
    const float* __restrict__ A, const float* __restrict__ W,
    const float* __restrict__ bias, float* __restrict__ C,
    int M, int N, int K, int act)
{
    __shared__ BF Ahs[128 * LLDA], Als[128 * LLDA];
    __shared__ BF Bhs[128 * LLDA], Bls[128 * LLDA];
    const int tid = threadIdx.x, lane = tid & 31, wid = tid >> 5;
    const int wm = wid & 3, wn = wid >> 2;
    const int grp = lane >> 2, tig = lane & 3;
    const long row0 = (long)blockIdx.y * 128;
    const int  col0 = blockIdx.x * 128;
    float acc[2][8][4] = {};
    const int arow = tid >> 1, acol0 = (tid & 1) * 16;
    const int brow = tid >> 3, bcol0 = (tid & 7) * 16;

    for (int k0 = 0; k0 < K; k0 += 32) {
#pragma unroll
        for (int j = 0; j < 4; j++) {
            int c = acol0 + j * 4;
            float4 v = make_float4(0.f, 0.f, 0.f, 0.f);
            if (row0 + arow < M && k0 + c < K)
                v = *(const float4*)&A[(row0 + arow) * (long)K + k0 + c];
            BF h, l; int o = arow * LLDA + c;
            split2(v.x, h, l); Ahs[o]     = h; Als[o]     = l;
            split2(v.y, h, l); Ahs[o + 1] = h; Als[o + 1] = l;
            split2(v.z, h, l); Ahs[o + 2] = h; Als[o + 2] = l;
            split2(v.w, h, l); Ahs[o + 3] = h; Als[o + 3] = l;
        }
#pragma unroll
        for (int j = 0; j < 4; j++) {
            int n = bcol0 + j * 4;
            float4 v = make_float4(0.f, 0.f, 0.f, 0.f);
            if (k0 + brow < K)
                v = *(const float4*)&W[(long)(k0 + brow) * N + col0 + n];
            BF h, l;
            split2(v.x, h, l); Bhs[(n + 0) * LLDA + brow] = h; Bls[(n + 0) * LLDA + brow] = l;
            split2(v.y, h, l); Bhs[(n + 1) * LLDA + brow] = h; Bls[(n + 1) * LLDA + brow] = l;
            split2(v.z, h, l); Bhs[(n + 2) * LLDA + brow] = h; Bls[(n + 2) * LLDA + brow] = l;
            split2(v.w, h, l); Bhs[(n + 3) * LLDA + brow] = h; Bls[(n + 3) * LLDA + brow] = l;
        }
        __syncthreads();
#pragma unroll
        for (int kk = 0; kk < 32; kk += 16) {
            uint32_t ah[2][4], al[2][4];
#pragma unroll
            for (int mt = 0; mt < 2; mt++) {
                int r = wm * 32 + mt * 16;
                int o  = (r + grp) * LLDA + kk + tig * 2;
                int o8 = o + 8 * LLDA;
                ah[mt][0] = *(const uint32_t*)&Ahs[o];
                ah[mt][1] = *(const uint32_t*)&Ahs[o8];
                ah[mt][2] = *(const uint32_t*)&Ahs[o + 8];
                ah[mt][3] = *(const uint32_t*)&Ahs[o8 + 8];
                al[mt][0] = *(const uint32_t*)&Als[o];
                al[mt][1] = *(const uint32_t*)&Als[o8];
                al[mt][2] = *(const uint32_t*)&Als[o + 8];
                al[mt][3] = *(const uint32_t*)&Als[o8 + 8];
            }
#pragma unroll
            for (int nt = 0; nt < 8; nt++) {
                int nn = wn * 64 + nt * 8 + grp;
                int o = nn * LLDA + kk + tig * 2;
                uint32_t b0 = *(const uint32_t*)&Bhs[o], b1 = *(const uint32_t*)&Bhs[o + 8];
                uint32_t c0 = *(const uint32_t*)&Bls[o], c1 = *(const uint32_t*)&Bls[o + 8];
#pragma unroll
                for (int mt = 0; mt < 2; mt++) {
                    mma2(acc[mt][nt], ah[mt], b0, b1);
                    mma2(acc[mt][nt], al[mt], b0, b1);
                    mma2(acc[mt][nt], ah[mt], c0, c1);
                }
            }
        }
        __syncthreads();
    }
#pragma unroll
    for (int mt = 0; mt < 2; mt++) {
#pragma unroll
        for (int nt = 0; nt < 8; nt++) {
            int c = col0 + wn * 64 + nt * 8 + tig * 2;
            float b0 = bias ? bias[c] : 0.f;
            float b1 = bias ? bias[c + 1] : 0.f;
            long r = row0 + wm * 32 + mt * 16 + grp;
            float v0 = acc[mt][nt][0] + b0, v1 = acc[mt][nt][1] + b1;
            float v2 = acc[mt][nt][2] + b0, v3 = acc[mt][nt][3] + b1;
            if (act) { v0=fmaxf(v0,0.f); v1=fmaxf(v1,0.f); v2=fmaxf(v2,0.f); v3=fmaxf(v3,0.f); }
            if (r < M)     *(float2*)&C[r * N + c]       = make_float2(v0, v1);
            if (r + 8 < M) *(float2*)&C[(r + 8) * N + c] = make_float2(v2, v3);
        }
    }
}

// ---------------- weight transpose+convert: out[n][k] = W[k][n] ----------
__global__ __launch_bounds__(256) void wconv_k(
    const float* __restrict__ W, BF* __restrict__ oh, BF* __restrict__ ol,
    int K, int N, long inS, long outS)
{
    __shared__ float t[32][33];
    const float* w = W + (long)blockIdx.z * inS;
    BF* ph = oh + (long)blockIdx.z * outS;
    BF* pl = ol + (long)blockIdx.z * outS;
    const int n0 = blockIdx.x * 32, k0 = blockIdx.y * 32;
    const int tx = threadIdx.x & 7, ty = threadIdx.x >> 3;
    float4 v = *(const float4*)&w[(long)(k0 + ty) * N + n0 + tx * 4];
    t[ty][tx * 4 + 0] = v.x; t[ty][tx * 4 + 1] = v.y;
    t[ty][tx * 4 + 2] = v.z; t[ty][tx * 4 + 3] = v.w;
    __syncthreads();
    float a0 = t[tx * 4 + 0][ty], a1 = t[tx * 4 + 1][ty];
    float a2 = t[tx * 4 + 2][ty], a3 = t[tx * 4 + 3][ty];
    BF h0, l0, h1, l1, h2, l2, h3, l3;
    split2(a0, h0, l0); split2(a1, h1, l1);
    split2(a2, h2, l2); split2(a3, h3, l3);
    long o = (long)(n0 + ty) * K + k0 + tx * 4;
    *(BF2*)&ph[o]     = BF2(h0, h1);
    *(BF2*)&ph[o + 2] = BF2(h2, h3);
    *(BF2*)&pl[o]     = BF2(l0, l1);
    *(BF2*)&pl[o + 2] = BF2(l2, l3);
}

// merged bias pack + UIN pad
__global__ void prep_k(const float* __restrict__ bq, const float* __restrict__ bk,
                       const float* __restrict__ bv, float* __restrict__ o,
                       BF* __restrict__ uh, BF* __restrict__ ul)
{
    int i = blockIdx.x * blockDim.x + threadIdx.x;
    if (i < 12288) {
        int l = i / 1536, j = i % 1536;
        float v;
        if (j < 512)       v = bq[l * 512 + j];
        else if (j < 1024) v = bk[l * 512 + j - 512];
        else               v = bv[l * 512 + j - 1024];
        o[i] = v;
    }
    if (i < 4096) {
        size_t p = 2808UL * 512UL + i;
        uh[p] = __float2bfloat16(0.f);
        ul[p] = __float2bfloat16(0.f);
    }
}

// ---------------- LayerNorm: warp per row ----------------
__global__ __launch_bounds__(256) void ln_row_k(
    const float* __restrict__ X, const float* __restrict__ g, const float* __restrict__ bta,
    float* __restrict__ outf, BF* __restrict__ oh, BF* __restrict__ ol, int D)
{
    const int wid = threadIdx.x >> 5, lane = threadIdx.x & 31;
    const int row = blockIdx.x * 8 + wid;
    const float4* x = (const float4*)(X + (long)row * D);
    const int cnt = D >> 7;
    float s = 0.f, s2 = 0.f;
    for (int i = 0; i < cnt; i++) {
        float4 a = x[lane + i * 32];
        s  += a.x + a.y + a.z + a.w;
        s2 += a.x * a.x + a.y * a.y + a.z * a.z + a.w * a.w;
    }
#pragma unroll
    for (int o = 16; o; o >>= 1) {
        s  += __shfl_xor_sync(~0u, s, o);
        s2 += __shfl_xor_sync(~0u, s2, o);
    }
    const float mean = s / D;
    const float inv = rsqrtf(s2 / D - mean * mean + 1e-5f);
    const float4* gg = (const float4*)g;
    const float4* bb = (const float4*)bta;
    for (int i = 0; i < cnt; i++) {
        int idx = lane + i * 32;
        float4 a = x[idx], gv = gg[idx], bv = bb[idx], o;
        o.x = (a.x - mean) * inv * gv.x + bv.x;
        o.y = (a.y - mean) * inv * gv.y + bv.y;
        o.z = (a.z - mean) * inv * gv.z + bv.z;
        o.w = (a.w - mean) * inv * gv.w + bv.w;
        if (outf) ((float4*)(outf + (long)row * D))[idx] = o;
        if (oh) {
            BF h0,l0,h1,l1,h2,l2,h3,l3;
            split2(o.x,h0,l0); split2(o.y,h1,l1);
            split2(o.z,h2,l2); split2(o.w,h3,l3);
            long base = (long)row * D + idx * 4;
            *(BF2*)&oh[base]     = BF2(h0,h1);
            *(BF2*)&oh[base + 2] = BF2(h2,h3);
            *(BF2*)&ol[base]     = BF2(l0,l1);
            *(BF2*)&ol[base + 2] = BF2(l2,l3);
        }
    }
}

// -------- double LN: res=S+HA+HB+HC; S=LN1(res); planes=LN2(S) ------------
__global__ __launch_bounds__(256) void ln2_k(
    const float* __restrict__ S, const float* __restrict__ HA,
    const float* __restrict__ HB_, const float* __restrict__ HC,
    const float* __restrict__ g1, const float* __restrict__ be1,
    const float* __restrict__ g2, const float* __restrict__ be2,
    float* __restrict__ Sout, BF* __restrict__ oh, BF* __restrict__ ol)
{
    const int wid = threadIdx.x >> 5, lane = threadIdx.x & 31;
    const int row = blockIdx.x * 8 + wid;   // 0..2559
    const float4* xs = (const float4*)(S   + (long)row * 512);
    const float4* xa = (const float4*)(HA  + (long)row * 512);
    const float4* xb = (const float4*)(HB_ + (long)row * 512);
    const float4* xc = (const float4*)(HC  + (long)row * 512);
    float4 R[4];
    float s = 0.f, s2 = 0.f;
#pragma unroll
    for (int i = 0; i < 4; i++) {
        int idx = lane + i * 32;
        float4 a = xs[idx], c = xa[idx], d = xb[idx], e = xc[idx];
        a.x += c.x + d.x + e.x; a.y += c.y + d.y + e.y;
        a.z += c.z + d.z + e.z; a.w += c.w + d.w + e.w;
        R[i] = a;
        s  += a.x + a.y + a.z + a.w;
        s2 += a.x * a.x + a.y * a.y + a.z * a.z + a.w * a.w;
    }
#pragma unroll
    for (int o = 16; o; o >>= 1) {
        s  += __shfl_xor_sync(~0u, s, o);
        s2 += __shfl_xor_sync(~0u, s2, o);
    }
    float mean = s * (1.f / 512.f);
    float inv = rsqrtf(s2 * (1.f / 512.f) - mean * mean + 1e-5f);
    const float4* g1v = (const float4*)g1; const float4* b1v = (const float4*)be1;
    float t = 0.f, t2 = 0.f;
#pragma unroll
    for (int i = 0; i < 4; i++) {
        int idx = lane + i * 32;
        float4 gv = g1v[idx], bv = b1v[idx], y;
        y.x = (R[i].x - mean) * inv * gv.x + bv.x;
        y.y = (R[i].y - mean) * inv * gv.y + bv.y;
        y.z = (R[i].z - mean) * inv * gv.z + bv.z;
        y.w = (R[i].w - mean) * inv * gv.w + bv.w;
        R[i] = y;
        ((float4*)(Sout + (long)row * 512))[idx] = y;
        t  += y.x + y.y + y.z + y.w;
        t2 += y.x * y.x + y.y * y.y + y.z * y.z + y.w * y.w;
    }
    if (!g2) return;
#pragma unroll
    for (int o = 16; o; o >>= 1) {
        t  += __shfl_xor_sync(~0u, t, o);
        t2 += __shfl_xor_sync(~0u, t2, o);
    }
    float mean2 = t * (1.f / 512.f);
    float inv2 = rsqrtf(t2 * (1.f / 512.f) - mean2 * mean2 + 1e-5f);
    const float4* g2v = (const float4*)g2; const float4* b2v = (const float4*)be2;
#pragma unroll
    for (int i = 0; i < 4; i++) {
        int idx = lane + i * 32;
        float4 gv = g2v[idx], bv = b2v[idx], z;
        z.x = (R[i].x - mean2) * inv2 * gv.x + bv.x;
        z.y = (R[i].y - mean2) * inv2 * gv.y + bv.y;
        z.z = (R[i].z - mean2) * inv2 * gv.z + bv.z;
        z.w = (R[i].w - mean2) * inv2 * gv.w + bv.w;
        BF h0,l0,h1,l1,h2,l2,h3,l3;
        split2(z.x,h0,l0); split2(z.y,h1,l1);
        split2(z.z,h2,l2); split2(z.w,h3,l3);
        long base = (long)row * 512 + idx * 4;
        *(BF2*)&oh[base]     = BF2(h0,h1);
        *(BF2*)&oh[base + 2] = BF2(h2,h3);
        *(BF2*)&ol[base]     = BF2(l0,l1);
        *(BF2*)&ol[base + 2] = BF2(l2,l3);
    }
}

// ---------------- misc ----------------
__global__ void initS_k(const float* __restrict__ X, float* __restrict__ S)
{
    const int t = blockIdx.x, b = blockIdx.y, d = threadIdx.x;
    int frame;
    if (t < RTn) {
        int si = t >> 2;
        int st = (si == 15) ? 256 : (si + 1) * 16;
        frame = st + (t & 3);
    } else frame = t - RTn;
    S[((size_t)t * Bn + b) * Dm_ + d] = X[(size_t)b * 133120 + (size_t)frame * Dm_ + d];
}

__global__ void mems0_k(const float* __restrict__ S, BF* __restrict__ uh,
                        BF* __restrict__ ul)
{
    const int s = blockIdx.x, b = blockIdx.y, d = threadIdx.x;
    size_t base = ((size_t)(RTn + s * 16) * Bn + b) * Dm_ + d;
    float acc = 0.f;
#pragma unroll
    for (int k = 0; k < 16; k++) acc += S[base + (size_t)k * Bn * Dm_];
    acc *= (1.f / 16.f);
    BF h, l; split2(acc, h, l);
    size_t o = ((size_t)s * Bn + b) * Dm_ + d;
    uh[o] = h; ul[o] = l;
}

__global__ void summary_pl_k(BF* __restrict__ uh, BF* __restrict__ ul)
{
    const int s = blockIdx.x, b = blockIdx.y, d = threadIdx.x;
    size_t base = ((size_t)((79 + s * 16) * Bn) + b) * Dm_ + d;
    float acc = 0.f;
#pragma unroll
    for (int k = 0; k < 16; k++) {
        size_t o = base + (size_t)k * Bn * Dm_;
        acc += __bfloat162float(uh[o]) + __bfloat162float(ul[o]);
    }
    acc *= (1.f / 16.f);
    BF h, l; split2(acc, h, l);
    size_t o = ((size_t)((335 + s) * Bn) + b) * Dm_ + d;
    uh[o] = h; ul[o] = l;
}

// ---------------- attention: 4 queries per CTA ----------------
__global__ __launch_bounds__(256) void attn_k(
    const float* __restrict__ QKV, const int* __restrict__ lengths,
    BF* __restrict__ Ah, BF* __restrict__ Al)
{
    __shared__ float sc[Hn][64];
    __shared__ short ki[Hn][64];
    const int b = blockIdx.y;
    const int h = threadIdx.x >> 5, lane = threadIdx.x & 31;

    int maxlr = 0;
#pragma unroll
    for (int i = 0; i < Bn; i++) maxlr = max(maxlr, lengths[i] >> 2);
    const int lrb = lengths[b] >> 2;
    const int g = lane >> 3, e = lane & 7;
    const float* Kb = QKV + (size_t)b * 1536 + 512 + h * DHn;
    const float* Vb = Kb + 512;

    for (int qq = 0; qq < 4; qq++) {
        const int qi = blockIdx.x * 4 + qq;
        int seg; bool summ = false;
        if (qi < RTn)      seg = qi >> 2;
        else if (qi < SN)  seg = (qi - RTn) >> 4;
        else             { seg = qi - SN; summ = true; }
        const int ms  = max(seg - 4, 0);
        const int ss  = max(seg * 16 - 32, 0);
        const int se  = min(seg * 16 + 16, Un);
        const int ue  = min(se, lrb + 256 - maxlr);
        const int rcs = 15 + seg * 4;

        const int c0 = summ ? 0 : (seg - ms);
        const int c2 = max(ue - ss, 0);
        const int n  = c0 + 4 + c2;

        for (int j = lane; j < n; j += 32) {
            int k;
            if (j < c0)          k = ms + j;
            else if (j < c0 + 4) k = rcs + (j - c0);
            else                 k = 79 + ss + (j - c0 - 4);
            ki[h][j] = (short)k;
        }
        __syncwarp();

        const float4* qv = (const float4*)(QKV + ((size_t)(15 + qi) * Bn + b) * 1536 + h * DHn);
        float4 q0 = qv[e * 2], q1 = qv[e * 2 + 1];
        q0.x *= 0.125f; q0.y *= 0.125f; q0.z *= 0.125f; q0.w *= 0.125f;
        q1.x *= 0.125f; q1.y *= 0.125f; q1.z *= 0.125f; q1.w *= 0.125f;

        for (int j0 = 0; j0 < n; j0 += 4) {
            int j = j0 + g;
            float p = 0.f;
            if (j < n) {
                const float4* kp = (const float4*)(Kb + (size_t)ki[h][j] * (Bn * 1536));
                float4 k0 = kp[e * 2], k1 = kp[e * 2 + 1];
                p = q0.x * k0.x + q0.y * k0.y + q0.z * k0.z + q0.w * k0.w
                  + q1.x * k1.x + q1.y * k1.y + q1.z * k1.z + q1.w * k1.w;
            }
            p += __shfl_xor_sync(~0u, p, 4);
            p += __shfl_xor_sync(~0u, p, 2);
            p += __shfl_xor_sync(~0u, p, 1);
            if (e == 0 && j < n) sc[h][j] = p;
        }
        __syncwarp();

        float m = -3.4e38f;
        for (int j = lane; j < n; j += 32) m = fmaxf(m, sc[h][j]);
#pragma unroll
        for (int o = 16; o; o >>= 1) m = fmaxf(m, __shfl_xor_sync(~0u, m, o));
        float sum = 0.f;
        for (int j = lane; j < n; j += 32) {
            float e2 = expf(sc[h][j] - m);
            sc[h][j] = e2;
            sum += e2;
        }
#pragma unroll
        for (int o = 16; o; o >>= 1) sum += __shfl_xor_sync(~0u, sum, o);
        __syncwarp();
        const float inv = 1.f / sum;

        float a0 = 0.f, a1 = 0.f;
        for (int j = 0; j < n; j++) {
            float p = sc[h][j];
            const float2 vp = *(const float2*)(Vb + (size_t)ki[h][j] * (Bn * 1536) + 2 * lane);
            a0 = fmaf(p, vp.x, a0);
            a1 = fmaf(p, vp.y, a1);
        }
        a0 *= inv; a1 *= inv;
        BF h0, l0, h1, l1;
        split2(a0, h0, l0); split2(a1, h1, l1);
        size_t op = ((size_t)qi * Bn + b) * Dm_ + h * DHn + 2 * lane;
        *(BF2*)&Ah[op] = BF2(h0, h1);
        *(BF2*)&Al[op] = BF2(l0, l1);
        __syncwarp();
    }
}

__global__ void transpose_pl_k(const float* __restrict__ S, BF* __restrict__ yh,
                               BF* __restrict__ yl)
{
    const int r = blockIdx.x, d = threadIdx.x;
    const int b = r >> 8, u = r & 255;
    float v = S[((size_t)(RTn + u) * Bn + b) * Dm_ + d];
    BF h, l; split2(v, h, l);
    yh[(size_t)r * Dm_ + d] = h;
    yl[(size_t)r * Dm_ + d] = l;
}

__global__ void lr_k(const int* __restrict__ lengths, float* __restrict__ out)
{
    int i = threadIdx.x;
    if (i < Bn) out[i] = (float)(lengths[i] >> 2);
}

// ---------------- host: tensormap plumbing ----------------
typedef CUresult (*EncFn)(CUtensorMap*, CUtensorMapDataType, cuuint32_t, void*,
                          const cuuint64_t*, const cuuint64_t*, const cuuint32_t*,
                          const cuuint32_t*, CUtensorMapInterleave, CUtensorMapSwizzle,
                          CUtensorMapL2promotion, CUtensorMapFloatOOBfill);

static EncFn get_enc() {
    void* p = nullptr;
    cudaDriverEntryPointQueryResult qr;
#if CUDART_VERSION >= 12050
    if (cudaGetDriverEntryPointByVersion("cuTensorMapEncodeTiled", &p, 12000,
                                         cudaEnableDefault, &qr) == cudaSuccess && p)
        return (EncFn)p;
    p = nullptr;
#endif
    cudaGetDriverEntryPoint("cuTensorMapEncodeTiled", &p, cudaEnableDefault, &qr);
    return (EncFn)p;
}

static CUtensorMap mkmap(EncFn enc, const BF* base, long K, long M, long planeStride,
                         unsigned boxM) {
    CUtensorMap m;
    cuuint64_t dims[3]    = {(cuuint64_t)K, (cuuint64_t)M, 2};
    cuuint64_t strides[2] = {(cuuint64_t)K * 2, (cuuint64_t)planeStride * 2};
    cuuint32_t box[3]     = {32, boxM, 1};
    cuuint32_t es[3]      = {1, 1, 1};
    enc(&m, CU_TENSOR_MAP_DATA_TYPE_BFLOAT16, 3, (void*)base, dims, strides, box, es,
        CU_TENSOR_MAP_INTERLEAVE_NONE, CU_TENSOR_MAP_SWIZZLE_64B,
        CU_TENSOR_MAP_L2_PROMOTION_L2_128B, CU_TENSOR_MAP_FLOAT_OOB_FILL_NONE);
    return m;
}

// ---------------- launch ----------------
extern "C" void kernel_launch(void* const* d_in, const int* in_sizes, int n_in,
                              void* d_out, int out_size)
{
    const float* input   = (const float*)d_in[0];
    const int*   lengths = (const int*)  d_in[1];
    const float* w_in    = (const float*)d_in[2];
    const float* ln_in_g = (const float*)d_in[3];
    const float* ln_in_b = (const float*)d_in[4];
    const float* wq = (const float*)d_in[5];
    const float* bq = (const float*)d_in[6];
    const float* wk = (const float*)d_in[7];
    const float* bk = (const float*)d_in[8];
    const float* wv = (const float*)d_in[9];
    const float* bv = (const float*)d_in[10];
    const float* wo = (const float*)d_in[11];
    const float* bo = (const float*)d_in[12];
    const float* ff_g = (const float*)d_in[13];
    const float* ff_b = (const float*)d_in[14];
    const float* w1 = (const float*)d_in[15];
    const float* b1 = (const float*)d_in[16];
    const float* w2 = (const float*)d_in[17];
    const float* b2 = (const float*)d_in[18];
    const float* lo_g = (const float*)d_in[19];
    const float* lo_b = (const float*)d_in[20];
    const float* w_out = (const float*)d_in[21];
    const float* b_out = (const float*)d_in[22];
    const float* lng = (const float*)d_in[23];
    const float* lnb = (const float*)d_in[24];
    float* out = (float*)d_out;

    float* fa = nullptr; BF* bf = nullptr;
    cudaGetSymbolAddress((void**)&fa, g_arena);
    cudaGetSymbolAddress((void**)&bf, g_bf);

    const int SM128 = 1024 + NST * (128 * 128 + 16384) + 128;  // 99456
    const int SM64  = 1024 + NST * (64 * 128 + 16384) + 128;   // 74880
    cudaFuncSetAttribute(gemm6<128>, cudaFuncAttributeMaxDynamicSharedMemorySize, SM128);
    cudaFuncSetAttribute(gemm6<64>,  cudaFuncAttributeMaxDynamicSharedMemorySize, SM64);

    float* X    = fa + F_X;
    float* S    = fa + F_S;
    float* QKVf = fa + F_QKV;
    float* H2A  = fa + F_H2A;
    float* Yb   = fa + F_YB;
    float* BQKV = fa + F_BQKV;

    BF* UINh = bf + BA_U;   BF* UINl = UINh + EU;
    BF* ATTh = bf + BA_AT;  BF* ATTl = ATTh + EAT;
    BF* HBh  = bf + BA_HB;  BF* HBl  = HBh + EHB;
    BF* FBh  = bf + BA_FB;  BF* FBl  = FBh + EFB;
    BF* YTh  = bf + BA_YT;  BF* YTl  = YTh + EYT;

    EncFn enc = get_enc();
    CUtensorMap mUIN = mkmap(enc, UINh, 512, 2816, EU, 128);
    CUtensorMap mATT = mkmap(enc, ATTh, 512, 2688, EAT, 64);
    CUtensorMap mHB  = mkmap(enc, HBh,  512, 2560, EHB, 128);
    CUtensorMap mFB  = mkmap(enc, FBh, 2048, 2560, EFB, 128);
    CUtensorMap mYT  = mkmap(enc, YTh,  512, 2048, EYT, 64);
    CUtensorMap mOUT = mkmap(enc, bf + BW_OUT, 512, 1024, EOUT, 128);
    CUtensorMap mWQKV[Ln], mWO[Ln], mW1[Ln], mW2[Ln];
    for (int l = 0; l < Ln; l++) {
        mWQKV[l] = mkmap(enc, bf + BW_QKV + (size_t)l * 2 * EQKV, 512, 1536, EQKV, 128);
        mWO[l]   = mkmap(enc, bf + BW_O   + (size_t)l * 2 * EQ,   512,  512, EQ, 128);
        mW1[l]   = mkmap(enc, bf + BW_1   + (size_t)l * 2 * EW1,  512, 2048, EW1, 128);
        mW2[l]   = mkmap(enc, bf + BW_2   + (size_t)l * 2 * EW1, 2048,  512, EW1, 128);
    }

    // ---- per-replay preprocessing ----
    gemm_tc<<<dim3(1, 65), 256>>>(input, w_in, nullptr, X, 8320, 128, 80, 0);
    initS_k<<<dim3(SN, Bn), Dm_>>>(X, S);
    mems0_k<<<dim3(15, Bn), Dm_>>>(S, UINh, UINl);

    wconv_k<<<dim3(16, 16, 8), 256>>>(wq, bf + BW_QKV,
                                      bf + BW_QKV + EQKV, 512, 512, EQ, 2 * EQKV);
    wconv_k<<<dim3(16, 16, 8), 256>>>(wk, bf + BW_QKV + 262144,
                                      bf + BW_QKV + EQKV + 262144, 512, 512, EQ, 2 * EQKV);
    wconv_k<<<dim3(16, 16, 8), 256>>>(wv, bf + BW_QKV + 524288,
                                      bf + BW_QKV + EQKV + 524288, 512, 512, EQ, 2 * EQKV);
    wconv_k<<<dim3(16, 16, 8), 256>>>(wo, bf + BW_O, bf + BW_O + EQ, 512, 512, EQ, 2 * EQ);
    wconv_k<<<dim3(64, 16, 8), 256>>>(w1, bf + BW_1, bf + BW_1 + EW1, 512, 2048, EW1, 2 * EW1);
    wconv_k<<<dim3(16, 64, 8), 256>>>(w2, bf + BW_2, bf + BW_2 + EW1, 2048, 512, EW1, 2 * EW1);
    wconv_k<<<dim3(32, 16, 1), 256>>>(w_out, bf + BW_OUT, bf + BW_OUT + EOUT, 512, 1024, 0, 0);
    prep_k<<<48, 256>>>(bq, bk, bv, BQKV, UINh, UINl);

    // layer-0 LN1: S -> UIN state planes (rows 120..2679)
    ln_row_k<<<SN * Bn / 8, 256>>>(S, ln_in_g, ln_in_b, nullptr,
                                   UINh + 120 * 512, UINl + 120 * 512, Dm_);

    for (int l = 0; l < Ln; l++) {
        summary_pl_k<<<dim3(NSEG, Bn), Dm_>>>(UINh, UINl);

        gemm6<128><<<dim3(12, 22, 1), 256, SM128>>>(mUIN, mWQKV[l], BQKV + l * 1536,
                                                    QKVf, 0, nullptr, nullptr,
                                                    1536, 512, 0, 0);

        attn_k<<<dim3(QN / 4, Bn), 256>>>(QKVf, lengths, ATTh, ATTl);

        gemm6<64><<<dim3(4, 42, 1), 256, SM64>>>(mATT, mWO[l], bo + l * Dm_,
                                                 S, 0, UINh, UINl,
                                                 512, 512, 0, 2);

        ln_row_k<<<SN * Bn / 8, 256>>>(S, ff_g + l * Dm_, ff_b + l * Dm_,
                                       nullptr, HBh, HBl, Dm_);
        gemm6<128><<<dim3(16, 20, 1), 256, SM128>>>(mHB, mW1[l], b1 + l * FFNn,
                                                    nullptr, 0, FBh, FBl,
                                                    2048, 512, 1, 1);
        // FFN2 split-K=3 (704 per chunk; TMA zero-fills K >= 2048)
        gemm6<128><<<dim3(4, 20, 3), 256, SM128>>>(mFB, mW2[l], b2 + l * Dm_,
                                                   H2A, 1310720, nullptr, nullptr,
                                                   512, 704, 0, 0);

        const float* g2 = (l + 1 < Ln) ? (ln_in_g + (l + 1) * Dm_) : nullptr;
        const float* b2n = (l + 1 < Ln) ? (ln_in_b + (l + 1) * Dm_) : nullptr;
        ln2_k<<<SN * Bn / 8, 256>>>(S, H2A, H2A + 1310720, H2A + 2621440,
                                    lo_g + l * Dm_, lo_b + l * Dm_, g2, b2n,
                                    S, UINh + 120 * 512, UINl + 120 * 512);
    }

    transpose_pl_k<<<2048, Dm_>>>(S, YTh, YTl);
    gemm6<64><<<dim3(8, 32, 1), 256, SM64>>>(mYT, mOUT, b_out,
                                             Yb, 0, nullptr, nullptr,
                                             1024, 512, 0, 0);
    ln_row_k<<<2048 / 8, 256>>>(Yb, lng, lnb, out, nullptr, nullptr, OUTn);

    if (out_size >= 2048 * 1024 + Bn)
        lr_k<<<1, 32>>>(lengths, out + 2048 * 1024);
}

// round 10
// speedup vs baseline: 5.2029x; 1.0068x over previous
#include <cuda_runtime.h>
#include <cuda_bf16.h>
#include <cuda.h>
#include <math.h>
#include <stdint.h>

typedef __nv_bfloat16 BF;
typedef __nv_bfloat162 BF2;

// ---------------- constants ----------------
#define Bn   8
#define Dm_  512
#define FFNn 2048
#define Ln   8
#define OUTn 1024
#define Hn   8
#define DHn  64
#define QN   336
#define SN   320
#define RTn  64
#define Un   256
#define NSEG 16

// token space: 0..14 mems | 15..78 rc | 79..334 utt | 335..350 summary | 351 pad
// row = token*8 + b;  M_UIN = 2816

// ------- float arena -------
#define F_X    0UL
#define F_S    (F_X + 1064960UL)
#define F_QKV  (F_S + 1310720UL)
#define F_H2A  (F_QKV + 4325376UL)
#define F_H2B  (F_H2A + 1310720UL)
#define F_H2C  (F_H2B + 1310720UL)
#define F_YB   (F_H2C + 1310720UL)
#define F_BQKV (F_YB + 2097152UL)
#define F_TOT  (F_BQKV + 12288UL)
__device__ __align__(1024) float g_arena[F_TOT];

// ------- bf16 arena -------
#define EQ    262144UL
#define EQKV  786432UL     // 1536*512
#define EW1   1048576UL
#define EOUT  524288UL
#define EU    1441792UL    // 2816*512
#define EAT   1376256UL    // 2688*512
#define EHB   1310720UL    // 2560*512
#define EFB   5242880UL    // 2560*2048
#define EYT   1048576UL    // 2048*512

#define BW_QKV 0UL
#define BW_O   (BW_QKV + 8UL*2UL*EQKV)
#define BW_1   (BW_O   + 8UL*2UL*EQ)
#define BW_2   (BW_1   + 8UL*2UL*EW1)
#define BW_OUT (BW_2   + 8UL*2UL*EW1)
#define BA_U   (BW_OUT + 2UL*EOUT)
#define BA_AT  (BA_U   + 2UL*EU)
#define BA_HB  (BA_AT  + 2UL*EAT)
#define BA_FB  (BA_HB  + 2UL*EHB)
#define BA_YT  (BA_FB  + 2UL*EFB)
#define B_TOT  (BA_YT  + 2UL*EYT)
__device__ __align__(1024) BF g_bf[B_TOT];

__device__ __forceinline__ void split2(float x, BF& h, BF& l) {
    h = __float2bfloat16(x);
    l = __float2bfloat16(x - __bfloat162float(h));
}

// ============ TMA / mbarrier primitives ============
__device__ __forceinline__ uint32_t smem_u32(const void* p) {
    return (uint32_t)__cvta_generic_to_shared(p);
}
__device__ __forceinline__ void mbar_init(uint32_t a, uint32_t cnt) {
    asm volatile("mbarrier.init.shared::cta.b64 [%0], %1;" :: "r"(a), "r"(cnt) : "memory");
}
__device__ __forceinline__ void mbar_expect(uint32_t a, uint32_t tx) {
    asm volatile("mbarrier.arrive.expect_tx.shared::cta.b64 _, [%0], %1;"
                 :: "r"(a), "r"(tx) : "memory");
}
__device__ __forceinline__ void mbar_arrive(uint32_t a) {
    asm volatile("mbarrier.arrive.shared::cta.b64 _, [%0];" :: "r"(a) : "memory");
}
__device__ __forceinline__ void mbar_wait(uint32_t a, uint32_t ph) {
    uint32_t done = 0;
    while (!done) {
        asm volatile(
            "{\n\t.reg .pred p;\n\t"
            "mbarrier.try_wait.parity.acquire.cta.shared::cta.b64 p, [%1], %2, 0x989680;\n\t"
            "selp.b32 %0, 1, 0, p;\n\t}"
            : "=r"(done) : "r"(a), "r"(ph) : "memory");
    }
}
__device__ __forceinline__ void tma3d(uint32_t dst, const void* map,
                                      int cx, int cy, int cz, uint32_t mbar) {
    asm volatile(
        "cp.async.bulk.tensor.3d.shared::cta.global.tile.mbarrier::complete_tx::bytes "
        "[%0], [%1, {%2, %3, %4}], [%5];"
        :: "r"(dst), "l"(map), "r"(cx), "r"(cy), "r"(cz), "r"(mbar) : "memory");
}
__device__ __forceinline__ void mma2(float c[4], const uint32_t a[4],
                                     uint32_t b0, uint32_t b1) {
    asm volatile(
        "mma.sync.aligned.m16n8k16.row.col.f32.bf16.bf16.f32 "
        "{%0,%1,%2,%3}, {%4,%5,%6,%7}, {%8,%9}, {%0,%1,%2,%3};\n"
        : "+f"(c[0]), "+f"(c[1]), "+f"(c[2]), "+f"(c[3])
        : "r"(a[0]), "r"(a[1]), "r"(a[2]), "r"(a[3]), "r"(b0), "r"(b1));
}
#define LDSM4(r, a) \
    asm volatile("ldmatrix.sync.aligned.m8n8.x4.shared.b16 {%0,%1,%2,%3}, [%4];" \
        : "=r"((r)[0]), "=r"((r)[1]), "=r"((r)[2]), "=r"((r)[3]) : "r"(a))

// ============ TMA-staged mma.sync GEMM (SW64, 32-K stages) ============
// C = act(A @ B^T + bias). grid (N/NT, M/MT, splitZ). TMA zero-fills OOB K.
// mode 0: fp32 Cf (+ z*czstride). mode 1: bf16 planes Ch/Cl.
// mode 2: fused O epilogue: rows<2560 S+=v; rows 2560..2679 planes=tanh(v).
#define NST 3

template <int MT, int NT>
__global__ __launch_bounds__(256, 2) void gemm6(
    const __grid_constant__ CUtensorMap tmA,
    const __grid_constant__ CUtensorMap tmB,
    const float* __restrict__ bias, float* __restrict__ Cf, long czstride,
    BF* __restrict__ Ch, BF* __restrict__ Cl,
    int N, int K, int act, int mode)
{
    constexpr int MSPAN = MT / 4;            // warp m-span
    constexpr int MTM   = MSPAN / 16;        // m16 tiles per warp
    constexpr int NSPAN = NT / 2;            // warp n-span
    constexpr int NNT   = NSPAN / 8;         // n8 tiles per warp
    constexpr int APL   = MT * 64;           // A plane bytes per stage
    constexpr int BPL   = NT * 64;           // B plane bytes per stage
    constexpr int STB   = 2 * APL + 2 * BPL; // stage bytes
    extern __shared__ __align__(16) char smx[];
    const uint32_t sb = smem_u32(smx);
    const uint32_t db = (sb + 1023) & ~1023u;
    const int tid = threadIdx.x, lane = tid & 31, wid = tid >> 5;
    const int wm = wid & 3, wn = wid >> 2;
    const int grp = lane >> 2, tig = lane & 3;
    const int row0 = blockIdx.y * MT, col0 = blockIdx.x * NT;
    const int kstart = blockIdx.z * K;
    if (Cf && mode == 0) Cf += (long)blockIdx.z * czstride;
    const float* bi = (bias && kstart == 0) ? bias : nullptr;
    const int T = K >> 5;

    const uint32_t barb = db + NST * STB;
    if (tid == 0) {
        for (int s = 0; s < NST; s++) {
            mbar_init(barb + s * 8, 1);
            mbar_init(barb + 64 + s * 8, 256);
        }
    }
    __syncthreads();

    if (tid == 0) {
        for (int s = 0; s < NST; s++) {
            uint32_t st = db + s * STB, fb = barb + s * 8;
            mbar_expect(fb, STB);
            tma3d(st,                 &tmA, kstart + s * 32, row0, 0, fb);
            tma3d(st + APL,           &tmA, kstart + s * 32, row0, 1, fb);
            tma3d(st + 2 * APL,       &tmB, kstart + s * 32, col0, 0, fb);
            tma3d(st + 2 * APL + BPL, &tmB, kstart + s * 32, col0, 1, fb);
        }
    }

    float acc[MTM][NNT][4] = {};
    // ldmatrix lane geometry (SW64: 64B rows; xor = ((row>>1)&3)<<4)
    const int lrow = (lane & 7) + (((lane >> 3) & 1) << 3);
    const int kofs = ((lane >> 4) & 1) * 8;
    const uint32_t msk = (uint32_t)((lrow >> 1) & 3) << 4;
    uint32_t arow_off[MTM], brow_off[NNT / 2];
#pragma unroll
    for (int mt = 0; mt < MTM; mt++)
        arow_off[mt] = (uint32_t)(wm * MSPAN + mt * 16 + lrow) * 64;
#pragma unroll
    for (int p = 0; p < NNT / 2; p++)
        brow_off[p] = (uint32_t)(wn * NSPAN + p * 16 + lrow) * 64;

    uint32_t pfm = 0, pem = 0;
    for (int i = 0; i < T; i++) {
        const int bslot = i % NST;
        const uint32_t fb = barb + bslot * 8, eb = barb + 64 + bslot * 8;
        mbar_wait(fb, (pfm >> bslot) & 1); pfm ^= (1u << bslot);
        const uint32_t sA = db + bslot * STB, sB = sA + 2 * APL;
#pragma unroll
        for (int kk = 0; kk < 32; kk += 16) {
            const uint32_t csw = ((uint32_t)((kk + kofs) * 2)) ^ msk;
            uint32_t ah[MTM][4], al_[MTM][4], bh[NNT / 2][4], bl_[NNT / 2][4];
#pragma unroll
            for (int mt = 0; mt < MTM; mt++) {
                uint32_t ad = sA + arow_off[mt] + csw;
                LDSM4(ah[mt], ad);
                LDSM4(al_[mt], ad + APL);
            }
#pragma unroll
            for (int p = 0; p < NNT / 2; p++) {
                uint32_t bd = sB + brow_off[p] + csw;
                LDSM4(bh[p], bd);
                LDSM4(bl_[p], bd + BPL);
            }
#pragma unroll
            for (int nt = 0; nt < NNT; nt++) {
                const int p = nt >> 1, s1 = nt & 1;
#pragma unroll
                for (int mt = 0; mt < MTM; mt++) {
                    mma2(acc[mt][nt], ah[mt],  bh[p][s1],  bh[p][2 + s1]);
                    mma2(acc[mt][nt], al_[mt], bh[p][s1],  bh[p][2 + s1]);
                    mma2(acc[mt][nt], ah[mt],  bl_[p][s1], bl_[p][2 + s1]);
                }
            }
        }
        mbar_arrive(eb);
        if (tid == 0 && i + NST < T) {
            mbar_wait(eb, (pem >> bslot) & 1); pem ^= (1u << bslot);
            uint32_t st = db + bslot * STB;
            mbar_expect(fb, STB);
            int k0 = kstart + (i + NST) * 32;
            tma3d(st,                 &tmA, k0, row0, 0, fb);
            tma3d(st + APL,           &tmA, k0, row0, 1, fb);
            tma3d(st + 2 * APL,       &tmB, k0, col0, 0, fb);
            tma3d(st + 2 * APL + BPL, &tmB, k0, col0, 1, fb);
        }
    }

#pragma unroll
    for (int mt = 0; mt < MTM; mt++) {
        const long r = row0 + wm * MSPAN + mt * 16 + grp;
#pragma unroll
        for (int nt = 0; nt < NNT; nt++) {
            const long c = col0 + wn * NSPAN + nt * 8 + tig * 2;
            float bb0 = bi ? bi[c] : 0.f, bb1 = bi ? bi[c + 1] : 0.f;
            float v0 = acc[mt][nt][0] + bb0, v1 = acc[mt][nt][1] + bb1;
            float v2 = acc[mt][nt][2] + bb0, v3 = acc[mt][nt][3] + bb1;
            if (act) {
                v0 = fmaxf(v0, 0.f); v1 = fmaxf(v1, 0.f);
                v2 = fmaxf(v2, 0.f); v3 = fmaxf(v3, 0.f);
            }
            if (mode == 0) {
                *(float2*)&Cf[r * N + c]       = make_float2(v0, v1);
                *(float2*)&Cf[(r + 8) * N + c] = make_float2(v2, v3);
            } else if (mode == 1) {
                BF h0, l0, h1, l1;
                split2(v0, h0, l0); split2(v1, h1, l1);
                *(BF2*)&Ch[r * N + c] = BF2(h0, h1);
                *(BF2*)&Cl[r * N + c] = BF2(l0, l1);
                split2(v2, h0, l0); split2(v3, h1, l1);
                *(BF2*)&Ch[(r + 8) * N + c] = BF2(h0, h1);
                *(BF2*)&Cl[(r + 8) * N + c] = BF2(l0, l1);
            } else {
#pragma unroll
                for (int rr = 0; rr < 2; rr++) {
                    long r2 = r + rr * 8;
                    float u0 = rr ? v2 : v0, u1 = rr ? v3 : v1;
                    if (r2 < 2560) {
                        float2 s = *(float2*)&Cf[r2 * 512 + c];
                        *(float2*)&Cf[r2 * 512 + c] = make_float2(s.x + u0, s.y + u1);
                    } else if (r2 < 2680) {
                        float t0 = tanhf(u0), t1 = tanhf(u1);
                        BF h0, l0, h1, l1;
                        split2(t0, h0, l0); split2(t1, h1, l1);
                        long o = (r2 - 2560) * 512 + c;
                        *(BF2*)&Ch[o] = BF2(h0, h1);
                        *(BF2*)&Cl[o] = BF2(l0, l1);
                    }
                }
            }
        }
    }
}

// ---------------- legacy in-kernel-convert GEMM (input proj, K=80) ---------
#define LLDA 40
__global__ __launch_bounds__(256) void gemm_tc(
    const float* __restrict__ A, const float* __restrict__ W,
    const float* __restrict__ bias, float* __restrict__ C,
    int M, int N, int K, int act)
{
    __shared__ BF Ahs[128 * LLDA], Als[128 * LLDA];
    __shared__ BF Bhs[128 * LLDA], Bls[128 * LLDA];
    const int tid = threadIdx.x, lane = tid & 31, wid = tid >> 5;
    const int wm = wid & 3, wn = wid >> 2;
    const int grp = lane >> 2, tig = lane & 3;
    const long row0 = (long)blockIdx.y * 128;
    const int  col0 = blockIdx.x * 128;
    float acc[2][8][4] = {};
    const int arow = tid >> 1, acol0 = (tid & 1) * 16;
    const int brow = tid >> 3, bcol0 = (tid & 7) * 16;

    for (int k0 = 0; k0 < K; k0 += 32) {
#pragma unroll
        for (int j = 0; j < 4; j++) {
            int c = acol0 + j * 4;
            float4 v = make_float4(0.f, 0.f, 0.f, 0.f);
            if (row0 + arow < M && k0 + c < K)
                v = *(const float4*)&A[(row0 + arow) * (long)K + k0 + c];
            BF h, l; int o = arow * LLDA + c;
            split2(v.x, h, l); Ahs[o]     = h; Als[o]     = l;
            split2(v.y, h, l); Ahs[o + 1] = h; Als[o + 1] = l;
            split2(v.z, h, l); Ahs[o + 2] = h; Als[o + 2] = l;
            split2(v.w, h, l); Ahs[o + 3] = h; Als[o + 3] = l;
        }
#pragma unroll
        for (int j = 0; j < 4; j++) {
            int n = bcol0 + j * 4;
            float4 v = make_float4(0.f, 0.f, 0.f, 0.f);
            if (k0 + brow < K)
                v = *(const float4*)&W[(long)(k0 + brow) * N + col0 + n];
            BF h, l;
            split2(v.x, h, l); Bhs[(n + 0) * LLDA + brow] = h; Bls[(n + 0) * LLDA + brow] = l;
            split2(v.y, h, l); Bhs[(n + 1) * LLDA + brow] = h; Bls[(n + 1) * LLDA + brow] = l;
            split2(v.z, h, l); Bhs[(n + 2) * LLDA + brow] = h; Bls[(n + 2) * LLDA + brow] = l;
            split2(v.w, h, l); Bhs[(n + 3) * LLDA + brow] = h; Bls[(n + 3) * LLDA + brow] = l;
        }
        __syncthreads();
#pragma unroll
        for (int kk = 0; kk < 32; kk += 16) {
            uint32_t ah[2][4], al[2][4];
#pragma unroll
            for (int mt = 0; mt < 2; mt++) {
                int r = wm * 32 + mt * 16;
                int o  = (r + grp) * LLDA + kk + tig * 2;
                int o8 = o + 8 * LLDA;
                ah[mt][0] = *(const uint32_t*)&Ahs[o];
                ah[mt][1] = *(const uint32_t*)&Ahs[o8];
                ah[mt][2] = *(const uint32_t*)&Ahs[o + 8];
                ah[mt][3] = *(const uint32_t*)&Ahs[o8 + 8];
                al[mt][0] = *(const uint32_t*)&Als[o];
                al[mt][1] = *(const uint32_t*)&Als[o8];
                al[mt][2] = *(const uint32_t*)&Als[o + 8];
                al[mt][3] = *(const uint32_t*)&Als[o8 + 8];
            }
#pragma unroll
            for (int nt = 0; nt < 8; nt++) {
                int nn = wn * 64 + nt * 8 + grp;
                int o = nn * LLDA + kk + tig * 2;
                uint32_t b0 = *(const uint32_t*)&Bhs[o], b1 = *(const uint32_t*)&Bhs[o + 8];
                uint32_t c0 = *(const uint32_t*)&Bls[o], c1 = *(const uint32_t*)&Bls[o + 8];
#pragma unroll
                for (int mt = 0; mt < 2; mt++) {
                    mma2(acc[mt][nt], ah[mt], b0, b1);
                    mma2(acc[mt][nt], al[mt], b0, b1);
                    mma2(acc[mt][nt], ah[mt], c0, c1);
                }
            }
        }
        __syncthreads();
    }
#pragma unroll
    for (int mt = 0; mt < 2; mt++) {
#pragma unroll
        for (int nt = 0; nt < 8; nt++) {
            int c = col0 + wn * 64 + nt * 8 + tig * 2;
            float b0 = bias ? bias[c] : 0.f;
            float b1 = bias ? bias[c + 1] : 0.f;
            long r = row0 + wm * 32 + mt * 16 + grp;
            float v0 = acc[mt][nt][0] + b0, v1 = acc[mt][nt][1] + b1;
            float v2 = acc[mt][nt][2] + b0, v3 = acc[mt][nt][3] + b1;
            if (act) { v0=fmaxf(v0,0.f); v1=fmaxf(v1,0.f); v2=fmaxf(v2,0.f); v3=fmaxf(v3,0.f); }
            if (r < M)     *(float2*)&C[r * N + c]       = make_float2(v0, v1);
            if (r + 8 < M) *(float2*)&C[(r + 8) * N + c] = make_float2(v2, v3);
        }
    }
}

// ---------------- weight transpose+convert: out[n][k] = W[k][n] ----------
__global__ __launch_bounds__(256) void wconv_k(
    const float* __restrict__ W, BF* __restrict__ oh, BF* __restrict__ ol,
    int K, int N, long inS, long outS)
{
    __shared__ float t[32][33];
    const float* w = W + (long)blockIdx.z * inS;
    BF* ph = oh + (long)blockIdx.z * outS;
    BF* pl = ol + (long)blockIdx.z * outS;
    const int n0 = blockIdx.x * 32, k0 = blockIdx.y * 32;
    const int tx = threadIdx.x & 7, ty = threadIdx.x >> 3;
    float4 v = *(const float4*)&w[(long)(k0 + ty) * N + n0 + tx * 4];
    t[ty][tx * 4 + 0] = v.x; t[ty][tx * 4 + 1] = v.y;
    t[ty][tx * 4 + 2] = v.z; t[ty][tx * 4 + 3] = v.w;
    __syncthreads();
    float a0 = t[tx * 4 + 0][ty], a1 = t[tx * 4 + 1][ty];
    float a2 = t[tx * 4 + 2][ty], a3 = t[tx * 4 + 3][ty];
    BF h0, l0, h1, l1, h2, l2, h3, l3;
    split2(a0, h0, l0); split2(a1, h1, l1);
    split2(a2, h2, l2); split2(a3, h3, l3);
    long o = (long)(n0 + ty) * K + k0 + tx * 4;
    *(BF2*)&ph[o]     = BF2(h0, h1);
    *(BF2*)&ph[o + 2] = BF2(h2, h3);
    *(BF2*)&pl[o]     = BF2(l0, l1);
    *(BF2*)&pl[o + 2] = BF2(l2, l3);
}

// merged bias pack + UIN pad
__global__ void prep_k(const float* __restrict__ bq, const float* __restrict__ bk,
                       const float* __restrict__ bv, float* __restrict__ o,
                       BF* __restrict__ uh, BF* __restrict__ ul)
{
    int i = blockIdx.x * blockDim.x + threadIdx.x;
    if (i < 12288) {
        int l = i / 1536, j = i % 1536;
        float v;
        if (j < 512)       v = bq[l * 512 + j];
        else if (j < 1024) v = bk[l * 512 + j - 512];
        else               v = bv[l * 512 + j - 1024];
        o[i] = v;
    }
    if (i < 4096) {
        size_t p = 2808UL * 512UL + i;
        uh[p] = __float2bfloat16(0.f);
        ul[p] = __float2bfloat16(0.f);
    }
}

// ---------------- LayerNorm: warp per row ----------------
__global__ __launch_bounds__(256) void ln_row_k(
    const float* __restrict__ X, const float* __restrict__ g, const float* __restrict__ bta,
    float* __restrict__ outf, BF* __restrict__ oh, BF* __restrict__ ol, int D)
{
    const int wid = threadIdx.x >> 5, lane = threadIdx.x & 31;
    const int row = blockIdx.x * 8 + wid;
    const float4* x = (const float4*)(X + (long)row * D);
    const int cnt = D >> 7;
    float s = 0.f, s2 = 0.f;
    for (int i = 0; i < cnt; i++) {
        float4 a = x[lane + i * 32];
        s  += a.x + a.y + a.z + a.w;
        s2 += a.x * a.x + a.y * a.y + a.z * a.z + a.w * a.w;
    }
#pragma unroll
    for (int o = 16; o; o >>= 1) {
        s  += __shfl_xor_sync(~0u, s, o);
        s2 += __shfl_xor_sync(~0u, s2, o);
    }
    const float mean = s / D;
    const float inv = rsqrtf(s2 / D - mean * mean + 1e-5f);
    const float4* gg = (const float4*)g;
    const float4* bb = (const float4*)bta;
    for (int i = 0; i < cnt; i++) {
        int idx = lane + i * 32;
        float4 a = x[idx], gv = gg[idx], bv = bb[idx], o;
        o.x = (a.x - mean) * inv * gv.x + bv.x;
        o.y = (a.y - mean) * inv * gv.y + bv.y;
        o.z = (a.z - mean) * inv * gv.z + bv.z;
        o.w = (a.w - mean) * inv * gv.w + bv.w;
        if (outf) ((float4*)(outf + (long)row * D))[idx] = o;
        if (oh) {
            BF h0,l0,h1,l1,h2,l2,h3,l3;
            split2(o.x,h0,l0); split2(o.y,h1,l1);
            split2(o.z,h2,l2); split2(o.w,h3,l3);
            long base = (long)row * D + idx * 4;
            *(BF2*)&oh[base]     = BF2(h0,h1);
            *(BF2*)&oh[base + 2] = BF2(h2,h3);
            *(BF2*)&ol[base]     = BF2(l0,l1);
            *(BF2*)&ol[base + 2] = BF2(l2,l3);
        }
    }
}

// -------- double LN: res=S+HA+HB+HC; S=LN1(res); planes=LN2(S) ------------
__global__ __launch_bounds__(256) void ln2_k(
    const float* __restrict__ S, const float* __restrict__ HA,
    const float* __restrict__ HB_, const float* __restrict__ HC,
    const float* __restrict__ g1, const float* __restrict__ be1,
    const float* __restrict__ g2, const float* __restrict__ be2,
    float* __restrict__ Sout, BF* __restrict__ oh, BF* __restrict__ ol)
{
    const int wid = threadIdx.x >> 5, lane = threadIdx.x & 31;
    const int row = blockIdx.x * 8 + wid;   // 0..2559
    const float4* xs = (const float4*)(S   + (long)row * 512);
    const float4* xa = (const float4*)(HA  + (long)row * 512);
    const float4* xb = (const float4*)(HB_ + (long)row * 512);
    const float4* xc = (const float4*)(HC  + (long)row * 512);
    float4 R[4];
    float s = 0.f, s2 = 0.f;
#pragma unroll
    for (int i = 0; i < 4; i++) {
        int idx = lane + i * 32;
        float4 a = xs[idx], c = xa[idx], d = xb[idx], e = xc[idx];
        a.x += c.x + d.x + e.x; a.y += c.y + d.y + e.y;
        a.z += c.z + d.z + e.z; a.w += c.w + d.w + e.w;
        R[i] = a;
        s  += a.x + a.y + a.z + a.w;
        s2 += a.x * a.x + a.y * a.y + a.z * a.z + a.w * a.w;
    }
#pragma unroll
    for (int o = 16; o; o >>= 1) {
        s  += __shfl_xor_sync(~0u, s, o);
        s2 += __shfl_xor_sync(~0u, s2, o);
    }
    float mean = s * (1.f / 512.f);
    float inv = rsqrtf(s2 * (1.f / 512.f) - mean * mean + 1e-5f);
    const float4* g1v = (const float4*)g1; const float4* b1v = (const float4*)be1;
    float t = 0.f, t2 = 0.f;
#pragma unroll
    for (int i = 0; i < 4; i++) {
        int idx = lane + i * 32;
        float4 gv = g1v[idx], bv = b1v[idx], y;
        y.x = (R[i].x - mean) * inv * gv.x + bv.x;
        y.y = (R[i].y - mean) * inv * gv.y + bv.y;
        y.z = (R[i].z - mean) * inv * gv.z + bv.z;
        y.w = (R[i].w - mean) * inv * gv.w + bv.w;
        R[i] = y;
        ((float4*)(Sout + (long)row * 512))[idx] = y;
        t  += y.x + y.y + y.z + y.w;
        t2 += y.x * y.x + y.y * y.y + y.z * y.z + y.w * y.w;
    }
    if (!g2) return;
#pragma unroll
    for (int o = 16; o; o >>= 1) {
        t  += __shfl_xor_sync(~0u, t, o);
        t2 += __shfl_xor_sync(~0u, t2, o);
    }
    float mean2 = t * (1.f / 512.f);
    float inv2 = rsqrtf(t2 * (1.f / 512.f) - mean2 * mean2 + 1e-5f);
    const float4* g2v = (const float4*)g2; const float4* b2v = (const float4*)be2;
#pragma unroll
    for (int i = 0; i < 4; i++) {
        int idx = lane + i * 32;
        float4 gv = g2v[idx], bv = b2v[idx], z;
        z.x = (R[i].x - mean2) * inv2 * gv.x + bv.x;
        z.y = (R[i].y - mean2) * inv2 * gv.y + bv.y;
        z.z = (R[i].z - mean2) * inv2 * gv.z + bv.z;
        z.w = (R[i].w - mean2) * inv2 * gv.w + bv.w;
        BF h0,l0,h1,l1,h2,l2,h3,l3;
        split2(z.x,h0,l0); split2(z.y,h1,l1);
        split2(z.z,h2,l2); split2(z.w,h3,l3);
        long base = (long)row * 512 + idx * 4;
        *(BF2*)&oh[base]     = BF2(h0,h1);
        *(BF2*)&oh[base + 2] = BF2(h2,h3);
        *(BF2*)&ol[base]     = BF2(l0,l1);
        *(BF2*)&ol[base + 2] = BF2(l2,l3);
    }
}

// ---------------- misc ----------------
__global__ void initS_k(const float* __restrict__ X, float* __restrict__ S)
{
    const int t = blockIdx.x, b = blockIdx.y, d = threadIdx.x;
    int frame;
    if (t < RTn) {
        int si = t >> 2;
        int st = (si == 15) ? 256 : (si + 1) * 16;
        frame = st + (t & 3);
    } else frame = t - RTn;
    S[((size_t)t * Bn + b) * Dm_ + d] = X[(size_t)b * 133120 + (size_t)frame * Dm_ + d];
}

__global__ void mems0_k(const float* __restrict__ S, BF* __restrict__ uh,
                        BF* __restrict__ ul)
{
    const int s = blockIdx.x, b = blockIdx.y, d = threadIdx.x;
    size_t base = ((size_t)(RTn + s * 16) * Bn + b) * Dm_ + d;
    float acc = 0.f;
#pragma unroll
    for (int k = 0; k < 16; k++) acc += S[base + (size_t)k * Bn * Dm_];
    acc *= (1.f / 16.f);
    BF h, l; split2(acc, h, l);
    size_t o = ((size_t)s * Bn + b) * Dm_ + d;
    uh[o] = h; ul[o] = l;
}

__global__ void summary_pl_k(BF* __restrict__ uh, BF* __restrict__ ul)
{
    const int s = blockIdx.x, b = blockIdx.y, d = threadIdx.x;
    size_t base = ((size_t)((79 + s * 16) * Bn) + b) * Dm_ + d;
    float acc = 0.f;
#pragma unroll
    for (int k = 0; k < 16; k++) {
        size_t o = base + (size_t)k * Bn * Dm_;
        acc += __bfloat162float(uh[o]) + __bfloat162float(ul[o]);
    }
    acc *= (1.f / 16.f);
    BF h, l; split2(acc, h, l);
    size_t o = ((size_t)((335 + s) * Bn) + b) * Dm_ + d;
    uh[o] = h; ul[o] = l;
}

// ---------------- attention: 4 queries per CTA ----------------
__global__ __launch_bounds__(256) void attn_k(
    const float* __restrict__ QKV, const int* __restrict__ lengths,
    BF* __restrict__ Ah, BF* __restrict__ Al)
{
    __shared__ float sc[Hn][64];
    __shared__ short ki[Hn][64];
    const int b = blockIdx.y;
    const int h = threadIdx.x >> 5, lane = threadIdx.x & 31;

    int maxlr = 0;
#pragma unroll
    for (int i = 0; i < Bn; i++) maxlr = max(maxlr, lengths[i] >> 2);
    const int lrb = lengths[b] >> 2;
    const int g = lane >> 3, e = lane & 7;
    const float* Kb = QKV + (size_t)b * 1536 + 512 + h * DHn;
    const float* Vb = Kb + 512;

    for (int qq = 0; qq < 4; qq++) {
        const int qi = blockIdx.x * 4 + qq;
        int seg; bool summ = false;
        if (qi < RTn)      seg = qi >> 2;
        else if (qi < SN)  seg = (qi - RTn) >> 4;
        else             { seg = qi - SN; summ = true; }
        const int ms  = max(seg - 4, 0);
        const int ss  = max(seg * 16 - 32, 0);
        const int se  = min(seg * 16 + 16, Un);
        const int ue  = min(se, lrb + 256 - maxlr);
        const int rcs = 15 + seg * 4;

        const int c0 = summ ? 0 : (seg - ms);
        const int c2 = max(ue - ss, 0);
        const int n  = c0 + 4 + c2;

        for (int j = lane; j < n; j += 32) {
            int k;
            if (j < c0)          k = ms + j;
            else if (j < c0 + 4) k = rcs + (j - c0);
            else                 k = 79 + ss + (j - c0 - 4);
            ki[h][j] = (short)k;
        }
        __syncwarp();

        const float4* qv = (const float4*)(QKV + ((size_t)(15 + qi) * Bn + b) * 1536 + h * DHn);
        float4 q0 = qv[e * 2], q1 = qv[e * 2 + 1];
        q0.x *= 0.125f; q0.y *= 0.125f; q0.z *= 0.125f; q0.w *= 0.125f;
        q1.x *= 0.125f; q1.y *= 0.125f; q1.z *= 0.125f; q1.w *= 0.125f;

        for (int j0 = 0; j0 < n; j0 += 4) {
            int j = j0 + g;
            float p = 0.f;
            if (j < n) {
                const float4* kp = (const float4*)(Kb + (size_t)ki[h][j] * (Bn * 1536));
                float4 k0 = kp[e * 2], k1 = kp[e * 2 + 1];
                p = q0.x * k0.x + q0.y * k0.y + q0.z * k0.z + q0.w * k0.w
                  + q1.x * k1.x + q1.y * k1.y + q1.z * k1.z + q1.w * k1.w;
            }
            p += __shfl_xor_sync(~0u, p, 4);
            p += __shfl_xor_sync(~0u, p, 2);
            p += __shfl_xor_sync(~0u, p, 1);
            if (e == 0 && j < n) sc[h][j] = p;
        }
        __syncwarp();

        float m = -3.4e38f;
        for (int j = lane; j < n; j += 32) m = fmaxf(m, sc[h][j]);
#pragma unroll
        for (int o = 16; o; o >>= 1) m = fmaxf(m, __shfl_xor_sync(~0u, m, o));
        float sum = 0.f;
        for (int j = lane; j < n; j += 32) {
            float e2 = expf(sc[h][j] - m);
            sc[h][j] = e2;
            sum += e2;
        }
#pragma unroll
        for (int o = 16; o; o >>= 1) sum += __shfl_xor_sync(~0u, sum, o);
        __syncwarp();
        const float inv = 1.f / sum;

        float a0 = 0.f, a1 = 0.f;
        for (int j = 0; j < n; j++) {
            float p = sc[h][j];
            const float2 vp = *(const float2*)(Vb + (size_t)ki[h][j] * (Bn * 1536) + 2 * lane);
            a0 = fmaf(p, vp.x, a0);
            a1 = fmaf(p, vp.y, a1);
        }
        a0 *= inv; a1 *= inv;
        BF h0, l0, h1, l1;
        split2(a0, h0, l0); split2(a1, h1, l1);
        size_t op = ((size_t)qi * Bn + b) * Dm_ + h * DHn + 2 * lane;
        *(BF2*)&Ah[op] = BF2(h0, h1);
        *(BF2*)&Al[op] = BF2(l0, l1);
        __syncwarp();
    }
}

__global__ void transpose_pl_k(const float* __restrict__ S, BF* __restrict__ yh,
                               BF* __restrict__ yl)
{
    const int r = blockIdx.x, d = threadIdx.x;
    const int b = r >> 8, u = r & 255;
    float v = S[((size_t)(RTn + u) * Bn + b) * Dm_ + d];
    BF h, l; split2(v, h, l);
    yh[(size_t)r * Dm_ + d] = h;
    yl[(size_t)r * Dm_ + d] = l;
}

__global__ void lr_k(const int* __restrict__ lengths, float* __restrict__ out)
{
    int i = threadIdx.x;
    if (i < Bn) out[i] = (float)(lengths[i] >> 2);
}

// ---------------- host: tensormap plumbing ----------------
typedef CUresult (*EncFn)(CUtensorMap*, CUtensorMapDataType, cuuint32_t, void*,
                          const cuuint64_t*, const cuuint64_t*, const cuuint32_t*,
                          const cuuint32_t*, CUtensorMapInterleave, CUtensorMapSwizzle,
                          CUtensorMapL2promotion, CUtensorMapFloatOOBfill);

static EncFn get_enc() {
    void* p = nullptr;
    cudaDriverEntryPointQueryResult qr;
#if CUDART_VERSION >= 12050
    if (cudaGetDriverEntryPointByVersion("cuTensorMapEncodeTiled", &p, 12000,
                                         cudaEnableDefault, &qr) == cudaSuccess && p)
        return (EncFn)p;
    p = nullptr;
#endif
    cudaGetDriverEntryPoint("cuTensorMapEncodeTiled", &p, cudaEnableDefault, &qr);
    return (EncFn)p;
}

static CUtensorMap mkmap(EncFn enc, const BF* base, long K, long M, long planeStride,
                         unsigned boxM) {
    CUtensorMap m;
    cuuint64_t dims[3]    = {(cuuint64_t)K, (cuuint64_t)M, 2};
    cuuint64_t strides[2] = {(cuuint64_t)K * 2, (cuuint64_t)planeStride * 2};
    cuuint32_t box[3]     = {32, boxM, 1};
    cuuint32_t es[3]      = {1, 1, 1};
    enc(&m, CU_TENSOR_MAP_DATA_TYPE_BFLOAT16, 3, (void*)base, dims, strides, box, es,
        CU_TENSOR_MAP_INTERLEAVE_NONE, CU_TENSOR_MAP_SWIZZLE_64B,
        CU_TENSOR_MAP_L2_PROMOTION_L2_128B, CU_TENSOR_MAP_FLOAT_OOB_FILL_NONE);
    return m;
}

// ---------------- launch ----------------
extern "C" void kernel_launch(void* const* d_in, const int* in_sizes, int n_in,
                              void* d_out, int out_size)
{
    const float* input   = (const float*)d_in[0];
    const int*   lengths = (const int*)  d_in[1];
    const float* w_in    = (const float*)d_in[2];
    const float* ln_in_g = (const float*)d_in[3];
    const float* ln_in_b = (const float*)d_in[4];
    const float* wq = (const float*)d_in[5];
    const float* bq = (const float*)d_in[6];
    const float* wk = (const float*)d_in[7];
    const float* bk = (const float*)d_in[8];
    const float* wv = (const float*)d_in[9];
    const float* bv = (const float*)d_in[10];
    const float* wo = (const float*)d_in[11];
    const float* bo = (const float*)d_in[12];
    const float* ff_g = (const float*)d_in[13];
    const float* ff_b = (const float*)d_in[14];
    const float* w1 = (const float*)d_in[15];
    const float* b1 = (const float*)d_in[16];
    const float* w2 = (const float*)d_in[17];
    const float* b2 = (const float*)d_in[18];
    const float* lo_g = (const float*)d_in[19];
    const float* lo_b = (const float*)d_in[20];
    const float* w_out = (const float*)d_in[21];
    const float* b_out = (const float*)d_in[22];
    const float* lng = (const float*)d_in[23];
    const float* lnb = (const float*)d_in[24];
    float* out = (float*)d_out;

    float* fa = nullptr; BF* bf = nullptr;
    cudaGetSymbolAddress((void**)&fa, g_arena);
    cudaGetSymbolAddress((void**)&bf, g_bf);

    const int SM_128_128 = 1024 + NST * (2 * 128 * 64 + 2 * 128 * 64) + 128;  // 99456
    const int SM_64_128  = 1024 + NST * (2 * 64 * 64 + 2 * 128 * 64) + 128;   // 74880
    const int SM_128_64  = 1024 + NST * (2 * 128 * 64 + 2 * 64 * 64) + 128;   // 74880
    cudaFuncSetAttribute(gemm6<128,128>, cudaFuncAttributeMaxDynamicSharedMemorySize, SM_128_128);
    cudaFuncSetAttribute(gemm6<64,128>,  cudaFuncAttributeMaxDynamicSharedMemorySize, SM_64_128);
    cudaFuncSetAttribute(gemm6<128,64>,  cudaFuncAttributeMaxDynamicSharedMemorySize, SM_128_64);

    float* X    = fa + F_X;
    float* S    = fa + F_S;
    float* QKVf = fa + F_QKV;
    float* H2A  = fa + F_H2A;
    float* Yb   = fa + F_YB;
    float* BQKV = fa + F_BQKV;

    BF* UINh = bf + BA_U;   BF* UINl = UINh + EU;
    BF* ATTh = bf + BA_AT;  BF* ATTl = ATTh + EAT;
    BF* HBh  = bf + BA_HB;  BF* HBl  = HBh + EHB;
    BF* FBh  = bf + BA_FB;  BF* FBl  = FBh + EFB;
    BF* YTh  = bf + BA_YT;  BF* YTl  = YTh + EYT;

    EncFn enc = get_enc();
    CUtensorMap mUIN = mkmap(enc, UINh, 512, 2816, EU, 128);
    CUtensorMap mATT = mkmap(enc, ATTh, 512, 2688, EAT, 64);
    CUtensorMap mHB  = mkmap(enc, HBh,  512, 2560, EHB, 128);
    CUtensorMap mFB  = mkmap(enc, FBh, 2048, 2560, EFB, 128);
    CUtensorMap mYT  = mkmap(enc, YTh,  512, 2048, EYT, 64);
    CUtensorMap mOUT = mkmap(enc, bf + BW_OUT, 512, 1024, EOUT, 128);
    CUtensorMap mWQKV[Ln], mWO[Ln], mW1[Ln], mW2[Ln];
    for (int l = 0; l < Ln; l++) {
        mWQKV[l] = mkmap(enc, bf + BW_QKV + (size_t)l * 2 * EQKV, 512, 1536, EQKV, 128);
        mWO[l]   = mkmap(enc, bf + BW_O   + (size_t)l * 2 * EQ,   512,  512, EQ, 128);
        mW1[l]   = mkmap(enc, bf + BW_1   + (size_t)l * 2 * EW1,  512, 2048, EW1, 64);
        mW2[l]   = mkmap(enc, bf + BW_2   + (size_t)l * 2 * EW1, 2048,  512, EW1, 128);
    }

    // ---- per-replay preprocessing ----
    gemm_tc<<<dim3(1, 65), 256>>>(input, w_in, nullptr, X, 8320, 128, 80, 0);
    initS_k<<<dim3(SN, Bn), Dm_>>>(X, S);
    mems0_k<<<dim3(15, Bn), Dm_>>>(S, UINh, UINl);

    wconv_k<<<dim3(16, 16, 8), 256>>>(wq, bf + BW_QKV,
                                      bf + BW_QKV + EQKV, 512, 512, EQ, 2 * EQKV);
    wconv_k<<<dim3(16, 16, 8), 256>>>(wk, bf + BW_QKV + 262144,
                                      bf + BW_QKV + EQKV + 262144, 512, 512, EQ, 2 * EQKV);
    wconv_k<<<dim3(16, 16, 8), 256>>>(wv, bf + BW_QKV + 524288,
                                      bf + BW_QKV + EQKV + 524288, 512, 512, EQ, 2 * EQKV);
    wconv_k<<<dim3(16, 16, 8), 256>>>(wo, bf + BW_O, bf + BW_O + EQ, 512, 512, EQ, 2 * EQ);
    wconv_k<<<dim3(64, 16, 8), 256>>>(w1, bf + BW_1, bf + BW_1 + EW1, 512, 2048, EW1, 2 * EW1);
    wconv_k<<<dim3(16, 64, 8), 256>>>(w2, bf + BW_2, bf + BW_2 + EW1, 2048, 512, EW1, 2 * EW1);
    wconv_k<<<dim3(32, 16, 1), 256>>>(w_out, bf + BW_OUT, bf + BW_OUT + EOUT, 512, 1024, 0, 0);
    prep_k<<<48, 256>>>(bq, bk, bv, BQKV, UINh, UINl);

    // layer-0 LN1: S -> UIN state planes (rows 120..2679)
    ln_row_k<<<SN * Bn / 8, 256>>>(S, ln_in_g, ln_in_b, nullptr,
                                   UINh + 120 * 512, UINl + 120 * 512, Dm_);

    for (int l = 0; l < Ln; l++) {
        summary_pl_k<<<dim3(NSEG, Bn), Dm_>>>(UINh, UINl);

        gemm6<128,128><<<dim3(12, 22, 1), 256, SM_128_128>>>(mUIN, mWQKV[l], BQKV + l * 1536,
                                                             QKVf, 0, nullptr, nullptr,
                                                             1536, 512, 0, 0);

        attn_k<<<dim3(QN / 4, Bn), 256>>>(QKVf, lengths, ATTh, ATTl);

        gemm6<64,128><<<dim3(4, 42, 1), 256, SM_64_128>>>(mATT, mWO[l], bo + l * Dm_,
                                                          S, 0, UINh, UINl,
                                                          512, 512, 0, 2);

        ln_row_k<<<SN * Bn / 8, 256>>>(S, ff_g + l * Dm_, ff_b + l * Dm_,
                                       nullptr, HBh, HBl, Dm_);
        // FFN1: 128x64 tiles -> 640 CTAs (was 320 = 1.08 waves of full CTAs)
        gemm6<128,64><<<dim3(32, 20, 1), 256, SM_128_64>>>(mHB, mW1[l], b1 + l * FFNn,
                                                           nullptr, 0, FBh, FBl,
                                                           2048, 512, 1, 1);
        // FFN2 split-K=3 (704 per chunk; TMA zero-fills K >= 2048)
        gemm6<128,128><<<dim3(4, 20, 3), 256, SM_128_128>>>(mFB, mW2[l], b2 + l * Dm_,
                                                            H2A, 1310720, nullptr, nullptr,
                                                            512, 704, 0, 0);

        const float* g2 = (l + 1 < Ln) ? (ln_in_g + (l + 1) * Dm_) : nullptr;
        const float* b2n = (l + 1 < Ln) ? (ln_in_b + (l + 1) * Dm_) : nullptr;
        ln2_k<<<SN * Bn / 8, 256>>>(S, H2A, H2A + 1310720, H2A + 2621440,
                                    lo_g + l * Dm_, lo_b + l * Dm_, g2, b2n,
                                    S, UINh + 120 * 512, UINl + 120 * 512);
    }

    transpose_pl_k<<<2048, Dm_>>>(S, YTh, YTl);
    gemm6<64,128><<<dim3(8, 32, 1), 256, SM_64_128>>>(mYT, mOUT, b_out,
                                                      Yb, 0, nullptr, nullptr,
                                                      1024, 512, 0, 0);
    ln_row_k<<<2048 / 8, 256>>>(Yb, lng, lnb, out, nullptr, nullptr, OUTn);

    if (out_size >= 2048 * 1024 + Bn)
        lr_k<<<1, 32>>>(lengths, out + 2048 * 1024);
}

// round 11
// speedup vs baseline: 6.4930x; 1.2480x over previous
#include <cuda_runtime.h>
#include <cuda_fp16.h>
#include <cuda.h>
#include <math.h>
#include <stdint.h>

typedef __half BF;
typedef __half2 BF2;

// ---------------- constants ----------------
#define Bn   8
#define Dm_  512
#define FFNn 2048
#define Ln   8
#define OUTn 1024
#define Hn   8
#define DHn  64
#define QN   336
#define SN   320
#define RTn  64
#define Un   256
#define NSEG 16

// token space: 0..14 mems | 15..78 rc | 79..334 utt | 335..350 summary | 351 pad
// row = token*8 + b;  M_UIN = 2816

// ------- float arena -------
#define F_X    0UL
#define F_S    (F_X + 1064960UL)
#define F_QKV  (F_S + 1310720UL)
#define F_H2A  (F_QKV + 4325376UL)
#define F_H2B  (F_H2A + 1310720UL)
#define F_H2C  (F_H2B + 1310720UL)
#define F_YB   (F_H2C + 1310720UL)
#define F_BQKV (F_YB + 2097152UL)
#define F_TOT  (F_BQKV + 12288UL)
__device__ __align__(1024) float g_arena[F_TOT];

// ------- fp16 arena (activations: hi plane at base, lo at base+E; weights: hi only) ----
#define EQ    262144UL
#define EQKV  786432UL     // 1536*512
#define EW1   1048576UL
#define EOUT  524288UL
#define EU    1441792UL    // 2816*512
#define EAT   1376256UL    // 2688*512
#define EHB   1310720UL    // 2560*512
#define EFB   5242880UL    // 2560*2048
#define EYT   1048576UL    // 2048*512

#define BW_QKV 0UL
#define BW_O   (BW_QKV + 8UL*2UL*EQKV)
#define BW_1   (BW_O   + 8UL*2UL*EQ)
#define BW_2   (BW_1   + 8UL*2UL*EW1)
#define BW_OUT (BW_2   + 8UL*2UL*EW1)
#define BA_U   (BW_OUT + 2UL*EOUT)
#define BA_AT  (BA_U   + 2UL*EU)
#define BA_HB  (BA_AT  + 2UL*EAT)
#define BA_FB  (BA_HB  + 2UL*EHB)
#define BA_YT  (BA_FB  + 2UL*EFB)
#define B_TOT  (BA_YT  + 2UL*EYT)
__device__ __align__(1024) BF g_bf[B_TOT];

__device__ __forceinline__ void split2(float x, BF& h, BF& l) {
    h = __float2half(x);
    l = __float2half(x - __half2float(h));
}
__device__ __forceinline__ BF2 mk2(BF a, BF b) { return __halves2half2(a, b); }

// ============ TMA / mbarrier primitives ============
__device__ __forceinline__ uint32_t smem_u32(const void* p) {
    return (uint32_t)__cvta_generic_to_shared(p);
}
__device__ __forceinline__ void mbar_init(uint32_t a, uint32_t cnt) {
    asm volatile("mbarrier.init.shared::cta.b64 [%0], %1;" :: "r"(a), "r"(cnt) : "memory");
}
__device__ __forceinline__ void mbar_expect(uint32_t a, uint32_t tx) {
    asm volatile("mbarrier.arrive.expect_tx.shared::cta.b64 _, [%0], %1;"
                 :: "r"(a), "r"(tx) : "memory");
}
__device__ __forceinline__ void mbar_arrive(uint32_t a) {
    asm volatile("mbarrier.arrive.shared::cta.b64 _, [%0];" :: "r"(a) : "memory");
}
__device__ __forceinline__ void mbar_wait(uint32_t a, uint32_t ph) {
    uint32_t done = 0;
    while (!done) {
        asm volatile(
            "{\n\t.reg .pred p;\n\t"
            "mbarrier.try_wait.parity.acquire.cta.shared::cta.b64 p, [%1], %2, 0x989680;\n\t"
            "selp.b32 %0, 1, 0, p;\n\t}"
            : "=r"(done) : "r"(a), "r"(ph) : "memory");
    }
}
__device__ __forceinline__ void tma3d(uint32_t dst, const void* map,
                                      int cx, int cy, int cz, uint32_t mbar) {
    asm volatile(
        "cp.async.bulk.tensor.3d.shared::cta.global.tile.mbarrier::complete_tx::bytes "
        "[%0], [%1, {%2, %3, %4}], [%5];"
        :: "r"(dst), "l"(map), "r"(cx), "r"(cy), "r"(cz), "r"(mbar) : "memory");
}
__device__ __forceinline__ void mma2(float c[4], const uint32_t a[4],
                                     uint32_t b0, uint32_t b1) {
    asm volatile(
        "mma.sync.aligned.m16n8k16.row.col.f32.f16.f16.f32 "
        "{%0,%1,%2,%3}, {%4,%5,%6,%7}, {%8,%9}, {%0,%1,%2,%3};\n"
        : "+f"(c[0]), "+f"(c[1]), "+f"(c[2]), "+f"(c[3])
        : "r"(a[0]), "r"(a[1]), "r"(a[2]), "r"(a[3]), "r"(b0), "r"(b1));
}
#define LDSM4(r, a) \
    asm volatile("ldmatrix.sync.aligned.m8n8.x4.shared.b16 {%0,%1,%2,%3}, [%4];" \
        : "=r"((r)[0]), "=r"((r)[1]), "=r"((r)[2]), "=r"((r)[3]) : "r"(a))

// ============ TMA-staged mma.sync GEMM (SW64, 32-K stages, fp16 2-pass) =====
// C = act(A @ B^T + bias). A: hi/lo fp16 planes (exact); B: hi plane only
// (weights rounded to fp16). grid (N/NT, M/MT, splitZ). TMA zero-fills OOB K.
// mode 0: fp32 Cf (+ z*czstride). mode 1: fp16 planes Ch/Cl.
// mode 2: fused O epilogue: rows<2560 S+=v; rows 2560..2679 planes=tanh(v).
#define NST 3

template <int MT, int NT>
__global__ __launch_bounds__(256, 2) void gemm6(
    const __grid_constant__ CUtensorMap tmA,
    const __grid_constant__ CUtensorMap tmB,
    const float* __restrict__ bias, float* __restrict__ Cf, long czstride,
    BF* __restrict__ Ch, BF* __restrict__ Cl,
    int N, int K, int act, int mode)
{
    constexpr int MSPAN = MT / 4;
    constexpr int MTM   = MSPAN / 16;
    constexpr int NSPAN = NT / 2;
    constexpr int NNT   = NSPAN / 8;
    constexpr int APL   = MT * 64;           // A plane bytes per stage
    constexpr int BPL   = NT * 64;           // B plane bytes per stage
    constexpr int STB   = 2 * APL + BPL;     // stage bytes (A hi+lo, B hi)
    extern __shared__ __align__(16) char smx[];
    const uint32_t sb = smem_u32(smx);
    const uint32_t db = (sb + 1023) & ~1023u;
    const int tid = threadIdx.x, lane = tid & 31, wid = tid >> 5;
    const int wm = wid & 3, wn = wid >> 2;
    const int grp = lane >> 2, tig = lane & 3;
    const int row0 = blockIdx.y * MT, col0 = blockIdx.x * NT;
    const int kstart = blockIdx.z * K;
    if (Cf && mode == 0) Cf += (long)blockIdx.z * czstride;
    const float* bi = (bias && kstart == 0) ? bias : nullptr;
    const int T = K >> 5;

    const uint32_t barb = db + NST * STB;
    if (tid == 0) {
        for (int s = 0; s < NST; s++) {
            mbar_init(barb + s * 8, 1);
            mbar_init(barb + 64 + s * 8, 256);
        }
    }
    __syncthreads();

    if (tid == 0) {
        for (int s = 0; s < NST; s++) {
            uint32_t st = db + s * STB, fb = barb + s * 8;
            mbar_expect(fb, STB);
            tma3d(st,           &tmA, kstart + s * 32, row0, 0, fb);
            tma3d(st + APL,     &tmA, kstart + s * 32, row0, 1, fb);
            tma3d(st + 2 * APL, &tmB, kstart + s * 32, col0, 0, fb);
        }
    }

    float acc[MTM][NNT][4] = {};
    // ldmatrix lane geometry (SW64: 64B rows; xor = ((row>>1)&3)<<4)
    const int lrow = (lane & 7) + (((lane >> 3) & 1) << 3);
    const int kofs = ((lane >> 4) & 1) * 8;
    const uint32_t msk = (uint32_t)((lrow >> 1) & 3) << 4;
    uint32_t arow_off[MTM], brow_off[NNT / 2];
#pragma unroll
    for (int mt = 0; mt < MTM; mt++)
        arow_off[mt] = (uint32_t)(wm * MSPAN + mt * 16 + lrow) * 64;
#pragma unroll
    for (int p = 0; p < NNT / 2; p++)
        brow_off[p] = (uint32_t)(wn * NSPAN + p * 16 + lrow) * 64;

    uint32_t pfm = 0, pem = 0;
    for (int i = 0; i < T; i++) {
        const int bslot = i % NST;
        const uint32_t fb = barb + bslot * 8, eb = barb + 64 + bslot * 8;
        mbar_wait(fb, (pfm >> bslot) & 1); pfm ^= (1u << bslot);
        const uint32_t sA = db + bslot * STB, sB = sA + 2 * APL;
#pragma unroll
        for (int kk = 0; kk < 32; kk += 16) {
            const uint32_t csw = ((uint32_t)((kk + kofs) * 2)) ^ msk;
            uint32_t ah[MTM][4], al_[MTM][4], bh[NNT / 2][4];
#pragma unroll
            for (int mt = 0; mt < MTM; mt++) {
                uint32_t ad = sA + arow_off[mt] + csw;
                LDSM4(ah[mt], ad);
                LDSM4(al_[mt], ad + APL);
            }
#pragma unroll
            for (int p = 0; p < NNT / 2; p++) {
                LDSM4(bh[p], sB + brow_off[p] + csw);
            }
#pragma unroll
            for (int nt = 0; nt < NNT; nt++) {
                const int p = nt >> 1, s1 = nt & 1;
#pragma unroll
                for (int mt = 0; mt < MTM; mt++) {
                    mma2(acc[mt][nt], ah[mt],  bh[p][s1], bh[p][2 + s1]);
                    mma2(acc[mt][nt], al_[mt], bh[p][s1], bh[p][2 + s1]);
                }
            }
        }
        mbar_arrive(eb);
        if (tid == 0 && i + NST < T) {
            mbar_wait(eb, (pem >> bslot) & 1); pem ^= (1u << bslot);
            uint32_t st = db + bslot * STB;
            mbar_expect(fb, STB);
            int k0 = kstart + (i + NST) * 32;
            tma3d(st,           &tmA, k0, row0, 0, fb);
            tma3d(st + APL,     &tmA, k0, row0, 1, fb);
            tma3d(st + 2 * APL, &tmB, k0, col0, 0, fb);
        }
    }

#pragma unroll
    for (int mt = 0; mt < MTM; mt++) {
        const long r = row0 + wm * MSPAN + mt * 16 + grp;
#pragma unroll
        for (int nt = 0; nt < NNT; nt++) {
            const long c = col0 + wn * NSPAN + nt * 8 + tig * 2;
            float bb0 = bi ? bi[c] : 0.f, bb1 = bi ? bi[c + 1] : 0.f;
            float v0 = acc[mt][nt][0] + bb0, v1 = acc[mt][nt][1] + bb1;
            float v2 = acc[mt][nt][2] + bb0, v3 = acc[mt][nt][3] + bb1;
            if (act) {
                v0 = fmaxf(v0, 0.f); v1 = fmaxf(v1, 0.f);
                v2 = fmaxf(v2, 0.f); v3 = fmaxf(v3, 0.f);
            }
            if (mode == 0) {
                *(float2*)&Cf[r * N + c]       = make_float2(v0, v1);
                *(float2*)&Cf[(r + 8) * N + c] = make_float2(v2, v3);
            } else if (mode == 1) {
                BF h0, l0, h1, l1;
                split2(v0, h0, l0); split2(v1, h1, l1);
                *(BF2*)&Ch[r * N + c] = mk2(h0, h1);
                *(BF2*)&Cl[r * N + c] = mk2(l0, l1);
                split2(v2, h0, l0); split2(v3, h1, l1);
                *(BF2*)&Ch[(r + 8) * N + c] = mk2(h0, h1);
                *(BF2*)&Cl[(r + 8) * N + c] = mk2(l0, l1);
            } else {
#pragma unroll
                for (int rr = 0; rr < 2; rr++) {
                    long r2 = r + rr * 8;
                    float u0 = rr ? v2 : v0, u1 = rr ? v3 : v1;
                    if (r2 < 2560) {
                        float2 s = *(float2*)&Cf[r2 * 512 + c];
                        *(float2*)&Cf[r2 * 512 + c] = make_float2(s.x + u0, s.y + u1);
                    } else if (r2 < 2680) {
                        float t0 = tanhf(u0), t1 = tanhf(u1);
                        BF h0, l0, h1, l1;
                        split2(t0, h0, l0); split2(t1, h1, l1);
                        long o = (r2 - 2560) * 512 + c;
                        *(BF2*)&Ch[o] = mk2(h0, h1);
                        *(BF2*)&Cl[o] = mk2(l0, l1);
                    }
                }
            }
        }
    }
}

// ---------------- legacy in-kernel-convert GEMM (input proj, K=80) ---------
#define LLDA 40
__global__ __launch_bounds__(256) void gemm_tc(
    const float* __restrict__ A, const float* __restrict__ W,
    const float* __restrict__ bias, float* __restrict__ C,
    int M, int N, int K, int act)
{
    __shared__ BF Ahs[128 * LLDA], Als[128 * LLDA];
    __shared__ BF Bhs[128 * LLDA];
    const int tid = threadIdx.x, lane = tid & 31, wid = tid >> 5;
    const int wm = wid & 3, wn = wid >> 2;
    const int grp = lane >> 2, tig = lane & 3;
    const long row0 = (long)blockIdx.y * 128;
    const int  col0 = blockIdx.x * 128;
    float acc[2][8][4] = {};
    const int arow = tid >> 1, acol0 = (tid & 1) * 16;
    const int brow = tid >> 3, bcol0 = (tid & 7) * 16;

    for (int k0 = 0; k0 < K; k0 += 32) {
#pragma unroll
        for (int j = 0; j < 4; j++) {
            int c = acol0 + j * 4;
            float4 v = make_float4(0.f, 0.f, 0.f, 0.f);
            if (row0 + arow < M && k0 + c < K)
                v = *(const float4*)&A[(row0 + arow) * (long)K + k0 + c];
            BF h, l; int o = arow * LLDA + c;
            split2(v.x, h, l); Ahs[o]     = h; Als[o]     = l;
            split2(v.y, h, l); Ahs[o + 1] = h; Als[o + 1] = l;
            split2(v.z, h, l); Ahs[o + 2] = h; Als[o + 2] = l;
            split2(v.w, h, l); Ahs[o + 3] = h; Als[o + 3] = l;
        }
#pragma unroll
        for (int j = 0; j < 4; j++) {
            int n = bcol0 + j * 4;
            float4 v = make_float4(0.f, 0.f, 0.f, 0.f);
            if (k0 + brow < K)
                v = *(const float4*)&W[(long)(k0 + brow) * N + col0 + n];
            Bhs[(n + 0) * LLDA + brow] = __float2half(v.x);
            Bhs[(n + 1) * LLDA + brow] = __float2half(v.y);
            Bhs[(n + 2) * LLDA + brow] = __float2half(v.z);
            Bhs[(n + 3) * LLDA + brow] = __float2half(v.w);
        }
        __syncthreads();
#pragma unroll
        for (int kk = 0; kk < 32; kk += 16) {
            uint32_t ah[2][4], al[2][4];
#pragma unroll
            for (int mt = 0; mt < 2; mt++) {
                int r = wm * 32 + mt * 16;
                int o  = (r + grp) * LLDA + kk + tig * 2;
                int o8 = o + 8 * LLDA;
                ah[mt][0] = *(const uint32_t*)&Ahs[o];
                ah[mt][1] = *(const uint32_t*)&Ahs[o8];
                ah[mt][2] = *(const uint32_t*)&Ahs[o + 8];
                ah[mt][3] = *(const uint32_t*)&Ahs[o8 + 8];
                al[mt][0] = *(const uint32_t*)&Als[o];
                al[mt][1] = *(const uint32_t*)&Als[o8];
                al[mt][2] = *(const uint32_t*)&Als[o + 8];
                al[mt][3] = *(const uint32_t*)&Als[o8 + 8];
            }
#pragma unroll
            for (int nt = 0; nt < 8; nt++) {
                int nn = wn * 64 + nt * 8 + grp;
                int o = nn * LLDA + kk + tig * 2;
                uint32_t b0 = *(const uint32_t*)&Bhs[o], b1 = *(const uint32_t*)&Bhs[o + 8];
#pragma unroll
                for (int mt = 0; mt < 2; mt++) {
                    mma2(acc[mt][nt], ah[mt], b0, b1);
                    mma2(acc[mt][nt], al[mt], b0, b1);
                }
            }
        }
        __syncthreads();
    }
#pragma unroll
    for (int mt = 0; mt < 2; mt++) {
#pragma unroll
        for (int nt = 0; nt < 8; nt++) {
            int c = col0 + wn * 64 + nt * 8 + tig * 2;
            float b0 = bias ? bias[c] : 0.f;
            float b1 = bias ? bias[c + 1] : 0.f;
            long r = row0 + wm * 32 + mt * 16 + grp;
            float v0 = acc[mt][nt][0] + b0, v1 = acc[mt][nt][1] + b1;
            float v2 = acc[mt][nt][2] + b0, v3 = acc[mt][nt][3] + b1;
            if (act) { v0=fmaxf(v0,0.f); v1=fmaxf(v1,0.f); v2=fmaxf(v2,0.f); v3=fmaxf(v3,0.f); }
            if (r < M)     *(float2*)&C[r * N + c]       = make_float2(v0, v1);
            if (r + 8 < M) *(float2*)&C[(r + 8) * N + c] = make_float2(v2, v3);
        }
    }
}

// ------- weight transpose+convert: out[n][k] = fp16(W[k][n]), hi plane only ----
__global__ __launch_bounds__(256) void wconv_k(
    const float* __restrict__ W, BF* __restrict__ oh,
    int K, int N, long inS, long outS)
{
    __shared__ float t[32][33];
    const float* w = W + (long)blockIdx.z * inS;
    BF* ph = oh + (long)blockIdx.z * outS;
    const int n0 = blockIdx.x * 32, k0 = blockIdx.y * 32;
    const int tx = threadIdx.x & 7, ty = threadIdx.x >> 3;
    float4 v = *(const float4*)&w[(long)(k0 + ty) * N + n0 + tx * 4];
    t[ty][tx * 4 + 0] = v.x; t[ty][tx * 4 + 1] = v.y;
    t[ty][tx * 4 + 2] = v.z; t[ty][tx * 4 + 3] = v.w;
    __syncthreads();
    float a0 = t[tx * 4 + 0][ty], a1 = t[tx * 4 + 1][ty];
    float a2 = t[tx * 4 + 2][ty], a3 = t[tx * 4 + 3][ty];
    long o = (long)(n0 + ty) * K + k0 + tx * 4;
    *(BF2*)&ph[o]     = mk2(__float2half(a0), __float2half(a1));
    *(BF2*)&ph[o + 2] = mk2(__float2half(a2), __float2half(a3));
}

// merged bias pack + UIN pad
__global__ void prep_k(const float* __restrict__ bq, const float* __restrict__ bk,
                       const float* __restrict__ bv, float* __restrict__ o,
                       BF* __restrict__ uh, BF* __restrict__ ul)
{
    int i = blockIdx.x * blockDim.x + threadIdx.x;
    if (i < 12288) {
        int l = i / 1536, j = i % 1536;
        float v;
        if (j < 512)       v = bq[l * 512 + j];
        else if (j < 1024) v = bk[l * 512 + j - 512];
        else               v = bv[l * 512 + j - 1024];
        o[i] = v;
    }
    if (i < 4096) {
        size_t p = 2808UL * 512UL + i;
        uh[p] = __float2half(0.f);
        ul[p] = __float2half(0.f);
    }
}

// ---------------- LayerNorm: warp per row ----------------
__global__ __launch_bounds__(256) void ln_row_k(
    const float* __restrict__ X, const float* __restrict__ g, const float* __restrict__ bta,
    float* __restrict__ outf, BF* __restrict__ oh, BF* __restrict__ ol, int D)
{
    const int wid = threadIdx.x >> 5, lane = threadIdx.x & 31;
    const int row = blockIdx.x * 8 + wid;
    const float4* x = (const float4*)(X + (long)row * D);
    const int cnt = D >> 7;
    float s = 0.f, s2 = 0.f;
    for (int i = 0; i < cnt; i++) {
        float4 a = x[lane + i * 32];
        s  += a.x + a.y + a.z + a.w;
        s2 += a.x * a.x + a.y * a.y + a.z * a.z + a.w * a.w;
    }
#pragma unroll
    for (int o = 16; o; o >>= 1) {
        s  += __shfl_xor_sync(~0u, s, o);
        s2 += __shfl_xor_sync(~0u, s2, o);
    }
    const float mean = s / D;
    const float inv = rsqrtf(s2 / D - mean * mean + 1e-5f);
    const float4* gg = (const float4*)g;
    const float4* bb = (const float4*)bta;
    for (int i = 0; i < cnt; i++) {
        int idx = lane + i * 32;
        float4 a = x[idx], gv = gg[idx], bv = bb[idx], o;
        o.x = (a.x - mean) * inv * gv.x + bv.x;
        o.y = (a.y - mean) * inv * gv.y + bv.y;
        o.z = (a.z - mean) * inv * gv.z + bv.z;
        o.w = (a.w - mean) * inv * gv.w + bv.w;
        if (outf) ((float4*)(outf + (long)row * D))[idx] = o;
        if (oh) {
            BF h0,l0,h1,l1,h2,l2,h3,l3;
            split2(o.x,h0,l0); split2(o.y,h1,l1);
            split2(o.z,h2,l2); split2(o.w,h3,l3);
            long base = (long)row * D + idx * 4;
            *(BF2*)&oh[base]     = mk2(h0,h1);
            *(BF2*)&oh[base + 2] = mk2(h2,h3);
            *(BF2*)&ol[base]     = mk2(l0,l1);
            *(BF2*)&ol[base + 2] = mk2(l2,l3);
        }
    }
}

// -------- double LN: res=S+HA+HB+HC; S=LN1(res); planes=LN2(S) ------------
__global__ __launch_bounds__(256) void ln2_k(
    const float* __restrict__ S, const float* __restrict__ HA,
    const float* __restrict__ HB_, const float* __restrict__ HC,
    const float* __restrict__ g1, const float* __restrict__ be1,
    const float* __restrict__ g2, const float* __restrict__ be2,
    float* __restrict__ Sout, BF* __restrict__ oh, BF* __restrict__ ol)
{
    const int wid = threadIdx.x >> 5, lane = threadIdx.x & 31;
    const int row = blockIdx.x * 8 + wid;   // 0..2559
    const float4* xs = (const float4*)(S   + (long)row * 512);
    const float4* xa = (const float4*)(HA  + (long)row * 512);
    const float4* xb = (const float4*)(HB_ + (long)row * 512);
    const float4* xc = (const float4*)(HC  + (long)row * 512);
    float4 R[4];
    float s = 0.f, s2 = 0.f;
#pragma unroll
    for (int i = 0; i < 4; i++) {
        int idx = lane + i * 32;
        float4 a = xs[idx], c = xa[idx], d = xb[idx], e = xc[idx];
        a.x += c.x + d.x + e.x; a.y += c.y + d.y + e.y;
        a.z += c.z + d.z + e.z; a.w += c.w + d.w + e.w;
        R[i] = a;
        s  += a.x + a.y + a.z + a.w;
        s2 += a.x * a.x + a.y * a.y + a.z * a.z + a.w * a.w;
    }
#pragma unroll
    for (int o = 16; o; o >>= 1) {
        s  += __shfl_xor_sync(~0u, s, o);
        s2 += __shfl_xor_sync(~0u, s2, o);
    }
    float mean = s * (1.f / 512.f);
    float inv = rsqrtf(s2 * (1.f / 512.f) - mean * mean + 1e-5f);
    const float4* g1v = (const float4*)g1; const float4* b1v = (const float4*)be1;
    float t = 0.f, t2 = 0.f;
#pragma unroll
    for (int i = 0; i < 4; i++) {
        int idx = lane + i * 32;
        float4 gv = g1v[idx], bv = b1v[idx], y;
        y.x = (R[i].x - mean) * inv * gv.x + bv.x;
        y.y = (R[i].y - mean) * inv * gv.y + bv.y;
        y.z = (R[i].z - mean) * inv * gv.z + bv.z;
        y.w = (R[i].w - mean) * inv * gv.w + bv.w;
        R[i] = y;
        ((float4*)(Sout + (long)row * 512))[idx] = y;
        t  += y.x + y.y + y.z + y.w;
        t2 += y.x * y.x + y.y * y.y + y.z * y.z + y.w * y.w;
    }
    if (!g2) return;
#pragma unroll
    for (int o = 16; o; o >>= 1) {
        t  += __shfl_xor_sync(~0u, t, o);
        t2 += __shfl_xor_sync(~0u, t2, o);
    }
    float mean2 = t * (1.f / 512.f);
    float inv2 = rsqrtf(t2 * (1.f / 512.f) - mean2 * mean2 + 1e-5f);
    const float4* g2v = (const float4*)g2; const float4* b2v = (const float4*)be2;
#pragma unroll
    for (int i = 0; i < 4; i++) {
        int idx = lane + i * 32;
        float4 gv = g2v[idx], bv = b2v[idx], z;
        z.x = (R[i].x - mean2) * inv2 * gv.x + bv.x;
        z.y = (R[i].y - mean2) * inv2 * gv.y + bv.y;
        z.z = (R[i].z - mean2) * inv2 * gv.z + bv.z;
        z.w = (R[i].w - mean2) * inv2 * gv.w + bv.w;
        BF h0,l0,h1,l1,h2,l2,h3,l3;
        split2(z.x,h0,l0); split2(z.y,h1,l1);
        split2(z.z,h2,l2); split2(z.w,h3,l3);
        long base = (long)row * 512 + idx * 4;
        *(BF2*)&oh[base]     = mk2(h0,h1);
        *(BF2*)&oh[base + 2] = mk2(h2,h3);
        *(BF2*)&ol[base]     = mk2(l0,l1);
        *(BF2*)&ol[base + 2] = mk2(l2,l3);
    }
}

// ---------------- misc ----------------
__global__ void initS_k(const float* __restrict__ X, float* __restrict__ S)
{
    const int t = blockIdx.x, b = blockIdx.y, d = threadIdx.x;
    int frame;
    if (t < RTn) {
        int si = t >> 2;
        int st = (si == 15) ? 256 : (si + 1) * 16;
        frame = st + (t & 3);
    } else frame = t - RTn;
    S[((size_t)t * Bn + b) * Dm_ + d] = X[(size_t)b * 133120 + (size_t)frame * Dm_ + d];
}

__global__ void mems0_k(const float* __restrict__ S, BF* __restrict__ uh,
                        BF* __restrict__ ul)
{
    const int s = blockIdx.x, b = blockIdx.y, d = threadIdx.x;
    size_t base = ((size_t)(RTn + s * 16) * Bn + b) * Dm_ + d;
    float acc = 0.f;
#pragma unroll
    for (int k = 0; k < 16; k++) acc += S[base + (size_t)k * Bn * Dm_];
    acc *= (1.f / 16.f);
    BF h, l; split2(acc, h, l);
    size_t o = ((size_t)s * Bn + b) * Dm_ + d;
    uh[o] = h; ul[o] = l;
}

__global__ void summary_pl_k(BF* __restrict__ uh, BF* __restrict__ ul)
{
    const int s = blockIdx.x, b = blockIdx.y, d = threadIdx.x;
    size_t base = ((size_t)((79 + s * 16) * Bn) + b) * Dm_ + d;
    float acc = 0.f;
#pragma unroll
    for (int k = 0; k < 16; k++) {
        size_t o = base + (size_t)k * Bn * Dm_;
        acc += __half2float(uh[o]) + __half2float(ul[o]);
    }
    acc *= (1.f / 16.f);
    BF h, l; split2(acc, h, l);
    size_t o = ((size_t)((335 + s) * Bn) + b) * Dm_ + d;
    uh[o] = h; ul[o] = l;
}

// ---------------- attention: 4 queries per CTA ----------------
__global__ __launch_bounds__(256) void attn_k(
    const float* __restrict__ QKV, const int* __restrict__ lengths,
    BF* __restrict__ Ah, BF* __restrict__ Al)
{
    __shared__ float sc[Hn][64];
    __shared__ short ki[Hn][64];
    const int b = blockIdx.y;
    const int h = threadIdx.x >> 5, lane = threadIdx.x & 31;

    int maxlr = 0;
#pragma unroll
    for (int i = 0; i < Bn; i++) maxlr = max(maxlr, lengths[i] >> 2);
    const int lrb = lengths[b] >> 2;
    const int g = lane >> 3, e = lane & 7;
    const float* Kb = QKV + (size_t)b * 1536 + 512 + h * DHn;
    const float* Vb = Kb + 512;

    for (int qq = 0; qq < 4; qq++) {
        const int qi = blockIdx.x * 4 + qq;
        int seg; bool summ = false;
        if (qi < RTn)      seg = qi >> 2;
        else if (qi < SN)  seg = (qi - RTn) >> 4;
        else             { seg = qi - SN; summ = true; }
        const int ms  = max(seg - 4, 0);
        const int ss  = max(seg * 16 - 32, 0);
        const int se  = min(seg * 16 + 16, Un);
        const int ue  = min(se, lrb + 256 - maxlr);
        const int rcs = 15 + seg * 4;

        const int c0 = summ ? 0 : (seg - ms);
        const int c2 = max(ue - ss, 0);
        const int n  = c0 + 4 + c2;

        for (int j = lane; j < n; j += 32) {
            int k;
            if (j < c0)          k = ms + j;
            else if (j < c0 + 4) k = rcs + (j - c0);
            else                 k = 79 + ss + (j - c0 - 4);
            ki[h][j] = (short)k;
        }
        __syncwarp();

        const float4* qv = (const float4*)(QKV + ((size_t)(15 + qi) * Bn + b) * 1536 + h * DHn);
        float4 q0 = qv[e * 2], q1 = qv[e * 2 + 1];
        q0.x *= 0.125f; q0.y *= 0.125f; q0.z *= 0.125f; q0.w *= 0.125f;
        q1.x *= 0.125f; q1.y *= 0.125f; q1.z *= 0.125f; q1.w *= 0.125f;

        for (int j0 = 0; j0 < n; j0 += 4) {
            int j = j0 + g;
            float p = 0.f;
            if (j < n) {
                const float4* kp = (const float4*)(Kb + (size_t)ki[h][j] * (Bn * 1536));
                float4 k0 = kp[e * 2], k1 = kp[e * 2 + 1];
                p = q0.x * k0.x + q0.y * k0.y + q0.z * k0.z + q0.w * k0.w
                  + q1.x * k1.x + q1.y * k1.y + q1.z * k1.z + q1.w * k1.w;
            }
            p += __shfl_xor_sync(~0u, p, 4);
            p += __shfl_xor_sync(~0u, p, 2);
            p += __shfl_xor_sync(~0u, p, 1);
            if (e == 0 && j < n) sc[h][j] = p;
        }
        __syncwarp();

        float m = -3.4e38f;
        for (int j = lane; j < n; j += 32) m = fmaxf(m, sc[h][j]);
#pragma unroll
        for (int o = 16; o; o >>= 1) m = fmaxf(m, __shfl_xor_sync(~0u, m, o));
        float sum = 0.f;
        for (int j = lane; j < n; j += 32) {
            float e2 = expf(sc[h][j] - m);
            sc[h][j] = e2;
            sum += e2;
        }
#pragma unroll
        for (int o = 16; o; o >>= 1) sum += __shfl_xor_sync(~0u, sum, o);
        __syncwarp();
        const float inv = 1.f / sum;

        float a0 = 0.f, a1 = 0.f;
        for (int j = 0; j < n; j++) {
            float p = sc[h][j];
            const float2 vp = *(const float2*)(Vb + (size_t)ki[h][j] * (Bn * 1536) + 2 * lane);
            a0 = fmaf(p, vp.x, a0);
            a1 = fmaf(p, vp.y, a1);
        }
        a0 *= inv; a1 *= inv;
        BF h0, l0, h1, l1;
        split2(a0, h0, l0); split2(a1, h1, l1);
        size_t op = ((size_t)qi * Bn + b) * Dm_ + h * DHn + 2 * lane;
        *(BF2*)&Ah[op] = mk2(h0, h1);
        *(BF2*)&Al[op] = mk2(l0, l1);
        __syncwarp();
    }
}

__global__ void transpose_pl_k(const float* __restrict__ S, BF* __restrict__ yh,
                               BF* __restrict__ yl)
{
    const int r = blockIdx.x, d = threadIdx.x;
    const int b = r >> 8, u = r & 255;
    float v = S[((size_t)(RTn + u) * Bn + b) * Dm_ + d];
    BF h, l; split2(v, h, l);
    yh[(size_t)r * Dm_ + d] = h;
    yl[(size_t)r * Dm_ + d] = l;
}

__global__ void lr_k(const int* __restrict__ lengths, float* __restrict__ out)
{
    int i = threadIdx.x;
    if (i < Bn) out[i] = (float)(lengths[i] >> 2);
}

// ---------------- host: tensormap plumbing ----------------
typedef CUresult (*EncFn)(CUtensorMap*, CUtensorMapDataType, cuuint32_t, void*,
                          const cuuint64_t*, const cuuint64_t*, const cuuint32_t*,
                          const cuuint32_t*, CUtensorMapInterleave, CUtensorMapSwizzle,
                          CUtensorMapL2promotion, CUtensorMapFloatOOBfill);

static EncFn get_enc() {
    void* p = nullptr;
    cudaDriverEntryPointQueryResult qr;
#if CUDART_VERSION >= 12050
    if (cudaGetDriverEntryPointByVersion("cuTensorMapEncodeTiled", &p, 12000,
                                         cudaEnableDefault, &qr) == cudaSuccess && p)
        return (EncFn)p;
    p = nullptr;
#endif
    cudaGetDriverEntryPoint("cuTensorMapEncodeTiled", &p, cudaEnableDefault, &qr);
    return (EncFn)p;
}

static CUtensorMap mkmap(EncFn enc, const BF* base, long K, long M, long planeStride,
                         unsigned boxM) {
    CUtensorMap m;
    cuuint64_t dims[3]    = {(cuuint64_t)K, (cuuint64_t)M, 2};
    cuuint64_t strides[2] = {(cuuint64_t)K * 2, (cuuint64_t)planeStride * 2};
    cuuint32_t box[3]     = {32, boxM, 1};
    cuuint32_t es[3]      = {1, 1, 1};
    enc(&m, CU_TENSOR_MAP_DATA_TYPE_FLOAT16, 3, (void*)base, dims, strides, box, es,
        CU_TENSOR_MAP_INTERLEAVE_NONE, CU_TENSOR_MAP_SWIZZLE_64B,
        CU_TENSOR_MAP_L2_PROMOTION_L2_128B, CU_TENSOR_MAP_FLOAT_OOB_FILL_NONE);
    return m;
}

// ---------------- launch ----------------
extern "C" void kernel_launch(void* const* d_in, const int* in_sizes, int n_in,
                              void* d_out, int out_size)
{
    const float* input   = (const float*)d_in[0];
    const int*   lengths = (const int*)  d_in[1];
    const float* w_in    = (const float*)d_in[2];
    const float* ln_in_g = (const float*)d_in[3];
    const float* ln_in_b = (const float*)d_in[4];
    const float* wq = (const float*)d_in[5];
    const float* bq = (const float*)d_in[6];
    const float* wk = (const float*)d_in[7];
    const float* bk = (const float*)d_in[8];
    const float* wv = (const float*)d_in[9];
    const float* bv = (const float*)d_in[10];
    const float* wo = (const float*)d_in[11];
    const float* bo = (const float*)d_in[12];
    const float* ff_g = (const float*)d_in[13];
    const float* ff_b = (const float*)d_in[14];
    const float* w1 = (const float*)d_in[15];
    const float* b1 = (const float*)d_in[16];
    const float* w2 = (const float*)d_in[17];
    const float* b2 = (const float*)d_in[18];
    const float* lo_g = (const float*)d_in[19];
    const float* lo_b = (const float*)d_in[20];
    const float* w_out = (const float*)d_in[21];
    const float* b_out = (const float*)d_in[22];
    const float* lng = (const float*)d_in[23];
    const float* lnb = (const float*)d_in[24];
    float* out = (float*)d_out;

    float* fa = nullptr; BF* bf = nullptr;
    cudaGetSymbolAddress((void**)&fa, g_arena);
    cudaGetSymbolAddress((void**)&bf, g_bf);

    const int SM_128_128 = 1024 + NST * (2 * 128 * 64 + 128 * 64) + 128;  // 74880
    const int SM_64_128  = 1024 + NST * (2 * 64 * 64 + 128 * 64) + 128;   // 50304
    const int SM_128_64  = 1024 + NST * (2 * 128 * 64 + 64 * 64) + 128;   // 62592
    cudaFuncSetAttribute(gemm6<128,128>, cudaFuncAttributeMaxDynamicSharedMemorySize, SM_128_128);
    cudaFuncSetAttribute(gemm6<64,128>,  cudaFuncAttributeMaxDynamicSharedMemorySize, SM_64_128);
    cudaFuncSetAttribute(gemm6<128,64>,  cudaFuncAttributeMaxDynamicSharedMemorySize, SM_128_64);

    float* X    = fa + F_X;
    float* S    = fa + F_S;
    float* QKVf = fa + F_QKV;
    float* H2A  = fa + F_H2A;
    float* Yb   = fa + F_YB;
    float* BQKV = fa + F_BQKV;

    BF* UINh = bf + BA_U;   BF* UINl = UINh + EU;
    BF* ATTh = bf + BA_AT;  BF* ATTl = ATTh + EAT;
    BF* HBh  = bf + BA_HB;  BF* HBl  = HBh + EHB;
    BF* FBh  = bf + BA_FB;  BF* FBl  = FBh + EFB;
    BF* YTh  = bf + BA_YT;  BF* YTl  = YTh + EYT;

    EncFn enc = get_enc();
    CUtensorMap mUIN = mkmap(enc, UINh, 512, 2816, EU, 128);
    CUtensorMap mATT = mkmap(enc, ATTh, 512, 2688, EAT, 64);
    CUtensorMap mHB  = mkmap(enc, HBh,  512, 2560, EHB, 128);
    CUtensorMap mFB  = mkmap(enc, FBh, 2048, 2560, EFB, 128);
    CUtensorMap mYT  = mkmap(enc, YTh,  512, 2048, EYT, 64);
    CUtensorMap mOUT = mkmap(enc, bf + BW_OUT, 512, 1024, EOUT, 128);
    CUtensorMap mWQKV[Ln], mWO[Ln], mW1[Ln], mW2[Ln];
    for (int l = 0; l < Ln; l++) {
        mWQKV[l] = mkmap(enc, bf + BW_QKV + (size_t)l * 2 * EQKV, 512, 1536, EQKV, 128);
        mWO[l]   = mkmap(enc, bf + BW_O   + (size_t)l * 2 * EQ,   512,  512, EQ, 128);
        mW1[l]   = mkmap(enc, bf + BW_1   + (size_t)l * 2 * EW1,  512, 2048, EW1, 64);
        mW2[l]   = mkmap(enc, bf + BW_2   + (size_t)l * 2 * EW1, 2048,  512, EW1, 128);
    }

    // ---- per-replay preprocessing ----
    gemm_tc<<<dim3(1, 65), 256>>>(input, w_in, nullptr, X, 8320, 128, 80, 0);
    initS_k<<<dim3(SN, Bn), Dm_>>>(X, S);
    mems0_k<<<dim3(15, Bn), Dm_>>>(S, UINh, UINl);

    wconv_k<<<dim3(16, 16, 8), 256>>>(wq, bf + BW_QKV, 512, 512, EQ, 2 * EQKV);
    wconv_k<<<dim3(16, 16, 8), 256>>>(wk, bf + BW_QKV + 262144, 512, 512, EQ, 2 * EQKV);
    wconv_k<<<dim3(16, 16, 8), 256>>>(wv, bf + BW_QKV + 524288, 512, 512, EQ, 2 * EQKV);
    wconv_k<<<dim3(16, 16, 8), 256>>>(wo, bf + BW_O, 512, 512, EQ, 2 * EQ);
    wconv_k<<<dim3(64, 16, 8), 256>>>(w1, bf + BW_1, 512, 2048, EW1, 2 * EW1);
    wconv_k<<<dim3(16, 64, 8), 256>>>(w2, bf + BW_2, 2048, 512, EW1, 2 * EW1);
    wconv_k<<<dim3(32, 16, 1), 256>>>(w_out, bf + BW_OUT, 512, 1024, 0, 0);
    prep_k<<<48, 256>>>(bq, bk, bv, BQKV, UINh, UINl);

    // layer-0 LN1: S -> UIN state planes (rows 120..2679)
    ln_row_k<<<SN * Bn / 8, 256>>>(S, ln_in_g, ln_in_b, nullptr,
                                   UINh + 120 * 512, UINl + 120 * 512, Dm_);

    for (int l = 0; l < Ln; l++) {
        summary_pl_k<<<dim3(NSEG, Bn), Dm_>>>(UINh, UINl);

        gemm6<128,128><<<dim3(12, 22, 1), 256, SM_128_128>>>(mUIN, mWQKV[l], BQKV + l * 1536,
                                                             QKVf, 0, nullptr, nullptr,
                                                             1536, 512, 0, 0);

        attn_k<<<dim3(QN / 4, Bn), 256>>>(QKVf, lengths, ATTh, ATTl);

        gemm6<64,128><<<dim3(4, 42, 1), 256, SM_64_128>>>(mATT, mWO[l], bo + l * Dm_,
                                                          S, 0, UINh, UINl,
                                                          512, 512, 0, 2);

        ln_row_k<<<SN * Bn / 8, 256>>>(S, ff_g + l * Dm_, ff_b + l * Dm_,
                                       nullptr, HBh, HBl, Dm_);
        gemm6<128,64><<<dim3(32, 20, 1), 256, SM_128_64>>>(mHB, mW1[l], b1 + l * FFNn,
                                                           nullptr, 0, FBh, FBl,
                                                           2048, 512, 1, 1);
        // FFN2 split-K=3 (704 per chunk; TMA zero-fills K >= 2048)
        gemm6<128,128><<<dim3(4, 20, 3), 256, SM_128_128>>>(mFB, mW2[l], b2 + l * Dm_,
                                                            H2A, 1310720, nullptr, nullptr,
                                                            512, 704, 0, 0);

        const float* g2 = (l + 1 < Ln) ? (ln_in_g + (l + 1) * Dm_) : nullptr;
        const float* b2n = (l + 1 < Ln) ? (ln_in_b + (l + 1) * Dm_) : nullptr;
        ln2_k<<<SN * Bn / 8, 256>>>(S, H2A, H2A + 1310720, H2A + 2621440,
                                    lo_g + l * Dm_, lo_b + l * Dm_, g2, b2n,
                                    S, UINh + 120 * 512, UINl + 120 * 512);
    }

    transpose_pl_k<<<2048, Dm_>>>(S, YTh, YTl);
    gemm6<64,128><<<dim3(8, 32, 1), 256, SM_64_128>>>(mYT, mOUT, b_out,
                                                      Yb, 0, nullptr, nullptr,
                                                      1024, 512, 0, 0);
    ln_row_k<<<2048 / 8, 256>>>(Yb, lng, lnb, out, nullptr, nullptr, OUTn);

    if (out_size >= 2048 * 1024 + Bn)
        lr_k<<<1, 32>>>(lengths, out + 2048 * 1024);
}

// round 12
// speedup vs baseline: 7.1583x; 1.1025x over previous
#include <cuda_runtime.h>
#include <cuda_fp16.h>
#include <cuda.h>
#include <math.h>
#include <stdint.h>

typedef __half BF;
typedef __half2 BF2;

// ---------------- constants ----------------
#define Bn   8
#define Dm_  512
#define FFNn 2048
#define Ln   8
#define OUTn 1024
#define Hn   8
#define DHn  64
#define QN   336
#define SN   320
#define RTn  64
#define Un   256
#define NSEG 16

// token space: 0..14 mems | 15..78 rc | 79..334 utt | 335..350 summary | 351 pad
// row = token*8 + b;  M_UIN = 2816

// ------- float arena -------
#define F_X    0UL
#define F_S    (F_X + 1064960UL)
#define F_QKV  (F_S + 1310720UL)
#define F_H2A  (F_QKV + 4325376UL)
#define F_H2B  (F_H2A + 1310720UL)
#define F_H2C  (F_H2B + 1310720UL)
#define F_YB   (F_H2C + 1310720UL)
#define F_BQKV (F_YB + 2097152UL)
#define F_TOT  (F_BQKV + 12288UL)
__device__ __align__(1024) float g_arena[F_TOT];

// ------- fp16 arena (activations: hi plane at base, lo at base+E; weights: hi only) ----
#define EQ    262144UL
#define EQKV  786432UL     // 1536*512
#define EW1   1048576UL
#define EOUT  524288UL
#define EU    1441792UL    // 2816*512
#define EAT   1376256UL    // 2688*512
#define EHB   1310720UL    // 2560*512
#define EFB   5242880UL    // 2560*2048
#define EYT   1048576UL    // 2048*512

#define BW_QKV 0UL
#define BW_O   (BW_QKV + 8UL*2UL*EQKV)
#define BW_1   (BW_O   + 8UL*2UL*EQ)
#define BW_2   (BW_1   + 8UL*2UL*EW1)
#define BW_OUT (BW_2   + 8UL*2UL*EW1)
#define BA_U   (BW_OUT + 2UL*EOUT)
#define BA_AT  (BA_U   + 2UL*EU)
#define BA_HB  (BA_AT  + 2UL*EAT)
#define BA_FB  (BA_HB  + 2UL*EHB)
#define BA_YT  (BA_FB  + 2UL*EFB)
#define B_TOT  (BA_YT  + 2UL*EYT)
__device__ __align__(1024) BF g_bf[B_TOT];

__device__ __forceinline__ void split2(float x, BF& h, BF& l) {
    h = __float2half(x);
    l = __float2half(x - __half2float(h));
}
__device__ __forceinline__ BF2 mk2(BF a, BF b) { return __halves2half2(a, b); }

// ============ TMA / mbarrier primitives ============
__device__ __forceinline__ uint32_t smem_u32(const void* p) {
    return (uint32_t)__cvta_generic_to_shared(p);
}
__device__ __forceinline__ void mbar_init(uint32_t a, uint32_t cnt) {
    asm volatile("mbarrier.init.shared::cta.b64 [%0], %1;" :: "r"(a), "r"(cnt) : "memory");
}
__device__ __forceinline__ void mbar_expect(uint32_t a, uint32_t tx) {
    asm volatile("mbarrier.arrive.expect_tx.shared::cta.b64 _, [%0], %1;"
                 :: "r"(a), "r"(tx) : "memory");
}
__device__ __forceinline__ void mbar_arrive(uint32_t a) {
    asm volatile("mbarrier.arrive.shared::cta.b64 _, [%0];" :: "r"(a) : "memory");
}
__device__ __forceinline__ void mbar_wait(uint32_t a, uint32_t ph) {
    uint32_t done = 0;
    while (!done) {
        asm volatile(
            "{\n\t.reg .pred p;\n\t"
            "mbarrier.try_wait.parity.acquire.cta.shared::cta.b64 p, [%1], %2, 0x989680;\n\t"
            "selp.b32 %0, 1, 0, p;\n\t}"
            : "=r"(done) : "r"(a), "r"(ph) : "memory");
    }
}
__device__ __forceinline__ void tma3d(uint32_t dst, const void* map,
                                      int cx, int cy, int cz, uint32_t mbar) {
    asm volatile(
        "cp.async.bulk.tensor.3d.shared::cta.global.tile.mbarrier::complete_tx::bytes "
        "[%0], [%1, {%2, %3, %4}], [%5];"
        :: "r"(dst), "l"(map), "r"(cx), "r"(cy), "r"(cz), "r"(mbar) : "memory");
}
__device__ __forceinline__ void mma2(float c[4], const uint32_t a[4],
                                     uint32_t b0, uint32_t b1) {
    asm volatile(
        "mma.sync.aligned.m16n8k16.row.col.f32.f16.f16.f32 "
        "{%0,%1,%2,%3}, {%4,%5,%6,%7}, {%8,%9}, {%0,%1,%2,%3};\n"
        : "+f"(c[0]), "+f"(c[1]), "+f"(c[2]), "+f"(c[3])
        : "r"(a[0]), "r"(a[1]), "r"(a[2]), "r"(a[3]), "r"(b0), "r"(b1));
}
#define LDSM4(r, a) \
    asm volatile("ldmatrix.sync.aligned.m8n8.x4.shared.b16 {%0,%1,%2,%3}, [%4];" \
        : "=r"((r)[0]), "=r"((r)[1]), "=r"((r)[2]), "=r"((r)[3]) : "r"(a))

// ============ TMA-staged mma.sync GEMM (SW64, 32-K stages, fp16) ============
// C = act(A @ B^T + bias). A: hi (+lo if AP==2) fp16 planes; B: hi plane.
// grid (N/NT, M/MT, splitZ). TMA zero-fills OOB K.
// mode 0: fp32 Cf (+ z*czstride). mode 1: fp16 planes Ch (+Cl if non-null).
// mode 2: fused O epilogue: rows<2560 S+=v; rows 2560..2679 planes=tanh(v).
#define NST 3

template <int MT, int NT, int AP>
__global__ __launch_bounds__(256, 2) void gemm6(
    const __grid_constant__ CUtensorMap tmA,
    const __grid_constant__ CUtensorMap tmB,
    const float* __restrict__ bias, float* __restrict__ Cf, long czstride,
    BF* __restrict__ Ch, BF* __restrict__ Cl,
    int N, int K, int act, int mode)
{
    constexpr int MSPAN = MT / 4;
    constexpr int MTM   = MSPAN / 16;
    constexpr int NSPAN = NT / 2;
    constexpr int NNT   = NSPAN / 8;
    constexpr int APL   = MT * 64;            // A plane bytes per stage
    constexpr int BPL   = NT * 64;            // B plane bytes per stage
    constexpr int STB   = AP * APL + BPL;     // stage bytes
    extern __shared__ __align__(16) char smx[];
    const uint32_t sb = smem_u32(smx);
    const uint32_t db = (sb + 1023) & ~1023u;
    const int tid = threadIdx.x, lane = tid & 31, wid = tid >> 5;
    const int wm = wid & 3, wn = wid >> 2;
    const int grp = lane >> 2, tig = lane & 3;
    const int row0 = blockIdx.y * MT, col0 = blockIdx.x * NT;
    const int kstart = blockIdx.z * K;
    if (Cf && mode == 0) Cf += (long)blockIdx.z * czstride;
    const float* bi = (bias && kstart == 0) ? bias : nullptr;
    const int T = K >> 5;

    const uint32_t barb = db + NST * STB;
    if (tid == 0) {
        for (int s = 0; s < NST; s++) {
            mbar_init(barb + s * 8, 1);
            mbar_init(barb + 64 + s * 8, 256);
        }
    }
    __syncthreads();

    if (tid == 0) {
        for (int s = 0; s < NST; s++) {
            uint32_t st = db + s * STB, fb = barb + s * 8;
            mbar_expect(fb, STB);
            tma3d(st, &tmA, kstart + s * 32, row0, 0, fb);
            if (AP == 2) tma3d(st + APL, &tmA, kstart + s * 32, row0, 1, fb);
            tma3d(st + AP * APL, &tmB, kstart + s * 32, col0, 0, fb);
        }
    }

    float acc[MTM][NNT][4] = {};
    // ldmatrix lane geometry (SW64: 64B rows; xor = ((row>>1)&3)<<4)
    const int lrow = (lane & 7) + (((lane >> 3) & 1) << 3);
    const int kofs = ((lane >> 4) & 1) * 8;
    const uint32_t msk = (uint32_t)((lrow >> 1) & 3) << 4;
    uint32_t arow_off[MTM], brow_off[NNT / 2];
#pragma unroll
    for (int mt = 0; mt < MTM; mt++)
        arow_off[mt] = (uint32_t)(wm * MSPAN + mt * 16 + lrow) * 64;
#pragma unroll
    for (int p = 0; p < NNT / 2; p++)
        brow_off[p] = (uint32_t)(wn * NSPAN + p * 16 + lrow) * 64;

    uint32_t pfm = 0, pem = 0;
    for (int i = 0; i < T; i++) {
        const int bslot = i % NST;
        const uint32_t fb = barb + bslot * 8, eb = barb + 64 + bslot * 8;
        mbar_wait(fb, (pfm >> bslot) & 1); pfm ^= (1u << bslot);
        const uint32_t sA = db + bslot * STB, sB = sA + AP * APL;
#pragma unroll
        for (int kk = 0; kk < 32; kk += 16) {
            const uint32_t csw = ((uint32_t)((kk + kofs) * 2)) ^ msk;
            uint32_t ah[MTM][4], al_[MTM][4], bh[NNT / 2][4];
#pragma unroll
            for (int mt = 0; mt < MTM; mt++) {
                uint32_t ad = sA + arow_off[mt] + csw;
                LDSM4(ah[mt], ad);
                if (AP == 2) LDSM4(al_[mt], ad + APL);
            }
#pragma unroll
            for (int p = 0; p < NNT / 2; p++) {
                LDSM4(bh[p], sB + brow_off[p] + csw);
            }
#pragma unroll
            for (int nt = 0; nt < NNT; nt++) {
                const int p = nt >> 1, s1 = nt & 1;
#pragma unroll
                for (int mt = 0; mt < MTM; mt++) {
                    mma2(acc[mt][nt], ah[mt], bh[p][s1], bh[p][2 + s1]);
                    if (AP == 2)
                        mma2(acc[mt][nt], al_[mt], bh[p][s1], bh[p][2 + s1]);
                }
            }
        }
        mbar_arrive(eb);
        if (tid == 0 && i + NST < T) {
            mbar_wait(eb, (pem >> bslot) & 1); pem ^= (1u << bslot);
            uint32_t st = db + bslot * STB;
            mbar_expect(fb, STB);
            int k0 = kstart + (i + NST) * 32;
            tma3d(st, &tmA, k0, row0, 0, fb);
            if (AP == 2) tma3d(st + APL, &tmA, k0, row0, 1, fb);
            tma3d(st + AP * APL, &tmB, k0, col0, 0, fb);
        }
    }

#pragma unroll
    for (int mt = 0; mt < MTM; mt++) {
        const long r = row0 + wm * MSPAN + mt * 16 + grp;
#pragma unroll
        for (int nt = 0; nt < NNT; nt++) {
            const long c = col0 + wn * NSPAN + nt * 8 + tig * 2;
            float bb0 = bi ? bi[c] : 0.f, bb1 = bi ? bi[c + 1] : 0.f;
            float v0 = acc[mt][nt][0] + bb0, v1 = acc[mt][nt][1] + bb1;
            float v2 = acc[mt][nt][2] + bb0, v3 = acc[mt][nt][3] + bb1;
            if (act) {
                v0 = fmaxf(v0, 0.f); v1 = fmaxf(v1, 0.f);
                v2 = fmaxf(v2, 0.f); v3 = fmaxf(v3, 0.f);
            }
            if (mode == 0) {
                *(float2*)&Cf[r * N + c]       = make_float2(v0, v1);
                *(float2*)&Cf[(r + 8) * N + c] = make_float2(v2, v3);
            } else if (mode == 1) {
                BF h0, l0, h1, l1;
                split2(v0, h0, l0); split2(v1, h1, l1);
                *(BF2*)&Ch[r * N + c] = mk2(h0, h1);
                if (Cl) *(BF2*)&Cl[r * N + c] = mk2(l0, l1);
                split2(v2, h0, l0); split2(v3, h1, l1);
                *(BF2*)&Ch[(r + 8) * N + c] = mk2(h0, h1);
                if (Cl) *(BF2*)&Cl[(r + 8) * N + c] = mk2(l0, l1);
            } else {
#pragma unroll
                for (int rr = 0; rr < 2; rr++) {
                    long r2 = r + rr * 8;
                    float u0 = rr ? v2 : v0, u1 = rr ? v3 : v1;
                    if (r2 < 2560) {
                        float2 s = *(float2*)&Cf[r2 * 512 + c];
                        *(float2*)&Cf[r2 * 512 + c] = make_float2(s.x + u0, s.y + u1);
                    } else if (r2 < 2680) {
                        float t0 = tanhf(u0), t1 = tanhf(u1);
                        BF h0, l0, h1, l1;
                        split2(t0, h0, l0); split2(t1, h1, l1);
                        long o = (r2 - 2560) * 512 + c;
                        *(BF2*)&Ch[o] = mk2(h0, h1);
                        *(BF2*)&Cl[o] = mk2(l0, l1);
                    }
                }
            }
        }
    }
}

// ---------------- legacy in-kernel-convert GEMM (input proj, K=80) ---------
#define LLDA 40
__global__ __launch_bounds__(256) void gemm_tc(
    const float* __restrict__ A, const float* __restrict__ W,
    const float* __restrict__ bias, float* __restrict__ C,
    int M, int N, int K, int act)
{
    __shared__ BF Ahs[128 * LLDA], Als[128 * LLDA];
    __shared__ BF Bhs[128 * LLDA];
    const int tid = threadIdx.x, lane = tid & 31, wid = tid >> 5;
    const int wm = wid & 3, wn = wid >> 2;
    const int grp = lane >> 2, tig = lane & 3;
    const long row0 = (long)blockIdx.y * 128;
    const int  col0 = blockIdx.x * 128;
    float acc[2][8][4] = {};
    const int arow = tid >> 1, acol0 = (tid & 1) * 16;
    const int brow = tid >> 3, bcol0 = (tid & 7) * 16;

    for (int k0 = 0; k0 < K; k0 += 32) {
#pragma unroll
        for (int j = 0; j < 4; j++) {
            int c = acol0 + j * 4;
            float4 v = make_float4(0.f, 0.f, 0.f, 0.f);
            if (row0 + arow < M && k0 + c < K)
                v = *(const float4*)&A[(row0 + arow) * (long)K + k0 + c];
            BF h, l; int o = arow * LLDA + c;
            split2(v.x, h, l); Ahs[o]     = h; Als[o]     = l;
            split2(v.y, h, l); Ahs[o + 1] = h; Als[o + 1] = l;
            split2(v.z, h, l); Ahs[o + 2] = h; Als[o + 2] = l;
            split2(v.w, h, l); Ahs[o + 3] = h; Als[o + 3] = l;
        }
#pragma unroll
        for (int j = 0; j < 4; j++) {
            int n = bcol0 + j * 4;
            float4 v = make_float4(0.f, 0.f, 0.f, 0.f);
            if (k0 + brow < K)
                v = *(const float4*)&W[(long)(k0 + brow) * N + col0 + n];
            Bhs[(n + 0) * LLDA + brow] = __float2half(v.x);
            Bhs[(n + 1) * LLDA + brow] = __float2half(v.y);
            Bhs[(n + 2) * LLDA + brow] = __float2half(v.z);
            Bhs[(n + 3) * LLDA + brow] = __float2half(v.w);
        }
        __syncthreads();
#pragma unroll
        for (int kk = 0; kk < 32; kk += 16) {
            uint32_t ah[2][4], al[2][4];
#pragma unroll
            for (int mt = 0; mt < 2; mt++) {
                int r = wm * 32 + mt * 16;
                int o  = (r + grp) * LLDA + kk + tig * 2;
                int o8 = o + 8 * LLDA;
                ah[mt][0] = *(const uint32_t*)&Ahs[o];
                ah[mt][1] = *(const uint32_t*)&Ahs[o8];
                ah[mt][2] = *(const uint32_t*)&Ahs[o + 8];
                ah[mt][3] = *(const uint32_t*)&Ahs[o8 + 8];
                al[mt][0] = *(const uint32_t*)&Als[o];
                al[mt][1] = *(const uint32_t*)&Als[o8];
                al[mt][2] = *(const uint32_t*)&Als[o + 8];
                al[mt][3] = *(const uint32_t*)&Als[o8 + 8];
            }
#pragma unroll
            for (int nt = 0; nt < 8; nt++) {
                int nn = wn * 64 + nt * 8 + grp;
                int o = nn * LLDA + kk + tig * 2;
                uint32_t b0 = *(const uint32_t*)&Bhs[o], b1 = *(const uint32_t*)&Bhs[o + 8];
#pragma unroll
                for (int mt = 0; mt < 2; mt++) {
                    mma2(acc[mt][nt], ah[mt], b0, b1);
                    mma2(acc[mt][nt], al[mt], b0, b1);
                }
            }
        }
        __syncthreads();
    }
#pragma unroll
    for (int mt = 0; mt < 2; mt++) {
#pragma unroll
        for (int nt = 0; nt < 8; nt++) {
            int c = col0 + wn * 64 + nt * 8 + tig * 2;
            float b0 = bias ? bias[c] : 0.f;
            float b1 = bias ? bias[c + 1] : 0.f;
            long r = row0 + wm * 32 + mt * 16 + grp;
            float v0 = acc[mt][nt][0] + b0, v1 = acc[mt][nt][1] + b1;
            float v2 = acc[mt][nt][2] + b0, v3 = acc[mt][nt][3] + b1;
            if (act) { v0=fmaxf(v0,0.f); v1=fmaxf(v1,0.f); v2=fmaxf(v2,0.f); v3=fmaxf(v3,0.f); }
            if (r < M)     *(float2*)&C[r * N + c]       = make_float2(v0, v1);
            if (r + 8 < M) *(float2*)&C[(r + 8) * N + c] = make_float2(v2, v3);
        }
    }
}

// ------- weight transpose+convert: out[n][k] = fp16(W[k][n]), hi plane only ----
__global__ __launch_bounds__(256) void wconv_k(
    const float* __restrict__ W, BF* __restrict__ oh,
    int K, int N, long inS, long outS)
{
    __shared__ float t[32][33];
    const float* w = W + (long)blockIdx.z * inS;
    BF* ph = oh + (long)blockIdx.z * outS;
    const int n0 = blockIdx.x * 32, k0 = blockIdx.y * 32;
    const int tx = threadIdx.x & 7, ty = threadIdx.x >> 3;
    float4 v = *(const float4*)&w[(long)(k0 + ty) * N + n0 + tx * 4];
    t[ty][tx * 4 + 0] = v.x; t[ty][tx * 4 + 1] = v.y;
    t[ty][tx * 4 + 2] = v.z; t[ty][tx * 4 + 3] = v.w;
    __syncthreads();
    float a0 = t[tx * 4 + 0][ty], a1 = t[tx * 4 + 1][ty];
    float a2 = t[tx * 4 + 2][ty], a3 = t[tx * 4 + 3][ty];
    long o = (long)(n0 + ty) * K + k0 + tx * 4;
    *(BF2*)&ph[o]     = mk2(__float2half(a0), __float2half(a1));
    *(BF2*)&ph[o + 2] = mk2(__float2half(a2), __float2half(a3));
}

// merged bias pack + UIN pad
__global__ void prep_k(const float* __restrict__ bq, const float* __restrict__ bk,
                       const float* __restrict__ bv, float* __restrict__ o,
                       BF* __restrict__ uh, BF* __restrict__ ul)
{
    int i = blockIdx.x * blockDim.x + threadIdx.x;
    if (i < 12288) {
        int l = i / 1536, j = i % 1536;
        float v;
        if (j < 512)       v = bq[l * 512 + j];
        else if (j < 1024) v = bk[l * 512 + j - 512];
        else               v = bv[l * 512 + j - 1024];
        o[i] = v;
    }
    if (i < 4096) {
        size_t p = 2808UL * 512UL + i;
        uh[p] = __float2half(0.f);
        ul[p] = __float2half(0.f);
    }
}

// ---------------- LayerNorm: warp per row ----------------
__global__ __launch_bounds__(256) void ln_row_k(
    const float* __restrict__ X, const float* __restrict__ g, const float* __restrict__ bta,
    float* __restrict__ outf, BF* __restrict__ oh, BF* __restrict__ ol, int D)
{
    const int wid = threadIdx.x >> 5, lane = threadIdx.x & 31;
    const int row = blockIdx.x * 8 + wid;
    const float4* x = (const float4*)(X + (long)row * D);
    const int cnt = D >> 7;
    float s = 0.f, s2 = 0.f;
    for (int i = 0; i < cnt; i++) {
        float4 a = x[lane + i * 32];
        s  += a.x + a.y + a.z + a.w;
        s2 += a.x * a.x + a.y * a.y + a.z * a.z + a.w * a.w;
    }
#pragma unroll
    for (int o = 16; o; o >>= 1) {
        s  += __shfl_xor_sync(~0u, s, o);
        s2 += __shfl_xor_sync(~0u, s2, o);
    }
    const float mean = s / D;
    const float inv = rsqrtf(s2 / D - mean * mean + 1e-5f);
    const float4* gg = (const float4*)g;
    const float4* bb = (const float4*)bta;
    for (int i = 0; i < cnt; i++) {
        int idx = lane + i * 32;
        float4 a = x[idx], gv = gg[idx], bv = bb[idx], o;
        o.x = (a.x - mean) * inv * gv.x + bv.x;
        o.y = (a.y - mean) * inv * gv.y + bv.y;
        o.z = (a.z - mean) * inv * gv.z + bv.z;
        o.w = (a.w - mean) * inv * gv.w + bv.w;
        if (outf) ((float4*)(outf + (long)row * D))[idx] = o;
        if (oh) {
            BF h0,l0,h1,l1,h2,l2,h3,l3;
            split2(o.x,h0,l0); split2(o.y,h1,l1);
            split2(o.z,h2,l2); split2(o.w,h3,l3);
            long base = (long)row * D + idx * 4;
            *(BF2*)&oh[base]     = mk2(h0,h1);
            *(BF2*)&oh[base + 2] = mk2(h2,h3);
            *(BF2*)&ol[base]     = mk2(l0,l1);
            *(BF2*)&ol[base + 2] = mk2(l2,l3);
        }
    }
}

// -------- double LN: res=S+HA+HB+HC; S=LN1(res); planes=LN2(S) ------------
__global__ __launch_bounds__(256) void ln2_k(
    const float* __restrict__ S, const float* __restrict__ HA,
    const float* __restrict__ HB_, const float* __restrict__ HC,
    const float* __restrict__ g1, const float* __restrict__ be1,
    const float* __restrict__ g2, const float* __restrict__ be2,
    float* __restrict__ Sout, BF* __restrict__ oh, BF* __restrict__ ol)
{
    const int wid = threadIdx.x >> 5, lane = threadIdx.x & 31;
    const int row = blockIdx.x * 8 + wid;   // 0..2559
    const float4* xs = (const float4*)(S   + (long)row * 512);
    const float4* xa = (const float4*)(HA  + (long)row * 512);
    const float4* xb = (const float4*)(HB_ + (long)row * 512);
    const float4* xc = (const float4*)(HC  + (long)row * 512);
    float4 R[4];
    float s = 0.f, s2 = 0.f;
#pragma unroll
    for (int i = 0; i < 4; i++) {
        int idx = lane + i * 32;
        float4 a = xs[idx], c = xa[idx], d = xb[idx], e = xc[idx];
        a.x += c.x + d.x + e.x; a.y += c.y + d.y + e.y;
        a.z += c.z + d.z + e.z; a.w += c.w + d.w + e.w;
        R[i] = a;
        s  += a.x + a.y + a.z + a.w;
        s2 += a.x * a.x + a.y * a.y + a.z * a.z + a.w * a.w;
    }
#pragma unroll
    for (int o = 16; o; o >>= 1) {
        s  += __shfl_xor_sync(~0u, s, o);
        s2 += __shfl_xor_sync(~0u, s2, o);
    }
    float mean = s * (1.f / 512.f);
    float inv = rsqrtf(s2 * (1.f / 512.f) - mean * mean + 1e-5f);
    const float4* g1v = (const float4*)g1; const float4* b1v = (const float4*)be1;
    float t = 0.f, t2 = 0.f;
#pragma unroll
    for (int i = 0; i < 4; i++) {
        int idx = lane + i * 32;
        float4 gv = g1v[idx], bv = b1v[idx], y;
        y.x = (R[i].x - mean) * inv * gv.x + bv.x;
        y.y = (R[i].y - mean) * inv * gv.y + bv.y;
        y.z = (R[i].z - mean) * inv * gv.z + bv.z;
        y.w = (R[i].w - mean) * inv * gv.w + bv.w;
        R[i] = y;
        ((float4*)(Sout + (long)row * 512))[idx] = y;
        t  += y.x + y.y + y.z + y.w;
        t2 += y.x * y.x + y.y * y.y + y.z * y.z + y.w * y.w;
    }
    if (!g2) return;
#pragma unroll
    for (int o = 16; o; o >>= 1) {
        t  += __shfl_xor_sync(~0u, t, o);
        t2 += __shfl_xor_sync(~0u, t2, o);
    }
    float mean2 = t * (1.f / 512.f);
    float inv2 = rsqrtf(t2 * (1.f / 512.f) - mean2 * mean2 + 1e-5f);
    const float4* g2v = (const float4*)g2; const float4* b2v = (const float4*)be2;
#pragma unroll
    for (int i = 0; i < 4; i++) {
        int idx = lane + i * 32;
        float4 gv = g2v[idx], bv = b2v[idx], z;
        z.x = (R[i].x - mean2) * inv2 * gv.x + bv.x;
        z.y = (R[i].y - mean2) * inv2 * gv.y + bv.y;
        z.z = (R[i].z - mean2) * inv2 * gv.z + bv.z;
        z.w = (R[i].w - mean2) * inv2 * gv.w + bv.w;
        BF h0,l0,h1,l1,h2,l2,h3,l3;
        split2(z.x,h0,l0); split2(z.y,h1,l1);
        split2(z.z,h2,l2); split2(z.w,h3,l3);
        long base = (long)row * 512 + idx * 4;
        *(BF2*)&oh[base]     = mk2(h0,h1);
        *(BF2*)&oh[base + 2] = mk2(h2,h3);
        *(BF2*)&ol[base]     = mk2(l0,l1);
        *(BF2*)&ol[base + 2] = mk2(l2,l3);
    }
}

// ---------------- misc ----------------
__global__ void initS_k(const float* __restrict__ X, float* __restrict__ S)
{
    const int t = blockIdx.x, b = blockIdx.y, d = threadIdx.x;
    int frame;
    if (t < RTn) {
        int si = t >> 2;
        int st = (si == 15) ? 256 : (si + 1) * 16;
        frame = st + (t & 3);
    } else frame = t - RTn;
    S[((size_t)t * Bn + b) * Dm_ + d] = X[(size_t)b * 133120 + (size_t)frame * Dm_ + d];
}

__global__ void mems0_k(const float* __restrict__ S, BF* __restrict__ uh,
                        BF* __restrict__ ul)
{
    const int s = blockIdx.x, b = blockIdx.y, d = threadIdx.x;
    size_t base = ((size_t)(RTn + s * 16) * Bn + b) * Dm_ + d;
    float acc = 0.f;
#pragma unroll
    for (int k = 0; k < 16; k++) acc += S[base + (size_t)k * Bn * Dm_];
    acc *= (1.f / 16.f);
    BF h, l; split2(acc, h, l);
    size_t o = ((size_t)s * Bn + b) * Dm_ + d;
    uh[o] = h; ul[o] = l;
}

__global__ void summary_pl_k(BF* __restrict__ uh, BF* __restrict__ ul)
{
    const int s = blockIdx.x, b = blockIdx.y, d = threadIdx.x;
    size_t base = ((size_t)((79 + s * 16) * Bn) + b) * Dm_ + d;
    float acc = 0.f;
#pragma unroll
    for (int k = 0; k < 16; k++) {
        size_t o = base + (size_t)k * Bn * Dm_;
        acc += __half2float(uh[o]) + __half2float(ul[o]);
    }
    acc *= (1.f / 16.f);
    BF h, l; split2(acc, h, l);
    size_t o = ((size_t)((335 + s) * Bn) + b) * Dm_ + d;
    uh[o] = h; ul[o] = l;
}

// ---------------- attention: 4 queries per CTA ----------------
__global__ __launch_bounds__(256) void attn_k(
    const float* __restrict__ QKV, const int* __restrict__ lengths,
    BF* __restrict__ Ah, BF* __restrict__ Al)
{
    __shared__ float sc[Hn][64];
    __shared__ short ki[Hn][64];
    const int b = blockIdx.y;
    const int h = threadIdx.x >> 5, lane = threadIdx.x & 31;

    int maxlr = 0;
#pragma unroll
    for (int i = 0; i < Bn; i++) maxlr = max(maxlr, lengths[i] >> 2);
    const int lrb = lengths[b] >> 2;
    const int g = lane >> 3, e = lane & 7;
    const float* Kb = QKV + (size_t)b * 1536 + 512 + h * DHn;
    const float* Vb = Kb + 512;

    for (int qq = 0; qq < 4; qq++) {
        const int qi = blockIdx.x * 4 + qq;
        int seg; bool summ = false;
        if (qi < RTn)      seg = qi >> 2;
        else if (qi < SN)  seg = (qi - RTn) >> 4;
        else             { seg = qi - SN; summ = true; }
        const int ms  = max(seg - 4, 0);
        const int ss  = max(seg * 16 - 32, 0);
        const int se  = min(seg * 16 + 16, Un);
        const int ue  = min(se, lrb + 256 - maxlr);
        const int rcs = 15 + seg * 4;

        const int c0 = summ ? 0 : (seg - ms);
        const int c2 = max(ue - ss, 0);
        const int n  = c0 + 4 + c2;

        for (int j = lane; j < n; j += 32) {
            int k;
            if (j < c0)          k = ms + j;
            else if (j < c0 + 4) k = rcs + (j - c0);
            else                 k = 79 + ss + (j - c0 - 4);
            ki[h][j] = (short)k;
        }
        __syncwarp();

        const float4* qv = (const float4*)(QKV + ((size_t)(15 + qi) * Bn + b) * 1536 + h * DHn);
        float4 q0 = qv[e * 2], q1 = qv[e * 2 + 1];
        q0.x *= 0.125f; q0.y *= 0.125f; q0.z *= 0.125f; q0.w *= 0.125f;
        q1.x *= 0.125f; q1.y *= 0.125f; q1.z *= 0.125f; q1.w *= 0.125f;

        for (int j0 = 0; j0 < n; j0 += 4) {
            int j = j0 + g;
            float p = 0.f;
            if (j < n) {
                const float4* kp = (const float4*)(Kb + (size_t)ki[h][j] * (Bn * 1536));
                float4 k0 = kp[e * 2], k1 = kp[e * 2 + 1];
                p = q0.x * k0.x + q0.y * k0.y + q0.z * k0.z + q0.w * k0.w
                  + q1.x * k1.x + q1.y * k1.y + q1.z * k1.z + q1.w * k1.w;
            }
            p += __shfl_xor_sync(~0u, p, 4);
            p += __shfl_xor_sync(~0u, p, 2);
            p += __shfl_xor_sync(~0u, p, 1);
            if (e == 0 && j < n) sc[h][j] = p;
        }
        __syncwarp();

        float m = -3.4e38f;
        for (int j = lane; j < n; j += 32) m = fmaxf(m, sc[h][j]);
#pragma unroll
        for (int o = 16; o; o >>= 1) m = fmaxf(m, __shfl_xor_sync(~0u, m, o));
        float sum = 0.f;
        for (int j = lane; j < n; j += 32) {
            float e2 = expf(sc[h][j] - m);
            sc[h][j] = e2;
            sum += e2;
        }
#pragma unroll
        for (int o = 16; o; o >>= 1) sum += __shfl_xor_sync(~0u, sum, o);
        __syncwarp();
        const float inv = 1.f / sum;

        float a0 = 0.f, a1 = 0.f;
        for (int j = 0; j < n; j++) {
            float p = sc[h][j];
            const float2 vp = *(const float2*)(Vb + (size_t)ki[h][j] * (Bn * 1536) + 2 * lane);
            a0 = fmaf(p, vp.x, a0);
            a1 = fmaf(p, vp.y, a1);
        }
        a0 *= inv; a1 *= inv;
        BF h0, l0, h1, l1;
        split2(a0, h0, l0); split2(a1, h1, l1);
        size_t op = ((size_t)qi * Bn + b) * Dm_ + h * DHn + 2 * lane;
        *(BF2*)&Ah[op] = mk2(h0, h1);
        *(BF2*)&Al[op] = mk2(l0, l1);
        __syncwarp();
    }
}

__global__ void transpose_pl_k(const float* __restrict__ S, BF* __restrict__ yh,
                               BF* __restrict__ yl)
{
    const int r = blockIdx.x, d = threadIdx.x;
    const int b = r >> 8, u = r & 255;
    float v = S[((size_t)(RTn + u) * Bn + b) * Dm_ + d];
    BF h, l; split2(v, h, l);
    yh[(size_t)r * Dm_ + d] = h;
    yl[(size_t)r * Dm_ + d] = l;
}

__global__ void lr_k(const int* __restrict__ lengths, float* __restrict__ out)
{
    int i = threadIdx.x;
    if (i < Bn) out[i] = (float)(lengths[i] >> 2);
}

// ---------------- host: tensormap plumbing ----------------
typedef CUresult (*EncFn)(CUtensorMap*, CUtensorMapDataType, cuuint32_t, void*,
                          const cuuint64_t*, const cuuint64_t*, const cuuint32_t*,
                          const cuuint32_t*, CUtensorMapInterleave, CUtensorMapSwizzle,
                          CUtensorMapL2promotion, CUtensorMapFloatOOBfill);

static EncFn get_enc() {
    void* p = nullptr;
    cudaDriverEntryPointQueryResult qr;
#if CUDART_VERSION >= 12050
    if (cudaGetDriverEntryPointByVersion("cuTensorMapEncodeTiled", &p, 12000,
                                         cudaEnableDefault, &qr) == cudaSuccess && p)
        return (EncFn)p;
    p = nullptr;
#endif
    cudaGetDriverEntryPoint("cuTensorMapEncodeTiled", &p, cudaEnableDefault, &qr);
    return (EncFn)p;
}

static CUtensorMap mkmap(EncFn enc, const BF* base, long K, long M, long planeStride,
                         unsigned boxM) {
    CUtensorMap m;
    cuuint64_t dims[3]    = {(cuuint64_t)K, (cuuint64_t)M, 2};
    cuuint64_t strides[2] = {(cuuint64_t)K * 2, (cuuint64_t)planeStride * 2};
    cuuint32_t box[3]     = {32, boxM, 1};
    cuuint32_t es[3]      = {1, 1, 1};
    enc(&m, CU_TENSOR_MAP_DATA_TYPE_FLOAT16, 3, (void*)base, dims, strides, box, es,
        CU_TENSOR_MAP_INTERLEAVE_NONE, CU_TENSOR_MAP_SWIZZLE_64B,
        CU_TENSOR_MAP_L2_PROMOTION_L2_128B, CU_TENSOR_MAP_FLOAT_OOB_FILL_NONE);
    return m;
}

// ---------------- launch ----------------
extern "C" void kernel_launch(void* const* d_in, const int* in_sizes, int n_in,
                              void* d_out, int out_size)
{
    const float* input   = (const float*)d_in[0];
    const int*   lengths = (const int*)  d_in[1];
    const float* w_in    = (const float*)d_in[2];
    const float* ln_in_g = (const float*)d_in[3];
    const float* ln_in_b = (const float*)d_in[4];
    const float* wq = (const float*)d_in[5];
    const float* bq = (const float*)d_in[6];
    const float* wk = (const float*)d_in[7];
    const float* bk = (const float*)d_in[8];
    const float* wv = (const float*)d_in[9];
    const float* bv = (const float*)d_in[10];
    const float* wo = (const float*)d_in[11];
    const float* bo = (const float*)d_in[12];
    const float* ff_g = (const float*)d_in[13];
    const float* ff_b = (const float*)d_in[14];
    const float* w1 = (const float*)d_in[15];
    const float* b1 = (const float*)d_in[16];
    const float* w2 = (const float*)d_in[17];
    const float* b2 = (const float*)d_in[18];
    const float* lo_g = (const float*)d_in[19];
    const float* lo_b = (const float*)d_in[20];
    const float* w_out = (const float*)d_in[21];
    const float* b_out = (const float*)d_in[22];
    const float* lng = (const float*)d_in[23];
    const float* lnb = (const float*)d_in[24];
    float* out = (float*)d_out;

    float* fa = nullptr; BF* bf = nullptr;
    cudaGetSymbolAddress((void**)&fa, g_arena);
    cudaGetSymbolAddress((void**)&bf, g_bf);

    const int SM_128_128_2 = 1024 + NST * (2 * 8192 + 8192) + 128;  // 74880
    const int SM_64_128_2  = 1024 + NST * (2 * 4096 + 8192) + 128;  // 50304
    const int SM_128_64_2  = 1024 + NST * (2 * 8192 + 4096) + 128;  // 62592
    const int SM_128_128_1 = 1024 + NST * (8192 + 8192) + 128;      // 50304
    cudaFuncSetAttribute(gemm6<128,128,2>, cudaFuncAttributeMaxDynamicSharedMemorySize, SM_128_128_2);
    cudaFuncSetAttribute(gemm6<64,128,2>,  cudaFuncAttributeMaxDynamicSharedMemorySize, SM_64_128_2);
    cudaFuncSetAttribute(gemm6<128,64,2>,  cudaFuncAttributeMaxDynamicSharedMemorySize, SM_128_64_2);
    cudaFuncSetAttribute(gemm6<128,128,1>, cudaFuncAttributeMaxDynamicSharedMemorySize, SM_128_128_1);

    float* X    = fa + F_X;
    float* S    = fa + F_S;
    float* QKVf = fa + F_QKV;
    float* H2A  = fa + F_H2A;
    float* Yb   = fa + F_YB;
    float* BQKV = fa + F_BQKV;

    BF* UINh = bf + BA_U;   BF* UINl = UINh + EU;
    BF* ATTh = bf + BA_AT;  BF* ATTl = ATTh + EAT;
    BF* HBh  = bf + BA_HB;  BF* HBl  = HBh + EHB;
    BF* FBh  = bf + BA_FB;
    BF* YTh  = bf + BA_YT;  BF* YTl  = YTh + EYT;

    EncFn enc = get_enc();
    CUtensorMap mUIN = mkmap(enc, UINh, 512, 2816, EU, 128);
    CUtensorMap mATT = mkmap(enc, ATTh, 512, 2688, EAT, 64);
    CUtensorMap mHB  = mkmap(enc, HBh,  512, 2560, EHB, 128);
    CUtensorMap mFB  = mkmap(enc, FBh, 2048, 2560, EFB, 128);
    CUtensorMap mYT  = mkmap(enc, YTh,  512, 2048, EYT, 64);
    CUtensorMap mOUT = mkmap(enc, bf + BW_OUT, 512, 1024, EOUT, 128);
    CUtensorMap mWQKV[Ln], mWO[Ln], mW1[Ln], mW2[Ln];
    for (int l = 0; l < Ln; l++) {
        mWQKV[l] = mkmap(enc, bf + BW_QKV + (size_t)l * 2 * EQKV, 512, 1536, EQKV, 128);
        mWO[l]   = mkmap(enc, bf + BW_O   + (size_t)l * 2 * EQ,   512,  512, EQ, 128);
        mW1[l]   = mkmap(enc, bf + BW_1   + (size_t)l * 2 * EW1,  512, 2048, EW1, 64);
        mW2[l]   = mkmap(enc, bf + BW_2   + (size_t)l * 2 * EW1, 2048,  512, EW1, 128);
    }

    // ---- per-replay preprocessing ----
    gemm_tc<<<dim3(1, 65), 256>>>(input, w_in, nullptr, X, 8320, 128, 80, 0);
    initS_k<<<dim3(SN, Bn), Dm_>>>(X, S);
    mems0_k<<<dim3(15, Bn), Dm_>>>(S, UINh, UINl);

    wconv_k<<<dim3(16, 16, 8), 256>>>(wq, bf + BW_QKV, 512, 512, EQ, 2 * EQKV);
    wconv_k<<<dim3(16, 16, 8), 256>>>(wk, bf + BW_QKV + 262144, 512, 512, EQ, 2 * EQKV);
    wconv_k<<<dim3(16, 16, 8), 256>>>(wv, bf + BW_QKV + 524288, 512, 512, EQ, 2 * EQKV);
    wconv_k<<<dim3(16, 16, 8), 256>>>(wo, bf + BW_O, 512, 512, EQ, 2 * EQ);
    wconv_k<<<dim3(64, 16, 8), 256>>>(w1, bf + BW_1, 512, 2048, EW1, 2 * EW1);
    wconv_k<<<dim3(16, 64, 8), 256>>>(w2, bf + BW_2, 2048, 512, EW1, 2 * EW1);
    wconv_k<<<dim3(32, 16, 1), 256>>>(w_out, bf + BW_OUT, 512, 1024, 0, 0);
    prep_k<<<48, 256>>>(bq, bk, bv, BQKV, UINh, UINl);

    // layer-0 LN1: S -> UIN state planes (rows 120..2679)
    ln_row_k<<<SN * Bn / 8, 256>>>(S, ln_in_g, ln_in_b, nullptr,
                                   UINh + 120 * 512, UINl + 120 * 512, Dm_);

    for (int l = 0; l < Ln; l++) {
        summary_pl_k<<<dim3(NSEG, Bn), Dm_>>>(UINh, UINl);

        gemm6<128,128,2><<<dim3(12, 22, 1), 256, SM_128_128_2>>>(
            mUIN, mWQKV[l], BQKV + l * 1536, QKVf, 0, nullptr, nullptr,
            1536, 512, 0, 0);

        attn_k<<<dim3(QN / 4, Bn), 256>>>(QKVf, lengths, ATTh, ATTl);

        gemm6<64,128,2><<<dim3(4, 42, 1), 256, SM_64_128_2>>>(
            mATT, mWO[l], bo + l * Dm_, S, 0, UINh, UINl, 512, 512, 0, 2);

        ln_row_k<<<SN * Bn / 8, 256>>>(S, ff_g + l * Dm_, ff_b + l * Dm_,
                                       nullptr, HBh, HBl, Dm_);
        // FFN1: hi plane only out (FFN2 is single-pass)
        gemm6<128,64,2><<<dim3(32, 20, 1), 256, SM_128_64_2>>>(
            mHB, mW1[l], b1 + l * FFNn, nullptr, 0, FBh, nullptr,
            2048, 512, 1, 1);
        // FFN2 single-pass fp16, split-K=3 (704 per chunk; TMA zero-fills K>=2048)
        gemm6<128,128,1><<<dim3(4, 20, 3), 256, SM_128_128_1>>>(
            mFB, mW2[l], b2 + l * Dm_, H2A, 1310720, nullptr, nullptr,
            512, 704, 0, 0);

        const float* g2 = (l + 1 < Ln) ? (ln_in_g + (l + 1) * Dm_) : nullptr;
        const float* b2n = (l + 1 < Ln) ? (ln_in_b + (l + 1) * Dm_) : nullptr;
        ln2_k<<<SN * Bn / 8, 256>>>(S, H2A, H2A + 1310720, H2A + 2621440,
                                    lo_g + l * Dm_, lo_b + l * Dm_, g2, b2n,
                                    S, UINh + 120 * 512, UINl + 120 * 512);
    }

    transpose_pl_k<<<2048, Dm_>>>(S, YTh, YTl);
    gemm6<64,128,2><<<dim3(8, 32, 1), 256, SM_64_128_2>>>(
        mYT, mOUT, b_out, Yb, 0, nullptr, nullptr, 1024, 512, 0, 0);
    ln_row_k<<<2048 / 8, 256>>>(Yb, lng, lnb, out, nullptr, nullptr, OUTn);

    if (out_size >= 2048 * 1024 + Bn)
        lr_k<<<1, 32>>>(lengths, out + 2048 * 1024);
}

// round 13
// speedup vs baseline: 8.0027x; 1.1180x over previous
#include <cuda_runtime.h>
#include <cuda_fp16.h>
#include <cuda.h>
#include <math.h>
#include <stdint.h>

typedef __half BF;
typedef __half2 BF2;

// ---------------- constants ----------------
#define Bn   8
#define Dm_  512
#define FFNn 2048
#define Ln   8
#define OUTn 1024
#define Hn   8
#define DHn  64
#define QN   336
#define SN   320
#define RTn  64
#define Un   256
#define NSEG 16

// token space: 0..14 mems | 15..78 rc | 79..334 utt | 335..350 summary | 351 pad
// row = token*8 + b;  M_UIN = 2816

// ------- float arena -------
#define F_X    0UL
#define F_S    (F_X + 1064960UL)
#define F_QKV  (F_S + 1310720UL)
#define F_H2A  (F_QKV + 4325376UL)
#define F_H2B  (F_H2A + 1310720UL)
#define F_H2C  (F_H2B + 1310720UL)
#define F_YB   (F_H2C + 1310720UL)
#define F_BQKV (F_YB + 2097152UL)
#define F_TOT  (F_BQKV + 12288UL)
__device__ __align__(1024) float g_arena[F_TOT];

// ------- fp16 arena ----
#define EQ    262144UL
#define EQKV  786432UL     // 1536*512
#define EW1   1048576UL
#define EOUT  524288UL
#define EU    1441792UL    // 2816*512
#define EAT   1376256UL    // 2688*512
#define EHB   1310720UL    // 2560*512
#define EFB   5242880UL    // 2560*2048
#define EYT   1048576UL    // 2048*512

#define BW_QKV 0UL
#define BW_O   (BW_QKV + 8UL*2UL*EQKV)
#define BW_1   (BW_O   + 8UL*2UL*EQ)
#define BW_2   (BW_1   + 8UL*2UL*EW1)
#define BW_OUT (BW_2   + 8UL*2UL*EW1)
#define BA_U   (BW_OUT + 2UL*EOUT)
#define BA_AT  (BA_U   + 2UL*EU)
#define BA_HB  (BA_AT  + 2UL*EAT)
#define BA_FB  (BA_HB  + 2UL*EHB)
#define BA_YT  (BA_FB  + 2UL*EFB)
#define B_TOT  (BA_YT  + 2UL*EYT)
__device__ __align__(1024) BF g_bf[B_TOT];

__device__ __forceinline__ void split2(float x, BF& h, BF& l) {
    h = __float2half(x);
    l = __float2half(x - __half2float(h));
}
__device__ __forceinline__ BF2 mk2(BF a, BF b) { return __halves2half2(a, b); }

// ============ TMA / mbarrier primitives ============
__device__ __forceinline__ uint32_t smem_u32(const void* p) {
    return (uint32_t)__cvta_generic_to_shared(p);
}
__device__ __forceinline__ void mbar_init(uint32_t a, uint32_t cnt) {
    asm volatile("mbarrier.init.shared::cta.b64 [%0], %1;" :: "r"(a), "r"(cnt) : "memory");
}
__device__ __forceinline__ void mbar_expect(uint32_t a, uint32_t tx) {
    asm volatile("mbarrier.arrive.expect_tx.shared::cta.b64 _, [%0], %1;"
                 :: "r"(a), "r"(tx) : "memory");
}
__device__ __forceinline__ void mbar_arrive(uint32_t a) {
    asm volatile("mbarrier.arrive.shared::cta.b64 _, [%0];" :: "r"(a) : "memory");
}
__device__ __forceinline__ void mbar_wait(uint32_t a, uint32_t ph) {
    uint32_t done = 0;
    while (!done) {
        asm volatile(
            "{\n\t.reg .pred p;\n\t"
            "mbarrier.try_wait.parity.acquire.cta.shared::cta.b64 p, [%1], %2, 0x989680;\n\t"
            "selp.b32 %0, 1, 0, p;\n\t}"
            : "=r"(done) : "r"(a), "r"(ph) : "memory");
    }
}
__device__ __forceinline__ void tma3d(uint32_t dst, const void* map,
                                      int cx, int cy, int cz, uint32_t mbar) {
    asm volatile(
        "cp.async.bulk.tensor.3d.shared::cta.global.tile.mbarrier::complete_tx::bytes "
        "[%0], [%1, {%2, %3, %4}], [%5];"
        :: "r"(dst), "l"(map), "r"(cx), "r"(cy), "r"(cz), "r"(mbar) : "memory");
}
__device__ __forceinline__ void mma2(float c[4], const uint32_t a[4],
                                     uint32_t b0, uint32_t b1) {
    asm volatile(
        "mma.sync.aligned.m16n8k16.row.col.f32.f16.f16.f32 "
        "{%0,%1,%2,%3}, {%4,%5,%6,%7}, {%8,%9}, {%0,%1,%2,%3};\n"
        : "+f"(c[0]), "+f"(c[1]), "+f"(c[2]), "+f"(c[3])
        : "r"(a[0]), "r"(a[1]), "r"(a[2]), "r"(a[3]), "r"(b0), "r"(b1));
}
#define LDSM4(r, a) \
    asm volatile("ldmatrix.sync.aligned.m8n8.x4.shared.b16 {%0,%1,%2,%3}, [%4];" \
        : "=r"((r)[0]), "=r"((r)[1]), "=r"((r)[2]), "=r"((r)[3]) : "r"(a))

// ============ TMA-staged mma.sync GEMM (SW64, 32-K stages, fp16) ============
// C = act(A @ B^T + bias). A: hi (+lo if AP==2) fp16 planes; B: hi plane.
// grid (N/NT, M/MT, splitZ). TMA zero-fills OOB K.
// mode 0: fp32 Cf (+ z*czstride). mode 1: fp16 planes Ch (+Cl if non-null).
// mode 2: fused O epilogue: rows<2560 S+=v; rows 2560..2679 planes=tanh(v).
#define NST 3

template <int MT, int NT, int AP>
__global__ __launch_bounds__(256, 2) void gemm6(
    const __grid_constant__ CUtensorMap tmA,
    const __grid_constant__ CUtensorMap tmB,
    const float* __restrict__ bias, float* __restrict__ Cf, long czstride,
    BF* __restrict__ Ch, BF* __restrict__ Cl,
    int N, int K, int act, int mode)
{
    constexpr int MSPAN = MT / 4;
    constexpr int MTM   = MSPAN / 16;
    constexpr int NSPAN = NT / 2;
    constexpr int NNT   = NSPAN / 8;
    constexpr int APL   = MT * 64;
    constexpr int BPL   = NT * 64;
    constexpr int STB   = AP * APL + BPL;
    extern __shared__ __align__(16) char smx[];
    const uint32_t sb = smem_u32(smx);
    const uint32_t db = (sb + 1023) & ~1023u;
    const int tid = threadIdx.x, lane = tid & 31, wid = tid >> 5;
    const int wm = wid & 3, wn = wid >> 2;
    const int grp = lane >> 2, tig = lane & 3;
    const int row0 = blockIdx.y * MT, col0 = blockIdx.x * NT;
    const int kstart = blockIdx.z * K;
    if (Cf && mode == 0) Cf += (long)blockIdx.z * czstride;
    const float* bi = (bias && kstart == 0) ? bias : nullptr;
    const int T = K >> 5;

    const uint32_t barb = db + NST * STB;
    if (tid == 0) {
        for (int s = 0; s < NST; s++) {
            mbar_init(barb + s * 8, 1);
            mbar_init(barb + 64 + s * 8, 256);
        }
    }
    __syncthreads();

    if (tid == 0) {
        for (int s = 0; s < NST; s++) {
            uint32_t st = db + s * STB, fb = barb + s * 8;
            mbar_expect(fb, STB);
            tma3d(st, &tmA, kstart + s * 32, row0, 0, fb);
            if (AP == 2) tma3d(st + APL, &tmA, kstart + s * 32, row0, 1, fb);
            tma3d(st + AP * APL, &tmB, kstart + s * 32, col0, 0, fb);
        }
    }

    float acc[MTM][NNT][4] = {};
    const int lrow = (lane & 7) + (((lane >> 3) & 1) << 3);
    const int kofs = ((lane >> 4) & 1) * 8;
    const uint32_t msk = (uint32_t)((lrow >> 1) & 3) << 4;
    uint32_t arow_off[MTM], brow_off[NNT / 2];
#pragma unroll
    for (int mt = 0; mt < MTM; mt++)
        arow_off[mt] = (uint32_t)(wm * MSPAN + mt * 16 + lrow) * 64;
#pragma unroll
    for (int p = 0; p < NNT / 2; p++)
        brow_off[p] = (uint32_t)(wn * NSPAN + p * 16 + lrow) * 64;

    uint32_t pfm = 0, pem = 0;
    for (int i = 0; i < T; i++) {
        const int bslot = i % NST;
        const uint32_t fb = barb + bslot * 8, eb = barb + 64 + bslot * 8;
        mbar_wait(fb, (pfm >> bslot) & 1); pfm ^= (1u << bslot);
        const uint32_t sA = db + bslot * STB, sB = sA + AP * APL;
#pragma unroll
        for (int kk = 0; kk < 32; kk += 16) {
            const uint32_t csw = ((uint32_t)((kk + kofs) * 2)) ^ msk;
            uint32_t ah[MTM][4], al_[MTM][4], bh[NNT / 2][4];
#pragma unroll
            for (int mt = 0; mt < MTM; mt++) {
                uint32_t ad = sA + arow_off[mt] + csw;
                LDSM4(ah[mt], ad);
                if (AP == 2) LDSM4(al_[mt], ad + APL);
            }
#pragma unroll
            for (int p = 0; p < NNT / 2; p++) {
                LDSM4(bh[p], sB + brow_off[p] + csw);
            }
#pragma unroll
            for (int nt = 0; nt < NNT; nt++) {
                const int p = nt >> 1, s1 = nt & 1;
#pragma unroll
                for (int mt = 0; mt < MTM; mt++) {
                    mma2(acc[mt][nt], ah[mt], bh[p][s1], bh[p][2 + s1]);
                    if (AP == 2)
                        mma2(acc[mt][nt], al_[mt], bh[p][s1], bh[p][2 + s1]);
                }
            }
        }
        mbar_arrive(eb);
        if (tid == 0 && i + NST < T) {
            mbar_wait(eb, (pem >> bslot) & 1); pem ^= (1u << bslot);
            uint32_t st = db + bslot * STB;
            mbar_expect(fb, STB);
            int k0 = kstart + (i + NST) * 32;
            tma3d(st, &tmA, k0, row0, 0, fb);
            if (AP == 2) tma3d(st + APL, &tmA, k0, row0, 1, fb);
            tma3d(st + AP * APL, &tmB, k0, col0, 0, fb);
        }
    }

#pragma unroll
    for (int mt = 0; mt < MTM; mt++) {
        const long r = row0 + wm * MSPAN + mt * 16 + grp;
#pragma unroll
        for (int nt = 0; nt < NNT; nt++) {
            const long c = col0 + wn * NSPAN + nt * 8 + tig * 2;
            float bb0 = bi ? bi[c] : 0.f, bb1 = bi ? bi[c + 1] : 0.f;
            float v0 = acc[mt][nt][0] + bb0, v1 = acc[mt][nt][1] + bb1;
            float v2 = acc[mt][nt][2] + bb0, v3 = acc[mt][nt][3] + bb1;
            if (act) {
                v0 = fmaxf(v0, 0.f); v1 = fmaxf(v1, 0.f);
                v2 = fmaxf(v2, 0.f); v3 = fmaxf(v3, 0.f);
            }
            if (mode == 0) {
                *(float2*)&Cf[r * N + c]       = make_float2(v0, v1);
                *(float2*)&Cf[(r + 8) * N + c] = make_float2(v2, v3);
            } else if (mode == 1) {
                BF h0, l0, h1, l1;
                split2(v0, h0, l0); split2(v1, h1, l1);
                *(BF2*)&Ch[r * N + c] = mk2(h0, h1);
                if (Cl) *(BF2*)&Cl[r * N + c] = mk2(l0, l1);
                split2(v2, h0, l0); split2(v3, h1, l1);
                *(BF2*)&Ch[(r + 8) * N + c] = mk2(h0, h1);
                if (Cl) *(BF2*)&Cl[(r + 8) * N + c] = mk2(l0, l1);
            } else {
#pragma unroll
                for (int rr = 0; rr < 2; rr++) {
                    long r2 = r + rr * 8;
                    float u0 = rr ? v2 : v0, u1 = rr ? v3 : v1;
                    if (r2 < 2560) {
                        float2 s = *(float2*)&Cf[r2 * 512 + c];
                        *(float2*)&Cf[r2 * 512 + c] = make_float2(s.x + u0, s.y + u1);
                    } else if (r2 < 2680) {
                        float t0 = tanhf(u0), t1 = tanhf(u1);
                        BF h0, l0, h1, l1;
                        split2(t0, h0, l0); split2(t1, h1, l1);
                        long o = (r2 - 2560) * 512 + c;
                        *(BF2*)&Ch[o] = mk2(h0, h1);
                        *(BF2*)&Cl[o] = mk2(l0, l1);
                    }
                }
            }
        }
    }
}

// ---------------- legacy in-kernel-convert GEMM (input proj, K=80) ---------
#define LLDA 40
__global__ __launch_bounds__(256) void gemm_tc(
    const float* __restrict__ A, const float* __restrict__ W,
    const float* __restrict__ bias, float* __restrict__ C,
    int M, int N, int K, int act)
{
    __shared__ BF Ahs[128 * LLDA], Als[128 * LLDA];
    __shared__ BF Bhs[128 * LLDA];
    const int tid = threadIdx.x, lane = tid & 31, wid = tid >> 5;
    const int wm = wid & 3, wn = wid >> 2;
    const int grp = lane >> 2, tig = lane & 3;
    const long row0 = (long)blockIdx.y * 128;
    const int  col0 = blockIdx.x * 128;
    float acc[2][8][4] = {};
    const int arow = tid >> 1, acol0 = (tid & 1) * 16;
    const int brow = tid >> 3, bcol0 = (tid & 7) * 16;

    for (int k0 = 0; k0 < K; k0 += 32) {
#pragma unroll
        for (int j = 0; j < 4; j++) {
            int c = acol0 + j * 4;
            float4 v = make_float4(0.f, 0.f, 0.f, 0.f);
            if (row0 + arow < M && k0 + c < K)
                v = *(const float4*)&A[(row0 + arow) * (long)K + k0 + c];
            BF h, l; int o = arow * LLDA + c;
            split2(v.x, h, l); Ahs[o]     = h; Als[o]     = l;
            split2(v.y, h, l); Ahs[o + 1] = h; Als[o + 1] = l;
            split2(v.z, h, l); Ahs[o + 2] = h; Als[o + 2] = l;
            split2(v.w, h, l); Ahs[o + 3] = h; Als[o + 3] = l;
        }
#pragma unroll
        for (int j = 0; j < 4; j++) {
            int n = bcol0 + j * 4;
            float4 v = make_float4(0.f, 0.f, 0.f, 0.f);
            if (k0 + brow < K)
                v = *(const float4*)&W[(long)(k0 + brow) * N + col0 + n];
            Bhs[(n + 0) * LLDA + brow] = __float2half(v.x);
            Bhs[(n + 1) * LLDA + brow] = __float2half(v.y);
            Bhs[(n + 2) * LLDA + brow] = __float2half(v.z);
            Bhs[(n + 3) * LLDA + brow] = __float2half(v.w);
        }
        __syncthreads();
#pragma unroll
        for (int kk = 0; kk < 32; kk += 16) {
            uint32_t ah[2][4], al[2][4];
#pragma unroll
            for (int mt = 0; mt < 2; mt++) {
                int r = wm * 32 + mt * 16;
                int o  = (r + grp) * LLDA + kk + tig * 2;
                int o8 = o + 8 * LLDA;
                ah[mt][0] = *(const uint32_t*)&Ahs[o];
                ah[mt][1] = *(const uint32_t*)&Ahs[o8];
                ah[mt][2] = *(const uint32_t*)&Ahs[o + 8];
                ah[mt][3] = *(const uint32_t*)&Ahs[o8 + 8];
                al[mt][0] = *(const uint32_t*)&Als[o];
                al[mt][1] = *(const uint32_t*)&Als[o8];
                al[mt][2] = *(const uint32_t*)&Als[o + 8];
                al[mt][3] = *(const uint32_t*)&Als[o8 + 8];
            }
#pragma unroll
            for (int nt = 0; nt < 8; nt++) {
                int nn = wn * 64 + nt * 8 + grp;
                int o = nn * LLDA + kk + tig * 2;
                uint32_t b0 = *(const uint32_t*)&Bhs[o], b1 = *(const uint32_t*)&Bhs[o + 8];
#pragma unroll
                for (int mt = 0; mt < 2; mt++) {
                    mma2(acc[mt][nt], ah[mt], b0, b1);
                    mma2(acc[mt][nt], al[mt], b0, b1);
                }
            }
        }
        __syncthreads();
    }
#pragma unroll
    for (int mt = 0; mt < 2; mt++) {
#pragma unroll
        for (int nt = 0; nt < 8; nt++) {
            int c = col0 + wn * 64 + nt * 8 + tig * 2;
            float b0 = bias ? bias[c] : 0.f;
            float b1 = bias ? bias[c + 1] : 0.f;
            long r = row0 + wm * 32 + mt * 16 + grp;
            float v0 = acc[mt][nt][0] + b0, v1 = acc[mt][nt][1] + b1;
            float v2 = acc[mt][nt][2] + b0, v3 = acc[mt][nt][3] + b1;
            if (act) { v0=fmaxf(v0,0.f); v1=fmaxf(v1,0.f); v2=fmaxf(v2,0.f); v3=fmaxf(v3,0.f); }
            if (r < M)     *(float2*)&C[r * N + c]       = make_float2(v0, v1);
            if (r + 8 < M) *(float2*)&C[(r + 8) * N + c] = make_float2(v2, v3);
        }
    }
}

// ------- weight transpose+convert: out[n][k] = fp16(W[k][n]) ----
__global__ __launch_bounds__(256) void wconv_k(
    const float* __restrict__ W, BF* __restrict__ oh,
    int K, int N, long inS, long outS)
{
    __shared__ float t[32][33];
    const float* w = W + (long)blockIdx.z * inS;
    BF* ph = oh + (long)blockIdx.z * outS;
    const int n0 = blockIdx.x * 32, k0 = blockIdx.y * 32;
    const int tx = threadIdx.x & 7, ty = threadIdx.x >> 3;
    float4 v = *(const float4*)&w[(long)(k0 + ty) * N + n0 + tx * 4];
    t[ty][tx * 4 + 0] = v.x; t[ty][tx * 4 + 1] = v.y;
    t[ty][tx * 4 + 2] = v.z; t[ty][tx * 4 + 3] = v.w;
    __syncthreads();
    float a0 = t[tx * 4 + 0][ty], a1 = t[tx * 4 + 1][ty];
    float a2 = t[tx * 4 + 2][ty], a3 = t[tx * 4 + 3][ty];
    long o = (long)(n0 + ty) * K + k0 + tx * 4;
    *(BF2*)&ph[o]     = mk2(__float2half(a0), __float2half(a1));
    *(BF2*)&ph[o + 2] = mk2(__float2half(a2), __float2half(a3));
}

// merged bias pack + UIN pad
__global__ void prep_k(const float* __restrict__ bq, const float* __restrict__ bk,
                       const float* __restrict__ bv, float* __restrict__ o,
                       BF* __restrict__ uh, BF* __restrict__ ul)
{
    int i = blockIdx.x * blockDim.x + threadIdx.x;
    if (i < 12288) {
        int l = i / 1536, j = i % 1536;
        float v;
        if (j < 512)       v = bq[l * 512 + j];
        else if (j < 1024) v = bk[l * 512 + j - 512];
        else               v = bv[l * 512 + j - 1024];
        o[i] = v;
    }
    if (i < 4096) {
        size_t p = 2808UL * 512UL + i;
        uh[p] = __float2half(0.f);
        ul[p] = __float2half(0.f);
    }
}

// ---------------- LayerNorm: warp per row (ol optional) ----------------
__global__ __launch_bounds__(256) void ln_row_k(
    const float* __restrict__ X, const float* __restrict__ g, const float* __restrict__ bta,
    float* __restrict__ outf, BF* __restrict__ oh, BF* __restrict__ ol, int D)
{
    const int wid = threadIdx.x >> 5, lane = threadIdx.x & 31;
    const int row = blockIdx.x * 8 + wid;
    const float4* x = (const float4*)(X + (long)row * D);
    const int cnt = D >> 7;
    float s = 0.f, s2 = 0.f;
    for (int i = 0; i < cnt; i++) {
        float4 a = x[lane + i * 32];
        s  += a.x + a.y + a.z + a.w;
        s2 += a.x * a.x + a.y * a.y + a.z * a.z + a.w * a.w;
    }
#pragma unroll
    for (int o = 16; o; o >>= 1) {
        s  += __shfl_xor_sync(~0u, s, o);
        s2 += __shfl_xor_sync(~0u, s2, o);
    }
    const float mean = s / D;
    const float inv = rsqrtf(s2 / D - mean * mean + 1e-5f);
    const float4* gg = (const float4*)g;
    const float4* bb = (const float4*)bta;
    for (int i = 0; i < cnt; i++) {
        int idx = lane + i * 32;
        float4 a = x[idx], gv = gg[idx], bv = bb[idx], o;
        o.x = (a.x - mean) * inv * gv.x + bv.x;
        o.y = (a.y - mean) * inv * gv.y + bv.y;
        o.z = (a.z - mean) * inv * gv.z + bv.z;
        o.w = (a.w - mean) * inv * gv.w + bv.w;
        if (outf) ((float4*)(outf + (long)row * D))[idx] = o;
        if (oh) {
            BF h0,l0,h1,l1,h2,l2,h3,l3;
            split2(o.x,h0,l0); split2(o.y,h1,l1);
            split2(o.z,h2,l2); split2(o.w,h3,l3);
            long base = (long)row * D + idx * 4;
            *(BF2*)&oh[base]     = mk2(h0,h1);
            *(BF2*)&oh[base + 2] = mk2(h2,h3);
            if (ol) {
                *(BF2*)&ol[base]     = mk2(l0,l1);
                *(BF2*)&ol[base + 2] = mk2(l2,l3);
            }
        }
    }
}

// -------- double LN: res=S+HA+HB+HC; S=LN1(res); planes=LN2(S) ------------
__global__ __launch_bounds__(256) void ln2_k(
    const float* __restrict__ S, const float* __restrict__ HA,
    const float* __restrict__ HB_, const float* __restrict__ HC,
    const float* __restrict__ g1, const float* __restrict__ be1,
    const float* __restrict__ g2, const float* __restrict__ be2,
    float* __restrict__ Sout, BF* __restrict__ oh, BF* __restrict__ ol)
{
    const int wid = threadIdx.x >> 5, lane = threadIdx.x & 31;
    const int row = blockIdx.x * 8 + wid;   // 0..2559
    const float4* xs = (const float4*)(S   + (long)row * 512);
    const float4* xa = (const float4*)(HA  + (long)row * 512);
    const float4* xb = (const float4*)(HB_ + (long)row * 512);
    const float4* xc = (const float4*)(HC  + (long)row * 512);
    float4 R[4];
    float s = 0.f, s2 = 0.f;
#pragma unroll
    for (int i = 0; i < 4; i++) {
        int idx = lane + i * 32;
        float4 a = xs[idx], c = xa[idx], d = xb[idx], e = xc[idx];
        a.x += c.x + d.x + e.x; a.y += c.y + d.y + e.y;
        a.z += c.z + d.z + e.z; a.w += c.w + d.w + e.w;
        R[i] = a;
        s  += a.x + a.y + a.z + a.w;
        s2 += a.x * a.x + a.y * a.y + a.z * a.z + a.w * a.w;
    }
#pragma unroll
    for (int o = 16; o; o >>= 1) {
        s  += __shfl_xor_sync(~0u, s, o);
        s2 += __shfl_xor_sync(~0u, s2, o);
    }
    float mean = s * (1.f / 512.f);
    float inv = rsqrtf(s2 * (1.f / 512.f) - mean * mean + 1e-5f);
    const float4* g1v = (const float4*)g1; const float4* b1v = (const float4*)be1;
    float t = 0.f, t2 = 0.f;
#pragma unroll
    for (int i = 0; i < 4; i++) {
        int idx = lane + i * 32;
        float4 gv = g1v[idx], bv = b1v[idx], y;
        y.x = (R[i].x - mean) * inv * gv.x + bv.x;
        y.y = (R[i].y - mean) * inv * gv.y + bv.y;
        y.z = (R[i].z - mean) * inv * gv.z + bv.z;
        y.w = (R[i].w - mean) * inv * gv.w + bv.w;
        R[i] = y;
        ((float4*)(Sout + (long)row * 512))[idx] = y;
        t  += y.x + y.y + y.z + y.w;
        t2 += y.x * y.x + y.y * y.y + y.z * y.z + y.w * y.w;
    }
    if (!g2) return;
#pragma unroll
    for (int o = 16; o; o >>= 1) {
        t  += __shfl_xor_sync(~0u, t, o);
        t2 += __shfl_xor_sync(~0u, t2, o);
    }
    float mean2 = t * (1.f / 512.f);
    float inv2 = rsqrtf(t2 * (1.f / 512.f) - mean2 * mean2 + 1e-5f);
    const float4* g2v = (const float4*)g2; const float4* b2v = (const float4*)be2;
#pragma unroll
    for (int i = 0; i < 4; i++) {
        int idx = lane + i * 32;
        float4 gv = g2v[idx], bv = b2v[idx], z;
        z.x = (R[i].x - mean2) * inv2 * gv.x + bv.x;
        z.y = (R[i].y - mean2) * inv2 * gv.y + bv.y;
        z.z = (R[i].z - mean2) * inv2 * gv.z + bv.z;
        z.w = (R[i].w - mean2) * inv2 * gv.w + bv.w;
        BF h0,l0,h1,l1,h2,l2,h3,l3;
        split2(z.x,h0,l0); split2(z.y,h1,l1);
        split2(z.z,h2,l2); split2(z.w,h3,l3);
        long base = (long)row * 512 + idx * 4;
        *(BF2*)&oh[base]     = mk2(h0,h1);
        *(BF2*)&oh[base + 2] = mk2(h2,h3);
        *(BF2*)&ol[base]     = mk2(l0,l1);
        *(BF2*)&ol[base + 2] = mk2(l2,l3);
    }
}

// ---------------- misc ----------------
__global__ void initS_k(const float* __restrict__ X, float* __restrict__ S)
{
    const int t = blockIdx.x, b = blockIdx.y, d = threadIdx.x;
    int frame;
    if (t < RTn) {
        int si = t >> 2;
        int st = (si == 15) ? 256 : (si + 1) * 16;
        frame = st + (t & 3);
    } else frame = t - RTn;
    S[((size_t)t * Bn + b) * Dm_ + d] = X[(size_t)b * 133120 + (size_t)frame * Dm_ + d];
}

__global__ void mems0_k(const float* __restrict__ S, BF* __restrict__ uh,
                        BF* __restrict__ ul)
{
    const int s = blockIdx.x, b = blockIdx.y, d = threadIdx.x;
    size_t base = ((size_t)(RTn + s * 16) * Bn + b) * Dm_ + d;
    float acc = 0.f;
#pragma unroll
    for (int k = 0; k < 16; k++) acc += S[base + (size_t)k * Bn * Dm_];
    acc *= (1.f / 16.f);
    BF h, l; split2(acc, h, l);
    size_t o = ((size_t)s * Bn + b) * Dm_ + d;
    uh[o] = h; ul[o] = l;
}

__global__ void summary_pl_k(BF* __restrict__ uh, BF* __restrict__ ul)
{
    const int s = blockIdx.x, b = blockIdx.y, d = threadIdx.x;
    size_t base = ((size_t)((79 + s * 16) * Bn) + b) * Dm_ + d;
    float acc = 0.f;
#pragma unroll
    for (int k = 0; k < 16; k++) {
        size_t o = base + (size_t)k * Bn * Dm_;
        acc += __half2float(uh[o]) + __half2float(ul[o]);
    }
    acc *= (1.f / 16.f);
    BF h, l; split2(acc, h, l);
    size_t o = ((size_t)((335 + s) * Bn) + b) * Dm_ + d;
    uh[o] = h; ul[o] = l;
}

// ---------------- attention: 4 queries per CTA (hi plane out only) ---------
__global__ __launch_bounds__(256) void attn_k(
    const float* __restrict__ QKV, const int* __restrict__ lengths,
    BF* __restrict__ Ah)
{
    __shared__ float sc[Hn][64];
    __shared__ short ki[Hn][64];
    const int b = blockIdx.y;
    const int h = threadIdx.x >> 5, lane = threadIdx.x & 31;

    int maxlr = 0;
#pragma unroll
    for (int i = 0; i < Bn; i++) maxlr = max(maxlr, lengths[i] >> 2);
    const int lrb = lengths[b] >> 2;
    const int g = lane >> 3, e = lane & 7;
    const float* Kb = QKV + (size_t)b * 1536 + 512 + h * DHn;
    const float* Vb = Kb + 512;

    for (int qq = 0; qq < 4; qq++) {
        const int qi = blockIdx.x * 4 + qq;
        int seg; bool summ = false;
        if (qi < RTn)      seg = qi >> 2;
        else if (qi < SN)  seg = (qi - RTn) >> 4;
        else             { seg = qi - SN; summ = true; }
        const int ms  = max(seg - 4, 0);
        const int ss  = max(seg * 16 - 32, 0);
        const int se  = min(seg * 16 + 16, Un);
        const int ue  = min(se, lrb + 256 - maxlr);
        const int rcs = 15 + seg * 4;

        const int c0 = summ ? 0 : (seg - ms);
        const int c2 = max(ue - ss, 0);
        const int n  = c0 + 4 + c2;

        for (int j = lane; j < n; j += 32) {
            int k;
            if (j < c0)          k = ms + j;
            else if (j < c0 + 4) k = rcs + (j - c0);
            else                 k = 79 + ss + (j - c0 - 4);
            ki[h][j] = (short)k;
        }
        __syncwarp();

        const float4* qv = (const float4*)(QKV + ((size_t)(15 + qi) * Bn + b) * 1536 + h * DHn);
        float4 q0 = qv[e * 2], q1 = qv[e * 2 + 1];
        q0.x *= 0.125f; q0.y *= 0.125f; q0.z *= 0.125f; q0.w *= 0.125f;
        q1.x *= 0.125f; q1.y *= 0.125f; q1.z *= 0.125f; q1.w *= 0.125f;

        for (int j0 = 0; j0 < n; j0 += 4) {
            int j = j0 + g;
            float p = 0.f;
            if (j < n) {
                const float4* kp = (const float4*)(Kb + (size_t)ki[h][j] * (Bn * 1536));
                float4 k0 = kp[e * 2], k1 = kp[e * 2 + 1];
                p = q0.x * k0.x + q0.y * k0.y + q0.z * k0.z + q0.w * k0.w
                  + q1.x * k1.x + q1.y * k1.y + q1.z * k1.z + q1.w * k1.w;
            }
            p += __shfl_xor_sync(~0u, p, 4);
            p += __shfl_xor_sync(~0u, p, 2);
            p += __shfl_xor_sync(~0u, p, 1);
            if (e == 0 && j < n) sc[h][j] = p;
        }
        __syncwarp();

        float m = -3.4e38f;
        for (int j = lane; j < n; j += 32) m = fmaxf(m, sc[h][j]);
#pragma unroll
        for (int o = 16; o; o >>= 1) m = fmaxf(m, __shfl_xor_sync(~0u, m, o));
        float sum = 0.f;
        for (int j = lane; j < n; j += 32) {
            float e2 = expf(sc[h][j] - m);
            sc[h][j] = e2;
            sum += e2;
        }
#pragma unroll
        for (int o = 16; o; o >>= 1) sum += __shfl_xor_sync(~0u, sum, o);
        __syncwarp();
        const float inv = 1.f / sum;

        float a0 = 0.f, a1 = 0.f;
        for (int j = 0; j < n; j++) {
            float p = sc[h][j];
            const float2 vp = *(const float2*)(Vb + (size_t)ki[h][j] * (Bn * 1536) + 2 * lane);
            a0 = fmaf(p, vp.x, a0);
            a1 = fmaf(p, vp.y, a1);
        }
        a0 *= inv; a1 *= inv;
        size_t op = ((size_t)qi * Bn + b) * Dm_ + h * DHn + 2 * lane;
        *(BF2*)&Ah[op] = mk2(__float2half(a0), __float2half(a1));
        __syncwarp();
    }
}

__global__ void transpose_pl_k(const float* __restrict__ S, BF* __restrict__ yh)
{
    const int r = blockIdx.x, d = threadIdx.x;
    const int b = r >> 8, u = r & 255;
    float v = S[((size_t)(RTn + u) * Bn + b) * Dm_ + d];
    yh[(size_t)r * Dm_ + d] = __float2half(v);
}

__global__ void lr_k(const int* __restrict__ lengths, float* __restrict__ out)
{
    int i = threadIdx.x;
    if (i < Bn) out[i] = (float)(lengths[i] >> 2);
}

// ---------------- host: tensormap plumbing ----------------
typedef CUresult (*EncFn)(CUtensorMap*, CUtensorMapDataType, cuuint32_t, void*,
                          const cuuint64_t*, const cuuint64_t*, const cuuint32_t*,
                          const cuuint32_t*, CUtensorMapInterleave, CUtensorMapSwizzle,
                          CUtensorMapL2promotion, CUtensorMapFloatOOBfill);

static EncFn get_enc() {
    void* p = nullptr;
    cudaDriverEntryPointQueryResult qr;
#if CUDART_VERSION >= 12050
    if (cudaGetDriverEntryPointByVersion("cuTensorMapEncodeTiled", &p, 12000,
                                         cudaEnableDefault, &qr) == cudaSuccess && p)
        return (EncFn)p;
    p = nullptr;
#endif
    cudaGetDriverEntryPoint("cuTensorMapEncodeTiled", &p, cudaEnableDefault, &qr);
    return (EncFn)p;
}

static CUtensorMap mkmap(EncFn enc, const BF* base, long K, long M, long planeStride,
                         unsigned boxM) {
    CUtensorMap m;
    cuuint64_t dims[3]    = {(cuuint64_t)K, (cuuint64_t)M, 2};
    cuuint64_t strides[2] = {(cuuint64_t)K * 2, (cuuint64_t)planeStride * 2};
    cuuint32_t box[3]     = {32, boxM, 1};
    cuuint32_t es[3]      = {1, 1, 1};
    enc(&m, CU_TENSOR_MAP_DATA_TYPE_FLOAT16, 3, (void*)base, dims, strides, box, es,
        CU_TENSOR_MAP_INTERLEAVE_NONE, CU_TENSOR_MAP_SWIZZLE_64B,
        CU_TENSOR_MAP_L2_PROMOTION_L2_128B, CU_TENSOR_MAP_FLOAT_OOB_FILL_NONE);
    return m;
}

// ---------------- launch ----------------
extern "C" void kernel_launch(void* const* d_in, const int* in_sizes, int n_in,
                              void* d_out, int out_size)
{
    const float* input   = (const float*)d_in[0];
    const int*   lengths = (const int*)  d_in[1];
    const float* w_in    = (const float*)d_in[2];
    const float* ln_in_g = (const float*)d_in[3];
    const float* ln_in_b = (const float*)d_in[4];
    const float* wq = (const float*)d_in[5];
    const float* bq = (const float*)d_in[6];
    const float* wk = (const float*)d_in[7];
    const float* bk = (const float*)d_in[8];
    const float* wv = (const float*)d_in[9];
    const float* bv = (const float*)d_in[10];
    const float* wo = (const float*)d_in[11];
    const float* bo = (const float*)d_in[12];
    const float* ff_g = (const float*)d_in[13];
    const float* ff_b = (const float*)d_in[14];
    const float* w1 = (const float*)d_in[15];
    const float* b1 = (const float*)d_in[16];
    const float* w2 = (const float*)d_in[17];
    const float* b2 = (const float*)d_in[18];
    const float* lo_g = (const float*)d_in[19];
    const float* lo_b = (const float*)d_in[20];
    const float* w_out = (const float*)d_in[21];
    const float* b_out = (const float*)d_in[22];
    const float* lng = (const float*)d_in[23];
    const float* lnb = (const float*)d_in[24];
    float* out = (float*)d_out;

    float* fa = nullptr; BF* bf = nullptr;
    cudaGetSymbolAddress((void**)&fa, g_arena);
    cudaGetSymbolAddress((void**)&bf, g_bf);

    const int SM_128_128_2 = 1024 + NST * (2 * 8192 + 8192) + 128;  // 74880
    const int SM_64_128_1  = 1024 + NST * (4096 + 8192) + 128;      // 38016
    const int SM_128_64_1  = 1024 + NST * (8192 + 4096) + 128;      // 38016
    const int SM_128_128_1 = 1024 + NST * (8192 + 8192) + 128;      // 50304
    cudaFuncSetAttribute(gemm6<128,128,2>, cudaFuncAttributeMaxDynamicSharedMemorySize, SM_128_128_2);
    cudaFuncSetAttribute(gemm6<64,128,1>,  cudaFuncAttributeMaxDynamicSharedMemorySize, SM_64_128_1);
    cudaFuncSetAttribute(gemm6<128,64,1>,  cudaFuncAttributeMaxDynamicSharedMemorySize, SM_128_64_1);
    cudaFuncSetAttribute(gemm6<128,128,1>, cudaFuncAttributeMaxDynamicSharedMemorySize, SM_128_128_1);

    float* X    = fa + F_X;
    float* S    = fa + F_S;
    float* QKVf = fa + F_QKV;
    float* H2A  = fa + F_H2A;
    float* Yb   = fa + F_YB;
    float* BQKV = fa + F_BQKV;

    BF* UINh = bf + BA_U;   BF* UINl = UINh + EU;
    BF* ATTh = bf + BA_AT;
    BF* HBh  = bf + BA_HB;
    BF* FBh  = bf + BA_FB;
    BF* YTh  = bf + BA_YT;

    EncFn enc = get_enc();
    CUtensorMap mUIN = mkmap(enc, UINh, 512, 2816, EU, 128);
    CUtensorMap mATT = mkmap(enc, ATTh, 512, 2688, EAT, 64);
    CUtensorMap mHB  = mkmap(enc, HBh,  512, 2560, EHB, 128);
    CUtensorMap mFB  = mkmap(enc, FBh, 2048, 2560, EFB, 128);
    CUtensorMap mYT  = mkmap(enc, YTh,  512, 2048, EYT, 64);
    CUtensorMap mOUT = mkmap(enc, bf + BW_OUT, 512, 1024, EOUT, 128);
    CUtensorMap mWQKV[Ln], mWO[Ln], mW1[Ln], mW2[Ln];
    for (int l = 0; l < Ln; l++) {
        mWQKV[l] = mkmap(enc, bf + BW_QKV + (size_t)l * 2 * EQKV, 512, 1536, EQKV, 128);
        mWO[l]   = mkmap(enc, bf + BW_O   + (size_t)l * 2 * EQ,   512,  512, EQ, 128);
        mW1[l]   = mkmap(enc, bf + BW_1   + (size_t)l * 2 * EW1,  512, 2048, EW1, 64);
        mW2[l]   = mkmap(enc, bf + BW_2   + (size_t)l * 2 * EW1, 2048,  512, EW1, 128);
    }

    // ---- per-replay preprocessing ----
    gemm_tc<<<dim3(1, 65), 256>>>(input, w_in, nullptr, X, 8320, 128, 80, 0);
    initS_k<<<dim3(SN, Bn), Dm_>>>(X, S);
    mems0_k<<<dim3(15, Bn), Dm_>>>(S, UINh, UINl);

    wconv_k<<<dim3(16, 16, 8), 256>>>(wq, bf + BW_QKV, 512, 512, EQ, 2 * EQKV);
    wconv_k<<<dim3(16, 16, 8), 256>>>(wk, bf + BW_QKV + 262144, 512, 512, EQ, 2 * EQKV);
    wconv_k<<<dim3(16, 16, 8), 256>>>(wv, bf + BW_QKV + 524288, 512, 512, EQ, 2 * EQKV);
    wconv_k<<<dim3(16, 16, 8), 256>>>(wo, bf + BW_O, 512, 512, EQ, 2 * EQ);
    wconv_k<<<dim3(64, 16, 8), 256>>>(w1, bf + BW_1, 512, 2048, EW1, 2 * EW1);
    wconv_k<<<dim3(16, 64, 8), 256>>>(w2, bf + BW_2, 2048, 512, EW1, 2 * EW1);
    wconv_k<<<dim3(32, 16, 1), 256>>>(w_out, bf + BW_OUT, 512, 1024, 0, 0);
    prep_k<<<48, 256>>>(bq, bk, bv, BQKV, UINh, UINl);

    // layer-0 LN1: S -> UIN state planes (rows 120..2679)
    ln_row_k<<<SN * Bn / 8, 256>>>(S, ln_in_g, ln_in_b, nullptr,
                                   UINh + 120 * 512, UINl + 120 * 512, Dm_);

    for (int l = 0; l < Ln; l++) {
        summary_pl_k<<<dim3(NSEG, Bn), Dm_>>>(UINh, UINl);

        gemm6<128,128,2><<<dim3(12, 22, 1), 256, SM_128_128_2>>>(
            mUIN, mWQKV[l], BQKV + l * 1536, QKVf, 0, nullptr, nullptr,
            1536, 512, 0, 0);

        attn_k<<<dim3(QN / 4, Bn), 256>>>(QKVf, lengths, ATTh);

        // O-proj single-pass; fused epilogue writes UIN mems planes (hi+lo)
        gemm6<64,128,1><<<dim3(4, 42, 1), 256, SM_64_128_1>>>(
            mATT, mWO[l], bo + l * Dm_, S, 0, UINh, UINl, 512, 512, 0, 2);

        ln_row_k<<<SN * Bn / 8, 256>>>(S, ff_g + l * Dm_, ff_b + l * Dm_,
                                       nullptr, HBh, nullptr, Dm_);
        // FFN1 single-pass, hi plane out
        gemm6<128,64,1><<<dim3(32, 20, 1), 256, SM_128_64_1>>>(
            mHB, mW1[l], b1 + l * FFNn, nullptr, 0, FBh, nullptr,
            2048, 512, 1, 1);
        // FFN2 single-pass, split-K=3 (704 per chunk; TMA zero-fills K>=2048)
        gemm6<128,128,1><<<dim3(4, 20, 3), 256, SM_128_128_1>>>(
            mFB, mW2[l], b2 + l * Dm_, H2A, 1310720, nullptr, nullptr,
            512, 704, 0, 0);

        const float* g2 = (l + 1 < Ln) ? (ln_in_g + (l + 1) * Dm_) : nullptr;
        const float* b2n = (l + 1 < Ln) ? (ln_in_b + (l + 1) * Dm_) : nullptr;
        ln2_k<<<SN * Bn / 8, 256>>>(S, H2A, H2A + 1310720, H2A + 2621440,
                                    lo_g + l * Dm_, lo_b + l * Dm_, g2, b2n,
                                    S, UINh + 120 * 512, UINl + 120 * 512);
    }

    transpose_pl_k<<<2048, Dm_>>>(S, YTh);
    gemm6<64,128,1><<<dim3(8, 32, 1), 256, SM_64_128_1>>>(
        mYT, mOUT, b_out, Yb, 0, nullptr, nullptr, 1024, 512, 0, 0);
    ln_row_k<<<2048 / 8, 256>>>(Yb, lng, lnb, out, nullptr, nullptr, OUTn);

    if (out_size >= 2048 * 1024 + Bn)
        lr_k<<<1, 32>>>(lengths, out + 2048 * 1024);
}

// round 14
// speedup vs baseline: 8.5725x; 1.0712x over previous
#include <cuda_runtime.h>
#include <cuda_fp16.h>
#include <cuda.h>
#include <math.h>
#include <stdint.h>

typedef __half BF;
typedef __half2 BF2;

// ---------------- constants ----------------
#define Bn   8
#define Dm_  512
#define FFNn 2048
#define Ln   8
#define OUTn 1024
#define Hn   8
#define DHn  64
#define QN   336
#define SN   320
#define RTn  64
#define Un   256
#define NSEG 16

// token space: 0..14 mems | 15..78 rc | 79..334 utt | 335..350 summary | 351 pad
// row = token*8 + b;  M_UIN = 2816

// ------- float arena -------
#define F_X    0UL
#define F_S    (F_X + 1064960UL)
#define F_QKV  (F_S + 1310720UL)
#define F_H2A  (F_QKV + 4325376UL)
#define F_H2B  (F_H2A + 1310720UL)
#define F_H2C  (F_H2B + 1310720UL)
#define F_YB   (F_H2C + 1310720UL)
#define F_BQKV (F_YB + 2097152UL)
#define F_TOT  (F_BQKV + 12288UL)
__device__ __align__(1024) float g_arena[F_TOT];

// ------- fp16 arena ----
#define EQ    262144UL
#define EQKV  786432UL     // 1536*512
#define EW1   1048576UL
#define EOUT  524288UL
#define EU    1441792UL    // 2816*512
#define EAT   1376256UL    // 2688*512
#define EHB   1310720UL    // 2560*512
#define EFB   5242880UL    // 2560*2048
#define EYT   1048576UL    // 2048*512

#define BW_QKV 0UL
#define BW_O   (BW_QKV + 8UL*2UL*EQKV)
#define BW_1   (BW_O   + 8UL*2UL*EQ)
#define BW_2   (BW_1   + 8UL*2UL*EW1)
#define BW_OUT (BW_2   + 8UL*2UL*EW1)
#define BA_U   (BW_OUT + 2UL*EOUT)
#define BA_AT  (BA_U   + 2UL*EU)
#define BA_HB  (BA_AT  + 2UL*EAT)
#define BA_FB  (BA_HB  + 2UL*EHB)
#define BA_YT  (BA_FB  + 2UL*EFB)
#define B_TOT  (BA_YT  + 2UL*EYT)
__device__ __align__(1024) BF g_bf[B_TOT];

__device__ __forceinline__ void split2(float x, BF& h, BF& l) {
    h = __float2half(x);
    l = __float2half(x - __half2float(h));
}
__device__ __forceinline__ BF2 mk2(BF a, BF b) { return __halves2half2(a, b); }

// ============ TMA / mbarrier primitives ============
__device__ __forceinline__ uint32_t smem_u32(const void* p) {
    return (uint32_t)__cvta_generic_to_shared(p);
}
__device__ __forceinline__ void mbar_init(uint32_t a, uint32_t cnt) {
    asm volatile("mbarrier.init.shared::cta.b64 [%0], %1;" :: "r"(a), "r"(cnt) : "memory");
}
__device__ __forceinline__ void mbar_expect(uint32_t a, uint32_t tx) {
    asm volatile("mbarrier.arrive.expect_tx.shared::cta.b64 _, [%0], %1;"
                 :: "r"(a), "r"(tx) : "memory");
}
__device__ __forceinline__ void mbar_arrive(uint32_t a) {
    asm volatile("mbarrier.arrive.shared::cta.b64 _, [%0];" :: "r"(a) : "memory");
}
__device__ __forceinline__ void mbar_wait(uint32_t a, uint32_t ph) {
    uint32_t done = 0;
    while (!done) {
        asm volatile(
            "{\n\t.reg .pred p;\n\t"
            "mbarrier.try_wait.parity.acquire.cta.shared::cta.b64 p, [%1], %2, 0x989680;\n\t"
            "selp.b32 %0, 1, 0, p;\n\t}"
            : "=r"(done) : "r"(a), "r"(ph) : "memory");
    }
}
__device__ __forceinline__ void tma3d(uint32_t dst, const void* map,
                                      int cx, int cy, int cz, uint32_t mbar) {
    asm volatile(
        "cp.async.bulk.tensor.3d.shared::cta.global.tile.mbarrier::complete_tx::bytes "
        "[%0], [%1, {%2, %3, %4}], [%5];"
        :: "r"(dst), "l"(map), "r"(cx), "r"(cy), "r"(cz), "r"(mbar) : "memory");
}
__device__ __forceinline__ void mma2(float c[4], const uint32_t a[4],
                                     uint32_t b0, uint32_t b1) {
    asm volatile(
        "mma.sync.aligned.m16n8k16.row.col.f32.f16.f16.f32 "
        "{%0,%1,%2,%3}, {%4,%5,%6,%7}, {%8,%9}, {%0,%1,%2,%3};\n"
        : "+f"(c[0]), "+f"(c[1]), "+f"(c[2]), "+f"(c[3])
        : "r"(a[0]), "r"(a[1]), "r"(a[2]), "r"(a[3]), "r"(b0), "r"(b1));
}
#define LDSM4(r, a) \
    asm volatile("ldmatrix.sync.aligned.m8n8.x4.shared.b16 {%0,%1,%2,%3}, [%4];" \
        : "=r"((r)[0]), "=r"((r)[1]), "=r"((r)[2]), "=r"((r)[3]) : "r"(a))

// ============ TMA-staged mma.sync GEMM (SW64, 32-K stages, fp16) ============
// C = act(A @ B^T + bias). A: hi (+lo if AP==2) fp16 planes; B: hi plane.
// grid (N/NT, M/MT, splitZ). TMA zero-fills OOB K.
// mode 0: fp32 Cf (+ z*czstride). mode 1: fp16 planes Ch (+Cl if non-null).
// mode 2: fused O epilogue: rows<2560 S+=v; rows 2560..2679 planes=tanh(v).
#define NST 3

template <int MT, int NT, int AP>
__global__ __launch_bounds__(256, 2) void gemm6(
    const __grid_constant__ CUtensorMap tmA,
    const __grid_constant__ CUtensorMap tmB,
    const float* __restrict__ bias, float* __restrict__ Cf, long czstride,
    BF* __restrict__ Ch, BF* __restrict__ Cl,
    int N, int K, int act, int mode)
{
    constexpr int MSPAN = MT / 4;
    constexpr int MTM   = MSPAN / 16;
    constexpr int NSPAN = NT / 2;
    constexpr int NNT   = NSPAN / 8;
    constexpr int APL   = MT * 64;
    constexpr int BPL   = NT * 64;
    constexpr int STB   = AP * APL + BPL;
    extern __shared__ __align__(16) char smx[];
    const uint32_t sb = smem_u32(smx);
    const uint32_t db = (sb + 1023) & ~1023u;
    const int tid = threadIdx.x, lane = tid & 31, wid = tid >> 5;
    const int wm = wid & 3, wn = wid >> 2;
    const int grp = lane >> 2, tig = lane & 3;
    const int row0 = blockIdx.y * MT, col0 = blockIdx.x * NT;
    const int kstart = blockIdx.z * K;
    if (Cf && mode == 0) Cf += (long)blockIdx.z * czstride;
    const float* bi = (bias && kstart == 0) ? bias : nullptr;
    const int T = K >> 5;

    const uint32_t barb = db + NST * STB;
    if (tid == 0) {
        for (int s = 0; s < NST; s++) {
            mbar_init(barb + s * 8, 1);
            mbar_init(barb + 64 + s * 8, 256);
        }
    }
    __syncthreads();

    if (tid == 0) {
        for (int s = 0; s < NST; s++) {
            uint32_t st = db + s * STB, fb = barb + s * 8;
            mbar_expect(fb, STB);
            tma3d(st, &tmA, kstart + s * 32, row0, 0, fb);
            if (AP == 2) tma3d(st + APL, &tmA, kstart + s * 32, row0, 1, fb);
            tma3d(st + AP * APL, &tmB, kstart + s * 32, col0, 0, fb);
        }
    }

    float acc[MTM][NNT][4] = {};
    const int lrow = (lane & 7) + (((lane >> 3) & 1) << 3);
    const int kofs = ((lane >> 4) & 1) * 8;
    const uint32_t msk = (uint32_t)((lrow >> 1) & 3) << 4;
    uint32_t arow_off[MTM], brow_off[NNT / 2];
#pragma unroll
    for (int mt = 0; mt < MTM; mt++)
        arow_off[mt] = (uint32_t)(wm * MSPAN + mt * 16 + lrow) * 64;
#pragma unroll
    for (int p = 0; p < NNT / 2; p++)
        brow_off[p] = (uint32_t)(wn * NSPAN + p * 16 + lrow) * 64;

    uint32_t pfm = 0, pem = 0;
    for (int i = 0; i < T; i++) {
        const int bslot = i % NST;
        const uint32_t fb = barb + bslot * 8, eb = barb + 64 + bslot * 8;
        mbar_wait(fb, (pfm >> bslot) & 1); pfm ^= (1u << bslot);
        const uint32_t sA = db + bslot * STB, sB = sA + AP * APL;
#pragma unroll
        for (int kk = 0; kk < 32; kk += 16) {
            const uint32_t csw = ((uint32_t)((kk + kofs) * 2)) ^ msk;
            uint32_t ah[MTM][4], al_[MTM][4], bh[NNT / 2][4];
#pragma unroll
            for (int mt = 0; mt < MTM; mt++) {
                uint32_t ad = sA + arow_off[mt] + csw;
                LDSM4(ah[mt], ad);
                if (AP == 2) LDSM4(al_[mt], ad + APL);
            }
#pragma unroll
            for (int p = 0; p < NNT / 2; p++) {
                LDSM4(bh[p], sB + brow_off[p] + csw);
            }
#pragma unroll
            for (int nt = 0; nt < NNT; nt++) {
                const int p = nt >> 1, s1 = nt & 1;
#pragma unroll
                for (int mt = 0; mt < MTM; mt++) {
                    mma2(acc[mt][nt], ah[mt], bh[p][s1], bh[p][2 + s1]);
                    if (AP == 2)
                        mma2(acc[mt][nt], al_[mt], bh[p][s1], bh[p][2 + s1]);
                }
            }
        }
        mbar_arrive(eb);
        if (tid == 0 && i + NST < T) {
            mbar_wait(eb, (pem >> bslot) & 1); pem ^= (1u << bslot);
            uint32_t st = db + bslot * STB;
            mbar_expect(fb, STB);
            int k0 = kstart + (i + NST) * 32;
            tma3d(st, &tmA, k0, row0, 0, fb);
            if (AP == 2) tma3d(st + APL, &tmA, k0, row0, 1, fb);
            tma3d(st + AP * APL, &tmB, k0, col0, 0, fb);
        }
    }

#pragma unroll
    for (int mt = 0; mt < MTM; mt++) {
        const long r = row0 + wm * MSPAN + mt * 16 + grp;
#pragma unroll
        for (int nt = 0; nt < NNT; nt++) {
            const long c = col0 + wn * NSPAN + nt * 8 + tig * 2;
            float bb0 = bi ? bi[c] : 0.f, bb1 = bi ? bi[c + 1] : 0.f;
            float v0 = acc[mt][nt][0] + bb0, v1 = acc[mt][nt][1] + bb1;
            float v2 = acc[mt][nt][2] + bb0, v3 = acc[mt][nt][3] + bb1;
            if (act) {
                v0 = fmaxf(v0, 0.f); v1 = fmaxf(v1, 0.f);
                v2 = fmaxf(v2, 0.f); v3 = fmaxf(v3, 0.f);
            }
            if (mode == 0) {
                *(float2*)&Cf[r * N + c]       = make_float2(v0, v1);
                *(float2*)&Cf[(r + 8) * N + c] = make_float2(v2, v3);
            } else if (mode == 1) {
                BF h0, l0, h1, l1;
                split2(v0, h0, l0); split2(v1, h1, l1);
                *(BF2*)&Ch[r * N + c] = mk2(h0, h1);
                if (Cl) *(BF2*)&Cl[r * N + c] = mk2(l0, l1);
                split2(v2, h0, l0); split2(v3, h1, l1);
                *(BF2*)&Ch[(r + 8) * N + c] = mk2(h0, h1);
                if (Cl) *(BF2*)&Cl[(r + 8) * N + c] = mk2(l0, l1);
            } else {
#pragma unroll
                for (int rr = 0; rr < 2; rr++) {
                    long r2 = r + rr * 8;
                    float u0 = rr ? v2 : v0, u1 = rr ? v3 : v1;
                    if (r2 < 2560) {
                        float2 s = *(float2*)&Cf[r2 * 512 + c];
                        *(float2*)&Cf[r2 * 512 + c] = make_float2(s.x + u0, s.y + u1);
                    } else if (r2 < 2680) {
                        float t0 = tanhf(u0), t1 = tanhf(u1);
                        long o = (r2 - 2560) * 512 + c;
                        *(BF2*)&Ch[o] = mk2(__float2half(t0), __float2half(t1));
                        if (Cl) {
                            BF l0 = __float2half(t0 - __half2float(__float2half(t0)));
                            BF l1 = __float2half(t1 - __half2float(__float2half(t1)));
                            *(BF2*)&Cl[o] = mk2(l0, l1);
                        }
                    }
                }
            }
        }
    }
}

// ---------------- legacy in-kernel-convert GEMM (input proj, K=80) ---------
#define LLDA 40
__global__ __launch_bounds__(256) void gemm_tc(
    const float* __restrict__ A, const float* __restrict__ W,
    const float* __restrict__ bias, float* __restrict__ C,
    int M, int N, int K, int act)
{
    __shared__ BF Ahs[128 * LLDA], Als[128 * LLDA];
    __shared__ BF Bhs[128 * LLDA];
    const int tid = threadIdx.x, lane = tid & 31, wid = tid >> 5;
    const int wm = wid & 3, wn = wid >> 2;
    const int grp = lane >> 2, tig = lane & 3;
    const long row0 = (long)blockIdx.y * 128;
    const int  col0 = blockIdx.x * 128;
    float acc[2][8][4] = {};
    const int arow = tid >> 1, acol0 = (tid & 1) * 16;
    const int brow = tid >> 3, bcol0 = (tid & 7) * 16;

    for (int k0 = 0; k0 < K; k0 += 32) {
#pragma unroll
        for (int j = 0; j < 4; j++) {
            int c = acol0 + j * 4;
            float4 v = make_float4(0.f, 0.f, 0.f, 0.f);
            if (row0 + arow < M && k0 + c < K)
                v = *(const float4*)&A[(row0 + arow) * (long)K + k0 + c];
            BF h, l; int o = arow * LLDA + c;
            split2(v.x, h, l); Ahs[o]     = h; Als[o]     = l;
            split2(v.y, h, l); Ahs[o + 1] = h; Als[o + 1] = l;
            split2(v.z, h, l); Ahs[o + 2] = h; Als[o + 2] = l;
            split2(v.w, h, l); Ahs[o + 3] = h; Als[o + 3] = l;
        }
#pragma unroll
        for (int j = 0; j < 4; j++) {
            int n = bcol0 + j * 4;
            float4 v = make_float4(0.f, 0.f, 0.f, 0.f);
            if (k0 + brow < K)
                v = *(const float4*)&W[(long)(k0 + brow) * N + col0 + n];
            Bhs[(n + 0) * LLDA + brow] = __float2half(v.x);
            Bhs[(n + 1) * LLDA + brow] = __float2half(v.y);
            Bhs[(n + 2) * LLDA + brow] = __float2half(v.z);
            Bhs[(n + 3) * LLDA + brow] = __float2half(v.w);
        }
        __syncthreads();
#pragma unroll
        for (int kk = 0; kk < 32; kk += 16) {
            uint32_t ah[2][4], al[2][4];
#pragma unroll
            for (int mt = 0; mt < 2; mt++) {
                int r = wm * 32 + mt * 16;
                int o  = (r + grp) * LLDA + kk + tig * 2;
                int o8 = o + 8 * LLDA;
                ah[mt][0] = *(const uint32_t*)&Ahs[o];
                ah[mt][1] = *(const uint32_t*)&Ahs[o8];
                ah[mt][2] = *(const uint32_t*)&Ahs[o + 8];
                ah[mt][3] = *(const uint32_t*)&Ahs[o8 + 8];
                al[mt][0] = *(const uint32_t*)&Als[o];
                al[mt][1] = *(const uint32_t*)&Als[o8];
                al[mt][2] = *(const uint32_t*)&Als[o + 8];
                al[mt][3] = *(const uint32_t*)&Als[o8 + 8];
            }
#pragma unroll
            for (int nt = 0; nt < 8; nt++) {
                int nn = wn * 64 + nt * 8 + grp;
                int o = nn * LLDA + kk + tig * 2;
                uint32_t b0 = *(const uint32_t*)&Bhs[o], b1 = *(const uint32_t*)&Bhs[o + 8];
#pragma unroll
                for (int mt = 0; mt < 2; mt++) {
                    mma2(acc[mt][nt], ah[mt], b0, b1);
                    mma2(acc[mt][nt], al[mt], b0, b1);
                }
            }
        }
        __syncthreads();
    }
#pragma unroll
    for (int mt = 0; mt < 2; mt++) {
#pragma unroll
        for (int nt = 0; nt < 8; nt++) {
            int c = col0 + wn * 64 + nt * 8 + tig * 2;
            float b0 = bias ? bias[c] : 0.f;
            float b1 = bias ? bias[c + 1] : 0.f;
            long r = row0 + wm * 32 + mt * 16 + grp;
            float v0 = acc[mt][nt][0] + b0, v1 = acc[mt][nt][1] + b1;
            float v2 = acc[mt][nt][2] + b0, v3 = acc[mt][nt][3] + b1;
            if (act) { v0=fmaxf(v0,0.f); v1=fmaxf(v1,0.f); v2=fmaxf(v2,0.f); v3=fmaxf(v3,0.f); }
            if (r < M)     *(float2*)&C[r * N + c]       = make_float2(v0, v1);
            if (r + 8 < M) *(float2*)&C[(r + 8) * N + c] = make_float2(v2, v3);
        }
    }
}

// ------- weight transpose+convert: out[n][k] = fp16(W[k][n]) ----
// 32k x 128n tile, 256 threads, 4 independent float4 loads/thread.
__global__ __launch_bounds__(256) void wconv_k(
    const float* __restrict__ W, BF* __restrict__ oh,
    int K, int N, long inS, long outS)
{
    __shared__ float t[32][129];
    const float* w = W + (long)blockIdx.z * inS;
    BF* ph = oh + (long)blockIdx.z * outS;
    const int n0 = blockIdx.x * 128, k0 = blockIdx.y * 32;
    const int r = threadIdx.x >> 5;       // 0..7
    const int c = threadIdx.x & 31;       // col group
#pragma unroll
    for (int i = 0; i < 4; i++) {
        int row = r + i * 8;
        float4 v = *(const float4*)&w[(long)(k0 + row) * N + n0 + c * 4];
        t[row][c * 4 + 0] = v.x; t[row][c * 4 + 1] = v.y;
        t[row][c * 4 + 2] = v.z; t[row][c * 4 + 3] = v.w;
    }
    __syncthreads();
    const int n = threadIdx.x >> 1, kc = (threadIdx.x & 1) * 16;
    __align__(16) BF h[16];
#pragma unroll
    for (int j = 0; j < 16; j++) h[j] = __float2half(t[kc + j][n]);
    long o = (long)(n0 + n) * K + k0 + kc;
    *(uint4*)&ph[o]     = *(uint4*)&h[0];
    *(uint4*)&ph[o + 8] = *(uint4*)&h[8];
}

// merged bias pack + UIN pad (hi plane only)
__global__ void prep_k(const float* __restrict__ bq, const float* __restrict__ bk,
                       const float* __restrict__ bv, float* __restrict__ o,
                       BF* __restrict__ uh)
{
    int i = blockIdx.x * blockDim.x + threadIdx.x;
    if (i < 12288) {
        int l = i / 1536, j = i % 1536;
        float v;
        if (j < 512)       v = bq[l * 512 + j];
        else if (j < 1024) v = bk[l * 512 + j - 512];
        else               v = bv[l * 512 + j - 1024];
        o[i] = v;
    }
    if (i < 4096) {
        size_t p = 2808UL * 512UL + i;
        uh[p] = __float2half(0.f);
    }
}

// ---------------- LayerNorm: warp per row (ol optional) ----------------
__global__ __launch_bounds__(256) void ln_row_k(
    const float* __restrict__ X, const float* __restrict__ g, const float* __restrict__ bta,
    float* __restrict__ outf, BF* __restrict__ oh, BF* __restrict__ ol, int D)
{
    const int wid = threadIdx.x >> 5, lane = threadIdx.x & 31;
    const int row = blockIdx.x * 8 + wid;
    const float4* x = (const float4*)(X + (long)row * D);
    const int cnt = D >> 7;
    float s = 0.f, s2 = 0.f;
    for (int i = 0; i < cnt; i++) {
        float4 a = x[lane + i * 32];
        s  += a.x + a.y + a.z + a.w;
        s2 += a.x * a.x + a.y * a.y + a.z * a.z + a.w * a.w;
    }
#pragma unroll
    for (int o = 16; o; o >>= 1) {
        s  += __shfl_xor_sync(~0u, s, o);
        s2 += __shfl_xor_sync(~0u, s2, o);
    }
    const float mean = s / D;
    const float inv = rsqrtf(s2 / D - mean * mean + 1e-5f);
    const float4* gg = (const float4*)g;
    const float4* bb = (const float4*)bta;
    for (int i = 0; i < cnt; i++) {
        int idx = lane + i * 32;
        float4 a = x[idx], gv = gg[idx], bv = bb[idx], o;
        o.x = (a.x - mean) * inv * gv.x + bv.x;
        o.y = (a.y - mean) * inv * gv.y + bv.y;
        o.z = (a.z - mean) * inv * gv.z + bv.z;
        o.w = (a.w - mean) * inv * gv.w + bv.w;
        if (outf) ((float4*)(outf + (long)row * D))[idx] = o;
        if (oh) {
            BF h0,l0,h1,l1,h2,l2,h3,l3;
            split2(o.x,h0,l0); split2(o.y,h1,l1);
            split2(o.z,h2,l2); split2(o.w,h3,l3);
            long base = (long)row * D + idx * 4;
            *(BF2*)&oh[base]     = mk2(h0,h1);
            *(BF2*)&oh[base + 2] = mk2(h2,h3);
            if (ol) {
                *(BF2*)&ol[base]     = mk2(l0,l1);
                *(BF2*)&ol[base + 2] = mk2(l2,l3);
            }
        }
    }
}

// -------- double LN: res=S+HA+HB+HC; S=LN1(res); planes=LN2(S) ------------
__global__ __launch_bounds__(256) void ln2_k(
    const float* __restrict__ S, const float* __restrict__ HA,
    const float* __restrict__ HB_, const float* __restrict__ HC,
    const float* __restrict__ g1, const float* __restrict__ be1,
    const float* __restrict__ g2, const float* __restrict__ be2,
    float* __restrict__ Sout, BF* __restrict__ oh)
{
    const int wid = threadIdx.x >> 5, lane = threadIdx.x & 31;
    const int row = blockIdx.x * 8 + wid;   // 0..2559
    const float4* xs = (const float4*)(S   + (long)row * 512);
    const float4* xa = (const float4*)(HA  + (long)row * 512);
    const float4* xb = (const float4*)(HB_ + (long)row * 512);
    const float4* xc = (const float4*)(HC  + (long)row * 512);
    float4 R[4];
    float s = 0.f, s2 = 0.f;
#pragma unroll
    for (int i = 0; i < 4; i++) {
        int idx = lane + i * 32;
        float4 a = xs[idx], c = xa[idx], d = xb[idx], e = xc[idx];
        a.x += c.x + d.x + e.x; a.y += c.y + d.y + e.y;
        a.z += c.z + d.z + e.z; a.w += c.w + d.w + e.w;
        R[i] = a;
        s  += a.x + a.y + a.z + a.w;
        s2 += a.x * a.x + a.y * a.y + a.z * a.z + a.w * a.w;
    }
#pragma unroll
    for (int o = 16; o; o >>= 1) {
        s  += __shfl_xor_sync(~0u, s, o);
        s2 += __shfl_xor_sync(~0u, s2, o);
    }
    float mean = s * (1.f / 512.f);
    float inv = rsqrtf(s2 * (1.f / 512.f) - mean * mean + 1e-5f);
    const float4* g1v = (const float4*)g1; const float4* b1v = (const float4*)be1;
    float t = 0.f, t2 = 0.f;
#pragma unroll
    for (int i = 0; i < 4; i++) {
        int idx = lane + i * 32;
        float4 gv = g1v[idx], bv = b1v[idx], y;
        y.x = (R[i].x - mean) * inv * gv.x + bv.x;
        y.y = (R[i].y - mean) * inv * gv.y + bv.y;
        y.z = (R[i].z - mean) * inv * gv.z + bv.z;
        y.w = (R[i].w - mean) * inv * gv.w + bv.w;
        R[i] = y;
        ((float4*)(Sout + (long)row * 512))[idx] = y;
        t  += y.x + y.y + y.z + y.w;
        t2 += y.x * y.x + y.y * y.y + y.z * y.z + y.w * y.w;
    }
    if (!g2) return;
#pragma unroll
    for (int o = 16; o; o >>= 1) {
        t  += __shfl_xor_sync(~0u, t, o);
        t2 += __shfl_xor_sync(~0u, t2, o);
    }
    float mean2 = t * (1.f / 512.f);
    float inv2 = rsqrtf(t2 * (1.f / 512.f) - mean2 * mean2 + 1e-5f);
    const float4* g2v = (const float4*)g2; const float4* b2v = (const float4*)be2;
#pragma unroll
    for (int i = 0; i < 4; i++) {
        int idx = lane + i * 32;
        float4 gv = g2v[idx], bv = b2v[idx], z;
        z.x = (R[i].x - mean2) * inv2 * gv.x + bv.x;
        z.y = (R[i].y - mean2) * inv2 * gv.y + bv.y;
        z.z = (R[i].z - mean2) * inv2 * gv.z + bv.z;
        z.w = (R[i].w - mean2) * inv2 * gv.w + bv.w;
        long base = (long)row * 512 + idx * 4;
        *(BF2*)&oh[base]     = mk2(__float2half(z.x), __float2half(z.y));
        *(BF2*)&oh[base + 2] = mk2(__float2half(z.z), __float2half(z.w));
    }
}

// ---------------- misc ----------------
__global__ void initS_k(const float* __restrict__ X, float* __restrict__ S)
{
    const int t = blockIdx.x, b = blockIdx.y, d = threadIdx.x;
    int frame;
    if (t < RTn) {
        int si = t >> 2;
        int st = (si == 15) ? 256 : (si + 1) * 16;
        frame = st + (t & 3);
    } else frame = t - RTn;
    S[((size_t)t * Bn + b) * Dm_ + d] = X[(size_t)b * 133120 + (size_t)frame * Dm_ + d];
}

__global__ void mems0_k(const float* __restrict__ S, BF* __restrict__ uh)
{
    const int s = blockIdx.x, b = blockIdx.y, d = threadIdx.x;
    size_t base = ((size_t)(RTn + s * 16) * Bn + b) * Dm_ + d;
    float acc = 0.f;
#pragma unroll
    for (int k = 0; k < 16; k++) acc += S[base + (size_t)k * Bn * Dm_];
    acc *= (1.f / 16.f);
    size_t o = ((size_t)s * Bn + b) * Dm_ + d;
    uh[o] = __float2half(acc);
}

__global__ void summary_pl_k(BF* __restrict__ uh)
{
    const int s = blockIdx.x, b = blockIdx.y, d = threadIdx.x;
    size_t base = ((size_t)((79 + s * 16) * Bn) + b) * Dm_ + d;
    float acc = 0.f;
#pragma unroll
    for (int k = 0; k < 16; k++)
        acc += __half2float(uh[base + (size_t)k * Bn * Dm_]);
    acc *= (1.f / 16.f);
    size_t o = ((size_t)((335 + s) * Bn) + b) * Dm_ + d;
    uh[o] = __float2half(acc);
}

// ---------------- attention: 4 queries per CTA (hi plane out only) ---------
__global__ __launch_bounds__(256) void attn_k(
    const float* __restrict__ QKV, const int* __restrict__ lengths,
    BF* __restrict__ Ah)
{
    __shared__ float sc[Hn][64];
    __shared__ short ki[Hn][64];
    const int b = blockIdx.y;
    const int h = threadIdx.x >> 5, lane = threadIdx.x & 31;

    int maxlr = 0;
#pragma unroll
    for (int i = 0; i < Bn; i++) maxlr = max(maxlr, lengths[i] >> 2);
    const int lrb = lengths[b] >> 2;
    const int g = lane >> 3, e = lane & 7;
    const float* Kb = QKV + (size_t)b * 1536 + 512 + h * DHn;
    const float* Vb = Kb + 512;

    for (int qq = 0; qq < 4; qq++) {
        const int qi = blockIdx.x * 4 + qq;
        int seg; bool summ = false;
        if (qi < RTn)      seg = qi >> 2;
        else if (qi < SN)  seg = (qi - RTn) >> 4;
        else             { seg = qi - SN; summ = true; }
        const int ms  = max(seg - 4, 0);
        const int ss  = max(seg * 16 - 32, 0);
        const int se  = min(seg * 16 + 16, Un);
        const int ue  = min(se, lrb + 256 - maxlr);
        const int rcs = 15 + seg * 4;

        const int c0 = summ ? 0 : (seg - ms);
        const int c2 = max(ue - ss, 0);
        const int n  = c0 + 4 + c2;

        for (int j = lane; j < n; j += 32) {
            int k;
            if (j < c0)          k = ms + j;
            else if (j < c0 + 4) k = rcs + (j - c0);
            else                 k = 79 + ss + (j - c0 - 4);
            ki[h][j] = (short)k;
        }
        __syncwarp();

        const float4* qv = (const float4*)(QKV + ((size_t)(15 + qi) * Bn + b) * 1536 + h * DHn);
        float4 q0 = qv[e * 2], q1 = qv[e * 2 + 1];
        q0.x *= 0.125f; q0.y *= 0.125f; q0.z *= 0.125f; q0.w *= 0.125f;
        q1.x *= 0.125f; q1.y *= 0.125f; q1.z *= 0.125f; q1.w *= 0.125f;

        for (int j0 = 0; j0 < n; j0 += 4) {
            int j = j0 + g;
            float p = 0.f;
            if (j < n) {
                const float4* kp = (const float4*)(Kb + (size_t)ki[h][j] * (Bn * 1536));
                float4 k0 = kp[e * 2], k1 = kp[e * 2 + 1];
                p = q0.x * k0.x + q0.y * k0.y + q0.z * k0.z + q0.w * k0.w
                  + q1.x * k1.x + q1.y * k1.y + q1.z * k1.z + q1.w * k1.w;
            }
            p += __shfl_xor_sync(~0u, p, 4);
            p += __shfl_xor_sync(~0u, p, 2);
            p += __shfl_xor_sync(~0u, p, 1);
            if (e == 0 && j < n) sc[h][j] = p;
        }
        __syncwarp();

        float m = -3.4e38f;
        for (int j = lane; j < n; j += 32) m = fmaxf(m, sc[h][j]);
#pragma unroll
        for (int o = 16; o; o >>= 1) m = fmaxf(m, __shfl_xor_sync(~0u, m, o));
        float sum = 0.f;
        for (int j = lane; j < n; j += 32) {
            float e2 = expf(sc[h][j] - m);
            sc[h][j] = e2;
            sum += e2;
        }
#pragma unroll
        for (int o = 16; o; o >>= 1) sum += __shfl_xor_sync(~0u, sum, o);
        __syncwarp();
        const float inv = 1.f / sum;

        float a0 = 0.f, a1 = 0.f;
        for (int j = 0; j < n; j++) {
            float p = sc[h][j];
            const float2 vp = *(const float2*)(Vb + (size_t)ki[h][j] * (Bn * 1536) + 2 * lane);
            a0 = fmaf(p, vp.x, a0);
            a1 = fmaf(p, vp.y, a1);
        }
        a0 *= inv; a1 *= inv;
        size_t op = ((size_t)qi * Bn + b) * Dm_ + h * DHn + 2 * lane;
        *(BF2*)&Ah[op] = mk2(__float2half(a0), __float2half(a1));
        __syncwarp();
    }
}

// transpose + hi/lo split for out-proj (2-pass A)
__global__ void transpose_pl_k(const float* __restrict__ S, BF* __restrict__ yh,
                               BF* __restrict__ yl)
{
    const int r = blockIdx.x, d = threadIdx.x;
    const int b = r >> 8, u = r & 255;
    float v = S[((size_t)(RTn + u) * Bn + b) * Dm_ + d];
    BF h, l; split2(v, h, l);
    yh[(size_t)r * Dm_ + d] = h;
    yl[(size_t)r * Dm_ + d] = l;
}

__global__ void lr_k(const int* __restrict__ lengths, float* __restrict__ out)
{
    int i = threadIdx.x;
    if (i < Bn) out[i] = (float)(lengths[i] >> 2);
}

// ---------------- host: tensormap plumbing ----------------
typedef CUresult (*EncFn)(CUtensorMap*, CUtensorMapDataType, cuuint32_t, void*,
                          const cuuint64_t*, const cuuint64_t*, const cuuint32_t*,
                          const cuuint32_t*, CUtensorMapInterleave, CUtensorMapSwizzle,
                          CUtensorMapL2promotion, CUtensorMapFloatOOBfill);

static EncFn get_enc() {
    void* p = nullptr;
    cudaDriverEntryPointQueryResult qr;
#if CUDART_VERSION >= 12050
    if (cudaGetDriverEntryPointByVersion("cuTensorMapEncodeTiled", &p, 12000,
                                         cudaEnableDefault, &qr) == cudaSuccess && p)
        return (EncFn)p;
    p = nullptr;
#endif
    cudaGetDriverEntryPoint("cuTensorMapEncodeTiled", &p, cudaEnableDefault, &qr);
    return (EncFn)p;
}

static CUtensorMap mkmap(EncFn enc, const BF* base, long K, long M, long planeStride,
                         unsigned boxM) {
    CUtensorMap m;
    cuuint64_t dims[3]    = {(cuuint64_t)K, (cuuint64_t)M, 2};
    cuuint64_t strides[2] = {(cuuint64_t)K * 2, (cuuint64_t)planeStride * 2};
    cuuint32_t box[3]     = {32, boxM, 1};
    cuuint32_t es[3]      = {1, 1, 1};
    enc(&m, CU_TENSOR_MAP_DATA_TYPE_FLOAT16, 3, (void*)base, dims, strides, box, es,
        CU_TENSOR_MAP_INTERLEAVE_NONE, CU_TENSOR_MAP_SWIZZLE_64B,
        CU_TENSOR_MAP_L2_PROMOTION_L2_128B, CU_TENSOR_MAP_FLOAT_OOB_FILL_NONE);
    return m;
}

// ---------------- launch ----------------
extern "C" void kernel_launch(void* const* d_in, const int* in_sizes, int n_in,
                              void* d_out, int out_size)
{
    const float* input   = (const float*)d_in[0];
    const int*   lengths = (const int*)  d_in[1];
    const float* w_in    = (const float*)d_in[2];
    const float* ln_in_g = (const float*)d_in[3];
    const float* ln_in_b = (const float*)d_in[4];
    const float* wq = (const float*)d_in[5];
    const float* bq = (const float*)d_in[6];
    const float* wk = (const float*)d_in[7];
    const float* bk = (const float*)d_in[8];
    const float* wv = (const float*)d_in[9];
    const float* bv = (const float*)d_in[10];
    const float* wo = (const float*)d_in[11];
    const float* bo = (const float*)d_in[12];
    const float* ff_g = (const float*)d_in[13];
    const float* ff_b = (const float*)d_in[14];
    const float* w1 = (const float*)d_in[15];
    const float* b1 = (const float*)d_in[16];
    const float* w2 = (const float*)d_in[17];
    const float* b2 = (const float*)d_in[18];
    const float* lo_g = (const float*)d_in[19];
    const float* lo_b = (const float*)d_in[20];
    const float* w_out = (const float*)d_in[21];
    const float* b_out = (const float*)d_in[22];
    const float* lng = (const float*)d_in[23];
    const float* lnb = (const float*)d_in[24];
    float* out = (float*)d_out;

    float* fa = nullptr; BF* bf = nullptr;
    cudaGetSymbolAddress((void**)&fa, g_arena);
    cudaGetSymbolAddress((void**)&bf, g_bf);

    const int SM_128_128_1 = 1024 + NST * (8192 + 8192) + 128;      // 50304
    const int SM_64_128_1  = 1024 + NST * (4096 + 8192) + 128;      // 38016
    const int SM_128_64_1  = 1024 + NST * (8192 + 4096) + 128;      // 38016
    const int SM_64_128_2  = 1024 + NST * (2 * 4096 + 8192) + 128;  // 50304
    cudaFuncSetAttribute(gemm6<128,128,1>, cudaFuncAttributeMaxDynamicSharedMemorySize, SM_128_128_1);
    cudaFuncSetAttribute(gemm6<64,128,1>,  cudaFuncAttributeMaxDynamicSharedMemorySize, SM_64_128_1);
    cudaFuncSetAttribute(gemm6<128,64,1>,  cudaFuncAttributeMaxDynamicSharedMemorySize, SM_128_64_1);
    cudaFuncSetAttribute(gemm6<64,128,2>,  cudaFuncAttributeMaxDynamicSharedMemorySize, SM_64_128_2);

    float* X    = fa + F_X;
    float* S    = fa + F_S;
    float* QKVf = fa + F_QKV;
    float* H2A  = fa + F_H2A;
    float* Yb   = fa + F_YB;
    float* BQKV = fa + F_BQKV;

    BF* UINh = bf + BA_U;
    BF* ATTh = bf + BA_AT;
    BF* HBh  = bf + BA_HB;
    BF* FBh  = bf + BA_FB;
    BF* YTh  = bf + BA_YT;  BF* YTl = YTh + EYT;

    EncFn enc = get_enc();
    CUtensorMap mUIN = mkmap(enc, UINh, 512, 2816, EU, 128);
    CUtensorMap mATT = mkmap(enc, ATTh, 512, 2688, EAT, 64);
    CUtensorMap mHB  = mkmap(enc, HBh,  512, 2560, EHB, 128);
    CUtensorMap mFB  = mkmap(enc, FBh, 2048, 2560, EFB, 128);
    CUtensorMap mYT  = mkmap(enc, YTh,  512, 2048, EYT, 64);
    CUtensorMap mOUT = mkmap(enc, bf + BW_OUT, 512, 1024, EOUT, 128);
    CUtensorMap mWQKV[Ln], mWO[Ln], mW1[Ln], mW2[Ln];
    for (int l = 0; l < Ln; l++) {
        mWQKV[l] = mkmap(enc, bf + BW_QKV + (size_t)l * 2 * EQKV, 512, 1536, EQKV, 128);
        mWO[l]   = mkmap(enc, bf + BW_O   + (size_t)l * 2 * EQ,   512,  512, EQ, 128);
        mW1[l]   = mkmap(enc, bf + BW_1   + (size_t)l * 2 * EW1,  512, 2048, EW1, 64);
        mW2[l]   = mkmap(enc, bf + BW_2   + (size_t)l * 2 * EW1, 2048,  512, EW1, 128);
    }

    // ---- per-replay preprocessing ----
    gemm_tc<<<dim3(1, 65), 256>>>(input, w_in, nullptr, X, 8320, 128, 80, 0);
    initS_k<<<dim3(SN, Bn), Dm_>>>(X, S);
    mems0_k<<<dim3(15, Bn), Dm_>>>(S, UINh);

    wconv_k<<<dim3(4, 16, 8), 256>>>(wq, bf + BW_QKV, 512, 512, EQ, 2 * EQKV);
    wconv_k<<<dim3(4, 16, 8), 256>>>(wk, bf + BW_QKV + 262144, 512, 512, EQ, 2 * EQKV);
    wconv_k<<<dim3(4, 16, 8), 256>>>(wv, bf + BW_QKV + 524288, 512, 512, EQ, 2 * EQKV);
    wconv_k<<<dim3(4, 16, 8), 256>>>(wo, bf + BW_O, 512, 512, EQ, 2 * EQ);
    wconv_k<<<dim3(16, 16, 8), 256>>>(w1, bf + BW_1, 512, 2048, EW1, 2 * EW1);
    wconv_k<<<dim3(4, 64, 8), 256>>>(w2, bf + BW_2, 2048, 512, EW1, 2 * EW1);
    wconv_k<<<dim3(8, 16, 1), 256>>>(w_out, bf + BW_OUT, 512, 1024, 0, 0);
    prep_k<<<48, 256>>>(bq, bk, bv, BQKV, UINh);

    // layer-0 LN1: S -> UIN state planes (rows 120..2679), hi only
    ln_row_k<<<SN * Bn / 8, 256>>>(S, ln_in_g, ln_in_b, nullptr,
                                   UINh + 120 * 512, nullptr, Dm_);

    for (int l = 0; l < Ln; l++) {
        summary_pl_k<<<dim3(NSEG, Bn), Dm_>>>(UINh);

        // QKV single-pass A
        gemm6<128,128,1><<<dim3(12, 22, 1), 256, SM_128_128_1>>>(
            mUIN, mWQKV[l], BQKV + l * 1536, QKVf, 0, nullptr, nullptr,
            1536, 512, 0, 0);

        attn_k<<<dim3(QN / 4, Bn), 256>>>(QKVf, lengths, ATTh);

        // O-proj single-pass; fused epilogue: S += out, UIN mems = tanh (hi only)
        gemm6<64,128,1><<<dim3(4, 42, 1), 256, SM_64_128_1>>>(
            mATT, mWO[l], bo + l * Dm_, S, 0, UINh, nullptr, 512, 512, 0, 2);

        ln_row_k<<<SN * Bn / 8, 256>>>(S, ff_g + l * Dm_, ff_b + l * Dm_,
                                       nullptr, HBh, nullptr, Dm_);
        // FFN1 single-pass, hi plane out
        gemm6<128,64,1><<<dim3(32, 20, 1), 256, SM_128_64_1>>>(
            mHB, mW1[l], b1 + l * FFNn, nullptr, 0, FBh, nullptr,
            2048, 512, 1, 1);
        // FFN2 single-pass, split-K=3 (704 per chunk; TMA zero-fills K>=2048)
        gemm6<128,128,1><<<dim3(4, 20, 3), 256, SM_128_128_1>>>(
            mFB, mW2[l], b2 + l * Dm_, H2A, 1310720, nullptr, nullptr,
            512, 704, 0, 0);

        const float* g2 = (l + 1 < Ln) ? (ln_in_g + (l + 1) * Dm_) : nullptr;
        const float* b2n = (l + 1 < Ln) ? (ln_in_b + (l + 1) * Dm_) : nullptr;
        ln2_k<<<SN * Bn / 8, 256>>>(S, H2A, H2A + 1310720, H2A + 2621440,
                                    lo_g + l * Dm_, lo_b + l * Dm_, g2, b2n,
                                    S, UINh + 120 * 512);
    }

    transpose_pl_k<<<2048, Dm_>>>(S, YTh, YTl);
    // out-proj 2-pass A (restored accuracy)
    gemm6<64,128,2><<<dim3(8, 32, 1), 256, SM_64_128_2>>>(
        mYT, mOUT, b_out, Yb, 0, nullptr, nullptr, 1024, 512, 0, 0);
    ln_row_k<<<2048 / 8, 256>>>(Yb, lng, lnb, out, nullptr, nullptr, OUTn);

    if (out_size >= 2048 * 1024 + Bn)
        lr_k<<<1, 32>>>(lengths, out + 2048 * 1024);
}